// round 4
// baseline (speedup 1.0000x reference)
#include <cuda_runtime.h>
#include <math.h>
#include <stdint.h>

// ---- problem constants ----
#define BSX 4096   // B*S
#define BB  2
#define SEQ 2048
#define EMB 768
#define TT  128
#define NH  12
#define DHD 64
#define FF  3072
#define KNN 16
#define CATW (EMB + TT)   // 896

// ---- scratch (device globals) ----
__device__ float g_hn[BSX * EMB];
__device__ float g_x[BSX * EMB];
__device__ float g_topo[BSX * TT];
__device__ float g_comb[BSX * TT];
__device__ float g_tmp256[BSX * 256];
__device__ float g_t[BSX * TT];
__device__ float g_q[BSX * EMB];
__device__ float g_k[BSX * EMB];
__device__ float g_v[BSX * EMB];
__device__ float g_ctx[BSX * EMB];
__device__ float g_cat[BSX * CATW];
__device__ float g_h1[BSX * EMB];
__device__ float g_y[BSX * EMB];
__device__ float g_ff[(long long)BSX * FF];
__device__ float g_knw[BSX * KNN];
__device__ int   g_kni[BSX * KNN];
__device__ float g_scores[(long long)BB * NH * SEQ * SEQ];

__device__ __forceinline__ void mma_tf32(float* c, const uint32_t* a, uint32_t b0, uint32_t b1) {
    asm volatile(
        "mma.sync.aligned.m16n8k8.row.col.f32.tf32.tf32.f32 "
        "{%0,%1,%2,%3},{%4,%5,%6,%7},{%8,%9},{%0,%1,%2,%3};"
        : "+f"(c[0]), "+f"(c[1]), "+f"(c[2]), "+f"(c[3])
        : "r"(a[0]), "r"(a[1]), "r"(a[2]), "r"(a[3]), "r"(b0), "r"(b1));
}

__device__ __forceinline__ void cpa16(void* s, const void* g) {
    unsigned sa = (unsigned)__cvta_generic_to_shared(s);
    asm volatile("cp.async.cg.shared.global [%0], [%1], 16;" :: "r"(sa), "l"(g));
}
__device__ __forceinline__ void cpa_commit() { asm volatile("cp.async.commit_group;"); }
__device__ __forceinline__ void cpa_wait2()  { asm volatile("cp.async.wait_group 2;"); }

// ============================================================================
// tf32 tensor-core GEMM, cp.async 3-stage pipeline. Block tile 128 x TN,
// 256 threads, 8 warps (warp tile 32 x TN/2). Raw fp32 bits used as tf32
// (hardware truncation). ACT: 0 none, 1 relu, 2 gelu, 3 sigmoid-mix
// (C = s*res + (1-s)*res2, s = sigmoid(acc+bias)); ACT!=3 & res: C += res.
// Requirements: M%128==0, N%TN==0, K%16==0, TN in {64,128}.
// ============================================================================
template<int TRANSB, int ACT, int TN>
__global__ void __launch_bounds__(256) tgemm(
    const float* __restrict__ A, const float* __restrict__ B,
    float* __restrict__ C, const float* __restrict__ bias,
    const float* __restrict__ res, const float* __restrict__ res2,
    int K, int lda, int ldb, int ldc, int ldr1, int ldr2,
    int zdiv, long long sA1, long long sA2,
    long long sB1, long long sB2, long long sC1, long long sC2)
{
    constexpr int NT    = TN / 16;
    constexpr int BITER = TN / 64;          // B chunks per thread per stage
    constexpr int BCOLS = TRANSB ? 20 : (TN + 8);

    extern __shared__ uint32_t sm[];
    uint32_t* As = sm;                      // [3][128][20]
    uint32_t* Bs = sm + 3 * 128 * 20;       // [3][BROWS][BCOLS]

    int z = blockIdx.z;
    long long zm = z % zdiv, zd = z / zdiv;
    A += zm * sA1 + zd * sA2;
    B += zm * sB1 + zd * sB2;
    long long co = zm * sC1 + zd * sC2;
    C += co;

    const int t    = threadIdx.x;
    const int lane = t & 31;
    const int wid  = t >> 5;
    const int lr   = lane >> 2;
    const int lc   = lane & 3;
    const int wm   = (wid & 3) * 32;
    const int wn   = (wid >> 2) * (TN / 2);
    const int bm   = blockIdx.y * 128;
    const int bn   = blockIdx.x * TN;

    float acc[2][NT][4];
    #pragma unroll
    for (int mt = 0; mt < 2; mt++)
        #pragma unroll
        for (int nt = 0; nt < NT; nt++)
            #pragma unroll
            for (int i = 0; i < 4; i++) acc[mt][nt][i] = 0.f;

    auto issue = [&](int buf, int k0) {
        #pragma unroll
        for (int i = 0; i < 2; i++) {
            int c = t + i * 256;
            int row = c >> 2, kq = (c & 3) << 2;
            cpa16(&As[((buf << 7) + row) * 20 + kq],
                  A + (long long)(bm + row) * lda + k0 + kq);
        }
        if (TRANSB) {
            #pragma unroll
            for (int i = 0; i < BITER; i++) {
                int c = t + i * 256;
                int row = c >> 2, kq = (c & 3) << 2;
                cpa16(&Bs[(buf * TN + row) * 20 + kq],
                      B + (long long)(bn + row) * ldb + k0 + kq);
            }
        } else {
            #pragma unroll
            for (int i = 0; i < BITER; i++) {
                int c = t + i * 256;
                int krow = c / (TN / 4), n4 = (c % (TN / 4)) << 2;
                cpa16(&Bs[(buf * 16 + krow) * BCOLS + n4],
                      B + (long long)(k0 + krow) * ldb + bn + n4);
            }
        }
        cpa_commit();
    };

    const int iters = K >> 4;
    issue(0, 0);
    issue(1, 16);

    for (int kb = 0; kb < iters; kb++) {
        int nst  = kb + 2;
        int nbuf = nst - (nst / 3) * 3;
        int nk0  = (nst < iters ? nst : iters - 1) << 4;
        issue(nbuf, nk0);
        cpa_wait2();
        __syncthreads();
        int cur = kb - (kb / 3) * 3;

        #pragma unroll
        for (int ks = 0; ks < 16; ks += 8) {
            uint32_t af[2][4];
            #pragma unroll
            for (int mt = 0; mt < 2; mt++) {
                int m = (cur << 7) + wm + mt * 16 + lr;
                af[mt][0] = As[m * 20 + ks + lc];
                af[mt][1] = As[(m + 8) * 20 + ks + lc];
                af[mt][2] = As[m * 20 + ks + lc + 4];
                af[mt][3] = As[(m + 8) * 20 + ks + lc + 4];
            }
            #pragma unroll
            for (int nt = 0; nt < NT; nt++) {
                int n = wn + nt * 8 + lr;
                uint32_t b0, b1;
                if (TRANSB) {
                    b0 = Bs[(cur * TN + n) * 20 + ks + lc];
                    b1 = Bs[(cur * TN + n) * 20 + ks + lc + 4];
                } else {
                    b0 = Bs[(cur * 16 + ks + lc) * BCOLS + n];
                    b1 = Bs[(cur * 16 + ks + lc + 4) * BCOLS + n];
                }
                #pragma unroll
                for (int mt = 0; mt < 2; mt++)
                    mma_tf32(acc[mt][nt], af[mt], b0, b1);
            }
        }
        __syncthreads();
    }

    // epilogue
    #pragma unroll
    for (int mt = 0; mt < 2; mt++) {
        #pragma unroll
        for (int nt = 0; nt < NT; nt++) {
            int mrow = bm + wm + mt * 16 + lr;
            int ncol = bn + wn + nt * 8 + 2 * lc;
            #pragma unroll
            for (int half = 0; half < 2; half++) {
                int m = mrow + half * 8;
                float v0 = acc[mt][nt][half * 2 + 0];
                float v1 = acc[mt][nt][half * 2 + 1];
                if (bias) { v0 += bias[ncol]; v1 += bias[ncol + 1]; }
                if (ACT == 1) { v0 = fmaxf(v0, 0.f); v1 = fmaxf(v1, 0.f); }
                if (ACT == 2) {
                    float u = v0;
                    v0 = 0.5f * u * (1.f + tanhf(0.7978845608028654f * (u + 0.044715f * u * u * u)));
                    u = v1;
                    v1 = 0.5f * u * (1.f + tanhf(0.7978845608028654f * (u + 0.044715f * u * u * u)));
                }
                long long off = (long long)m * ldc + ncol;
                if (ACT == 3) {
                    float s0 = 1.f / (1.f + expf(-v0));
                    float s1 = 1.f / (1.f + expf(-v1));
                    long long o1 = (long long)m * ldr1 + ncol;
                    long long o2 = (long long)m * ldr2 + ncol;
                    float2 r1 = *(const float2*)(res + o1);
                    float2 r2 = *(const float2*)(res2 + o2);
                    v0 = s0 * r1.x + (1.f - s0) * r2.x;
                    v1 = s1 * r1.y + (1.f - s1) * r2.y;
                } else if (res) {
                    float2 r1 = *(const float2*)(res + (long long)m * ldr1 + ncol);
                    v0 += r1.x; v1 += r1.y;
                }
                float2 o2v = {v0, v1};
                *(float2*)(C + off) = o2v;
            }
        }
    }
}

// ---- fused: hn = h/(||h||+1e-8) ; x = LN1(h) ----
__global__ void l2ln_k(const float* __restrict__ h,
                       const float* __restrict__ gma, const float* __restrict__ bta)
{
    int row = blockIdx.x, t = threadIdx.x;
    const float* xr = h + (long long)row * EMB;
    __shared__ float sh[EMB];
    __shared__ float r1[256], r2[256];
    float s = 0.f, ss = 0.f;
    for (int i = t; i < EMB; i += 256) { float v = xr[i]; sh[i] = v; s += v; ss += v * v; }
    r1[t] = s; r2[t] = ss; __syncthreads();
    for (int st = 128; st > 0; st >>= 1) {
        if (t < st) { r1[t] += r1[t + st]; r2[t] += r2[t + st]; }
        __syncthreads();
    }
    float mu   = r1[0] / EMB;
    float var  = r2[0] / EMB - mu * mu;
    float ri   = rsqrtf(var + 1e-6f);
    float invn = 1.f / (sqrtf(r2[0]) + 1e-8f);
    for (int i = t; i < EMB; i += 256) {
        float v = sh[i];
        g_hn[(long long)row * EMB + i] = v * invn;
        g_x [(long long)row * EMB + i] = (v - mu) * ri * gma[i] + bta[i];
    }
}

// ---- layernorm (two-pass; eps 1e-6) ----
__global__ void ln_k(const float* __restrict__ x, float* __restrict__ o,
                     const float* __restrict__ gma, const float* __restrict__ bta, int D)
{
    int row = blockIdx.x, t = threadIdx.x;
    const float* xr = x + (long long)row * D;
    __shared__ float red[256];
    __shared__ float s_mu, s_ri;
    float s = 0.f;
    for (int i = t; i < D; i += 256) s += xr[i];
    red[t] = s; __syncthreads();
    for (int st = 128; st > 0; st >>= 1) { if (t < st) red[t] += red[t + st]; __syncthreads(); }
    if (t == 0) s_mu = red[0] / D;
    __syncthreads();
    float mu = s_mu;
    float v = 0.f;
    for (int i = t; i < D; i += 256) { float d = xr[i] - mu; v += d * d; }
    __syncthreads();
    red[t] = v; __syncthreads();
    for (int st = 128; st > 0; st >>= 1) { if (t < st) red[t] += red[t + st]; __syncthreads(); }
    if (t == 0) s_ri = rsqrtf(red[0] / D + 1e-6f);
    __syncthreads();
    float ri = s_ri;
    for (int i = t; i < D; i += 256)
        o[(long long)row * D + i] = (xr[i] - mu) * ri * gma[i] + bta[i];
}

// ---- k-NN: 16 iterated argmins over shared-memory distance row ----
__global__ void knn_k()
{
    int row = blockIdx.x;
    int b = row / SEQ, i = row % SEQ;
    const float* dr = g_scores + (long long)row * SEQ;
    __shared__ float sd[SEQ];
    __shared__ float rv[256];
    __shared__ int   ri[256];
    __shared__ float knd[KNN];
    __shared__ int   sel[KNN];
    int t = threadIdx.x;
    for (int j = t; j < SEQ; j += 256)
        sd[j] = (j == i) ? 1e9f : (1.f - dr[j]);
    __syncthreads();
    for (int it = 0; it < KNN; it++) {
        float bv = 1e30f; int bi = 0x7fffffff;
        for (int j = t; j < SEQ; j += 256) {
            float d = sd[j];
            if (d < bv || (d == bv && j < bi)) { bv = d; bi = j; }
        }
        rv[t] = bv; ri[t] = bi; __syncthreads();
        for (int st = 128; st > 0; st >>= 1) {
            if (t < st) {
                float ov = rv[t + st]; int oi = ri[t + st];
                if (ov < rv[t] || (ov == rv[t] && oi < ri[t])) { rv[t] = ov; ri[t] = oi; }
            }
            __syncthreads();
        }
        if (t == 0) { knd[it] = rv[0]; sel[it] = ri[0]; sd[ri[0]] = 1e9f; }
        __syncthreads();
    }
    if (t == 0) {
        float w[KNN], sum = 0.f;
        for (int k2 = 0; k2 < KNN; k2++) { w[k2] = expf(knd[0] - knd[k2]); sum += w[k2]; }
        float inv = 1.f / sum;
        for (int k2 = 0; k2 < KNN; k2++) {
            g_knw[row * KNN + k2] = w[k2] * inv;
            g_kni[row * KNN + k2] = b * SEQ + sel[k2];
        }
    }
}

// ---- combined = topo + sum_k w_k * topo[nbr_k] ----
__global__ void combine_k()
{
    int row = blockIdx.x, t = threadIdx.x; // 128 threads
    float acc = g_topo[(long long)row * TT + t];
    #pragma unroll
    for (int k2 = 0; k2 < KNN; k2++)
        acc += g_knw[row * KNN + k2] * g_topo[(long long)g_kni[row * KNN + k2] * TT + t];
    g_comb[(long long)row * TT + t] = acc;
}

// ---- attention softmax: row in registers, 1R + 1W ----
__global__ void attn_softmax_k(const int* __restrict__ mask)
{
    int q = blockIdx.x, z = blockIdx.y, b = z / NH;
    float* row = g_scores + (long long)z * SEQ * SEQ + (long long)q * SEQ;
    const int* mrow = mask + b * SEQ;
    int t = threadIdx.x;
    __shared__ float red[256];
    float vals[8];
    float mx = -1e30f;
    #pragma unroll
    for (int i = 0; i < 8; i++) {
        int k2 = t + i * 256;
        float v = row[k2] * 0.125f;
        if (mrow[k2] == 0) v = -10000.f;
        vals[i] = v; mx = fmaxf(mx, v);
    }
    red[t] = mx; __syncthreads();
    for (int st = 128; st > 0; st >>= 1) { if (t < st) red[t] = fmaxf(red[t], red[t + st]); __syncthreads(); }
    mx = red[0];
    __syncthreads();
    float sum = 0.f;
    #pragma unroll
    for (int i = 0; i < 8; i++) { vals[i] = expf(vals[i] - mx); sum += vals[i]; }
    red[t] = sum; __syncthreads();
    for (int st = 128; st > 0; st >>= 1) { if (t < st) red[t] += red[t + st]; __syncthreads(); }
    float inv = 1.f / red[0];
    #pragma unroll
    for (int i = 0; i < 8; i++) row[t + i * 256] = vals[i] * inv;
}

// ============================================================================
template<int TRANSB, int TN>
static int smem_bytes() {
    int a = 3 * 128 * 20 * 4;
    int b = TRANSB ? 3 * TN * 20 * 4 : 3 * 16 * (TN + 8) * 4;
    return a + b;
}

extern "C" void kernel_launch(void* const* d_in, const int* in_sizes, int n_in,
                              void* d_out, int out_size)
{
    const float* h      = (const float*)d_in[0];
    const int*   mask   = (const int*)  d_in[1];
    const float* W_topo = (const float*)d_in[2];
    const float* b_topo = (const float*)d_in[3];
    const float* W_m1   = (const float*)d_in[4];
    const float* b_m1   = (const float*)d_in[5];
    const float* W_m2   = (const float*)d_in[6];
    const float* b_m2   = (const float*)d_in[7];
    const float* ln_t_s = (const float*)d_in[8];
    const float* ln_t_b = (const float*)d_in[9];
    const float* W_p1   = (const float*)d_in[10];
    const float* b_p1   = (const float*)d_in[11];
    const float* W_p2   = (const float*)d_in[12];
    const float* b_p2   = (const float*)d_in[13];
    const float* ln1_s  = (const float*)d_in[14];
    const float* ln1_b  = (const float*)d_in[15];
    const float* Wq     = (const float*)d_in[16];
    const float* Wk     = (const float*)d_in[17];
    const float* Wv     = (const float*)d_in[18];
    const float* W_gate = (const float*)d_in[19];
    const float* b_gate = (const float*)d_in[20];
    const float* W_o    = (const float*)d_in[21];
    const float* b_o    = (const float*)d_in[22];
    const float* ln2_s  = (const float*)d_in[23];
    const float* ln2_b  = (const float*)d_in[24];
    const float* W_f1   = (const float*)d_in[25];
    const float* b_f1   = (const float*)d_in[26];
    const float* W_f2   = (const float*)d_in[27];
    const float* b_f2   = (const float*)d_in[28];
    float* out = (float*)d_out;

    float *hn, *x, *topo, *comb, *tmp256, *tt, *q, *k, *v, *ctx, *cat, *h1, *y, *ff, *scores;
    cudaGetSymbolAddress((void**)&hn,     g_hn);
    cudaGetSymbolAddress((void**)&x,      g_x);
    cudaGetSymbolAddress((void**)&topo,   g_topo);
    cudaGetSymbolAddress((void**)&comb,   g_comb);
    cudaGetSymbolAddress((void**)&tmp256, g_tmp256);
    cudaGetSymbolAddress((void**)&tt,     g_t);
    cudaGetSymbolAddress((void**)&q,      g_q);
    cudaGetSymbolAddress((void**)&k,      g_k);
    cudaGetSymbolAddress((void**)&v,      g_v);
    cudaGetSymbolAddress((void**)&ctx,    g_ctx);
    cudaGetSymbolAddress((void**)&cat,    g_cat);
    cudaGetSymbolAddress((void**)&h1,     g_h1);
    cudaGetSymbolAddress((void**)&y,      g_y);
    cudaGetSymbolAddress((void**)&ff,     g_ff);
    cudaGetSymbolAddress((void**)&scores, g_scores);

    const long long SE  = (long long)SEQ * EMB;
    const long long SS  = (long long)SEQ * SEQ;
    const long long HSS = (long long)NH * SS;

    const int sm_nn128 = smem_bytes<0, 128>();
    const int sm_tb128 = smem_bytes<1, 128>();
    const int sm_nn64  = smem_bytes<0, 64>();
    cudaFuncSetAttribute((const void*)tgemm<0, 0, 128>, cudaFuncAttributeMaxDynamicSharedMemorySize, sm_nn128);
    cudaFuncSetAttribute((const void*)tgemm<0, 1, 128>, cudaFuncAttributeMaxDynamicSharedMemorySize, sm_nn128);
    cudaFuncSetAttribute((const void*)tgemm<0, 2, 128>, cudaFuncAttributeMaxDynamicSharedMemorySize, sm_nn128);
    cudaFuncSetAttribute((const void*)tgemm<0, 3, 128>, cudaFuncAttributeMaxDynamicSharedMemorySize, sm_nn128);
    cudaFuncSetAttribute((const void*)tgemm<1, 0, 128>, cudaFuncAttributeMaxDynamicSharedMemorySize, sm_tb128);
    cudaFuncSetAttribute((const void*)tgemm<0, 0, 64>,  cudaFuncAttributeMaxDynamicSharedMemorySize, sm_nn64);

    // 1. hn = normalize(h); x = LN1(h)   (fused)
    l2ln_k<<<BSX, 256>>>(h, ln1_s, ln1_b);

    // 2. topo = h @ W_topo + b_topo
    tgemm<0, 0, 128><<<dim3(1, 32, 1), 256, sm_nn128>>>(h, W_topo, topo, b_topo, nullptr, nullptr,
        EMB, EMB, TT, TT, 0, 0, 1, 0, 0, 0, 0, 0, 0);

    // 3. dot[b] = hn[b] @ hn[b]^T
    tgemm<1, 0, 128><<<dim3(16, 16, 2), 256, sm_tb128>>>(hn, hn, scores, nullptr, nullptr, nullptr,
        EMB, EMB, EMB, SEQ, 0, 0, 2, SE, 0, SE, 0, SS, 0);

    // 4. per-row top-16 NN + weights; combine
    knn_k<<<BSX, 256>>>();
    combine_k<<<BSX, TT>>>();

    // 5. topo MLP + LN_t
    tgemm<0, 1, 128><<<dim3(2, 32, 1), 256, sm_nn128>>>(comb, W_m1, tmp256, b_m1, nullptr, nullptr,
        TT, TT, 256, 256, 0, 0, 1, 0, 0, 0, 0, 0, 0);
    tgemm<0, 0, 128><<<dim3(1, 32, 1), 256, sm_nn128>>>(tmp256, W_m2, tt, b_m2, nullptr, nullptr,
        256, 256, TT, TT, 0, 0, 1, 0, 0, 0, 0, 0, 0);
    ln_k<<<BSX, 256>>>(tt, tt, ln_t_s, ln_t_b, TT);

    // 6. pf = relu(t@W_p1+b_p1)@W_p2+b_p2  -> written into cat[:, EMB:]
    tgemm<0, 1, 128><<<dim3(1, 32, 1), 256, sm_nn128>>>(tt, W_p1, tmp256, b_p1, nullptr, nullptr,
        TT, TT, TT, TT, 0, 0, 1, 0, 0, 0, 0, 0, 0);
    tgemm<0, 0, 128><<<dim3(1, 32, 1), 256, sm_nn128>>>(tmp256, W_p2, cat + EMB, b_p2, nullptr, nullptr,
        TT, TT, TT, CATW, 0, 0, 1, 0, 0, 0, 0, 0, 0);

    // 7. q/k/v
    tgemm<0, 0, 128><<<dim3(6, 32, 1), 256, sm_nn128>>>(x, Wq, q, nullptr, nullptr, nullptr,
        EMB, EMB, EMB, EMB, 0, 0, 1, 0, 0, 0, 0, 0, 0);
    tgemm<0, 0, 128><<<dim3(6, 32, 1), 256, sm_nn128>>>(x, Wk, k, nullptr, nullptr, nullptr,
        EMB, EMB, EMB, EMB, 0, 0, 1, 0, 0, 0, 0, 0, 0);
    tgemm<0, 0, 128><<<dim3(6, 32, 1), 256, sm_nn128>>>(x, Wv, v, nullptr, nullptr, nullptr,
        EMB, EMB, EMB, EMB, 0, 0, 1, 0, 0, 0, 0, 0, 0);

    // 8. scores[b,h] = q @ k^T
    tgemm<1, 0, 128><<<dim3(16, 16, BB * NH), 256, sm_tb128>>>(q, k, scores, nullptr, nullptr, nullptr,
        DHD, EMB, EMB, SEQ, 0, 0, NH, DHD, SE, DHD, SE, SS, HSS);

    // 9. softmax
    attn_softmax_k<<<dim3(SEQ, BB * NH), 256>>>(mask);

    // 10. ctx = probs @ v  -> written into cat[:, :EMB] per head
    tgemm<0, 0, 64><<<dim3(1, 16, BB * NH), 256, sm_nn64>>>(scores, v, cat, nullptr, nullptr, nullptr,
        SEQ, SEQ, EMB, CATW, 0, 0, NH, SS, HSS, DHD, SE, DHD, (long long)SEQ * CATW);

    // 11. gate-mix: ctx = sigmoid(cat@W_gate+b_gate)*ctx_cat + (1-s)*x
    tgemm<0, 3, 128><<<dim3(6, 32, 1), 256, sm_nn128>>>(cat, W_gate, ctx, b_gate, cat, x,
        CATW, CATW, EMB, EMB, CATW, EMB, 1, 0, 0, 0, 0, 0, 0);

    // 12. h1 = h + ctx @ W_o + b_o
    tgemm<0, 0, 128><<<dim3(6, 32, 1), 256, sm_nn128>>>(ctx, W_o, h1, b_o, h, nullptr,
        EMB, EMB, EMB, EMB, EMB, 0, 1, 0, 0, 0, 0, 0, 0);

    // 13. FFN
    ln_k<<<BSX, 256>>>(h1, y, ln2_s, ln2_b, EMB);
    tgemm<0, 2, 128><<<dim3(24, 32, 1), 256, sm_nn128>>>(y, W_f1, ff, b_f1, nullptr, nullptr,
        EMB, EMB, FF, FF, 0, 0, 1, 0, 0, 0, 0, 0, 0);
    tgemm<0, 0, 128><<<dim3(6, 32, 1), 256, sm_nn128>>>(ff, W_f2, out, b_f2, h1, nullptr,
        FF, FF, EMB, EMB, EMB, 0, 1, 0, 0, 0, 0, 0, 0);
}

// round 5
// speedup vs baseline: 1.0009x; 1.0009x over previous
#include <cuda_runtime.h>
#include <math.h>
#include <stdint.h>

// ---- problem constants ----
#define BSX 4096   // B*S
#define BB  2
#define SEQ 2048
#define EMB 768
#define TT  128
#define NH  12
#define DHD 64
#define FF  3072
#define KNN 16
#define CATW (EMB + TT)   // 896

// ---- scratch (device globals) ----
__device__ float g_hn[BSX * EMB];
__device__ float g_x[BSX * EMB];
__device__ float g_topo[BSX * TT];
__device__ float g_comb[BSX * TT];
__device__ float g_tmp256[BSX * 256];
__device__ float g_t[BSX * TT];
__device__ float g_q[BSX * EMB];
__device__ float g_k[BSX * EMB];
__device__ float g_v[BSX * EMB];
__device__ float g_ctx[BSX * EMB];
__device__ float g_cat[BSX * CATW];
__device__ float g_h1[BSX * EMB];
__device__ float g_y[BSX * EMB];
__device__ float g_ff[(long long)BSX * FF];
__device__ float g_knw[BSX * KNN];
__device__ int   g_kni[BSX * KNN];
__device__ float g_scores[(long long)BB * NH * SEQ * SEQ];

__device__ __forceinline__ void mma_tf32(float* c, const uint32_t* a, uint32_t b0, uint32_t b1) {
    asm volatile(
        "mma.sync.aligned.m16n8k8.row.col.f32.tf32.tf32.f32 "
        "{%0,%1,%2,%3},{%4,%5,%6,%7},{%8,%9},{%0,%1,%2,%3};"
        : "+f"(c[0]), "+f"(c[1]), "+f"(c[2]), "+f"(c[3])
        : "r"(a[0]), "r"(a[1]), "r"(a[2]), "r"(a[3]), "r"(b0), "r"(b1));
}

__device__ __forceinline__ void cpa16(void* s, const void* g) {
    unsigned sa = (unsigned)__cvta_generic_to_shared(s);
    asm volatile("cp.async.cg.shared.global [%0], [%1], 16;" :: "r"(sa), "l"(g));
}
__device__ __forceinline__ void cpa_commit() { asm volatile("cp.async.commit_group;"); }
__device__ __forceinline__ void cpa_wait2()  { asm volatile("cp.async.wait_group 2;"); }

// ============================================================================
// tf32 tensor-core GEMM, cp.async 3-stage pipeline. Block tile 128 x TN,
// 256 threads, 8 warps (warp tile 32 x TN/2). Raw fp32 bits used as tf32
// (hardware truncation). ACT: 0 none, 1 relu, 2 gelu, 3 sigmoid-mix
// (C = s*res + (1-s)*res2, s = sigmoid(acc+bias)); ACT!=3 & res: C += res.
// Requirements: M%128==0, N%TN==0, K%16==0, TN in {64,128}.
// ============================================================================
template<int TRANSB, int ACT, int TN>
__global__ void __launch_bounds__(256) tgemm(
    const float* __restrict__ A, const float* __restrict__ B,
    float* __restrict__ C, const float* __restrict__ bias,
    const float* __restrict__ res, const float* __restrict__ res2,
    int K, int lda, int ldb, int ldc, int ldr1, int ldr2,
    int zdiv, long long sA1, long long sA2,
    long long sB1, long long sB2, long long sC1, long long sC2)
{
    constexpr int NT    = TN / 16;
    constexpr int BITER = TN / 64;          // B chunks per thread per stage
    constexpr int BCOLS = TRANSB ? 20 : (TN + 8);

    extern __shared__ uint32_t sm[];
    uint32_t* As = sm;                      // [3][128][20]
    uint32_t* Bs = sm + 3 * 128 * 20;       // [3][BROWS][BCOLS]

    int z = blockIdx.z;
    long long zm = z % zdiv, zd = z / zdiv;
    A += zm * sA1 + zd * sA2;
    B += zm * sB1 + zd * sB2;
    long long co = zm * sC1 + zd * sC2;
    C += co;

    const int t    = threadIdx.x;
    const int lane = t & 31;
    const int wid  = t >> 5;
    const int lr   = lane >> 2;
    const int lc   = lane & 3;
    const int wm   = (wid & 3) * 32;
    const int wn   = (wid >> 2) * (TN / 2);
    const int bm   = blockIdx.y * 128;
    const int bn   = blockIdx.x * TN;

    float acc[2][NT][4];
    #pragma unroll
    for (int mt = 0; mt < 2; mt++)
        #pragma unroll
        for (int nt = 0; nt < NT; nt++)
            #pragma unroll
            for (int i = 0; i < 4; i++) acc[mt][nt][i] = 0.f;

    auto issue = [&](int buf, int k0) {
        #pragma unroll
        for (int i = 0; i < 2; i++) {
            int c = t + i * 256;
            int row = c >> 2, kq = (c & 3) << 2;
            cpa16(&As[((buf << 7) + row) * 20 + kq],
                  A + (long long)(bm + row) * lda + k0 + kq);
        }
        if (TRANSB) {
            #pragma unroll
            for (int i = 0; i < BITER; i++) {
                int c = t + i * 256;
                int row = c >> 2, kq = (c & 3) << 2;
                cpa16(&Bs[(buf * TN + row) * 20 + kq],
                      B + (long long)(bn + row) * ldb + k0 + kq);
            }
        } else {
            #pragma unroll
            for (int i = 0; i < BITER; i++) {
                int c = t + i * 256;
                int krow = c / (TN / 4), n4 = (c % (TN / 4)) << 2;
                cpa16(&Bs[(buf * 16 + krow) * BCOLS + n4],
                      B + (long long)(k0 + krow) * ldb + bn + n4);
            }
        }
        cpa_commit();
    };

    const int iters = K >> 4;
    issue(0, 0);
    issue(1, 16);

    for (int kb = 0; kb < iters; kb++) {
        int nst  = kb + 2;
        int nbuf = nst - (nst / 3) * 3;
        int nk0  = (nst < iters ? nst : iters - 1) << 4;
        issue(nbuf, nk0);
        cpa_wait2();
        __syncthreads();
        int cur = kb - (kb / 3) * 3;

        #pragma unroll
        for (int ks = 0; ks < 16; ks += 8) {
            uint32_t af[2][4];
            #pragma unroll
            for (int mt = 0; mt < 2; mt++) {
                int m = (cur << 7) + wm + mt * 16 + lr;
                af[mt][0] = As[m * 20 + ks + lc];
                af[mt][1] = As[(m + 8) * 20 + ks + lc];
                af[mt][2] = As[m * 20 + ks + lc + 4];
                af[mt][3] = As[(m + 8) * 20 + ks + lc + 4];
            }
            #pragma unroll
            for (int nt = 0; nt < NT; nt++) {
                int n = wn + nt * 8 + lr;
                uint32_t b0, b1;
                if (TRANSB) {
                    b0 = Bs[(cur * TN + n) * 20 + ks + lc];
                    b1 = Bs[(cur * TN + n) * 20 + ks + lc + 4];
                } else {
                    b0 = Bs[(cur * 16 + ks + lc) * BCOLS + n];
                    b1 = Bs[(cur * 16 + ks + lc + 4) * BCOLS + n];
                }
                #pragma unroll
                for (int mt = 0; mt < 2; mt++)
                    mma_tf32(acc[mt][nt], af[mt], b0, b1);
            }
        }
        __syncthreads();
    }

    // epilogue
    #pragma unroll
    for (int mt = 0; mt < 2; mt++) {
        #pragma unroll
        for (int nt = 0; nt < NT; nt++) {
            int mrow = bm + wm + mt * 16 + lr;
            int ncol = bn + wn + nt * 8 + 2 * lc;
            #pragma unroll
            for (int half = 0; half < 2; half++) {
                int m = mrow + half * 8;
                float v0 = acc[mt][nt][half * 2 + 0];
                float v1 = acc[mt][nt][half * 2 + 1];
                if (bias) { v0 += bias[ncol]; v1 += bias[ncol + 1]; }
                if (ACT == 1) { v0 = fmaxf(v0, 0.f); v1 = fmaxf(v1, 0.f); }
                if (ACT == 2) {
                    float u = v0;
                    v0 = 0.5f * u * (1.f + tanhf(0.7978845608028654f * (u + 0.044715f * u * u * u)));
                    u = v1;
                    v1 = 0.5f * u * (1.f + tanhf(0.7978845608028654f * (u + 0.044715f * u * u * u)));
                }
                long long off = (long long)m * ldc + ncol;
                if (ACT == 3) {
                    float s0 = 1.f / (1.f + expf(-v0));
                    float s1 = 1.f / (1.f + expf(-v1));
                    long long o1 = (long long)m * ldr1 + ncol;
                    long long o2 = (long long)m * ldr2 + ncol;
                    float2 r1 = *(const float2*)(res + o1);
                    float2 r2 = *(const float2*)(res2 + o2);
                    v0 = s0 * r1.x + (1.f - s0) * r2.x;
                    v1 = s1 * r1.y + (1.f - s1) * r2.y;
                } else if (res) {
                    float2 r1 = *(const float2*)(res + (long long)m * ldr1 + ncol);
                    v0 += r1.x; v1 += r1.y;
                }
                float2 o2v = {v0, v1};
                *(float2*)(C + off) = o2v;
            }
        }
    }
}

// ---- fused: hn = h/(||h||+1e-8) ; x = LN1(h) ----
__global__ void l2ln_k(const float* __restrict__ h,
                       const float* __restrict__ gma, const float* __restrict__ bta)
{
    int row = blockIdx.x, t = threadIdx.x;
    const float* xr = h + (long long)row * EMB;
    __shared__ float sh[EMB];
    __shared__ float r1[256], r2[256];
    float s = 0.f, ss = 0.f;
    for (int i = t; i < EMB; i += 256) { float v = xr[i]; sh[i] = v; s += v; ss += v * v; }
    r1[t] = s; r2[t] = ss; __syncthreads();
    for (int st = 128; st > 0; st >>= 1) {
        if (t < st) { r1[t] += r1[t + st]; r2[t] += r2[t + st]; }
        __syncthreads();
    }
    float mu   = r1[0] / EMB;
    float var  = r2[0] / EMB - mu * mu;
    float ri   = rsqrtf(var + 1e-6f);
    float invn = 1.f / (sqrtf(r2[0]) + 1e-8f);
    for (int i = t; i < EMB; i += 256) {
        float v = sh[i];
        g_hn[(long long)row * EMB + i] = v * invn;
        g_x [(long long)row * EMB + i] = (v - mu) * ri * gma[i] + bta[i];
    }
}

// ---- layernorm (two-pass; eps 1e-6) ----
__global__ void ln_k(const float* __restrict__ x, float* __restrict__ o,
                     const float* __restrict__ gma, const float* __restrict__ bta, int D)
{
    int row = blockIdx.x, t = threadIdx.x;
    const float* xr = x + (long long)row * D;
    __shared__ float red[256];
    __shared__ float s_mu, s_ri;
    float s = 0.f;
    for (int i = t; i < D; i += 256) s += xr[i];
    red[t] = s; __syncthreads();
    for (int st = 128; st > 0; st >>= 1) { if (t < st) red[t] += red[t + st]; __syncthreads(); }
    if (t == 0) s_mu = red[0] / D;
    __syncthreads();
    float mu = s_mu;
    float v = 0.f;
    for (int i = t; i < D; i += 256) { float d = xr[i] - mu; v += d * d; }
    __syncthreads();
    red[t] = v; __syncthreads();
    for (int st = 128; st > 0; st >>= 1) { if (t < st) red[t] += red[t + st]; __syncthreads(); }
    if (t == 0) s_ri = rsqrtf(red[0] / D + 1e-6f);
    __syncthreads();
    float ri = s_ri;
    for (int i = t; i < D; i += 256)
        o[(long long)row * D + i] = (xr[i] - mu) * ri * gma[i] + bta[i];
}

// ---- k-NN: 16 iterated argmins over shared-memory distance row ----
__global__ void knn_k()
{
    int row = blockIdx.x;
    int b = row / SEQ, i = row % SEQ;
    const float* dr = g_scores + (long long)row * SEQ;
    __shared__ float sd[SEQ];
    __shared__ float rv[256];
    __shared__ int   ri[256];
    __shared__ float knd[KNN];
    __shared__ int   sel[KNN];
    int t = threadIdx.x;
    for (int j = t; j < SEQ; j += 256)
        sd[j] = (j == i) ? 1e9f : (1.f - dr[j]);
    __syncthreads();
    for (int it = 0; it < KNN; it++) {
        float bv = 1e30f; int bi = 0x7fffffff;
        for (int j = t; j < SEQ; j += 256) {
            float d = sd[j];
            if (d < bv || (d == bv && j < bi)) { bv = d; bi = j; }
        }
        rv[t] = bv; ri[t] = bi; __syncthreads();
        for (int st = 128; st > 0; st >>= 1) {
            if (t < st) {
                float ov = rv[t + st]; int oi = ri[t + st];
                if (ov < rv[t] || (ov == rv[t] && oi < ri[t])) { rv[t] = ov; ri[t] = oi; }
            }
            __syncthreads();
        }
        if (t == 0) { knd[it] = rv[0]; sel[it] = ri[0]; sd[ri[0]] = 1e9f; }
        __syncthreads();
    }
    if (t == 0) {
        float w[KNN], sum = 0.f;
        for (int k2 = 0; k2 < KNN; k2++) { w[k2] = expf(knd[0] - knd[k2]); sum += w[k2]; }
        float inv = 1.f / sum;
        for (int k2 = 0; k2 < KNN; k2++) {
            g_knw[row * KNN + k2] = w[k2] * inv;
            g_kni[row * KNN + k2] = b * SEQ + sel[k2];
        }
    }
}

// ---- combined = topo + sum_k w_k * topo[nbr_k] ----
__global__ void combine_k()
{
    int row = blockIdx.x, t = threadIdx.x; // 128 threads
    float acc = g_topo[(long long)row * TT + t];
    #pragma unroll
    for (int k2 = 0; k2 < KNN; k2++)
        acc += g_knw[row * KNN + k2] * g_topo[(long long)g_kni[row * KNN + k2] * TT + t];
    g_comb[(long long)row * TT + t] = acc;
}

// ---- attention softmax: row in registers, 1R + 1W ----
__global__ void attn_softmax_k(const int* __restrict__ mask)
{
    int q = blockIdx.x, z = blockIdx.y, b = z / NH;
    float* row = g_scores + (long long)z * SEQ * SEQ + (long long)q * SEQ;
    const int* mrow = mask + b * SEQ;
    int t = threadIdx.x;
    __shared__ float red[256];
    float vals[8];
    float mx = -1e30f;
    #pragma unroll
    for (int i = 0; i < 8; i++) {
        int k2 = t + i * 256;
        float v = row[k2] * 0.125f;
        if (mrow[k2] == 0) v = -10000.f;
        vals[i] = v; mx = fmaxf(mx, v);
    }
    red[t] = mx; __syncthreads();
    for (int st = 128; st > 0; st >>= 1) { if (t < st) red[t] = fmaxf(red[t], red[t + st]); __syncthreads(); }
    mx = red[0];
    __syncthreads();
    float sum = 0.f;
    #pragma unroll
    for (int i = 0; i < 8; i++) { vals[i] = expf(vals[i] - mx); sum += vals[i]; }
    red[t] = sum; __syncthreads();
    for (int st = 128; st > 0; st >>= 1) { if (t < st) red[t] += red[t + st]; __syncthreads(); }
    float inv = 1.f / red[0];
    #pragma unroll
    for (int i = 0; i < 8; i++) row[t + i * 256] = vals[i] * inv;
}

// ============================================================================
template<int TRANSB, int TN>
static int smem_bytes() {
    int a = 3 * 128 * 20 * 4;
    int b = TRANSB ? 3 * TN * 20 * 4 : 3 * 16 * (TN + 8) * 4;
    return a + b;
}

extern "C" void kernel_launch(void* const* d_in, const int* in_sizes, int n_in,
                              void* d_out, int out_size)
{
    const float* h      = (const float*)d_in[0];
    const int*   mask   = (const int*)  d_in[1];
    const float* W_topo = (const float*)d_in[2];
    const float* b_topo = (const float*)d_in[3];
    const float* W_m1   = (const float*)d_in[4];
    const float* b_m1   = (const float*)d_in[5];
    const float* W_m2   = (const float*)d_in[6];
    const float* b_m2   = (const float*)d_in[7];
    const float* ln_t_s = (const float*)d_in[8];
    const float* ln_t_b = (const float*)d_in[9];
    const float* W_p1   = (const float*)d_in[10];
    const float* b_p1   = (const float*)d_in[11];
    const float* W_p2   = (const float*)d_in[12];
    const float* b_p2   = (const float*)d_in[13];
    const float* ln1_s  = (const float*)d_in[14];
    const float* ln1_b  = (const float*)d_in[15];
    const float* Wq     = (const float*)d_in[16];
    const float* Wk     = (const float*)d_in[17];
    const float* Wv     = (const float*)d_in[18];
    const float* W_gate = (const float*)d_in[19];
    const float* b_gate = (const float*)d_in[20];
    const float* W_o    = (const float*)d_in[21];
    const float* b_o    = (const float*)d_in[22];
    const float* ln2_s  = (const float*)d_in[23];
    const float* ln2_b  = (const float*)d_in[24];
    const float* W_f1   = (const float*)d_in[25];
    const float* b_f1   = (const float*)d_in[26];
    const float* W_f2   = (const float*)d_in[27];
    const float* b_f2   = (const float*)d_in[28];
    float* out = (float*)d_out;

    float *hn, *x, *topo, *comb, *tmp256, *tt, *q, *k, *v, *ctx, *cat, *h1, *y, *ff, *scores;
    cudaGetSymbolAddress((void**)&hn,     g_hn);
    cudaGetSymbolAddress((void**)&x,      g_x);
    cudaGetSymbolAddress((void**)&topo,   g_topo);
    cudaGetSymbolAddress((void**)&comb,   g_comb);
    cudaGetSymbolAddress((void**)&tmp256, g_tmp256);
    cudaGetSymbolAddress((void**)&tt,     g_t);
    cudaGetSymbolAddress((void**)&q,      g_q);
    cudaGetSymbolAddress((void**)&k,      g_k);
    cudaGetSymbolAddress((void**)&v,      g_v);
    cudaGetSymbolAddress((void**)&ctx,    g_ctx);
    cudaGetSymbolAddress((void**)&cat,    g_cat);
    cudaGetSymbolAddress((void**)&h1,     g_h1);
    cudaGetSymbolAddress((void**)&y,      g_y);
    cudaGetSymbolAddress((void**)&ff,     g_ff);
    cudaGetSymbolAddress((void**)&scores, g_scores);

    const long long SE  = (long long)SEQ * EMB;
    const long long SS  = (long long)SEQ * SEQ;
    const long long HSS = (long long)NH * SS;

    const int sm_nn128 = smem_bytes<0, 128>();
    const int sm_tb128 = smem_bytes<1, 128>();
    const int sm_nn64  = smem_bytes<0, 64>();
    cudaFuncSetAttribute((const void*)tgemm<0, 0, 128>, cudaFuncAttributeMaxDynamicSharedMemorySize, sm_nn128);
    cudaFuncSetAttribute((const void*)tgemm<0, 1, 128>, cudaFuncAttributeMaxDynamicSharedMemorySize, sm_nn128);
    cudaFuncSetAttribute((const void*)tgemm<0, 2, 128>, cudaFuncAttributeMaxDynamicSharedMemorySize, sm_nn128);
    cudaFuncSetAttribute((const void*)tgemm<0, 3, 128>, cudaFuncAttributeMaxDynamicSharedMemorySize, sm_nn128);
    cudaFuncSetAttribute((const void*)tgemm<1, 0, 128>, cudaFuncAttributeMaxDynamicSharedMemorySize, sm_tb128);
    cudaFuncSetAttribute((const void*)tgemm<0, 0, 64>,  cudaFuncAttributeMaxDynamicSharedMemorySize, sm_nn64);

    // 1. hn = normalize(h); x = LN1(h)   (fused)
    l2ln_k<<<BSX, 256>>>(h, ln1_s, ln1_b);

    // 2. topo = h @ W_topo + b_topo
    tgemm<0, 0, 128><<<dim3(1, 32, 1), 256, sm_nn128>>>(h, W_topo, topo, b_topo, nullptr, nullptr,
        EMB, EMB, TT, TT, 0, 0, 1, 0, 0, 0, 0, 0, 0);

    // 3. dot[b] = hn[b] @ hn[b]^T
    tgemm<1, 0, 128><<<dim3(16, 16, 2), 256, sm_tb128>>>(hn, hn, scores, nullptr, nullptr, nullptr,
        EMB, EMB, EMB, SEQ, 0, 0, 2, SE, 0, SE, 0, SS, 0);

    // 4. per-row top-16 NN + weights; combine
    knn_k<<<BSX, 256>>>();
    combine_k<<<BSX, TT>>>();

    // 5. topo MLP + LN_t
    tgemm<0, 1, 128><<<dim3(2, 32, 1), 256, sm_nn128>>>(comb, W_m1, tmp256, b_m1, nullptr, nullptr,
        TT, TT, 256, 256, 0, 0, 1, 0, 0, 0, 0, 0, 0);
    tgemm<0, 0, 128><<<dim3(1, 32, 1), 256, sm_nn128>>>(tmp256, W_m2, tt, b_m2, nullptr, nullptr,
        256, 256, TT, TT, 0, 0, 1, 0, 0, 0, 0, 0, 0);
    ln_k<<<BSX, 256>>>(tt, tt, ln_t_s, ln_t_b, TT);

    // 6. pf = relu(t@W_p1+b_p1)@W_p2+b_p2  -> written into cat[:, EMB:]
    tgemm<0, 1, 128><<<dim3(1, 32, 1), 256, sm_nn128>>>(tt, W_p1, tmp256, b_p1, nullptr, nullptr,
        TT, TT, TT, TT, 0, 0, 1, 0, 0, 0, 0, 0, 0);
    tgemm<0, 0, 128><<<dim3(1, 32, 1), 256, sm_nn128>>>(tmp256, W_p2, cat + EMB, b_p2, nullptr, nullptr,
        TT, TT, TT, CATW, 0, 0, 1, 0, 0, 0, 0, 0, 0);

    // 7. q/k/v
    tgemm<0, 0, 128><<<dim3(6, 32, 1), 256, sm_nn128>>>(x, Wq, q, nullptr, nullptr, nullptr,
        EMB, EMB, EMB, EMB, 0, 0, 1, 0, 0, 0, 0, 0, 0);
    tgemm<0, 0, 128><<<dim3(6, 32, 1), 256, sm_nn128>>>(x, Wk, k, nullptr, nullptr, nullptr,
        EMB, EMB, EMB, EMB, 0, 0, 1, 0, 0, 0, 0, 0, 0);
    tgemm<0, 0, 128><<<dim3(6, 32, 1), 256, sm_nn128>>>(x, Wv, v, nullptr, nullptr, nullptr,
        EMB, EMB, EMB, EMB, 0, 0, 1, 0, 0, 0, 0, 0, 0);

    // 8. scores[b,h] = q @ k^T
    tgemm<1, 0, 128><<<dim3(16, 16, BB * NH), 256, sm_tb128>>>(q, k, scores, nullptr, nullptr, nullptr,
        DHD, EMB, EMB, SEQ, 0, 0, NH, DHD, SE, DHD, SE, SS, HSS);

    // 9. softmax
    attn_softmax_k<<<dim3(SEQ, BB * NH), 256>>>(mask);

    // 10. ctx = probs @ v  -> written into cat[:, :EMB] per head
    tgemm<0, 0, 64><<<dim3(1, 16, BB * NH), 256, sm_nn64>>>(scores, v, cat, nullptr, nullptr, nullptr,
        SEQ, SEQ, EMB, CATW, 0, 0, NH, SS, HSS, DHD, SE, DHD, (long long)SEQ * CATW);

    // 11. gate-mix: ctx = sigmoid(cat@W_gate+b_gate)*ctx_cat + (1-s)*x
    tgemm<0, 3, 128><<<dim3(6, 32, 1), 256, sm_nn128>>>(cat, W_gate, ctx, b_gate, cat, x,
        CATW, CATW, EMB, EMB, CATW, EMB, 1, 0, 0, 0, 0, 0, 0);

    // 12. h1 = h + ctx @ W_o + b_o
    tgemm<0, 0, 128><<<dim3(6, 32, 1), 256, sm_nn128>>>(ctx, W_o, h1, b_o, h, nullptr,
        EMB, EMB, EMB, EMB, EMB, 0, 1, 0, 0, 0, 0, 0, 0);

    // 13. FFN
    ln_k<<<BSX, 256>>>(h1, y, ln2_s, ln2_b, EMB);
    tgemm<0, 2, 128><<<dim3(24, 32, 1), 256, sm_nn128>>>(y, W_f1, ff, b_f1, nullptr, nullptr,
        EMB, EMB, FF, FF, 0, 0, 1, 0, 0, 0, 0, 0, 0);
    tgemm<0, 0, 128><<<dim3(6, 32, 1), 256, sm_nn128>>>(ff, W_f2, out, b_f2, h1, nullptr,
        FF, FF, EMB, EMB, EMB, 0, 1, 0, 0, 0, 0, 0, 0);
}

// round 6
// speedup vs baseline: 1.0315x; 1.0305x over previous
#include <cuda_runtime.h>
#include <cuda_fp16.h>
#include <math.h>
#include <stdint.h>

// ---- problem constants ----
#define BSX 4096   // B*S
#define BB  2
#define SEQ 2048
#define EMB 768
#define TT  128
#define NH  12
#define DHD 64
#define FF  3072
#define KNN 16
#define CATW (EMB + TT)   // 896

// ---- scratch (device globals) ----
__device__ float g_hn[BSX * EMB];
__device__ float g_x[BSX * EMB];
__device__ float g_topo[BSX * TT];
__device__ float g_comb[BSX * TT];
__device__ float g_tmp256[BSX * 256];
__device__ float g_t[BSX * TT];
__device__ float g_q[BSX * EMB];
__device__ float g_k[BSX * EMB];
__device__ float g_v[BSX * EMB];
__device__ float g_ctx[BSX * EMB];
__device__ float g_cat[BSX * CATW];
__device__ float g_h1[BSX * EMB];
__device__ float g_y[BSX * EMB];
__device__ float g_ff[(long long)BSX * FF];
__device__ float g_knw[BSX * KNN];
__device__ int   g_kni[BSX * KNN];
__device__ float  g_dist[(long long)BB * SEQ * SEQ];          // 33.5 MB fp32
__device__ __half g_scoresh[(long long)BB * NH * SEQ * SEQ];  // 201 MB fp16

__device__ __forceinline__ void mma_tf32(float* c, const uint32_t* a, uint32_t b0, uint32_t b1) {
    asm volatile(
        "mma.sync.aligned.m16n8k8.row.col.f32.tf32.tf32.f32 "
        "{%0,%1,%2,%3},{%4,%5,%6,%7},{%8,%9},{%0,%1,%2,%3};"
        : "+f"(c[0]), "+f"(c[1]), "+f"(c[2]), "+f"(c[3])
        : "r"(a[0]), "r"(a[1]), "r"(a[2]), "r"(a[3]), "r"(b0), "r"(b1));
}

__device__ __forceinline__ void cpa16(void* s, const void* g) {
    unsigned sa = (unsigned)__cvta_generic_to_shared(s);
    asm volatile("cp.async.cg.shared.global [%0], [%1], 16;" :: "r"(sa), "l"(g));
}
__device__ __forceinline__ void cpa_commit() { asm volatile("cp.async.commit_group;"); }
__device__ __forceinline__ void cpa_wait2()  { asm volatile("cp.async.wait_group 2;"); }

// ============================================================================
// tf32 tensor-core GEMM, cp.async 3-stage pipeline. Block tile 128 x TN,
// 256 threads, 8 warps (warp tile 32 x TN/2).
// ACT: 0 none, 1 relu, 2 gelu, 3 sigmoid-mix (C = s*res + (1-s)*res2).
// AH: A operand stored as __half in gmem. CH: C written as __half.
// Requirements: M%128==0, N%TN==0, K%16==0, TN in {64,128}.
// ============================================================================
template<int TRANSB, int ACT, int TN, int AH, int CH>
__global__ void __launch_bounds__(256) tgemm(
    const void* __restrict__ Av, const float* __restrict__ B,
    void* __restrict__ Cv, const float* __restrict__ bias,
    const float* __restrict__ res, const float* __restrict__ res2,
    int K, int lda, int ldb, int ldc, int ldr1, int ldr2,
    int zdiv, long long sA1, long long sA2,
    long long sB1, long long sB2, long long sC1, long long sC2)
{
    constexpr int NT    = TN / 16;
    constexpr int BITER = TN / 64;
    constexpr int BCOLS = TRANSB ? 20 : (TN + 8);
    constexpr int AP    = AH ? 24 : 20;                      // A shared row pitch (elems)
    constexpr int AWORDS = AH ? (3 * 128 * 24 / 2) : (3 * 128 * 20); // uint32 words

    extern __shared__ uint32_t sm[];
    uint32_t* As  = sm;
    __half*   hAs = (__half*)sm;
    uint32_t* Bs  = sm + AWORDS;

    int z = blockIdx.z;
    long long zm = z % zdiv, zd = z / zdiv;
    const char* Abase = (const char*)Av + (zm * sA1 + zd * sA2) * (AH ? 2 : 4);
    B += zm * sB1 + zd * sB2;
    long long co = zm * sC1 + zd * sC2;
    char* Cbase = (char*)Cv + co * (CH ? 2 : 4);

    const int t    = threadIdx.x;
    const int lane = t & 31;
    const int wid  = t >> 5;
    const int lr   = lane >> 2;
    const int lc   = lane & 3;
    const int wm   = (wid & 3) * 32;
    const int wn   = (wid >> 2) * (TN / 2);
    const int bm   = blockIdx.y * 128;
    const int bn   = blockIdx.x * TN;

    float acc[2][NT][4];
    #pragma unroll
    for (int mt = 0; mt < 2; mt++)
        #pragma unroll
        for (int nt = 0; nt < NT; nt++)
            #pragma unroll
            for (int i = 0; i < 4; i++) acc[mt][nt][i] = 0.f;

    auto issue = [&](int buf, int k0) {
        if (AH) {
            int row = t >> 1, kq = (t & 1) * 8;
            cpa16(&hAs[(buf * 128 + row) * AP + kq],
                  Abase + ((long long)(bm + row) * lda + k0 + kq) * 2);
        } else {
            #pragma unroll
            for (int i = 0; i < 2; i++) {
                int c = t + i * 256;
                int row = c >> 2, kq = (c & 3) << 2;
                cpa16(&As[(buf * 128 + row) * AP + kq],
                      Abase + ((long long)(bm + row) * lda + k0 + kq) * 4);
            }
        }
        if (TRANSB) {
            #pragma unroll
            for (int i = 0; i < BITER; i++) {
                int c = t + i * 256;
                int row = c >> 2, kq = (c & 3) << 2;
                cpa16(&Bs[(buf * TN + row) * 20 + kq],
                      B + (long long)(bn + row) * ldb + k0 + kq);
            }
        } else {
            #pragma unroll
            for (int i = 0; i < BITER; i++) {
                int c = t + i * 256;
                int krow = c / (TN / 4), n4 = (c % (TN / 4)) << 2;
                cpa16(&Bs[(buf * 16 + krow) * BCOLS + n4],
                      B + (long long)(k0 + krow) * ldb + bn + n4);
            }
        }
        cpa_commit();
    };

    const int iters = K >> 4;
    issue(0, 0);
    issue(1, 16);

    for (int kb = 0; kb < iters; kb++) {
        int nst  = kb + 2;
        int nbuf = nst - (nst / 3) * 3;
        int nk0  = (nst < iters ? nst : iters - 1) << 4;
        issue(nbuf, nk0);
        cpa_wait2();
        __syncthreads();
        int cur = kb - (kb / 3) * 3;

        #pragma unroll
        for (int ks = 0; ks < 16; ks += 8) {
            uint32_t af[2][4];
            #pragma unroll
            for (int mt = 0; mt < 2; mt++) {
                int m = cur * 128 + wm + mt * 16 + lr;
                if (AH) {
                    af[mt][0] = __float_as_uint(__half2float(hAs[m * AP + ks + lc]));
                    af[mt][1] = __float_as_uint(__half2float(hAs[(m + 8) * AP + ks + lc]));
                    af[mt][2] = __float_as_uint(__half2float(hAs[m * AP + ks + lc + 4]));
                    af[mt][3] = __float_as_uint(__half2float(hAs[(m + 8) * AP + ks + lc + 4]));
                } else {
                    af[mt][0] = As[m * AP + ks + lc];
                    af[mt][1] = As[(m + 8) * AP + ks + lc];
                    af[mt][2] = As[m * AP + ks + lc + 4];
                    af[mt][3] = As[(m + 8) * AP + ks + lc + 4];
                }
            }
            #pragma unroll
            for (int nt = 0; nt < NT; nt++) {
                int n = wn + nt * 8 + lr;
                uint32_t b0, b1;
                if (TRANSB) {
                    b0 = Bs[(cur * TN + n) * 20 + ks + lc];
                    b1 = Bs[(cur * TN + n) * 20 + ks + lc + 4];
                } else {
                    b0 = Bs[(cur * 16 + ks + lc) * BCOLS + n];
                    b1 = Bs[(cur * 16 + ks + lc + 4) * BCOLS + n];
                }
                #pragma unroll
                for (int mt = 0; mt < 2; mt++)
                    mma_tf32(acc[mt][nt], af[mt], b0, b1);
            }
        }
        __syncthreads();
    }

    // epilogue
    #pragma unroll
    for (int mt = 0; mt < 2; mt++) {
        #pragma unroll
        for (int nt = 0; nt < NT; nt++) {
            int mrow = bm + wm + mt * 16 + lr;
            int ncol = bn + wn + nt * 8 + 2 * lc;
            #pragma unroll
            for (int half = 0; half < 2; half++) {
                int m = mrow + half * 8;
                float v0 = acc[mt][nt][half * 2 + 0];
                float v1 = acc[mt][nt][half * 2 + 1];
                if (bias) { v0 += bias[ncol]; v1 += bias[ncol + 1]; }
                if (ACT == 1) { v0 = fmaxf(v0, 0.f); v1 = fmaxf(v1, 0.f); }
                if (ACT == 2) {
                    float u = v0;
                    v0 = 0.5f * u * (1.f + tanhf(0.7978845608028654f * (u + 0.044715f * u * u * u)));
                    u = v1;
                    v1 = 0.5f * u * (1.f + tanhf(0.7978845608028654f * (u + 0.044715f * u * u * u)));
                }
                long long off = (long long)m * ldc + ncol;
                if (ACT == 3) {
                    float s0 = 1.f / (1.f + expf(-v0));
                    float s1 = 1.f / (1.f + expf(-v1));
                    long long o1 = (long long)m * ldr1 + ncol;
                    long long o2 = (long long)m * ldr2 + ncol;
                    float2 r1 = *(const float2*)(res + o1);
                    float2 r2 = *(const float2*)(res2 + o2);
                    v0 = s0 * r1.x + (1.f - s0) * r2.x;
                    v1 = s1 * r1.y + (1.f - s1) * r2.y;
                } else if (res) {
                    float2 r1 = *(const float2*)(res + (long long)m * ldr1 + ncol);
                    v0 += r1.x; v1 += r1.y;
                }
                if (CH) {
                    __half2 hv;
                    hv.x = __float2half(v0);
                    hv.y = __float2half(v1);
                    *(__half2*)((__half*)Cbase + off) = hv;
                } else {
                    float2 o2v = {v0, v1};
                    *(float2*)((float*)Cbase + off) = o2v;
                }
            }
        }
    }
}

// ---- fused: hn = h/(||h||+1e-8) ; x = LN1(h) ----
__global__ void l2ln_k(const float* __restrict__ h,
                       const float* __restrict__ gma, const float* __restrict__ bta)
{
    int row = blockIdx.x, t = threadIdx.x;
    const float* xr = h + (long long)row * EMB;
    __shared__ float sh[EMB];
    __shared__ float r1[256], r2[256];
    float s = 0.f, ss = 0.f;
    for (int i = t; i < EMB; i += 256) { float v = xr[i]; sh[i] = v; s += v; ss += v * v; }
    r1[t] = s; r2[t] = ss; __syncthreads();
    for (int st = 128; st > 0; st >>= 1) {
        if (t < st) { r1[t] += r1[t + st]; r2[t] += r2[t + st]; }
        __syncthreads();
    }
    float mu   = r1[0] / EMB;
    float var  = r2[0] / EMB - mu * mu;
    float ri   = rsqrtf(var + 1e-6f);
    float invn = 1.f / (sqrtf(r2[0]) + 1e-8f);
    for (int i = t; i < EMB; i += 256) {
        float v = sh[i];
        g_hn[(long long)row * EMB + i] = v * invn;
        g_x [(long long)row * EMB + i] = (v - mu) * ri * gma[i] + bta[i];
    }
}

// ---- layernorm (two-pass; eps 1e-6) ----
__global__ void ln_k(const float* __restrict__ x, float* __restrict__ o,
                     const float* __restrict__ gma, const float* __restrict__ bta, int D)
{
    int row = blockIdx.x, t = threadIdx.x;
    const float* xr = x + (long long)row * D;
    __shared__ float red[256];
    __shared__ float s_mu, s_ri;
    float s = 0.f;
    for (int i = t; i < D; i += 256) s += xr[i];
    red[t] = s; __syncthreads();
    for (int st = 128; st > 0; st >>= 1) { if (t < st) red[t] += red[t + st]; __syncthreads(); }
    if (t == 0) s_mu = red[0] / D;
    __syncthreads();
    float mu = s_mu;
    float v = 0.f;
    for (int i = t; i < D; i += 256) { float d = xr[i] - mu; v += d * d; }
    __syncthreads();
    red[t] = v; __syncthreads();
    for (int st = 128; st > 0; st >>= 1) { if (t < st) red[t] += red[t + st]; __syncthreads(); }
    if (t == 0) s_ri = rsqrtf(red[0] / D + 1e-6f);
    __syncthreads();
    float ri = s_ri;
    for (int i = t; i < D; i += 256)
        o[(long long)row * D + i] = (xr[i] - mu) * ri * gma[i] + bta[i];
}

// ---- k-NN v2: hierarchical warp top-16, zero block barriers in hot loop ----
__global__ void knn_k()
{
    int row = blockIdx.x;
    int b = row >> 11, i = row & (SEQ - 1);
    const float* dr = g_dist + (long long)row * SEQ;
    int t = threadIdx.x, lane = t & 31, w = t >> 5;

    // each warp owns 256 contiguous j: packed key = (dist_bits << 32) | j
    unsigned long long v[8];
    int base = w * 256;
    #pragma unroll
    for (int r = 0; r < 8; r++) {
        int j = base + r * 32 + lane;
        float d = (j == i) ? 1e9f : (1.f - dr[j]);
        v[r] = ((unsigned long long)__float_as_uint(d) << 32) | (unsigned)j;
    }

    __shared__ unsigned long long cand[128];
    #pragma unroll
    for (int it = 0; it < KNN; it++) {
        unsigned long long m = v[0];
        #pragma unroll
        for (int r = 1; r < 8; r++) m = (v[r] < m) ? v[r] : m;
        #pragma unroll
        for (int s = 16; s > 0; s >>= 1) {
            unsigned long long o = __shfl_xor_sync(0xffffffffu, m, s);
            m = (o < m) ? o : m;
        }
        if (lane == 0) cand[w * KNN + it] = m;
        #pragma unroll
        for (int r = 0; r < 8; r++) if (v[r] == m) v[r] = ~0ull;
    }
    __syncthreads();

    if (w == 0) {
        __shared__ unsigned long long fin[KNN];
        unsigned long long c[4];
        #pragma unroll
        for (int r = 0; r < 4; r++) c[r] = cand[r * 32 + lane];
        #pragma unroll
        for (int it = 0; it < KNN; it++) {
            unsigned long long m01 = (c[0] < c[1]) ? c[0] : c[1];
            unsigned long long m23 = (c[2] < c[3]) ? c[2] : c[3];
            unsigned long long m = (m01 < m23) ? m01 : m23;
            #pragma unroll
            for (int s = 16; s > 0; s >>= 1) {
                unsigned long long o = __shfl_xor_sync(0xffffffffu, m, s);
                m = (o < m) ? o : m;
            }
            if (lane == 0) fin[it] = m;
            #pragma unroll
            for (int r = 0; r < 4; r++) if (c[r] == m) c[r] = ~0ull;
        }
        __syncwarp();
        if (lane < KNN) {
            float d0 = __uint_as_float((unsigned)(fin[0] >> 32));
            float dk = __uint_as_float((unsigned)(fin[lane] >> 32));
            float wk = expf(d0 - dk);
            float sum = wk;
            #pragma unroll
            for (int s = 8; s > 0; s >>= 1) sum += __shfl_xor_sync(0xffffu, sum, s);
            g_knw[row * KNN + lane] = wk / sum;
            g_kni[row * KNN + lane] = b * SEQ + (int)(fin[lane] & 0xffffffffu);
        }
    }
}

// ---- combined = topo + sum_k w_k * topo[nbr_k] ----
__global__ void combine_k()
{
    int row = blockIdx.x, t = threadIdx.x; // 128 threads
    float acc = g_topo[(long long)row * TT + t];
    #pragma unroll
    for (int k2 = 0; k2 < KNN; k2++)
        acc += g_knw[row * KNN + k2] * g_topo[(long long)g_kni[row * KNN + k2] * TT + t];
    g_comb[(long long)row * TT + t] = acc;
}

// ---- attention softmax over fp16 scores: row in registers, 1R + 1W ----
__global__ void attn_softmax_k(const int* __restrict__ mask)
{
    int q = blockIdx.x, z = blockIdx.y, b = z / NH;
    __half* row = g_scoresh + (long long)z * SEQ * SEQ + (long long)q * SEQ;
    const int* mrow = mask + b * SEQ;
    int t = threadIdx.x;
    __shared__ float red[256];
    float vals[8];
    float mx = -1e30f;
    #pragma unroll
    for (int i = 0; i < 8; i++) {
        int k2 = t + i * 256;
        float v = __half2float(row[k2]) * 0.125f;
        if (mrow[k2] == 0) v = -10000.f;
        vals[i] = v; mx = fmaxf(mx, v);
    }
    red[t] = mx; __syncthreads();
    for (int st = 128; st > 0; st >>= 1) { if (t < st) red[t] = fmaxf(red[t], red[t + st]); __syncthreads(); }
    mx = red[0];
    __syncthreads();
    float sum = 0.f;
    #pragma unroll
    for (int i = 0; i < 8; i++) { vals[i] = expf(vals[i] - mx); sum += vals[i]; }
    red[t] = sum; __syncthreads();
    for (int st = 128; st > 0; st >>= 1) { if (t < st) red[t] += red[t + st]; __syncthreads(); }
    float inv = 1.f / red[0];
    #pragma unroll
    for (int i = 0; i < 8; i++) row[t + i * 256] = __float2half(vals[i] * inv);
}

// ============================================================================
template<int TRANSB, int TN, int AH>
static int smem_bytes() {
    int a = AH ? 3 * 128 * 24 * 2 : 3 * 128 * 20 * 4;
    int b = TRANSB ? 3 * TN * 20 * 4 : 3 * 16 * (TN + 8) * 4;
    return a + b;
}

extern "C" void kernel_launch(void* const* d_in, const int* in_sizes, int n_in,
                              void* d_out, int out_size)
{
    const float* h      = (const float*)d_in[0];
    const int*   mask   = (const int*)  d_in[1];
    const float* W_topo = (const float*)d_in[2];
    const float* b_topo = (const float*)d_in[3];
    const float* W_m1   = (const float*)d_in[4];
    const float* b_m1   = (const float*)d_in[5];
    const float* W_m2   = (const float*)d_in[6];
    const float* b_m2   = (const float*)d_in[7];
    const float* ln_t_s = (const float*)d_in[8];
    const float* ln_t_b = (const float*)d_in[9];
    const float* W_p1   = (const float*)d_in[10];
    const float* b_p1   = (const float*)d_in[11];
    const float* W_p2   = (const float*)d_in[12];
    const float* b_p2   = (const float*)d_in[13];
    const float* ln1_s  = (const float*)d_in[14];
    const float* ln1_b  = (const float*)d_in[15];
    const float* Wq     = (const float*)d_in[16];
    const float* Wk     = (const float*)d_in[17];
    const float* Wv     = (const float*)d_in[18];
    const float* W_gate = (const float*)d_in[19];
    const float* b_gate = (const float*)d_in[20];
    const float* W_o    = (const float*)d_in[21];
    const float* b_o    = (const float*)d_in[22];
    const float* ln2_s  = (const float*)d_in[23];
    const float* ln2_b  = (const float*)d_in[24];
    const float* W_f1   = (const float*)d_in[25];
    const float* b_f1   = (const float*)d_in[26];
    const float* W_f2   = (const float*)d_in[27];
    const float* b_f2   = (const float*)d_in[28];
    float* out = (float*)d_out;

    float *hn, *x, *topo, *comb, *tmp256, *tt, *q, *k, *v, *ctx, *cat, *h1, *y, *ff, *dist;
    __half* scoresh;
    cudaGetSymbolAddress((void**)&hn,      g_hn);
    cudaGetSymbolAddress((void**)&x,       g_x);
    cudaGetSymbolAddress((void**)&topo,    g_topo);
    cudaGetSymbolAddress((void**)&comb,    g_comb);
    cudaGetSymbolAddress((void**)&tmp256,  g_tmp256);
    cudaGetSymbolAddress((void**)&tt,      g_t);
    cudaGetSymbolAddress((void**)&q,       g_q);
    cudaGetSymbolAddress((void**)&k,       g_k);
    cudaGetSymbolAddress((void**)&v,       g_v);
    cudaGetSymbolAddress((void**)&ctx,     g_ctx);
    cudaGetSymbolAddress((void**)&cat,     g_cat);
    cudaGetSymbolAddress((void**)&h1,      g_h1);
    cudaGetSymbolAddress((void**)&y,       g_y);
    cudaGetSymbolAddress((void**)&ff,      g_ff);
    cudaGetSymbolAddress((void**)&dist,    g_dist);
    cudaGetSymbolAddress((void**)&scoresh, g_scoresh);

    const long long SE  = (long long)SEQ * EMB;
    const long long SS  = (long long)SEQ * SEQ;
    const long long HSS = (long long)NH * SS;

    const int sm_nn128 = smem_bytes<0, 128, 0>();
    const int sm_tb128 = smem_bytes<1, 128, 0>();
    const int sm_pv64  = smem_bytes<0, 64, 1>();
    cudaFuncSetAttribute((const void*)tgemm<0, 0, 128, 0, 0>, cudaFuncAttributeMaxDynamicSharedMemorySize, sm_nn128);
    cudaFuncSetAttribute((const void*)tgemm<0, 1, 128, 0, 0>, cudaFuncAttributeMaxDynamicSharedMemorySize, sm_nn128);
    cudaFuncSetAttribute((const void*)tgemm<0, 2, 128, 0, 0>, cudaFuncAttributeMaxDynamicSharedMemorySize, sm_nn128);
    cudaFuncSetAttribute((const void*)tgemm<0, 3, 128, 0, 0>, cudaFuncAttributeMaxDynamicSharedMemorySize, sm_nn128);
    cudaFuncSetAttribute((const void*)tgemm<1, 0, 128, 0, 0>, cudaFuncAttributeMaxDynamicSharedMemorySize, sm_tb128);
    cudaFuncSetAttribute((const void*)tgemm<1, 0, 128, 0, 1>, cudaFuncAttributeMaxDynamicSharedMemorySize, sm_tb128);
    cudaFuncSetAttribute((const void*)tgemm<0, 0, 64, 1, 0>,  cudaFuncAttributeMaxDynamicSharedMemorySize, sm_pv64);

    // 1. hn = normalize(h); x = LN1(h)   (fused)
    l2ln_k<<<BSX, 256>>>(h, ln1_s, ln1_b);

    // 2. topo = h @ W_topo + b_topo
    tgemm<0, 0, 128, 0, 0><<<dim3(1, 32, 1), 256, sm_nn128>>>(h, W_topo, topo, b_topo, nullptr, nullptr,
        EMB, EMB, TT, TT, 0, 0, 1, 0, 0, 0, 0, 0, 0);

    // 3. dist dot[b] = hn[b] @ hn[b]^T  (fp32)
    tgemm<1, 0, 128, 0, 0><<<dim3(16, 16, 2), 256, sm_tb128>>>(hn, hn, dist, nullptr, nullptr, nullptr,
        EMB, EMB, EMB, SEQ, 0, 0, 2, SE, 0, SE, 0, SS, 0);

    // 4. per-row top-16 NN + weights; combine
    knn_k<<<BSX, 256>>>();
    combine_k<<<BSX, TT>>>();

    // 5. topo MLP + LN_t
    tgemm<0, 1, 128, 0, 0><<<dim3(2, 32, 1), 256, sm_nn128>>>(comb, W_m1, tmp256, b_m1, nullptr, nullptr,
        TT, TT, 256, 256, 0, 0, 1, 0, 0, 0, 0, 0, 0);
    tgemm<0, 0, 128, 0, 0><<<dim3(1, 32, 1), 256, sm_nn128>>>(tmp256, W_m2, tt, b_m2, nullptr, nullptr,
        256, 256, TT, TT, 0, 0, 1, 0, 0, 0, 0, 0, 0);
    ln_k<<<BSX, 256>>>(tt, tt, ln_t_s, ln_t_b, TT);

    // 6. pf -> cat[:, EMB:]
    tgemm<0, 1, 128, 0, 0><<<dim3(1, 32, 1), 256, sm_nn128>>>(tt, W_p1, tmp256, b_p1, nullptr, nullptr,
        TT, TT, TT, TT, 0, 0, 1, 0, 0, 0, 0, 0, 0);
    tgemm<0, 0, 128, 0, 0><<<dim3(1, 32, 1), 256, sm_nn128>>>(tmp256, W_p2, cat + EMB, b_p2, nullptr, nullptr,
        TT, TT, TT, CATW, 0, 0, 1, 0, 0, 0, 0, 0, 0);

    // 7. q/k/v
    tgemm<0, 0, 128, 0, 0><<<dim3(6, 32, 1), 256, sm_nn128>>>(x, Wq, q, nullptr, nullptr, nullptr,
        EMB, EMB, EMB, EMB, 0, 0, 1, 0, 0, 0, 0, 0, 0);
    tgemm<0, 0, 128, 0, 0><<<dim3(6, 32, 1), 256, sm_nn128>>>(x, Wk, k, nullptr, nullptr, nullptr,
        EMB, EMB, EMB, EMB, 0, 0, 1, 0, 0, 0, 0, 0, 0);
    tgemm<0, 0, 128, 0, 0><<<dim3(6, 32, 1), 256, sm_nn128>>>(x, Wv, v, nullptr, nullptr, nullptr,
        EMB, EMB, EMB, EMB, 0, 0, 1, 0, 0, 0, 0, 0, 0);

    // 8. scores[b,h] = q @ k^T  (fp16 out)
    tgemm<1, 0, 128, 0, 1><<<dim3(16, 16, BB * NH), 256, sm_tb128>>>(q, k, scoresh, nullptr, nullptr, nullptr,
        DHD, EMB, EMB, SEQ, 0, 0, NH, DHD, SE, DHD, SE, SS, HSS);

    // 9. softmax (fp16 in/out)
    attn_softmax_k<<<dim3(SEQ, BB * NH), 256>>>(mask);

    // 10. ctx = probs @ v  -> cat[:, :EMB] per head  (fp16 A)
    tgemm<0, 0, 64, 1, 0><<<dim3(1, 16, BB * NH), 256, sm_pv64>>>(scoresh, v, cat, nullptr, nullptr, nullptr,
        SEQ, SEQ, EMB, CATW, 0, 0, NH, SS, HSS, DHD, SE, DHD, (long long)SEQ * CATW);

    // 11. gate-mix: ctx = sigmoid(cat@W_gate+b_gate)*ctx_cat + (1-s)*x
    tgemm<0, 3, 128, 0, 0><<<dim3(6, 32, 1), 256, sm_nn128>>>(cat, W_gate, ctx, b_gate, cat, x,
        CATW, CATW, EMB, EMB, CATW, EMB, 1, 0, 0, 0, 0, 0, 0);

    // 12. h1 = h + ctx @ W_o + b_o
    tgemm<0, 0, 128, 0, 0><<<dim3(6, 32, 1), 256, sm_nn128>>>(ctx, W_o, h1, b_o, h, nullptr,
        EMB, EMB, EMB, EMB, EMB, 0, 1, 0, 0, 0, 0, 0, 0);

    // 13. FFN
    ln_k<<<BSX, 256>>>(h1, y, ln2_s, ln2_b, EMB);
    tgemm<0, 2, 128, 0, 0><<<dim3(24, 32, 1), 256, sm_nn128>>>(y, W_f1, ff, b_f1, nullptr, nullptr,
        EMB, EMB, FF, FF, 0, 0, 1, 0, 0, 0, 0, 0, 0);
    tgemm<0, 0, 128, 0, 0><<<dim3(6, 32, 1), 256, sm_nn128>>>(ff, W_f2, out, b_f2, h1, nullptr,
        FF, FF, EMB, EMB, EMB, 0, 1, 0, 0, 0, 0, 0, 0);
}

// round 7
// speedup vs baseline: 1.1691x; 1.1335x over previous
#include <cuda_runtime.h>
#include <math.h>
#include <stdint.h>

// ---- problem constants ----
#define BSX 4096   // B*S
#define BB  2
#define SEQ 2048
#define EMB 768
#define TT  128
#define NH  12
#define DHD 64
#define FF  3072
#define KNN 16
#define CATW (EMB + TT)   // 896

// ---- scratch (device globals) ----
__device__ float g_hn[BSX * EMB];
__device__ float g_x[BSX * EMB];
__device__ float g_topo[BSX * TT];
__device__ float g_comb[BSX * TT];
__device__ float g_tmp256[BSX * 256];
__device__ float g_t[BSX * TT];
__device__ float g_q[BSX * EMB];
__device__ float g_k[BSX * EMB];
__device__ float g_v[BSX * EMB];
__device__ float g_ctx[BSX * EMB];
__device__ float g_cat[BSX * CATW];
__device__ float g_h1[BSX * EMB];
__device__ float g_y[BSX * EMB];
__device__ float g_ff[(long long)BSX * FF];
__device__ float g_knw[BSX * KNN];
__device__ int   g_kni[BSX * KNN];
__device__ float g_dist[(long long)BB * SEQ * SEQ];   // 33.5 MB fp32

__device__ __forceinline__ void mma_tf32(float* c, const uint32_t* a, uint32_t b0, uint32_t b1) {
    asm volatile(
        "mma.sync.aligned.m16n8k8.row.col.f32.tf32.tf32.f32 "
        "{%0,%1,%2,%3},{%4,%5,%6,%7},{%8,%9},{%0,%1,%2,%3};"
        : "+f"(c[0]), "+f"(c[1]), "+f"(c[2]), "+f"(c[3])
        : "r"(a[0]), "r"(a[1]), "r"(a[2]), "r"(a[3]), "r"(b0), "r"(b1));
}

__device__ __forceinline__ void cpa16(void* s, const void* g) {
    unsigned sa = (unsigned)__cvta_generic_to_shared(s);
    asm volatile("cp.async.cg.shared.global [%0], [%1], 16;" :: "r"(sa), "l"(g));
}
__device__ __forceinline__ void cpa_commit() { asm volatile("cp.async.commit_group;"); }
__device__ __forceinline__ void cpa_wait2()  { asm volatile("cp.async.wait_group 2;"); }
__device__ __forceinline__ void cpa_wait1()  { asm volatile("cp.async.wait_group 1;"); }
__device__ __forceinline__ void cpa_wait0()  { asm volatile("cp.async.wait_group 0;"); }

// ============================================================================
// tf32 tensor-core GEMM, cp.async 3-stage pipeline (unchanged from R6, fp32 only)
// ============================================================================
template<int TRANSB, int ACT, int TN>
__global__ void __launch_bounds__(256) tgemm(
    const float* __restrict__ A, const float* __restrict__ B,
    float* __restrict__ C, const float* __restrict__ bias,
    const float* __restrict__ res, const float* __restrict__ res2,
    int K, int lda, int ldb, int ldc, int ldr1, int ldr2,
    int zdiv, long long sA1, long long sA2,
    long long sB1, long long sB2, long long sC1, long long sC2)
{
    constexpr int NT    = TN / 16;
    constexpr int BITER = TN / 64;
    constexpr int BCOLS = TRANSB ? 20 : (TN + 8);

    extern __shared__ uint32_t sm[];
    uint32_t* As = sm;                      // [3][128][20]
    uint32_t* Bs = sm + 3 * 128 * 20;

    int z = blockIdx.z;
    long long zm = z % zdiv, zd = z / zdiv;
    A += zm * sA1 + zd * sA2;
    B += zm * sB1 + zd * sB2;
    long long co = zm * sC1 + zd * sC2;
    C += co;

    const int t    = threadIdx.x;
    const int lane = t & 31;
    const int wid  = t >> 5;
    const int lr   = lane >> 2;
    const int lc   = lane & 3;
    const int wm   = (wid & 3) * 32;
    const int wn   = (wid >> 2) * (TN / 2);
    const int bm   = blockIdx.y * 128;
    const int bn   = blockIdx.x * TN;

    float acc[2][NT][4];
    #pragma unroll
    for (int mt = 0; mt < 2; mt++)
        #pragma unroll
        for (int nt = 0; nt < NT; nt++)
            #pragma unroll
            for (int i = 0; i < 4; i++) acc[mt][nt][i] = 0.f;

    auto issue = [&](int buf, int k0) {
        #pragma unroll
        for (int i = 0; i < 2; i++) {
            int c = t + i * 256;
            int row = c >> 2, kq = (c & 3) << 2;
            cpa16(&As[(buf * 128 + row) * 20 + kq],
                  A + (long long)(bm + row) * lda + k0 + kq);
        }
        if (TRANSB) {
            #pragma unroll
            for (int i = 0; i < BITER; i++) {
                int c = t + i * 256;
                int row = c >> 2, kq = (c & 3) << 2;
                cpa16(&Bs[(buf * TN + row) * 20 + kq],
                      B + (long long)(bn + row) * ldb + k0 + kq);
            }
        } else {
            #pragma unroll
            for (int i = 0; i < BITER; i++) {
                int c = t + i * 256;
                int krow = c / (TN / 4), n4 = (c % (TN / 4)) << 2;
                cpa16(&Bs[(buf * 16 + krow) * BCOLS + n4],
                      B + (long long)(k0 + krow) * ldb + bn + n4);
            }
        }
        cpa_commit();
    };

    const int iters = K >> 4;
    issue(0, 0);
    issue(1, 16);

    for (int kb = 0; kb < iters; kb++) {
        int nst  = kb + 2;
        int nbuf = nst - (nst / 3) * 3;
        int nk0  = (nst < iters ? nst : iters - 1) << 4;
        issue(nbuf, nk0);
        cpa_wait2();
        __syncthreads();
        int cur = kb - (kb / 3) * 3;

        #pragma unroll
        for (int ks = 0; ks < 16; ks += 8) {
            uint32_t af[2][4];
            #pragma unroll
            for (int mt = 0; mt < 2; mt++) {
                int m = cur * 128 + wm + mt * 16 + lr;
                af[mt][0] = As[m * 20 + ks + lc];
                af[mt][1] = As[(m + 8) * 20 + ks + lc];
                af[mt][2] = As[m * 20 + ks + lc + 4];
                af[mt][3] = As[(m + 8) * 20 + ks + lc + 4];
            }
            #pragma unroll
            for (int nt = 0; nt < NT; nt++) {
                int n = wn + nt * 8 + lr;
                uint32_t b0, b1;
                if (TRANSB) {
                    b0 = Bs[(cur * TN + n) * 20 + ks + lc];
                    b1 = Bs[(cur * TN + n) * 20 + ks + lc + 4];
                } else {
                    b0 = Bs[(cur * 16 + ks + lc) * BCOLS + n];
                    b1 = Bs[(cur * 16 + ks + lc + 4) * BCOLS + n];
                }
                #pragma unroll
                for (int mt = 0; mt < 2; mt++)
                    mma_tf32(acc[mt][nt], af[mt], b0, b1);
            }
        }
        __syncthreads();
    }

    #pragma unroll
    for (int mt = 0; mt < 2; mt++) {
        #pragma unroll
        for (int nt = 0; nt < NT; nt++) {
            int mrow = bm + wm + mt * 16 + lr;
            int ncol = bn + wn + nt * 8 + 2 * lc;
            #pragma unroll
            for (int half = 0; half < 2; half++) {
                int m = mrow + half * 8;
                float v0 = acc[mt][nt][half * 2 + 0];
                float v1 = acc[mt][nt][half * 2 + 1];
                if (bias) { v0 += bias[ncol]; v1 += bias[ncol + 1]; }
                if (ACT == 1) { v0 = fmaxf(v0, 0.f); v1 = fmaxf(v1, 0.f); }
                if (ACT == 2) {
                    float u = v0;
                    v0 = 0.5f * u * (1.f + tanhf(0.7978845608028654f * (u + 0.044715f * u * u * u)));
                    u = v1;
                    v1 = 0.5f * u * (1.f + tanhf(0.7978845608028654f * (u + 0.044715f * u * u * u)));
                }
                long long off = (long long)m * ldc + ncol;
                if (ACT == 3) {
                    float s0 = 1.f / (1.f + expf(-v0));
                    float s1 = 1.f / (1.f + expf(-v1));
                    long long o1 = (long long)m * ldr1 + ncol;
                    long long o2 = (long long)m * ldr2 + ncol;
                    float2 r1 = *(const float2*)(res + o1);
                    float2 r2 = *(const float2*)(res2 + o2);
                    v0 = s0 * r1.x + (1.f - s0) * r2.x;
                    v1 = s1 * r1.y + (1.f - s1) * r2.y;
                } else if (res) {
                    float2 r1 = *(const float2*)(res + (long long)m * ldr1 + ncol);
                    v0 += r1.x; v1 += r1.y;
                }
                float2 o2v = {v0, v1};
                *(float2*)(C + off) = o2v;
            }
        }
    }
}

// ============================================================================
// Flash attention: per block 128 q-rows x one (b,h). 8 warps, 16 q-rows each
// (warp-private softmax stats). K/V streamed in 128-key tiles, double-buffered
// cp.async. Probs staged in warp-private smem (pitch 132). Output -> g_cat.
// smem: sP[128][132] | sK[2][128][68] | sV[2][128][72]  = 210944 B
// ============================================================================
#define FS_P  0
#define FS_K  16896
#define FS_V  34304
#define FS_TOT_BYTES 210944

__global__ void __launch_bounds__(256) flash_k(
    const float* __restrict__ q, const float* __restrict__ k,
    const float* __restrict__ v, const int* __restrict__ mask,
    float* __restrict__ outc)
{
    extern __shared__ float fs[];
    float* sP = fs + FS_P;
    float* sK = fs + FS_K;
    float* sV = fs + FS_V;

    const int t = threadIdx.x, lane = t & 31, w = t >> 5;
    const int lr = lane >> 2, lc = lane & 3;
    const int z = blockIdx.y, b = z / NH, hh = z % NH;
    const int bm = blockIdx.x * 128;
    const long long base = (long long)b * SEQ * EMB + hh * DHD;
    const float* qp = q + base;
    const float* kp = k + base;
    const float* vp = v + base;
    const int* mrow = mask + b * SEQ;

    // stage Q tile into sP (group 0)
    #pragma unroll
    for (int j = 0; j < 8; j++) {
        int flat = t + j * 256;
        int row = flat >> 4, q4 = (flat & 15) << 2;
        cpa16(&sP[row * 132 + q4], qp + (long long)(bm + row) * EMB + q4);
    }
    cpa_commit();

    auto issueKV = [&](int kt) {
        int buf = kt & 1;
        #pragma unroll
        for (int j = 0; j < 8; j++) {
            int flat = t + j * 256;
            int row = flat >> 4, q4 = (flat & 15) << 2;
            cpa16(&sK[buf * 8704 + row * 68 + q4],
                  kp + (long long)(kt * 128 + row) * EMB + q4);
        }
        #pragma unroll
        for (int j = 0; j < 8; j++) {
            int flat = t + j * 256;
            int row = flat >> 4, q4 = (flat & 15) << 2;
            cpa16(&sV[buf * 9216 + row * 72 + q4],
                  vp + (long long)(kt * 128 + row) * EMB + q4);
        }
        cpa_commit();
    };
    issueKV(0);

    cpa_wait1();         // Q staged (KV0 may still be in flight)
    __syncthreads();

    // extract Q fragments to registers
    const int wq = w * 16;
    uint32_t qf[8][4];
    #pragma unroll
    for (int ks = 0; ks < 8; ks++) {
        qf[ks][0] = __float_as_uint(sP[(wq + lr)     * 132 + ks * 8 + lc]);
        qf[ks][1] = __float_as_uint(sP[(wq + lr + 8) * 132 + ks * 8 + lc]);
        qf[ks][2] = __float_as_uint(sP[(wq + lr)     * 132 + ks * 8 + lc + 4]);
        qf[ks][3] = __float_as_uint(sP[(wq + lr + 8) * 132 + ks * 8 + lc + 4]);
    }
    __syncthreads();     // everyone done reading Q from sP

    float ctx[8][4];
    #pragma unroll
    for (int nt = 0; nt < 8; nt++)
        #pragma unroll
        for (int i = 0; i < 4; i++) ctx[nt][i] = 0.f;
    float m0 = -1e30f, m1 = -1e30f, l0 = 0.f, l1 = 0.f;

    for (int kt = 0; kt < 16; kt++) {
        if (kt + 1 < 16) { issueKV(kt + 1); cpa_wait1(); }
        else             { cpa_wait0(); }
        __syncthreads();
        const float* bK = &sK[(kt & 1) * 8704];
        const float* bV = &sV[(kt & 1) * 9216];

        // ---- S = Q K^T (16 n8-tiles x 8 k8-steps) ----
        float S[16][4];
        #pragma unroll
        for (int nt = 0; nt < 16; nt++)
            #pragma unroll
            for (int i = 0; i < 4; i++) S[nt][i] = 0.f;
        #pragma unroll
        for (int nt = 0; nt < 16; nt++) {
            #pragma unroll
            for (int ks = 0; ks < 8; ks++) {
                uint32_t b0 = __float_as_uint(bK[(nt * 8 + lr) * 68 + ks * 8 + lc]);
                uint32_t b1 = __float_as_uint(bK[(nt * 8 + lr) * 68 + ks * 8 + lc + 4]);
                mma_tf32(S[nt], qf[ks], b0, b1);
            }
        }

        // ---- scale + mask + row max ----
        float nm0 = -1e30f, nm1 = -1e30f;
        #pragma unroll
        for (int nt = 0; nt < 16; nt++) {
            int c0 = kt * 128 + nt * 8 + 2 * lc;
            int2 mg = *(const int2*)&mrow[c0];
            float s0 = S[nt][0] * 0.125f, s1 = S[nt][1] * 0.125f;
            float s2 = S[nt][2] * 0.125f, s3 = S[nt][3] * 0.125f;
            if (mg.x == 0) { s0 = -10000.f; s2 = -10000.f; }
            if (mg.y == 0) { s1 = -10000.f; s3 = -10000.f; }
            S[nt][0] = s0; S[nt][1] = s1; S[nt][2] = s2; S[nt][3] = s3;
            nm0 = fmaxf(nm0, fmaxf(s0, s1));
            nm1 = fmaxf(nm1, fmaxf(s2, s3));
        }
        nm0 = fmaxf(nm0, __shfl_xor_sync(0xffffffffu, nm0, 1));
        nm0 = fmaxf(nm0, __shfl_xor_sync(0xffffffffu, nm0, 2));
        nm1 = fmaxf(nm1, __shfl_xor_sync(0xffffffffu, nm1, 1));
        nm1 = fmaxf(nm1, __shfl_xor_sync(0xffffffffu, nm1, 2));
        float M0 = fmaxf(m0, nm0), M1 = fmaxf(m1, nm1);
        float a0 = expf(m0 - M0), a1 = expf(m1 - M1);

        // ---- exp, row sum, store P to warp-private smem ----
        float r0 = 0.f, r1 = 0.f;
        #pragma unroll
        for (int nt = 0; nt < 16; nt++) {
            float p0 = expf(S[nt][0] - M0), p1 = expf(S[nt][1] - M0);
            float p2 = expf(S[nt][2] - M1), p3 = expf(S[nt][3] - M1);
            r0 += p0 + p1; r1 += p2 + p3;
            float2 w0 = {p0, p1}, w1 = {p2, p3};
            *(float2*)&sP[(wq + lr)     * 132 + nt * 8 + 2 * lc] = w0;
            *(float2*)&sP[(wq + lr + 8) * 132 + nt * 8 + 2 * lc] = w1;
        }
        r0 += __shfl_xor_sync(0xffffffffu, r0, 1);
        r0 += __shfl_xor_sync(0xffffffffu, r0, 2);
        r1 += __shfl_xor_sync(0xffffffffu, r1, 1);
        r1 += __shfl_xor_sync(0xffffffffu, r1, 2);
        l0 = l0 * a0 + r0;
        l1 = l1 * a1 + r1;
        m0 = M0; m1 = M1;
        #pragma unroll
        for (int nt = 0; nt < 8; nt++) {
            ctx[nt][0] *= a0; ctx[nt][1] *= a0;
            ctx[nt][2] *= a1; ctx[nt][3] *= a1;
        }
        __syncwarp();

        // ---- ctx += P V (16 k8-steps over keys, 8 n8-tiles over d) ----
        #pragma unroll
        for (int ks = 0; ks < 16; ks++) {
            uint32_t af[4];
            af[0] = __float_as_uint(sP[(wq + lr)     * 132 + ks * 8 + lc]);
            af[1] = __float_as_uint(sP[(wq + lr + 8) * 132 + ks * 8 + lc]);
            af[2] = __float_as_uint(sP[(wq + lr)     * 132 + ks * 8 + lc + 4]);
            af[3] = __float_as_uint(sP[(wq + lr + 8) * 132 + ks * 8 + lc + 4]);
            #pragma unroll
            for (int nt = 0; nt < 8; nt++) {
                uint32_t b0 = __float_as_uint(bV[(ks * 8 + lc)     * 72 + nt * 8 + lr]);
                uint32_t b1 = __float_as_uint(bV[(ks * 8 + lc + 4) * 72 + nt * 8 + lr]);
                mma_tf32(ctx[nt], af, b0, b1);
            }
        }
        __syncthreads();   // all warps done with sK/sV before next overwrite
    }

    // ---- epilogue: normalize, write into cat[:, :EMB] ----
    float il0 = 1.f / l0, il1 = 1.f / l1;
    #pragma unroll
    for (int nt = 0; nt < 8; nt++) {
        long long row0 = (long long)b * SEQ + bm + wq + lr;
        int col = hh * DHD + nt * 8 + 2 * lc;
        float2 o0 = {ctx[nt][0] * il0, ctx[nt][1] * il0};
        float2 o1 = {ctx[nt][2] * il1, ctx[nt][3] * il1};
        *(float2*)&outc[row0 * CATW + col] = o0;
        *(float2*)&outc[(row0 + 8) * CATW + col] = o1;
    }
}

// ---- fused: hn = h/(||h||+1e-8) ; x = LN1(h) ----
__global__ void l2ln_k(const float* __restrict__ h,
                       const float* __restrict__ gma, const float* __restrict__ bta)
{
    int row = blockIdx.x, t = threadIdx.x;
    const float* xr = h + (long long)row * EMB;
    __shared__ float sh[EMB];
    __shared__ float r1[256], r2[256];
    float s = 0.f, ss = 0.f;
    for (int i = t; i < EMB; i += 256) { float v = xr[i]; sh[i] = v; s += v; ss += v * v; }
    r1[t] = s; r2[t] = ss; __syncthreads();
    for (int st = 128; st > 0; st >>= 1) {
        if (t < st) { r1[t] += r1[t + st]; r2[t] += r2[t + st]; }
        __syncthreads();
    }
    float mu   = r1[0] / EMB;
    float var  = r2[0] / EMB - mu * mu;
    float ri   = rsqrtf(var + 1e-6f);
    float invn = 1.f / (sqrtf(r2[0]) + 1e-8f);
    for (int i = t; i < EMB; i += 256) {
        float v = sh[i];
        g_hn[(long long)row * EMB + i] = v * invn;
        g_x [(long long)row * EMB + i] = (v - mu) * ri * gma[i] + bta[i];
    }
}

// ---- layernorm (two-pass; eps 1e-6) ----
__global__ void ln_k(const float* __restrict__ x, float* __restrict__ o,
                     const float* __restrict__ gma, const float* __restrict__ bta, int D)
{
    int row = blockIdx.x, t = threadIdx.x;
    const float* xr = x + (long long)row * D;
    __shared__ float red[256];
    __shared__ float s_mu, s_ri;
    float s = 0.f;
    for (int i = t; i < D; i += 256) s += xr[i];
    red[t] = s; __syncthreads();
    for (int st = 128; st > 0; st >>= 1) { if (t < st) red[t] += red[t + st]; __syncthreads(); }
    if (t == 0) s_mu = red[0] / D;
    __syncthreads();
    float mu = s_mu;
    float v = 0.f;
    for (int i = t; i < D; i += 256) { float d = xr[i] - mu; v += d * d; }
    __syncthreads();
    red[t] = v; __syncthreads();
    for (int st = 128; st > 0; st >>= 1) { if (t < st) red[t] += red[t + st]; __syncthreads(); }
    if (t == 0) s_ri = rsqrtf(red[0] / D + 1e-6f);
    __syncthreads();
    float ri = s_ri;
    for (int i = t; i < D; i += 256)
        o[(long long)row * D + i] = (xr[i] - mu) * ri * gma[i] + bta[i];
}

// ---- k-NN: hierarchical warp top-16 ----
__global__ void knn_k()
{
    int row = blockIdx.x;
    int b = row >> 11, i = row & (SEQ - 1);
    const float* dr = g_dist + (long long)row * SEQ;
    int t = threadIdx.x, lane = t & 31, w = t >> 5;

    unsigned long long v[8];
    int base = w * 256;
    #pragma unroll
    for (int r = 0; r < 8; r++) {
        int j = base + r * 32 + lane;
        float d = (j == i) ? 1e9f : (1.f - dr[j]);
        v[r] = ((unsigned long long)__float_as_uint(d) << 32) | (unsigned)j;
    }

    __shared__ unsigned long long cand[128];
    #pragma unroll
    for (int it = 0; it < KNN; it++) {
        unsigned long long m = v[0];
        #pragma unroll
        for (int r = 1; r < 8; r++) m = (v[r] < m) ? v[r] : m;
        #pragma unroll
        for (int s = 16; s > 0; s >>= 1) {
            unsigned long long o = __shfl_xor_sync(0xffffffffu, m, s);
            m = (o < m) ? o : m;
        }
        if (lane == 0) cand[w * KNN + it] = m;
        #pragma unroll
        for (int r = 0; r < 8; r++) if (v[r] == m) v[r] = ~0ull;
    }
    __syncthreads();

    if (w == 0) {
        __shared__ unsigned long long fin[KNN];
        unsigned long long c[4];
        #pragma unroll
        for (int r = 0; r < 4; r++) c[r] = cand[r * 32 + lane];
        #pragma unroll
        for (int it = 0; it < KNN; it++) {
            unsigned long long m01 = (c[0] < c[1]) ? c[0] : c[1];
            unsigned long long m23 = (c[2] < c[3]) ? c[2] : c[3];
            unsigned long long m = (m01 < m23) ? m01 : m23;
            #pragma unroll
            for (int s = 16; s > 0; s >>= 1) {
                unsigned long long o = __shfl_xor_sync(0xffffffffu, m, s);
                m = (o < m) ? o : m;
            }
            if (lane == 0) fin[it] = m;
            #pragma unroll
            for (int r = 0; r < 4; r++) if (c[r] == m) c[r] = ~0ull;
        }
        __syncwarp();
        if (lane < KNN) {
            float d0 = __uint_as_float((unsigned)(fin[0] >> 32));
            float dk = __uint_as_float((unsigned)(fin[lane] >> 32));
            float wk = expf(d0 - dk);
            float sum = wk;
            #pragma unroll
            for (int s = 8; s > 0; s >>= 1) sum += __shfl_xor_sync(0xffffu, sum, s);
            g_knw[row * KNN + lane] = wk / sum;
            g_kni[row * KNN + lane] = b * SEQ + (int)(fin[lane] & 0xffffffffu);
        }
    }
}

// ---- combined = topo + sum_k w_k * topo[nbr_k] ----
__global__ void combine_k()
{
    int row = blockIdx.x, t = threadIdx.x; // 128 threads
    float acc = g_topo[(long long)row * TT + t];
    #pragma unroll
    for (int k2 = 0; k2 < KNN; k2++)
        acc += g_knw[row * KNN + k2] * g_topo[(long long)g_kni[row * KNN + k2] * TT + t];
    g_comb[(long long)row * TT + t] = acc;
}

// ============================================================================
template<int TRANSB, int TN>
static int smem_bytes() {
    int a = 3 * 128 * 20 * 4;
    int b = TRANSB ? 3 * TN * 20 * 4 : 3 * 16 * (TN + 8) * 4;
    return a + b;
}

extern "C" void kernel_launch(void* const* d_in, const int* in_sizes, int n_in,
                              void* d_out, int out_size)
{
    const float* h      = (const float*)d_in[0];
    const int*   mask   = (const int*)  d_in[1];
    const float* W_topo = (const float*)d_in[2];
    const float* b_topo = (const float*)d_in[3];
    const float* W_m1   = (const float*)d_in[4];
    const float* b_m1   = (const float*)d_in[5];
    const float* W_m2   = (const float*)d_in[6];
    const float* b_m2   = (const float*)d_in[7];
    const float* ln_t_s = (const float*)d_in[8];
    const float* ln_t_b = (const float*)d_in[9];
    const float* W_p1   = (const float*)d_in[10];
    const float* b_p1   = (const float*)d_in[11];
    const float* W_p2   = (const float*)d_in[12];
    const float* b_p2   = (const float*)d_in[13];
    const float* ln1_s  = (const float*)d_in[14];
    const float* ln1_b  = (const float*)d_in[15];
    const float* Wq     = (const float*)d_in[16];
    const float* Wk     = (const float*)d_in[17];
    const float* Wv     = (const float*)d_in[18];
    const float* W_gate = (const float*)d_in[19];
    const float* b_gate = (const float*)d_in[20];
    const float* W_o    = (const float*)d_in[21];
    const float* b_o    = (const float*)d_in[22];
    const float* ln2_s  = (const float*)d_in[23];
    const float* ln2_b  = (const float*)d_in[24];
    const float* W_f1   = (const float*)d_in[25];
    const float* b_f1   = (const float*)d_in[26];
    const float* W_f2   = (const float*)d_in[27];
    const float* b_f2   = (const float*)d_in[28];
    float* out = (float*)d_out;

    float *hn, *x, *topo, *comb, *tmp256, *tt, *q, *k, *v, *ctx, *cat, *h1, *y, *ff, *dist;
    cudaGetSymbolAddress((void**)&hn,     g_hn);
    cudaGetSymbolAddress((void**)&x,      g_x);
    cudaGetSymbolAddress((void**)&topo,   g_topo);
    cudaGetSymbolAddress((void**)&comb,   g_comb);
    cudaGetSymbolAddress((void**)&tmp256, g_tmp256);
    cudaGetSymbolAddress((void**)&tt,     g_t);
    cudaGetSymbolAddress((void**)&q,      g_q);
    cudaGetSymbolAddress((void**)&k,      g_k);
    cudaGetSymbolAddress((void**)&v,      g_v);
    cudaGetSymbolAddress((void**)&ctx,    g_ctx);
    cudaGetSymbolAddress((void**)&cat,    g_cat);
    cudaGetSymbolAddress((void**)&h1,     g_h1);
    cudaGetSymbolAddress((void**)&y,      g_y);
    cudaGetSymbolAddress((void**)&ff,     g_ff);
    cudaGetSymbolAddress((void**)&dist,   g_dist);

    const long long SE = (long long)SEQ * EMB;
    const long long SS = (long long)SEQ * SEQ;

    const int sm_nn128 = smem_bytes<0, 128>();
    const int sm_tb128 = smem_bytes<1, 128>();
    cudaFuncSetAttribute((const void*)tgemm<0, 0, 128>, cudaFuncAttributeMaxDynamicSharedMemorySize, sm_nn128);
    cudaFuncSetAttribute((const void*)tgemm<0, 1, 128>, cudaFuncAttributeMaxDynamicSharedMemorySize, sm_nn128);
    cudaFuncSetAttribute((const void*)tgemm<0, 2, 128>, cudaFuncAttributeMaxDynamicSharedMemorySize, sm_nn128);
    cudaFuncSetAttribute((const void*)tgemm<0, 3, 128>, cudaFuncAttributeMaxDynamicSharedMemorySize, sm_nn128);
    cudaFuncSetAttribute((const void*)tgemm<1, 0, 128>, cudaFuncAttributeMaxDynamicSharedMemorySize, sm_tb128);
    cudaFuncSetAttribute((const void*)flash_k, cudaFuncAttributeMaxDynamicSharedMemorySize, FS_TOT_BYTES);

    // 1. hn = normalize(h); x = LN1(h)
    l2ln_k<<<BSX, 256>>>(h, ln1_s, ln1_b);

    // 2. topo = h @ W_topo + b_topo
    tgemm<0, 0, 128><<<dim3(1, 32, 1), 256, sm_nn128>>>(h, W_topo, topo, b_topo, nullptr, nullptr,
        EMB, EMB, TT, TT, 0, 0, 1, 0, 0, 0, 0, 0, 0);

    // 3. dist dot[b] = hn[b] @ hn[b]^T
    tgemm<1, 0, 128><<<dim3(16, 16, 2), 256, sm_tb128>>>(hn, hn, dist, nullptr, nullptr, nullptr,
        EMB, EMB, EMB, SEQ, 0, 0, 2, SE, 0, SE, 0, SS, 0);

    // 4. knn + combine
    knn_k<<<BSX, 256>>>();
    combine_k<<<BSX, TT>>>();

    // 5. topo MLP + LN_t
    tgemm<0, 1, 128><<<dim3(2, 32, 1), 256, sm_nn128>>>(comb, W_m1, tmp256, b_m1, nullptr, nullptr,
        TT, TT, 256, 256, 0, 0, 1, 0, 0, 0, 0, 0, 0);
    tgemm<0, 0, 128><<<dim3(1, 32, 1), 256, sm_nn128>>>(tmp256, W_m2, tt, b_m2, nullptr, nullptr,
        256, 256, TT, TT, 0, 0, 1, 0, 0, 0, 0, 0, 0);
    ln_k<<<BSX, 256>>>(tt, tt, ln_t_s, ln_t_b, TT);

    // 6. pf -> cat[:, EMB:]
    tgemm<0, 1, 128><<<dim3(1, 32, 1), 256, sm_nn128>>>(tt, W_p1, tmp256, b_p1, nullptr, nullptr,
        TT, TT, TT, TT, 0, 0, 1, 0, 0, 0, 0, 0, 0);
    tgemm<0, 0, 128><<<dim3(1, 32, 1), 256, sm_nn128>>>(tmp256, W_p2, cat + EMB, b_p2, nullptr, nullptr,
        TT, TT, TT, CATW, 0, 0, 1, 0, 0, 0, 0, 0, 0);

    // 7. q/k/v
    tgemm<0, 0, 128><<<dim3(6, 32, 1), 256, sm_nn128>>>(x, Wq, q, nullptr, nullptr, nullptr,
        EMB, EMB, EMB, EMB, 0, 0, 1, 0, 0, 0, 0, 0, 0);
    tgemm<0, 0, 128><<<dim3(6, 32, 1), 256, sm_nn128>>>(x, Wk, k, nullptr, nullptr, nullptr,
        EMB, EMB, EMB, EMB, 0, 0, 1, 0, 0, 0, 0, 0, 0);
    tgemm<0, 0, 128><<<dim3(6, 32, 1), 256, sm_nn128>>>(x, Wv, v, nullptr, nullptr, nullptr,
        EMB, EMB, EMB, EMB, 0, 0, 1, 0, 0, 0, 0, 0, 0);

    // 8+9+10. fused flash attention -> cat[:, :EMB]
    flash_k<<<dim3(16, BB * NH), 256, FS_TOT_BYTES>>>(q, k, v, mask, cat);

    // 11. gate-mix: ctx = sigmoid(cat@W_gate+b_gate)*ctx_cat + (1-s)*x
    tgemm<0, 3, 128><<<dim3(6, 32, 1), 256, sm_nn128>>>(cat, W_gate, ctx, b_gate, cat, x,
        CATW, CATW, EMB, EMB, CATW, EMB, 1, 0, 0, 0, 0, 0, 0);

    // 12. h1 = h + ctx @ W_o + b_o
    tgemm<0, 0, 128><<<dim3(6, 32, 1), 256, sm_nn128>>>(ctx, W_o, h1, b_o, h, nullptr,
        EMB, EMB, EMB, EMB, EMB, 0, 1, 0, 0, 0, 0, 0, 0);

    // 13. FFN
    ln_k<<<BSX, 256>>>(h1, y, ln2_s, ln2_b, EMB);
    tgemm<0, 2, 128><<<dim3(24, 32, 1), 256, sm_nn128>>>(y, W_f1, ff, b_f1, nullptr, nullptr,
        EMB, EMB, FF, FF, 0, 0, 1, 0, 0, 0, 0, 0, 0);
    tgemm<0, 0, 128><<<dim3(6, 32, 1), 256, sm_nn128>>>(ff, W_f2, out, b_f2, h1, nullptr,
        FF, FF, EMB, EMB, EMB, 0, 1, 0, 0, 0, 0, 0, 0);
}

// round 8
// speedup vs baseline: 1.4539x; 1.2435x over previous
#include <cuda_runtime.h>
#include <cuda_fp16.h>
#include <math.h>
#include <stdint.h>

// ---- problem constants ----
#define BSX 4096   // B*S
#define BB  2
#define SEQ 2048
#define EMB 768
#define TT  128
#define NH  12
#define DHD 64
#define FF  3072
#define KNN 16
#define CATW (EMB + TT)   // 896

// ---- fp32 scratch ----
__device__ float g_x[BSX * EMB];          // LN1(h), fp32 for gate-mix residual
__device__ float g_topo[BSX * TT];
__device__ float g_tt[BSX * TT];          // topo MLP out pre-LN
__device__ float g_h1[BSX * EMB];
__device__ float g_knw[BSX * KNN];
__device__ int   g_kni[BSX * KNN];
__device__ float g_dist[(long long)BB * SEQ * SEQ];   // 33.5 MB

// ---- fp16 scratch ----
__device__ __half g_hh[BSX * EMB];
__device__ __half g_hnh[BSX * EMB];
__device__ __half g_xh[BSX * EMB];
__device__ __half g_combh[BSX * TT];
__device__ __half g_tmp256h[BSX * 256];
__device__ __half g_tth[BSX * TT];
__device__ __half g_qh[BSX * EMB];
__device__ __half g_kh[BSX * EMB];
__device__ __half g_vh[BSX * EMB];
__device__ __half g_cath[BSX * CATW];
__device__ __half g_ctxh[BSX * EMB];
__device__ __half g_yh[BSX * EMB];
__device__ __half g_ffh[(long long)BSX * FF];

// ---- transposed fp16 weights [N][K] ----
__device__ __half g_wt_topo[TT * EMB];
__device__ __half g_wt_m1[256 * TT];
__device__ __half g_wt_m2[TT * 256];
__device__ __half g_wt_p1[TT * TT];
__device__ __half g_wt_p2[TT * TT];
__device__ __half g_wt_q[EMB * EMB];
__device__ __half g_wt_k[EMB * EMB];
__device__ __half g_wt_v[EMB * EMB];
__device__ __half g_wt_gate[EMB * CATW];
__device__ __half g_wt_o[EMB * EMB];
__device__ __half g_wt_f1[FF * EMB];
__device__ __half g_wt_f2[EMB * FF];

__device__ __forceinline__ void mma_f16(float* c, const uint32_t* a, uint32_t b0, uint32_t b1) {
    asm volatile(
        "mma.sync.aligned.m16n8k16.row.col.f32.f16.f16.f32 "
        "{%0,%1,%2,%3},{%4,%5,%6,%7},{%8,%9},{%0,%1,%2,%3};"
        : "+f"(c[0]), "+f"(c[1]), "+f"(c[2]), "+f"(c[3])
        : "r"(a[0]), "r"(a[1]), "r"(a[2]), "r"(a[3]), "r"(b0), "r"(b1));
}

__device__ __forceinline__ void cpa16(void* s, const void* g) {
    unsigned sa = (unsigned)__cvta_generic_to_shared(s);
    asm volatile("cp.async.cg.shared.global [%0], [%1], 16;" :: "r"(sa), "l"(g));
}
__device__ __forceinline__ void cpa_commit() { asm volatile("cp.async.commit_group;"); }
__device__ __forceinline__ void cpa_wait2()  { asm volatile("cp.async.wait_group 2;"); }
__device__ __forceinline__ void cpa_wait1()  { asm volatile("cp.async.wait_group 1;"); }
__device__ __forceinline__ void cpa_wait0()  { asm volatile("cp.async.wait_group 0;"); }

__device__ __forceinline__ uint32_t ldh2(const __half* p) {
    return *(const uint32_t*)p;
}

__device__ __forceinline__ void ldsm2t(uint32_t& b0, uint32_t& b1, const __half* p) {
    uint32_t a = (uint32_t)__cvta_generic_to_shared(p);
    asm volatile("ldmatrix.sync.aligned.m8n8.x2.trans.shared.b16 {%0,%1}, [%2];"
                 : "=r"(b0), "=r"(b1) : "r"(a));
}

// ============================================================================
// fp16 tensor-core GEMM (m16n8k16), cp.async 3-stage pipeline.
// Block tile 128x128, 256 threads, 8 warps (warp tile 32x64).
// A [M,K] fp16 row-major; B [N,K] fp16 row-major (K-major / "transposed").
// ACT: 0 none, 1 relu, 2 gelu, 3 sigmoid-mix (C = s*res + (1-s)*res2).
// CH: write C as half. RH: res pointer is half (used by ACT3).
// Requirements: M%128==0, N%128==0, K%16==0.
// Smem = 36864 B (fits default 48KB carveout).
// ============================================================================
template<int ACT, int CH, int RH>
__global__ void __launch_bounds__(256) hgemm(
    const __half* __restrict__ A, const __half* __restrict__ B,
    void* __restrict__ Cv, const float* __restrict__ bias,
    const void* __restrict__ resv, const float* __restrict__ res2,
    int K, int lda, int ldb, int ldc, int ldr1, int ldr2,
    int zdiv, long long sA1, long long sA2,
    long long sB1, long long sB2, long long sC1, long long sC2)
{
    extern __shared__ __half hs[];
    __half* As = hs;                 // [3][128][24]
    __half* Bs = hs + 3 * 128 * 24;  // [3][128][24]

    int z = blockIdx.z;
    long long zm = z % zdiv, zd = z / zdiv;
    A += zm * sA1 + zd * sA2;
    B += zm * sB1 + zd * sB2;
    long long co = zm * sC1 + zd * sC2;

    const int t    = threadIdx.x;
    const int lane = t & 31;
    const int wid  = t >> 5;
    const int lr   = lane >> 2;
    const int lc   = lane & 3;
    const int wm   = (wid & 3) * 32;
    const int wn   = (wid >> 2) * 64;
    const int bm   = blockIdx.y * 128;
    const int bn   = blockIdx.x * 128;

    float acc[2][8][4];
    #pragma unroll
    for (int mt = 0; mt < 2; mt++)
        #pragma unroll
        for (int nt = 0; nt < 8; nt++)
            #pragma unroll
            for (int i = 0; i < 4; i++) acc[mt][nt][i] = 0.f;

    auto issue = [&](int buf, int k0) {
        int row = t >> 1, kq = (t & 1) * 8;
        cpa16(&As[(buf * 128 + row) * 24 + kq],
              A + (long long)(bm + row) * lda + k0 + kq);
        cpa16(&Bs[(buf * 128 + row) * 24 + kq],
              B + (long long)(bn + row) * ldb + k0 + kq);
        cpa_commit();
    };

    const int iters = K >> 4;
    issue(0, 0);
    issue(1, 16);

    for (int kb = 0; kb < iters; kb++) {
        int nst  = kb + 2;
        int nbuf = nst - (nst / 3) * 3;
        int nk0  = (nst < iters ? nst : iters - 1) << 4;
        issue(nbuf, nk0);
        cpa_wait2();
        __syncthreads();
        int cur = kb - (kb / 3) * 3;
        const __half* Ab = &As[cur * 128 * 24];
        const __half* Bb = &Bs[cur * 128 * 24];

        uint32_t af[2][4];
        #pragma unroll
        for (int mt = 0; mt < 2; mt++) {
            int m = wm + mt * 16 + lr;
            af[mt][0] = ldh2(Ab + m * 24 + 2 * lc);
            af[mt][1] = ldh2(Ab + (m + 8) * 24 + 2 * lc);
            af[mt][2] = ldh2(Ab + m * 24 + 2 * lc + 8);
            af[mt][3] = ldh2(Ab + (m + 8) * 24 + 2 * lc + 8);
        }
        #pragma unroll
        for (int nt = 0; nt < 8; nt++) {
            int n = wn + nt * 8 + lr;
            uint32_t b0 = ldh2(Bb + n * 24 + 2 * lc);
            uint32_t b1 = ldh2(Bb + n * 24 + 2 * lc + 8);
            #pragma unroll
            for (int mt = 0; mt < 2; mt++)
                mma_f16(acc[mt][nt], af[mt], b0, b1);
        }
        __syncthreads();
    }

    // epilogue
    const float* res = (const float*)resv;
    const __half* resh = (const __half*)resv;
    #pragma unroll
    for (int mt = 0; mt < 2; mt++) {
        #pragma unroll
        for (int nt = 0; nt < 8; nt++) {
            int mrow = bm + wm + mt * 16 + lr;
            int ncol = bn + wn + nt * 8 + 2 * lc;
            #pragma unroll
            for (int half_ = 0; half_ < 2; half_++) {
                int m = mrow + half_ * 8;
                float v0 = acc[mt][nt][half_ * 2 + 0];
                float v1 = acc[mt][nt][half_ * 2 + 1];
                if (bias) { v0 += bias[ncol]; v1 += bias[ncol + 1]; }
                if (ACT == 1) { v0 = fmaxf(v0, 0.f); v1 = fmaxf(v1, 0.f); }
                if (ACT == 2) {
                    float u = v0;
                    v0 = 0.5f * u * (1.f + tanhf(0.7978845608028654f * (u + 0.044715f * u * u * u)));
                    u = v1;
                    v1 = 0.5f * u * (1.f + tanhf(0.7978845608028654f * (u + 0.044715f * u * u * u)));
                }
                long long off = (long long)m * ldc + ncol + co;
                if (ACT == 3) {
                    float s0 = 1.f / (1.f + expf(-v0));
                    float s1 = 1.f / (1.f + expf(-v1));
                    long long o1 = (long long)m * ldr1 + ncol;
                    long long o2 = (long long)m * ldr2 + ncol;
                    float r1x, r1y;
                    if (RH) {
                        __half2 rh = *(const __half2*)(resh + o1);
                        r1x = __half2float(rh.x); r1y = __half2float(rh.y);
                    } else {
                        float2 r1 = *(const float2*)(res + o1);
                        r1x = r1.x; r1y = r1.y;
                    }
                    float2 r2 = *(const float2*)(res2 + o2);
                    v0 = s0 * r1x + (1.f - s0) * r2.x;
                    v1 = s1 * r1y + (1.f - s1) * r2.y;
                } else if (resv) {
                    float2 r1 = *(const float2*)(res + (long long)m * ldr1 + ncol + co);
                    v0 += r1.x; v1 += r1.y;
                }
                if (CH) {
                    __half2 hv = __floats2half2_rn(v0, v1);
                    *(__half2*)((__half*)Cv + off) = hv;
                } else {
                    float2 o2v = {v0, v1};
                    *(float2*)((float*)Cv + off) = o2v;
                }
            }
        }
    }
}

// ============================================================================
// Flash attention fp16: block = 128 q-rows x one (b,h). 8 warps, 16 q-rows
// each (warp-private stats). K/V fp16 streamed 128-key tiles double-buffered.
// Probs fp16 in warp-private smem. PV B-operand via ldmatrix.x2.trans.
// smem halves: sP[128][136] | sK[2][128][72] | sV[2][128][72] = 108544 B
// ============================================================================
#define FS_P 0
#define FS_K 17408
#define FS_V 35840
#define FS_TOT_BYTES 108544

__global__ void __launch_bounds__(256) flash_k(
    const __half* __restrict__ q, const __half* __restrict__ k,
    const __half* __restrict__ v, const int* __restrict__ mask,
    __half* __restrict__ outc)
{
    extern __shared__ __half fh[];
    __half* sP = fh + FS_P;
    __half* sK = fh + FS_K;
    __half* sV = fh + FS_V;

    const int t = threadIdx.x, lane = t & 31, w = t >> 5;
    const int lr = lane >> 2, lc = lane & 3;
    const int z = blockIdx.y, b = z / NH, hh = z % NH;
    const int bm = blockIdx.x * 128;
    const long long base = (long long)b * SEQ * EMB + hh * DHD;
    const __half* qp = q + base;
    const __half* kp = k + base;
    const __half* vp = v + base;
    const int* mrow = mask + b * SEQ;

    // stage Q tile (128 x 64 halves) into sP cols 0..63  (group 0)
    #pragma unroll
    for (int j = 0; j < 4; j++) {
        int flat = t + j * 256;
        int row = flat >> 3, q8 = (flat & 7) << 3;
        cpa16(&sP[row * 136 + q8], qp + (long long)(bm + row) * EMB + q8);
    }
    cpa_commit();

    auto issueKV = [&](int kt) {
        int buf = kt & 1;
        #pragma unroll
        for (int j = 0; j < 4; j++) {
            int flat = t + j * 256;
            int row = flat >> 3, q8 = (flat & 7) << 3;
            cpa16(&sK[buf * 9216 + row * 72 + q8],
                  kp + (long long)(kt * 128 + row) * EMB + q8);
        }
        #pragma unroll
        for (int j = 0; j < 4; j++) {
            int flat = t + j * 256;
            int row = flat >> 3, q8 = (flat & 7) << 3;
            cpa16(&sV[buf * 9216 + row * 72 + q8],
                  vp + (long long)(kt * 128 + row) * EMB + q8);
        }
        cpa_commit();
    };
    issueKV(0);

    cpa_wait1();
    __syncthreads();

    // Q fragments (4 k16-steps over dh=64)
    const int wq = w * 16;
    uint32_t qf[4][4];
    #pragma unroll
    for (int ks = 0; ks < 4; ks++) {
        qf[ks][0] = ldh2(sP + (wq + lr) * 136 + ks * 16 + 2 * lc);
        qf[ks][1] = ldh2(sP + (wq + lr + 8) * 136 + ks * 16 + 2 * lc);
        qf[ks][2] = ldh2(sP + (wq + lr) * 136 + ks * 16 + 2 * lc + 8);
        qf[ks][3] = ldh2(sP + (wq + lr + 8) * 136 + ks * 16 + 2 * lc + 8);
    }
    __syncthreads();

    float ctx[8][4];
    #pragma unroll
    for (int nt = 0; nt < 8; nt++)
        #pragma unroll
        for (int i = 0; i < 4; i++) ctx[nt][i] = 0.f;
    float m0 = -1e30f, m1 = -1e30f, l0 = 0.f, l1 = 0.f;

    for (int kt = 0; kt < 16; kt++) {
        if (kt + 1 < 16) { issueKV(kt + 1); cpa_wait1(); }
        else             { cpa_wait0(); }
        __syncthreads();
        const __half* bK = &sK[(kt & 1) * 9216];
        const __half* bV = &sV[(kt & 1) * 9216];

        // ---- S = Q K^T ----
        float S[16][4];
        #pragma unroll
        for (int nt = 0; nt < 16; nt++)
            #pragma unroll
            for (int i = 0; i < 4; i++) S[nt][i] = 0.f;
        #pragma unroll
        for (int nt = 0; nt < 16; nt++) {
            #pragma unroll
            for (int ks = 0; ks < 4; ks++) {
                uint32_t b0 = ldh2(bK + (nt * 8 + lr) * 72 + ks * 16 + 2 * lc);
                uint32_t b1 = ldh2(bK + (nt * 8 + lr) * 72 + ks * 16 + 2 * lc + 8);
                mma_f16(S[nt], qf[ks], b0, b1);
            }
        }

        // ---- scale + mask + row max ----
        float nm0 = -1e30f, nm1 = -1e30f;
        #pragma unroll
        for (int nt = 0; nt < 16; nt++) {
            int c0 = kt * 128 + nt * 8 + 2 * lc;
            int2 mg = *(const int2*)&mrow[c0];
            float s0 = S[nt][0] * 0.125f, s1 = S[nt][1] * 0.125f;
            float s2 = S[nt][2] * 0.125f, s3 = S[nt][3] * 0.125f;
            if (mg.x == 0) { s0 = -10000.f; s2 = -10000.f; }
            if (mg.y == 0) { s1 = -10000.f; s3 = -10000.f; }
            S[nt][0] = s0; S[nt][1] = s1; S[nt][2] = s2; S[nt][3] = s3;
            nm0 = fmaxf(nm0, fmaxf(s0, s1));
            nm1 = fmaxf(nm1, fmaxf(s2, s3));
        }
        nm0 = fmaxf(nm0, __shfl_xor_sync(0xffffffffu, nm0, 1));
        nm0 = fmaxf(nm0, __shfl_xor_sync(0xffffffffu, nm0, 2));
        nm1 = fmaxf(nm1, __shfl_xor_sync(0xffffffffu, nm1, 1));
        nm1 = fmaxf(nm1, __shfl_xor_sync(0xffffffffu, nm1, 2));
        float M0 = fmaxf(m0, nm0), M1 = fmaxf(m1, nm1);
        float a0 = expf(m0 - M0), a1 = expf(m1 - M1);

        // ---- exp, row sum, store P (fp16) ----
        float r0 = 0.f, r1 = 0.f;
        #pragma unroll
        for (int nt = 0; nt < 16; nt++) {
            float p0 = expf(S[nt][0] - M0), p1 = expf(S[nt][1] - M0);
            float p2 = expf(S[nt][2] - M1), p3 = expf(S[nt][3] - M1);
            r0 += p0 + p1; r1 += p2 + p3;
            *(__half2*)(sP + (wq + lr) * 136 + nt * 8 + 2 * lc)     = __floats2half2_rn(p0, p1);
            *(__half2*)(sP + (wq + lr + 8) * 136 + nt * 8 + 2 * lc) = __floats2half2_rn(p2, p3);
        }
        r0 += __shfl_xor_sync(0xffffffffu, r0, 1);
        r0 += __shfl_xor_sync(0xffffffffu, r0, 2);
        r1 += __shfl_xor_sync(0xffffffffu, r1, 1);
        r1 += __shfl_xor_sync(0xffffffffu, r1, 2);
        l0 = l0 * a0 + r0;
        l1 = l1 * a1 + r1;
        m0 = M0; m1 = M1;
        #pragma unroll
        for (int nt = 0; nt < 8; nt++) {
            ctx[nt][0] *= a0; ctx[nt][1] *= a0;
            ctx[nt][2] *= a1; ctx[nt][3] *= a1;
        }
        __syncwarp();

        // ---- ctx += P V : 8 k16-steps over keys, 8 n8-tiles over dh ----
        #pragma unroll
        for (int ks = 0; ks < 8; ks++) {
            uint32_t af[4];
            af[0] = ldh2(sP + (wq + lr) * 136 + ks * 16 + 2 * lc);
            af[1] = ldh2(sP + (wq + lr + 8) * 136 + ks * 16 + 2 * lc);
            af[2] = ldh2(sP + (wq + lr) * 136 + ks * 16 + 2 * lc + 8);
            af[3] = ldh2(sP + (wq + lr + 8) * 136 + ks * 16 + 2 * lc + 8);
            #pragma unroll
            for (int nt = 0; nt < 8; nt++) {
                uint32_t b0, b1;
                ldsm2t(b0, b1, bV + (ks * 16 + (lane & 15)) * 72 + nt * 8);
                mma_f16(ctx[nt], af, b0, b1);
            }
        }
        __syncthreads();
    }

    // ---- epilogue: normalize, write half2 into cat[:, :EMB] ----
    float il0 = 1.f / l0, il1 = 1.f / l1;
    #pragma unroll
    for (int nt = 0; nt < 8; nt++) {
        long long row0 = (long long)b * SEQ + bm + wq + lr;
        int col = hh * DHD + nt * 8 + 2 * lc;
        *(__half2*)&outc[row0 * CATW + col] = __floats2half2_rn(ctx[nt][0] * il0, ctx[nt][1] * il0);
        *(__half2*)&outc[(row0 + 8) * CATW + col] = __floats2half2_rn(ctx[nt][2] * il1, ctx[nt][3] * il1);
    }
}

// ---- weight transpose + fp32->fp16: in [K][N] -> out [N][K] ----
__global__ void wt_k(const float* __restrict__ in, __half* __restrict__ out, int K, int N)
{
    __shared__ float tile[32][33];
    int bx = blockIdx.x * 32, by = blockIdx.y * 32;
    int tx = threadIdx.x, ty = threadIdx.y;
    #pragma unroll
    for (int j = ty; j < 32; j += 8)
        tile[j][tx] = in[(long long)(by + j) * N + bx + tx];
    __syncthreads();
    #pragma unroll
    for (int j = ty; j < 32; j += 8)
        out[(long long)(bx + j) * K + by + tx] = __float2half(tile[tx][j]);
}

// ---- fp32 -> fp16 bulk convert (4 elems/thread) ----
__global__ void f2h4_k(const float* __restrict__ in, __half* __restrict__ out, int n4)
{
    int i = blockIdx.x * 256 + threadIdx.x;
    if (i < n4) {
        float4 f = ((const float4*)in)[i];
        ((__half2*)out)[i * 2]     = __floats2half2_rn(f.x, f.y);
        ((__half2*)out)[i * 2 + 1] = __floats2half2_rn(f.z, f.w);
    }
}

// ---- fused: hn_h = fp16(h/(||h||+1e-8)) ; x = LN1(h) fp32 + fp16 ----
__global__ void l2ln_k(const float* __restrict__ h,
                       const float* __restrict__ gma, const float* __restrict__ bta)
{
    int row = blockIdx.x, t = threadIdx.x;
    const float* xr = h + (long long)row * EMB;
    __shared__ float sh[EMB];
    __shared__ float r1[256], r2[256];
    float s = 0.f, ss = 0.f;
    for (int i = t; i < EMB; i += 256) { float v = xr[i]; sh[i] = v; s += v; ss += v * v; }
    r1[t] = s; r2[t] = ss; __syncthreads();
    for (int st = 128; st > 0; st >>= 1) {
        if (t < st) { r1[t] += r1[t + st]; r2[t] += r2[t + st]; }
        __syncthreads();
    }
    float mu   = r1[0] / EMB;
    float var  = r2[0] / EMB - mu * mu;
    float ri   = rsqrtf(var + 1e-6f);
    float invn = 1.f / (sqrtf(r2[0]) + 1e-8f);
    for (int i = t; i < EMB; i += 256) {
        float v = sh[i];
        g_hnh[(long long)row * EMB + i] = __float2half(v * invn);
        float xo = (v - mu) * ri * gma[i] + bta[i];
        g_x [(long long)row * EMB + i] = xo;
        g_xh[(long long)row * EMB + i] = __float2half(xo);
    }
}

// ---- layernorm -> fp16 output ----
__global__ void lnh_k(const float* __restrict__ x, __half* __restrict__ oh,
                      const float* __restrict__ gma, const float* __restrict__ bta, int D)
{
    int row = blockIdx.x, t = threadIdx.x;
    const float* xr = x + (long long)row * D;
    __shared__ float red[256];
    __shared__ float s_mu, s_ri;
    float s = 0.f;
    for (int i = t; i < D; i += 256) s += xr[i];
    red[t] = s; __syncthreads();
    for (int st = 128; st > 0; st >>= 1) { if (t < st) red[t] += red[t + st]; __syncthreads(); }
    if (t == 0) s_mu = red[0] / D;
    __syncthreads();
    float mu = s_mu;
    float v = 0.f;
    for (int i = t; i < D; i += 256) { float d = xr[i] - mu; v += d * d; }
    __syncthreads();
    red[t] = v; __syncthreads();
    for (int st = 128; st > 0; st >>= 1) { if (t < st) red[t] += red[t + st]; __syncthreads(); }
    if (t == 0) s_ri = rsqrtf(red[0] / D + 1e-6f);
    __syncthreads();
    float ri = s_ri;
    for (int i = t; i < D; i += 256)
        oh[(long long)row * D + i] = __float2half((xr[i] - mu) * ri * gma[i] + bta[i]);
}

// ---- k-NN: hierarchical warp top-16 ----
__global__ void knn_k()
{
    int row = blockIdx.x;
    int b = row >> 11, i = row & (SEQ - 1);
    const float* dr = g_dist + (long long)row * SEQ;
    int t = threadIdx.x, lane = t & 31, w = t >> 5;

    unsigned long long v[8];
    int base = w * 256;
    #pragma unroll
    for (int r = 0; r < 8; r++) {
        int j = base + r * 32 + lane;
        float d = (j == i) ? 1e9f : (1.f - dr[j]);
        v[r] = ((unsigned long long)__float_as_uint(d) << 32) | (unsigned)j;
    }

    __shared__ unsigned long long cand[128];
    #pragma unroll
    for (int it = 0; it < KNN; it++) {
        unsigned long long m = v[0];
        #pragma unroll
        for (int r = 1; r < 8; r++) m = (v[r] < m) ? v[r] : m;
        #pragma unroll
        for (int s = 16; s > 0; s >>= 1) {
            unsigned long long o = __shfl_xor_sync(0xffffffffu, m, s);
            m = (o < m) ? o : m;
        }
        if (lane == 0) cand[w * KNN + it] = m;
        #pragma unroll
        for (int r = 0; r < 8; r++) if (v[r] == m) v[r] = ~0ull;
    }
    __syncthreads();

    if (w == 0) {
        __shared__ unsigned long long fin[KNN];
        unsigned long long c[4];
        #pragma unroll
        for (int r = 0; r < 4; r++) c[r] = cand[r * 32 + lane];
        #pragma unroll
        for (int it = 0; it < KNN; it++) {
            unsigned long long m01 = (c[0] < c[1]) ? c[0] : c[1];
            unsigned long long m23 = (c[2] < c[3]) ? c[2] : c[3];
            unsigned long long m = (m01 < m23) ? m01 : m23;
            #pragma unroll
            for (int s = 16; s > 0; s >>= 1) {
                unsigned long long o = __shfl_xor_sync(0xffffffffu, m, s);
                m = (o < m) ? o : m;
            }
            if (lane == 0) fin[it] = m;
            #pragma unroll
            for (int r = 0; r < 4; r++) if (c[r] == m) c[r] = ~0ull;
        }
        __syncwarp();
        if (lane < KNN) {
            float d0 = __uint_as_float((unsigned)(fin[0] >> 32));
            float dk = __uint_as_float((unsigned)(fin[lane] >> 32));
            float wk = expf(d0 - dk);
            float sum = wk;
            #pragma unroll
            for (int s = 8; s > 0; s >>= 1) sum += __shfl_xor_sync(0xffffu, sum, s);
            g_knw[row * KNN + lane] = wk / sum;
            g_kni[row * KNN + lane] = b * SEQ + (int)(fin[lane] & 0xffffffffu);
        }
    }
}

// ---- combined = topo + sum_k w_k * topo[nbr_k]  -> fp16 ----
__global__ void combine_k()
{
    int row = blockIdx.x, t = threadIdx.x; // 128 threads
    float acc = g_topo[(long long)row * TT + t];
    #pragma unroll
    for (int k2 = 0; k2 < KNN; k2++)
        acc += g_knw[row * KNN + k2] * g_topo[(long long)g_kni[row * KNN + k2] * TT + t];
    g_combh[(long long)row * TT + t] = __float2half(acc);
}

// ============================================================================
#define HG_SMEM (3 * 128 * 24 * 2 * 2)   // 36864 B

extern "C" void kernel_launch(void* const* d_in, const int* in_sizes, int n_in,
                              void* d_out, int out_size)
{
    const float* h      = (const float*)d_in[0];
    const int*   mask   = (const int*)  d_in[1];
    const float* W_topo = (const float*)d_in[2];
    const float* b_topo = (const float*)d_in[3];
    const float* W_m1   = (const float*)d_in[4];
    const float* b_m1   = (const float*)d_in[5];
    const float* W_m2   = (const float*)d_in[6];
    const float* b_m2   = (const float*)d_in[7];
    const float* ln_t_s = (const float*)d_in[8];
    const float* ln_t_b = (const float*)d_in[9];
    const float* W_p1   = (const float*)d_in[10];
    const float* b_p1   = (const float*)d_in[11];
    const float* W_p2   = (const float*)d_in[12];
    const float* b_p2   = (const float*)d_in[13];
    const float* ln1_s  = (const float*)d_in[14];
    const float* ln1_b  = (const float*)d_in[15];
    const float* Wq     = (const float*)d_in[16];
    const float* Wk     = (const float*)d_in[17];
    const float* Wv     = (const float*)d_in[18];
    const float* W_gate = (const float*)d_in[19];
    const float* b_gate = (const float*)d_in[20];
    const float* W_o    = (const float*)d_in[21];
    const float* b_o    = (const float*)d_in[22];
    const float* ln2_s  = (const float*)d_in[23];
    const float* ln2_b  = (const float*)d_in[24];
    const float* W_f1   = (const float*)d_in[25];
    const float* b_f1   = (const float*)d_in[26];
    const float* W_f2   = (const float*)d_in[27];
    const float* b_f2   = (const float*)d_in[28];
    float* out = (float*)d_out;

    float *x, *topo, *tt, *h1, *dist;
    __half *hh, *hnh, *xh, *combh, *tmp256h, *tth, *qh, *kh, *vh, *cath, *ctxh, *yh, *ffh;
    __half *wt_topo, *wt_m1, *wt_m2, *wt_p1, *wt_p2, *wt_q, *wt_k_, *wt_v, *wt_gate, *wt_o, *wt_f1, *wt_f2;
    cudaGetSymbolAddress((void**)&x,       g_x);
    cudaGetSymbolAddress((void**)&topo,    g_topo);
    cudaGetSymbolAddress((void**)&tt,      g_tt);
    cudaGetSymbolAddress((void**)&h1,      g_h1);
    cudaGetSymbolAddress((void**)&dist,    g_dist);
    cudaGetSymbolAddress((void**)&hh,      g_hh);
    cudaGetSymbolAddress((void**)&hnh,     g_hnh);
    cudaGetSymbolAddress((void**)&xh,      g_xh);
    cudaGetSymbolAddress((void**)&combh,   g_combh);
    cudaGetSymbolAddress((void**)&tmp256h, g_tmp256h);
    cudaGetSymbolAddress((void**)&tth,     g_tth);
    cudaGetSymbolAddress((void**)&qh,      g_qh);
    cudaGetSymbolAddress((void**)&kh,      g_kh);
    cudaGetSymbolAddress((void**)&vh,      g_vh);
    cudaGetSymbolAddress((void**)&cath,    g_cath);
    cudaGetSymbolAddress((void**)&ctxh,    g_ctxh);
    cudaGetSymbolAddress((void**)&yh,      g_yh);
    cudaGetSymbolAddress((void**)&ffh,     g_ffh);
    cudaGetSymbolAddress((void**)&wt_topo, g_wt_topo);
    cudaGetSymbolAddress((void**)&wt_m1,   g_wt_m1);
    cudaGetSymbolAddress((void**)&wt_m2,   g_wt_m2);
    cudaGetSymbolAddress((void**)&wt_p1,   g_wt_p1);
    cudaGetSymbolAddress((void**)&wt_p2,   g_wt_p2);
    cudaGetSymbolAddress((void**)&wt_q,    g_wt_q);
    cudaGetSymbolAddress((void**)&wt_k_,   g_wt_k);
    cudaGetSymbolAddress((void**)&wt_v,    g_wt_v);
    cudaGetSymbolAddress((void**)&wt_gate, g_wt_gate);
    cudaGetSymbolAddress((void**)&wt_o,    g_wt_o);
    cudaGetSymbolAddress((void**)&wt_f1,   g_wt_f1);
    cudaGetSymbolAddress((void**)&wt_f2,   g_wt_f2);

    const long long SE = (long long)SEQ * EMB;
    const long long SS = (long long)SEQ * SEQ;

    cudaFuncSetAttribute((const void*)flash_k, cudaFuncAttributeMaxDynamicSharedMemorySize, FS_TOT_BYTES);

    dim3 tb(32, 8);
    // ---- weight transposes (in [K][N] -> out [N][K] fp16) ----
    wt_k<<<dim3(TT / 32, EMB / 32), tb>>>(W_topo, wt_topo, EMB, TT);
    wt_k<<<dim3(256 / 32, TT / 32), tb>>>(W_m1, wt_m1, TT, 256);
    wt_k<<<dim3(TT / 32, 256 / 32), tb>>>(W_m2, wt_m2, 256, TT);
    wt_k<<<dim3(TT / 32, TT / 32), tb>>>(W_p1, wt_p1, TT, TT);
    wt_k<<<dim3(TT / 32, TT / 32), tb>>>(W_p2, wt_p2, TT, TT);
    wt_k<<<dim3(EMB / 32, EMB / 32), tb>>>(Wq, wt_q, EMB, EMB);
    wt_k<<<dim3(EMB / 32, EMB / 32), tb>>>(Wk, wt_k_, EMB, EMB);
    wt_k<<<dim3(EMB / 32, EMB / 32), tb>>>(Wv, wt_v, EMB, EMB);
    wt_k<<<dim3(EMB / 32, CATW / 32), tb>>>(W_gate, wt_gate, CATW, EMB);
    wt_k<<<dim3(EMB / 32, EMB / 32), tb>>>(W_o, wt_o, EMB, EMB);
    wt_k<<<dim3(FF / 32, EMB / 32), tb>>>(W_f1, wt_f1, EMB, FF);
    wt_k<<<dim3(EMB / 32, FF / 32), tb>>>(W_f2, wt_f2, FF, EMB);

    // ---- h -> fp16 ----
    f2h4_k<<<(BSX * EMB / 4 + 255) / 256, 256>>>(h, hh, BSX * EMB / 4);

    // 1. hn_h = normalize(h); x = LN1(h) (fp32 + fp16)
    l2ln_k<<<BSX, 256>>>(h, ln1_s, ln1_b);

    // 2. topo = h @ W_topo + b_topo  (fp32 out, feeds combine gather)
    hgemm<0, 0, 0><<<dim3(1, 32, 1), 256, HG_SMEM>>>(hh, wt_topo, topo, b_topo, nullptr, nullptr,
        EMB, EMB, EMB, TT, 0, 0, 1, 0, 0, 0, 0, 0, 0);

    // 3. dist dot[b] = hn[b] @ hn[b]^T
    hgemm<0, 0, 0><<<dim3(16, 16, 2), 256, HG_SMEM>>>(hnh, hnh, dist, nullptr, nullptr, nullptr,
        EMB, EMB, EMB, SEQ, 0, 0, 2, SE, 0, SE, 0, SS, 0);

    // 4. knn + combine (-> fp16)
    knn_k<<<BSX, 256>>>();
    combine_k<<<BSX, TT>>>();

    // 5. topo MLP + LN_t
    hgemm<1, 1, 0><<<dim3(2, 32, 1), 256, HG_SMEM>>>(combh, wt_m1, tmp256h, b_m1, nullptr, nullptr,
        TT, TT, TT, 256, 0, 0, 1, 0, 0, 0, 0, 0, 0);
    hgemm<0, 0, 0><<<dim3(1, 32, 1), 256, HG_SMEM>>>(tmp256h, wt_m2, tt, b_m2, nullptr, nullptr,
        256, 256, 256, TT, 0, 0, 1, 0, 0, 0, 0, 0, 0);
    lnh_k<<<BSX, 256>>>(tt, tth, ln_t_s, ln_t_b, TT);

    // 6. pf -> cat[:, EMB:] (fp16)
    hgemm<1, 1, 0><<<dim3(1, 32, 1), 256, HG_SMEM>>>(tth, wt_p1, tmp256h, b_p1, nullptr, nullptr,
        TT, TT, TT, TT, 0, 0, 1, 0, 0, 0, 0, 0, 0);
    hgemm<0, 1, 0><<<dim3(1, 32, 1), 256, HG_SMEM>>>(tmp256h, wt_p2, cath + EMB, b_p2, nullptr, nullptr,
        TT, TT, TT, CATW, 0, 0, 1, 0, 0, 0, 0, 0, 0);

    // 7. q/k/v (fp16 out)
    hgemm<0, 1, 0><<<dim3(6, 32, 1), 256, HG_SMEM>>>(xh, wt_q, qh, nullptr, nullptr, nullptr,
        EMB, EMB, EMB, EMB, 0, 0, 1, 0, 0, 0, 0, 0, 0);
    hgemm<0, 1, 0><<<dim3(6, 32, 1), 256, HG_SMEM>>>(xh, wt_k_, kh, nullptr, nullptr, nullptr,
        EMB, EMB, EMB, EMB, 0, 0, 1, 0, 0, 0, 0, 0, 0);
    hgemm<0, 1, 0><<<dim3(6, 32, 1), 256, HG_SMEM>>>(xh, wt_v, vh, nullptr, nullptr, nullptr,
        EMB, EMB, EMB, EMB, 0, 0, 1, 0, 0, 0, 0, 0, 0);

    // 8. fused flash attention -> cat[:, :EMB] (fp16)
    flash_k<<<dim3(16, BB * NH), 256, FS_TOT_BYTES>>>(qh, kh, vh, mask, cath);

    // 9. gate-mix: ctx_h = sigmoid(cat@W_gate+b)*cat_ctx + (1-s)*x
    hgemm<3, 1, 1><<<dim3(6, 32, 1), 256, HG_SMEM>>>(cath, wt_gate, ctxh, b_gate, cath, x,
        CATW, CATW, CATW, EMB, CATW, EMB, 1, 0, 0, 0, 0, 0, 0);

    // 10. h1 = h + ctx @ W_o + b_o (fp32)
    hgemm<0, 0, 0><<<dim3(6, 32, 1), 256, HG_SMEM>>>(ctxh, wt_o, h1, b_o, h, nullptr,
        EMB, EMB, EMB, EMB, EMB, 0, 1, 0, 0, 0, 0, 0, 0);

    // 11. FFN
    lnh_k<<<BSX, 256>>>(h1, yh, ln2_s, ln2_b, EMB);
    hgemm<2, 1, 0><<<dim3(24, 32, 1), 256, HG_SMEM>>>(yh, wt_f1, ffh, b_f1, nullptr, nullptr,
        EMB, EMB, EMB, FF, 0, 0, 1, 0, 0, 0, 0, 0, 0);
    hgemm<0, 0, 0><<<dim3(6, 32, 1), 256, HG_SMEM>>>(ffh, wt_f2, out, b_f2, h1, nullptr,
        FF, FF, FF, EMB, EMB, 0, 1, 0, 0, 0, 0, 0, 0);
}

// round 9
// speedup vs baseline: 1.6643x; 1.1447x over previous
#include <cuda_runtime.h>
#include <cuda_fp16.h>
#include <math.h>
#include <stdint.h>

// ---- problem constants ----
#define BSX 4096   // B*S
#define BB  2
#define SEQ 2048
#define EMB 768
#define TT  128
#define NH  12
#define DHD 64
#define FF  3072
#define KNN 16
#define CATW (EMB + TT)   // 896
#define QKVW (3 * EMB)    // 2304

// ---- fp32 scratch ----
__device__ float g_x[BSX * EMB];
__device__ float g_topo[BSX * TT];
__device__ float g_tt[BSX * TT];
__device__ float g_h1[BSX * EMB];
__device__ float g_knw[BSX * KNN];
__device__ int   g_kni[BSX * KNN];
__device__ float g_dist[(long long)BB * SEQ * SEQ];

// ---- fp16 scratch ----
__device__ __half g_hh[BSX * EMB];
__device__ __half g_hnh[BSX * EMB];
__device__ __half g_xh[BSX * EMB];
__device__ __half g_combh[BSX * TT];
__device__ __half g_tmp256h[BSX * 256];
__device__ __half g_tth[BSX * TT];
__device__ __half g_qkvh[(long long)BSX * QKVW];
__device__ __half g_cath[BSX * CATW];
__device__ __half g_ctxh[BSX * EMB];
__device__ __half g_yh[BSX * EMB];
__device__ __half g_ffh[(long long)BSX * FF];

// ---- transposed fp16 weights [N][K] ----
__device__ __half g_wt_topo[TT * EMB];
__device__ __half g_wt_m1[256 * TT];
__device__ __half g_wt_m2[TT * 256];
__device__ __half g_wt_p1[TT * TT];
__device__ __half g_wt_p2[TT * TT];
__device__ __half g_wt_qkv[QKVW * EMB];
__device__ __half g_wt_gate[EMB * CATW];
__device__ __half g_wt_o[EMB * EMB];
__device__ __half g_wt_f1[FF * EMB];
__device__ __half g_wt_f2[EMB * FF];

__device__ __forceinline__ void mma_f16(float* c, const uint32_t* a, uint32_t b0, uint32_t b1) {
    asm volatile(
        "mma.sync.aligned.m16n8k16.row.col.f32.f16.f16.f32 "
        "{%0,%1,%2,%3},{%4,%5,%6,%7},{%8,%9},{%0,%1,%2,%3};"
        : "+f"(c[0]), "+f"(c[1]), "+f"(c[2]), "+f"(c[3])
        : "r"(a[0]), "r"(a[1]), "r"(a[2]), "r"(a[3]), "r"(b0), "r"(b1));
}

__device__ __forceinline__ void cpa16(void* s, const void* g) {
    unsigned sa = (unsigned)__cvta_generic_to_shared(s);
    asm volatile("cp.async.cg.shared.global [%0], [%1], 16;" :: "r"(sa), "l"(g));
}
__device__ __forceinline__ void cpa_commit() { asm volatile("cp.async.commit_group;"); }
__device__ __forceinline__ void cpa_wait2()  { asm volatile("cp.async.wait_group 2;"); }
__device__ __forceinline__ void cpa_wait1()  { asm volatile("cp.async.wait_group 1;"); }
__device__ __forceinline__ void cpa_wait0()  { asm volatile("cp.async.wait_group 0;"); }

__device__ __forceinline__ uint32_t ldh2(const __half* p) {
    return *(const uint32_t*)p;
}

__device__ __forceinline__ void ldsm2t(uint32_t& b0, uint32_t& b1, const __half* p) {
    uint32_t a = (uint32_t)__cvta_generic_to_shared(p);
    asm volatile("ldmatrix.sync.aligned.m8n8.x2.trans.shared.b16 {%0,%1}, [%2];"
                 : "=r"(b0), "=r"(b1) : "r"(a));
}

// ============================================================================
// fp16 tensor-core GEMM (m16n8k16), cp.async 3-stage pipeline.
// Block tile 128x128, 256 threads, 8 warps (warp tile 32x64).
// A [M,K] fp16 row-major; B [N,K] fp16 row-major (K-major).
// ACT: 0 none, 1 relu, 2 gelu, 3 sigmoid-mix. CH: C half. RH: res half (ACT3).
// ============================================================================
template<int ACT, int CH, int RH>
__global__ void __launch_bounds__(256) hgemm(
    const __half* __restrict__ A, const __half* __restrict__ B,
    void* __restrict__ Cv, const float* __restrict__ bias,
    const void* __restrict__ resv, const float* __restrict__ res2,
    int K, int lda, int ldb, int ldc, int ldr1, int ldr2,
    int zdiv, long long sA1, long long sA2,
    long long sB1, long long sB2, long long sC1, long long sC2)
{
    extern __shared__ __half hs[];
    __half* As = hs;                 // [3][128][24]
    __half* Bs = hs + 3 * 128 * 24;  // [3][128][24]

    int z = blockIdx.z;
    long long zm = z % zdiv, zd = z / zdiv;
    A += zm * sA1 + zd * sA2;
    B += zm * sB1 + zd * sB2;
    long long co = zm * sC1 + zd * sC2;

    const int t    = threadIdx.x;
    const int lane = t & 31;
    const int wid  = t >> 5;
    const int lr   = lane >> 2;
    const int lc   = lane & 3;
    const int wm   = (wid & 3) * 32;
    const int wn   = (wid >> 2) * 64;
    const int bm   = blockIdx.y * 128;
    const int bn   = blockIdx.x * 128;

    float acc[2][8][4];
    #pragma unroll
    for (int mt = 0; mt < 2; mt++)
        #pragma unroll
        for (int nt = 0; nt < 8; nt++)
            #pragma unroll
            for (int i = 0; i < 4; i++) acc[mt][nt][i] = 0.f;

    auto issue = [&](int buf, int k0) {
        int row = t >> 1, kq = (t & 1) * 8;
        cpa16(&As[(buf * 128 + row) * 24 + kq],
              A + (long long)(bm + row) * lda + k0 + kq);
        cpa16(&Bs[(buf * 128 + row) * 24 + kq],
              B + (long long)(bn + row) * ldb + k0 + kq);
        cpa_commit();
    };

    const int iters = K >> 4;
    issue(0, 0);
    issue(1, 16);

    for (int kb = 0; kb < iters; kb++) {
        int nst  = kb + 2;
        int nbuf = nst - (nst / 3) * 3;
        int nk0  = (nst < iters ? nst : iters - 1) << 4;
        issue(nbuf, nk0);
        cpa_wait2();
        __syncthreads();
        int cur = kb - (kb / 3) * 3;
        const __half* Ab = &As[cur * 128 * 24];
        const __half* Bb = &Bs[cur * 128 * 24];

        uint32_t af[2][4];
        #pragma unroll
        for (int mt = 0; mt < 2; mt++) {
            int m = wm + mt * 16 + lr;
            af[mt][0] = ldh2(Ab + m * 24 + 2 * lc);
            af[mt][1] = ldh2(Ab + (m + 8) * 24 + 2 * lc);
            af[mt][2] = ldh2(Ab + m * 24 + 2 * lc + 8);
            af[mt][3] = ldh2(Ab + (m + 8) * 24 + 2 * lc + 8);
        }
        #pragma unroll
        for (int nt = 0; nt < 8; nt++) {
            int n = wn + nt * 8 + lr;
            uint32_t b0 = ldh2(Bb + n * 24 + 2 * lc);
            uint32_t b1 = ldh2(Bb + n * 24 + 2 * lc + 8);
            #pragma unroll
            for (int mt = 0; mt < 2; mt++)
                mma_f16(acc[mt][nt], af[mt], b0, b1);
        }
        __syncthreads();
    }

    // epilogue
    const float* res = (const float*)resv;
    const __half* resh = (const __half*)resv;
    #pragma unroll
    for (int mt = 0; mt < 2; mt++) {
        #pragma unroll
        for (int nt = 0; nt < 8; nt++) {
            int mrow = bm + wm + mt * 16 + lr;
            int ncol = bn + wn + nt * 8 + 2 * lc;
            #pragma unroll
            for (int half_ = 0; half_ < 2; half_++) {
                int m = mrow + half_ * 8;
                float v0 = acc[mt][nt][half_ * 2 + 0];
                float v1 = acc[mt][nt][half_ * 2 + 1];
                if (bias) { v0 += bias[ncol]; v1 += bias[ncol + 1]; }
                if (ACT == 1) { v0 = fmaxf(v0, 0.f); v1 = fmaxf(v1, 0.f); }
                if (ACT == 2) {
                    float u = v0;
                    v0 = 0.5f * u * (1.f + tanhf(0.7978845608028654f * (u + 0.044715f * u * u * u)));
                    u = v1;
                    v1 = 0.5f * u * (1.f + tanhf(0.7978845608028654f * (u + 0.044715f * u * u * u)));
                }
                long long off = (long long)m * ldc + ncol + co;
                if (ACT == 3) {
                    float s0 = 1.f / (1.f + expf(-v0));
                    float s1 = 1.f / (1.f + expf(-v1));
                    long long o1 = (long long)m * ldr1 + ncol;
                    long long o2 = (long long)m * ldr2 + ncol;
                    float r1x, r1y;
                    if (RH) {
                        __half2 rh = *(const __half2*)(resh + o1);
                        r1x = __half2float(rh.x); r1y = __half2float(rh.y);
                    } else {
                        float2 r1 = *(const float2*)(res + o1);
                        r1x = r1.x; r1y = r1.y;
                    }
                    float2 r2 = *(const float2*)(res2 + o2);
                    v0 = s0 * r1x + (1.f - s0) * r2.x;
                    v1 = s1 * r1y + (1.f - s1) * r2.y;
                } else if (resv) {
                    float2 r1 = *(const float2*)(res + (long long)m * ldr1 + ncol + co);
                    v0 += r1.x; v1 += r1.y;
                }
                if (CH) {
                    __half2 hv = __floats2half2_rn(v0, v1);
                    *(__half2*)((__half*)Cv + off) = hv;
                } else {
                    float2 o2v = {v0, v1};
                    *(float2*)((float*)Cv + off) = o2v;
                }
            }
        }
    }
}

// ============================================================================
// Flash attention fp16 over fused qkv buffer [BSX][2304].
// smem: sP[128][136] | sK[2][128][72] | sV[2][128][72] = 108544 B
// ============================================================================
#define FS_P 0
#define FS_K 17408
#define FS_V 35840
#define FS_TOT_BYTES 108544

__global__ void __launch_bounds__(256) flash_k(
    const __half* __restrict__ qkv, const int* __restrict__ mask,
    __half* __restrict__ outc)
{
    extern __shared__ __half fh[];
    __half* sP = fh + FS_P;
    __half* sK = fh + FS_K;
    __half* sV = fh + FS_V;

    const int t = threadIdx.x, lane = t & 31, w = t >> 5;
    const int lr = lane >> 2, lc = lane & 3;
    const int z = blockIdx.y, b = z / NH, hh = z % NH;
    const int bm = blockIdx.x * 128;
    const long long base = (long long)b * SEQ * QKVW + hh * DHD;
    const __half* qp = qkv + base;
    const __half* kp = qkv + base + EMB;
    const __half* vp = qkv + base + 2 * EMB;
    const int* mrow = mask + b * SEQ;

    #pragma unroll
    for (int j = 0; j < 4; j++) {
        int flat = t + j * 256;
        int row = flat >> 3, q8 = (flat & 7) << 3;
        cpa16(&sP[row * 136 + q8], qp + (long long)(bm + row) * QKVW + q8);
    }
    cpa_commit();

    auto issueKV = [&](int kt) {
        int buf = kt & 1;
        #pragma unroll
        for (int j = 0; j < 4; j++) {
            int flat = t + j * 256;
            int row = flat >> 3, q8 = (flat & 7) << 3;
            cpa16(&sK[buf * 9216 + row * 72 + q8],
                  kp + (long long)(kt * 128 + row) * QKVW + q8);
        }
        #pragma unroll
        for (int j = 0; j < 4; j++) {
            int flat = t + j * 256;
            int row = flat >> 3, q8 = (flat & 7) << 3;
            cpa16(&sV[buf * 9216 + row * 72 + q8],
                  vp + (long long)(kt * 128 + row) * QKVW + q8);
        }
        cpa_commit();
    };
    issueKV(0);

    cpa_wait1();
    __syncthreads();

    const int wq = w * 16;
    uint32_t qf[4][4];
    #pragma unroll
    for (int ks = 0; ks < 4; ks++) {
        qf[ks][0] = ldh2(sP + (wq + lr) * 136 + ks * 16 + 2 * lc);
        qf[ks][1] = ldh2(sP + (wq + lr + 8) * 136 + ks * 16 + 2 * lc);
        qf[ks][2] = ldh2(sP + (wq + lr) * 136 + ks * 16 + 2 * lc + 8);
        qf[ks][3] = ldh2(sP + (wq + lr + 8) * 136 + ks * 16 + 2 * lc + 8);
    }
    __syncthreads();

    float ctx[8][4];
    #pragma unroll
    for (int nt = 0; nt < 8; nt++)
        #pragma unroll
        for (int i = 0; i < 4; i++) ctx[nt][i] = 0.f;
    float m0 = -1e30f, m1 = -1e30f, l0 = 0.f, l1 = 0.f;

    for (int kt = 0; kt < 16; kt++) {
        if (kt + 1 < 16) { issueKV(kt + 1); cpa_wait1(); }
        else             { cpa_wait0(); }
        __syncthreads();
        const __half* bK = &sK[(kt & 1) * 9216];
        const __half* bV = &sV[(kt & 1) * 9216];

        float S[16][4];
        #pragma unroll
        for (int nt = 0; nt < 16; nt++)
            #pragma unroll
            for (int i = 0; i < 4; i++) S[nt][i] = 0.f;
        #pragma unroll
        for (int nt = 0; nt < 16; nt++) {
            #pragma unroll
            for (int ks = 0; ks < 4; ks++) {
                uint32_t b0 = ldh2(bK + (nt * 8 + lr) * 72 + ks * 16 + 2 * lc);
                uint32_t b1 = ldh2(bK + (nt * 8 + lr) * 72 + ks * 16 + 2 * lc + 8);
                mma_f16(S[nt], qf[ks], b0, b1);
            }
        }

        float nm0 = -1e30f, nm1 = -1e30f;
        #pragma unroll
        for (int nt = 0; nt < 16; nt++) {
            int c0 = kt * 128 + nt * 8 + 2 * lc;
            int2 mg = *(const int2*)&mrow[c0];
            float s0 = S[nt][0] * 0.125f, s1 = S[nt][1] * 0.125f;
            float s2 = S[nt][2] * 0.125f, s3 = S[nt][3] * 0.125f;
            if (mg.x == 0) { s0 = -10000.f; s2 = -10000.f; }
            if (mg.y == 0) { s1 = -10000.f; s3 = -10000.f; }
            S[nt][0] = s0; S[nt][1] = s1; S[nt][2] = s2; S[nt][3] = s3;
            nm0 = fmaxf(nm0, fmaxf(s0, s1));
            nm1 = fmaxf(nm1, fmaxf(s2, s3));
        }
        nm0 = fmaxf(nm0, __shfl_xor_sync(0xffffffffu, nm0, 1));
        nm0 = fmaxf(nm0, __shfl_xor_sync(0xffffffffu, nm0, 2));
        nm1 = fmaxf(nm1, __shfl_xor_sync(0xffffffffu, nm1, 1));
        nm1 = fmaxf(nm1, __shfl_xor_sync(0xffffffffu, nm1, 2));
        float M0 = fmaxf(m0, nm0), M1 = fmaxf(m1, nm1);
        float a0 = expf(m0 - M0), a1 = expf(m1 - M1);

        float r0 = 0.f, r1 = 0.f;
        #pragma unroll
        for (int nt = 0; nt < 16; nt++) {
            float p0 = expf(S[nt][0] - M0), p1 = expf(S[nt][1] - M0);
            float p2 = expf(S[nt][2] - M1), p3 = expf(S[nt][3] - M1);
            r0 += p0 + p1; r1 += p2 + p3;
            *(__half2*)(sP + (wq + lr) * 136 + nt * 8 + 2 * lc)     = __floats2half2_rn(p0, p1);
            *(__half2*)(sP + (wq + lr + 8) * 136 + nt * 8 + 2 * lc) = __floats2half2_rn(p2, p3);
        }
        r0 += __shfl_xor_sync(0xffffffffu, r0, 1);
        r0 += __shfl_xor_sync(0xffffffffu, r0, 2);
        r1 += __shfl_xor_sync(0xffffffffu, r1, 1);
        r1 += __shfl_xor_sync(0xffffffffu, r1, 2);
        l0 = l0 * a0 + r0;
        l1 = l1 * a1 + r1;
        m0 = M0; m1 = M1;
        #pragma unroll
        for (int nt = 0; nt < 8; nt++) {
            ctx[nt][0] *= a0; ctx[nt][1] *= a0;
            ctx[nt][2] *= a1; ctx[nt][3] *= a1;
        }
        __syncwarp();

        #pragma unroll
        for (int ks = 0; ks < 8; ks++) {
            uint32_t af[4];
            af[0] = ldh2(sP + (wq + lr) * 136 + ks * 16 + 2 * lc);
            af[1] = ldh2(sP + (wq + lr + 8) * 136 + ks * 16 + 2 * lc);
            af[2] = ldh2(sP + (wq + lr) * 136 + ks * 16 + 2 * lc + 8);
            af[3] = ldh2(sP + (wq + lr + 8) * 136 + ks * 16 + 2 * lc + 8);
            #pragma unroll
            for (int nt = 0; nt < 8; nt++) {
                uint32_t b0, b1;
                ldsm2t(b0, b1, bV + (ks * 16 + (lane & 15)) * 72 + nt * 8);
                mma_f16(ctx[nt], af, b0, b1);
            }
        }
        __syncthreads();
    }

    float il0 = 1.f / l0, il1 = 1.f / l1;
    #pragma unroll
    for (int nt = 0; nt < 8; nt++) {
        long long row0 = (long long)b * SEQ + bm + wq + lr;
        int col = hh * DHD + nt * 8 + 2 * lc;
        *(__half2*)&outc[row0 * CATW + col] = __floats2half2_rn(ctx[nt][0] * il0, ctx[nt][1] * il0);
        *(__half2*)&outc[(row0 + 8) * CATW + col] = __floats2half2_rn(ctx[nt][2] * il1, ctx[nt][3] * il1);
    }
}

// ---- weight transpose + fp32->fp16: in [K][N] -> out [N][K] ----
__global__ void wt_k(const float* __restrict__ in, __half* __restrict__ out, int K, int N)
{
    __shared__ float tile[32][33];
    int bx = blockIdx.x * 32, by = blockIdx.y * 32;
    int tx = threadIdx.x, ty = threadIdx.y;
    #pragma unroll
    for (int j = ty; j < 32; j += 8)
        tile[j][tx] = in[(long long)(by + j) * N + bx + tx];
    __syncthreads();
    #pragma unroll
    for (int j = ty; j < 32; j += 8)
        out[(long long)(bx + j) * K + by + tx] = __float2half(tile[tx][j]);
}

// ---- fp32 -> fp16 bulk convert ----
__global__ void f2h4_k(const float* __restrict__ in, __half* __restrict__ out, int n4)
{
    int i = blockIdx.x * 256 + threadIdx.x;
    if (i < n4) {
        float4 f = ((const float4*)in)[i];
        ((__half2*)out)[i * 2]     = __floats2half2_rn(f.x, f.y);
        ((__half2*)out)[i * 2 + 1] = __floats2half2_rn(f.z, f.w);
    }
}

// ---- fused: hn_h = fp16(h/(||h||+1e-8)) ; x = LN1(h) fp32 + fp16 ----
__global__ void l2ln_k(const float* __restrict__ h,
                       const float* __restrict__ gma, const float* __restrict__ bta)
{
    int row = blockIdx.x, t = threadIdx.x;
    const float* xr = h + (long long)row * EMB;
    __shared__ float sh[EMB];
    __shared__ float r1[256], r2[256];
    float s = 0.f, ss = 0.f;
    for (int i = t; i < EMB; i += 256) { float v = xr[i]; sh[i] = v; s += v; ss += v * v; }
    r1[t] = s; r2[t] = ss; __syncthreads();
    for (int st = 128; st > 0; st >>= 1) {
        if (t < st) { r1[t] += r1[t + st]; r2[t] += r2[t + st]; }
        __syncthreads();
    }
    float mu   = r1[0] / EMB;
    float var  = r2[0] / EMB - mu * mu;
    float ri   = rsqrtf(var + 1e-6f);
    float invn = 1.f / (sqrtf(r2[0]) + 1e-8f);
    for (int i = t; i < EMB; i += 256) {
        float v = sh[i];
        g_hnh[(long long)row * EMB + i] = __float2half(v * invn);
        float xo = (v - mu) * ri * gma[i] + bta[i];
        g_x [(long long)row * EMB + i] = xo;
        g_xh[(long long)row * EMB + i] = __float2half(xo);
    }
}

// ---- layernorm -> fp16 output ----
__global__ void lnh_k(const float* __restrict__ x, __half* __restrict__ oh,
                      const float* __restrict__ gma, const float* __restrict__ bta, int D)
{
    int row = blockIdx.x, t = threadIdx.x;
    const float* xr = x + (long long)row * D;
    __shared__ float red[256];
    __shared__ float s_mu, s_ri;
    float s = 0.f;
    for (int i = t; i < D; i += 256) s += xr[i];
    red[t] = s; __syncthreads();
    for (int st = 128; st > 0; st >>= 1) { if (t < st) red[t] += red[t + st]; __syncthreads(); }
    if (t == 0) s_mu = red[0] / D;
    __syncthreads();
    float mu = s_mu;
    float v = 0.f;
    for (int i = t; i < D; i += 256) { float d = xr[i] - mu; v += d * d; }
    __syncthreads();
    red[t] = v; __syncthreads();
    for (int st = 128; st > 0; st >>= 1) { if (t < st) red[t] += red[t + st]; __syncthreads(); }
    if (t == 0) s_ri = rsqrtf(red[0] / D + 1e-6f);
    __syncthreads();
    float ri = s_ri;
    for (int i = t; i < D; i += 256)
        oh[(long long)row * D + i] = __float2half((xr[i] - mu) * ri * gma[i] + bta[i]);
}

// ---- k-NN: hierarchical warp top-16 ----
__global__ void knn_k()
{
    int row = blockIdx.x;
    int b = row >> 11, i = row & (SEQ - 1);
    const float* dr = g_dist + (long long)row * SEQ;
    int t = threadIdx.x, lane = t & 31, w = t >> 5;

    unsigned long long v[8];
    int base = w * 256;
    #pragma unroll
    for (int r = 0; r < 8; r++) {
        int j = base + r * 32 + lane;
        float d = (j == i) ? 1e9f : (1.f - dr[j]);
        v[r] = ((unsigned long long)__float_as_uint(d) << 32) | (unsigned)j;
    }

    __shared__ unsigned long long cand[128];
    #pragma unroll
    for (int it = 0; it < KNN; it++) {
        unsigned long long m = v[0];
        #pragma unroll
        for (int r = 1; r < 8; r++) m = (v[r] < m) ? v[r] : m;
        #pragma unroll
        for (int s = 16; s > 0; s >>= 1) {
            unsigned long long o = __shfl_xor_sync(0xffffffffu, m, s);
            m = (o < m) ? o : m;
        }
        if (lane == 0) cand[w * KNN + it] = m;
        #pragma unroll
        for (int r = 0; r < 8; r++) if (v[r] == m) v[r] = ~0ull;
    }
    __syncthreads();

    if (w == 0) {
        __shared__ unsigned long long fin[KNN];
        unsigned long long c[4];
        #pragma unroll
        for (int r = 0; r < 4; r++) c[r] = cand[r * 32 + lane];
        #pragma unroll
        for (int it = 0; it < KNN; it++) {
            unsigned long long m01 = (c[0] < c[1]) ? c[0] : c[1];
            unsigned long long m23 = (c[2] < c[3]) ? c[2] : c[3];
            unsigned long long m = (m01 < m23) ? m01 : m23;
            #pragma unroll
            for (int s = 16; s > 0; s >>= 1) {
                unsigned long long o = __shfl_xor_sync(0xffffffffu, m, s);
                m = (o < m) ? o : m;
            }
            if (lane == 0) fin[it] = m;
            #pragma unroll
            for (int r = 0; r < 4; r++) if (c[r] == m) c[r] = ~0ull;
        }
        __syncwarp();
        if (lane < KNN) {
            float d0 = __uint_as_float((unsigned)(fin[0] >> 32));
            float dk = __uint_as_float((unsigned)(fin[lane] >> 32));
            float wk = expf(d0 - dk);
            float sum = wk;
            #pragma unroll
            for (int s = 8; s > 0; s >>= 1) sum += __shfl_xor_sync(0xffffu, sum, s);
            g_knw[row * KNN + lane] = wk / sum;
            g_kni[row * KNN + lane] = b * SEQ + (int)(fin[lane] & 0xffffffffu);
        }
    }
}

// ---- combined = topo + sum_k w_k * topo[nbr_k]  -> fp16 ----
__global__ void combine_k()
{
    int row = blockIdx.x, t = threadIdx.x;
    float acc = g_topo[(long long)row * TT + t];
    #pragma unroll
    for (int k2 = 0; k2 < KNN; k2++)
        acc += g_knw[row * KNN + k2] * g_topo[(long long)g_kni[row * KNN + k2] * TT + t];
    g_combh[(long long)row * TT + t] = __float2half(acc);
}

// ============================================================================
#define HG_SMEM (3 * 128 * 24 * 2 * 2)   // 36864 B

extern "C" void kernel_launch(void* const* d_in, const int* in_sizes, int n_in,
                              void* d_out, int out_size)
{
    const float* h      = (const float*)d_in[0];
    const int*   mask   = (const int*)  d_in[1];
    const float* W_topo = (const float*)d_in[2];
    const float* b_topo = (const float*)d_in[3];
    const float* W_m1   = (const float*)d_in[4];
    const float* b_m1   = (const float*)d_in[5];
    const float* W_m2   = (const float*)d_in[6];
    const float* b_m2   = (const float*)d_in[7];
    const float* ln_t_s = (const float*)d_in[8];
    const float* ln_t_b = (const float*)d_in[9];
    const float* W_p1   = (const float*)d_in[10];
    const float* b_p1   = (const float*)d_in[11];
    const float* W_p2   = (const float*)d_in[12];
    const float* b_p2   = (const float*)d_in[13];
    const float* ln1_s  = (const float*)d_in[14];
    const float* ln1_b  = (const float*)d_in[15];
    const float* Wq     = (const float*)d_in[16];
    const float* Wk     = (const float*)d_in[17];
    const float* Wv     = (const float*)d_in[18];
    const float* W_gate = (const float*)d_in[19];
    const float* b_gate = (const float*)d_in[20];
    const float* W_o    = (const float*)d_in[21];
    const float* b_o    = (const float*)d_in[22];
    const float* ln2_s  = (const float*)d_in[23];
    const float* ln2_b  = (const float*)d_in[24];
    const float* W_f1   = (const float*)d_in[25];
    const float* b_f1   = (const float*)d_in[26];
    const float* W_f2   = (const float*)d_in[27];
    const float* b_f2   = (const float*)d_in[28];
    float* out = (float*)d_out;

    float *x, *topo, *tt, *h1, *dist;
    __half *hh, *hnh, *xh, *combh, *tmp256h, *tth, *qkvh, *cath, *ctxh, *yh, *ffh;
    __half *wt_topo, *wt_m1, *wt_m2, *wt_p1, *wt_p2, *wt_qkv, *wt_gate, *wt_o, *wt_f1, *wt_f2;
    cudaGetSymbolAddress((void**)&x,       g_x);
    cudaGetSymbolAddress((void**)&topo,    g_topo);
    cudaGetSymbolAddress((void**)&tt,      g_tt);
    cudaGetSymbolAddress((void**)&h1,      g_h1);
    cudaGetSymbolAddress((void**)&dist,    g_dist);
    cudaGetSymbolAddress((void**)&hh,      g_hh);
    cudaGetSymbolAddress((void**)&hnh,     g_hnh);
    cudaGetSymbolAddress((void**)&xh,      g_xh);
    cudaGetSymbolAddress((void**)&combh,   g_combh);
    cudaGetSymbolAddress((void**)&tmp256h, g_tmp256h);
    cudaGetSymbolAddress((void**)&tth,     g_tth);
    cudaGetSymbolAddress((void**)&qkvh,    g_qkvh);
    cudaGetSymbolAddress((void**)&cath,    g_cath);
    cudaGetSymbolAddress((void**)&ctxh,    g_ctxh);
    cudaGetSymbolAddress((void**)&yh,      g_yh);
    cudaGetSymbolAddress((void**)&ffh,     g_ffh);
    cudaGetSymbolAddress((void**)&wt_topo, g_wt_topo);
    cudaGetSymbolAddress((void**)&wt_m1,   g_wt_m1);
    cudaGetSymbolAddress((void**)&wt_m2,   g_wt_m2);
    cudaGetSymbolAddress((void**)&wt_p1,   g_wt_p1);
    cudaGetSymbolAddress((void**)&wt_p2,   g_wt_p2);
    cudaGetSymbolAddress((void**)&wt_qkv,  g_wt_qkv);
    cudaGetSymbolAddress((void**)&wt_gate, g_wt_gate);
    cudaGetSymbolAddress((void**)&wt_o,    g_wt_o);
    cudaGetSymbolAddress((void**)&wt_f1,   g_wt_f1);
    cudaGetSymbolAddress((void**)&wt_f2,   g_wt_f2);

    const long long SE = (long long)SEQ * EMB;
    const long long SS = (long long)SEQ * SEQ;

    cudaFuncSetAttribute((const void*)flash_k, cudaFuncAttributeMaxDynamicSharedMemorySize, FS_TOT_BYTES);

    // ---- streams/events (created once, outside any capture) ----
    static cudaStream_t st1 = nullptr, st2 = nullptr;
    static cudaEvent_t e_fork, e_ln, e_b1, e_w2;
    if (!st1) {
        cudaStreamCreateWithFlags(&st1, cudaStreamNonBlocking);
        cudaStreamCreateWithFlags(&st2, cudaStreamNonBlocking);
        cudaEventCreateWithFlags(&e_fork, cudaEventDisableTiming);
        cudaEventCreateWithFlags(&e_ln,   cudaEventDisableTiming);
        cudaEventCreateWithFlags(&e_b1,   cudaEventDisableTiming);
        cudaEventCreateWithFlags(&e_w2,   cudaEventDisableTiming);
    }

    dim3 tb(32, 8);

    // ---- fork ----
    cudaEventRecord(e_fork, 0);
    cudaStreamWaitEvent(st1, e_fork, 0);
    cudaStreamWaitEvent(st2, e_fork, 0);

    // ---- s0: LN1 + l2norm (needed by both branches' GEMM inputs) ----
    l2ln_k<<<BSX, 256>>>(h, ln1_s, ln1_b);
    cudaEventRecord(e_ln, 0);

    // ---- s2: tail weight transposes ----
    wt_k<<<dim3(EMB / 32, CATW / 32), tb, 0, st2>>>(W_gate, wt_gate, CATW, EMB);
    wt_k<<<dim3(EMB / 32, EMB / 32),  tb, 0, st2>>>(W_o, wt_o, EMB, EMB);
    wt_k<<<dim3(FF / 32, EMB / 32),   tb, 0, st2>>>(W_f1, wt_f1, EMB, FF);
    wt_k<<<dim3(EMB / 32, FF / 32),   tb, 0, st2>>>(W_f2, wt_f2, FF, EMB);
    cudaEventRecord(e_w2, st2);

    // ---- s1: topo branch ----
    wt_k<<<dim3(TT / 32, EMB / 32), tb, 0, st1>>>(W_topo, wt_topo, EMB, TT);
    wt_k<<<dim3(256 / 32, TT / 32), tb, 0, st1>>>(W_m1, wt_m1, TT, 256);
    wt_k<<<dim3(TT / 32, 256 / 32), tb, 0, st1>>>(W_m2, wt_m2, 256, TT);
    wt_k<<<dim3(TT / 32, TT / 32),  tb, 0, st1>>>(W_p1, wt_p1, TT, TT);
    wt_k<<<dim3(TT / 32, TT / 32),  tb, 0, st1>>>(W_p2, wt_p2, TT, TT);
    f2h4_k<<<(BSX * EMB / 4 + 255) / 256, 256, 0, st1>>>(h, hh, BSX * EMB / 4);
    hgemm<0, 0, 0><<<dim3(1, 32, 1), 256, HG_SMEM, st1>>>(hh, wt_topo, topo, b_topo, nullptr, nullptr,
        EMB, EMB, EMB, TT, 0, 0, 1, 0, 0, 0, 0, 0, 0);
    cudaStreamWaitEvent(st1, e_ln, 0);
    hgemm<0, 0, 0><<<dim3(16, 16, 2), 256, HG_SMEM, st1>>>(hnh, hnh, dist, nullptr, nullptr, nullptr,
        EMB, EMB, EMB, SEQ, 0, 0, 2, SE, 0, SE, 0, SS, 0);
    knn_k<<<BSX, 256, 0, st1>>>();
    combine_k<<<BSX, TT, 0, st1>>>();
    hgemm<1, 1, 0><<<dim3(2, 32, 1), 256, HG_SMEM, st1>>>(combh, wt_m1, tmp256h, b_m1, nullptr, nullptr,
        TT, TT, TT, 256, 0, 0, 1, 0, 0, 0, 0, 0, 0);
    hgemm<0, 0, 0><<<dim3(1, 32, 1), 256, HG_SMEM, st1>>>(tmp256h, wt_m2, tt, b_m2, nullptr, nullptr,
        256, 256, 256, TT, 0, 0, 1, 0, 0, 0, 0, 0, 0);
    lnh_k<<<BSX, 256, 0, st1>>>(tt, tth, ln_t_s, ln_t_b, TT);
    hgemm<1, 1, 0><<<dim3(1, 32, 1), 256, HG_SMEM, st1>>>(tth, wt_p1, tmp256h, b_p1, nullptr, nullptr,
        TT, TT, TT, TT, 0, 0, 1, 0, 0, 0, 0, 0, 0);
    hgemm<0, 1, 0><<<dim3(1, 32, 1), 256, HG_SMEM, st1>>>(tmp256h, wt_p2, cath + EMB, b_p2, nullptr, nullptr,
        TT, TT, TT, CATW, 0, 0, 1, 0, 0, 0, 0, 0, 0);
    cudaEventRecord(e_b1, st1);

    // ---- s0: attention branch (fused QKV) ----
    wt_k<<<dim3(EMB / 32, EMB / 32), tb>>>(Wq, wt_qkv, EMB, EMB);
    wt_k<<<dim3(EMB / 32, EMB / 32), tb>>>(Wk, wt_qkv + (long long)EMB * EMB, EMB, EMB);
    wt_k<<<dim3(EMB / 32, EMB / 32), tb>>>(Wv, wt_qkv + 2LL * EMB * EMB, EMB, EMB);
    hgemm<0, 1, 0><<<dim3(QKVW / 128, 32, 1), 256, HG_SMEM>>>(xh, wt_qkv, qkvh, nullptr, nullptr, nullptr,
        EMB, EMB, EMB, QKVW, 0, 0, 1, 0, 0, 0, 0, 0, 0);
    flash_k<<<dim3(16, BB * NH), 256, FS_TOT_BYTES>>>(qkvh, mask, cath);

    // ---- join ----
    cudaStreamWaitEvent(0, e_b1, 0);
    cudaStreamWaitEvent(0, e_w2, 0);

    // ---- tail ----
    hgemm<3, 1, 1><<<dim3(6, 32, 1), 256, HG_SMEM>>>(cath, wt_gate, ctxh, b_gate, cath, x,
        CATW, CATW, CATW, EMB, CATW, EMB, 1, 0, 0, 0, 0, 0, 0);
    hgemm<0, 0, 0><<<dim3(6, 32, 1), 256, HG_SMEM>>>(ctxh, wt_o, h1, b_o, h, nullptr,
        EMB, EMB, EMB, EMB, EMB, 0, 1, 0, 0, 0, 0, 0, 0);
    lnh_k<<<BSX, 256>>>(h1, yh, ln2_s, ln2_b, EMB);
    hgemm<2, 1, 0><<<dim3(24, 32, 1), 256, HG_SMEM>>>(yh, wt_f1, ffh, b_f1, nullptr, nullptr,
        EMB, EMB, EMB, FF, 0, 0, 1, 0, 0, 0, 0, 0, 0);
    hgemm<0, 0, 0><<<dim3(6, 32, 1), 256, HG_SMEM>>>(ffh, wt_f2, out, b_f2, h1, nullptr,
        FF, FF, FF, EMB, EMB, 0, 1, 0, 0, 0, 0, 0, 0);
}

// round 11
// speedup vs baseline: 2.1084x; 1.2668x over previous
#include <cuda_runtime.h>
#include <cuda_fp16.h>
#include <math.h>
#include <stdint.h>

// ---- problem constants ----
#define BSX 4096   // B*S
#define BB  2
#define SEQ 2048
#define EMB 768
#define TT  128
#define NH  12
#define DHD 64
#define FF  3072
#define KNN 16
#define CATW (EMB + TT)   // 896
#define QKVW (3 * EMB)    // 2304

// ---- fp32 scratch ----
__device__ float g_x[BSX * EMB];
__device__ float g_topo[BSX * TT];
__device__ float g_tt[BSX * TT];
__device__ float g_h1[BSX * EMB];
__device__ float g_dist[(long long)BB * SEQ * SEQ];

// ---- fp16 scratch ----
__device__ __half g_hh[BSX * EMB];
__device__ __half g_hnh[BSX * EMB];
__device__ __half g_xh[BSX * EMB];
__device__ __half g_combh[BSX * TT];
__device__ __half g_tmp256h[BSX * 256];
__device__ __half g_tth[BSX * TT];
__device__ __half g_qkvh[(long long)BSX * QKVW];
__device__ __half g_cath[BSX * CATW];
__device__ __half g_ctxh[BSX * EMB];
__device__ __half g_yh[BSX * EMB];
__device__ __half g_ffh[(long long)BSX * FF];

// ---- transposed fp16 weights [N][K] ----
__device__ __half g_wt_topo[TT * EMB];
__device__ __half g_wt_m1[256 * TT];
__device__ __half g_wt_m2[TT * 256];
__device__ __half g_wt_p1[TT * TT];
__device__ __half g_wt_p2[TT * TT];
__device__ __half g_wt_qkv[QKVW * EMB];
__device__ __half g_wt_gate[EMB * CATW];
__device__ __half g_wt_o[EMB * EMB];
__device__ __half g_wt_f1[FF * EMB];
__device__ __half g_wt_f2[EMB * FF];

__device__ __forceinline__ void mma_f16(float* c, const uint32_t* a, uint32_t b0, uint32_t b1) {
    asm volatile(
        "mma.sync.aligned.m16n8k16.row.col.f32.f16.f16.f32 "
        "{%0,%1,%2,%3},{%4,%5,%6,%7},{%8,%9},{%0,%1,%2,%3};"
        : "+f"(c[0]), "+f"(c[1]), "+f"(c[2]), "+f"(c[3])
        : "r"(a[0]), "r"(a[1]), "r"(a[2]), "r"(a[3]), "r"(b0), "r"(b1));
}

__device__ __forceinline__ void cpa16(void* s, const void* g) {
    unsigned sa = (unsigned)__cvta_generic_to_shared(s);
    asm volatile("cp.async.cg.shared.global [%0], [%1], 16;" :: "r"(sa), "l"(g));
}
__device__ __forceinline__ void cpa_commit() { asm volatile("cp.async.commit_group;"); }
__device__ __forceinline__ void cpa_wait1()  { asm volatile("cp.async.wait_group 1;"); }
__device__ __forceinline__ void cpa_wait0()  { asm volatile("cp.async.wait_group 0;"); }

__device__ __forceinline__ uint32_t ldh2(const __half* p) {
    return *(const uint32_t*)p;
}

__device__ __forceinline__ void ldsm4(uint32_t* r, uint32_t addr) {
    asm volatile("ldmatrix.sync.aligned.m8n8.x4.shared.b16 {%0,%1,%2,%3}, [%4];"
                 : "=r"(r[0]), "=r"(r[1]), "=r"(r[2]), "=r"(r[3]) : "r"(addr));
}

__device__ __forceinline__ void ldsm2t(uint32_t& b0, uint32_t& b1, const __half* p) {
    uint32_t a = (uint32_t)__cvta_generic_to_shared(p);
    asm volatile("ldmatrix.sync.aligned.m8n8.x2.trans.shared.b16 {%0,%1}, [%2];"
                 : "=r"(b0), "=r"(b1) : "r"(a));
}

// ============================================================================
// fp16 tensor-core GEMM (m16n8k16), cp.async 3-stage pipeline, ldmatrix
// fragment loads, ONE __syncthreads per k16 stage (issue-after-compute).
// Block tile 128x128, 256 threads, 8 warps (warp tile 32x64).
// A [M,K] fp16 row-major; B [N,K] fp16 row-major (K-major).
// ACT: 0 none, 1 relu, 2 gelu, 3 sigmoid-mix. CH: C half. RH: res half (ACT3).
// ============================================================================
#define HSTG (128 * 24)   // halves per stage per operand

template<int ACT, int CH, int RH>
__global__ void __launch_bounds__(256) hgemm(
    const __half* __restrict__ A, const __half* __restrict__ B,
    void* __restrict__ Cv, const float* __restrict__ bias,
    const void* __restrict__ resv, const float* __restrict__ res2,
    int K, int lda, int ldb, int ldc, int ldr1, int ldr2,
    int zdiv, long long sA1, long long sA2,
    long long sB1, long long sB2, long long sC1, long long sC2)
{
    extern __shared__ __half hs[];
    __half* As = hs;                 // [3][128][24]
    __half* Bs = hs + 3 * HSTG;      // [3][128][24]

    int z = blockIdx.z;
    long long zm = z % zdiv, zd = z / zdiv;
    A += zm * sA1 + zd * sA2;
    B += zm * sB1 + zd * sB2;
    long long co = zm * sC1 + zd * sC2;

    const int t    = threadIdx.x;
    const int lane = t & 31;
    const int wid  = t >> 5;
    const int lr   = lane >> 2;
    const int lc   = lane & 3;
    const int wm   = (wid & 3) * 32;
    const int wn   = (wid >> 2) * 64;
    const int bm   = blockIdx.y * 128;
    const int bn   = blockIdx.x * 128;

    const uint32_t sbase = (uint32_t)__cvta_generic_to_shared(hs);
    // per-lane ldmatrix byte offsets (row pitch 24 halves = 48 B)
    const uint32_t offA = (uint32_t)((lane & 15) * 48 + (lane >> 4) * 16);
    const uint32_t offB = (uint32_t)((((lane >> 4) & 1) * 8 + (lane & 7)) * 48 + ((lane >> 3) & 1) * 16);

    float acc[2][8][4];
    #pragma unroll
    for (int mt = 0; mt < 2; mt++)
        #pragma unroll
        for (int nt = 0; nt < 8; nt++)
            #pragma unroll
            for (int i = 0; i < 4; i++) acc[mt][nt][i] = 0.f;

    auto issue = [&](int buf, int k0) {
        int row = t >> 1, kq = (t & 1) * 8;
        cpa16(&As[buf * HSTG + row * 24 + kq],
              A + (long long)(bm + row) * lda + k0 + kq);
        cpa16(&Bs[buf * HSTG + row * 24 + kq],
              B + (long long)(bn + row) * ldb + k0 + kq);
        cpa_commit();
    };

    const int iters = K >> 4;
    issue(0, 0);
    issue(1, 16);

    for (int kb = 0; kb < iters; kb++) {
        cpa_wait1();
        __syncthreads();
        int cur = kb - (kb / 3) * 3;
        uint32_t aB = sbase + (uint32_t)cur * (HSTG * 2);
        uint32_t bB = sbase + (uint32_t)(3 + cur) * (HSTG * 2);

        uint32_t af[2][4];
        #pragma unroll
        for (int mt = 0; mt < 2; mt++)
            ldsm4(af[mt], aB + (wm + mt * 16) * 48 + offA);

        #pragma unroll
        for (int p = 0; p < 4; p++) {
            uint32_t bb[4];
            ldsm4(bb, bB + (wn + p * 16) * 48 + offB);
            #pragma unroll
            for (int sub = 0; sub < 2; sub++)
                #pragma unroll
                for (int mt = 0; mt < 2; mt++)
                    mma_f16(acc[mt][p * 2 + sub], af[mt], bb[sub * 2], bb[sub * 2 + 1]);
        }

        int nst  = kb + 2;
        int nbuf = nst - (nst / 3) * 3;
        int nk0  = (nst < iters ? nst : iters - 1) << 4;
        issue(nbuf, nk0);
    }

    // epilogue
    const float* res = (const float*)resv;
    const __half* resh = (const __half*)resv;
    #pragma unroll
    for (int mt = 0; mt < 2; mt++) {
        #pragma unroll
        for (int nt = 0; nt < 8; nt++) {
            int mrow = bm + wm + mt * 16 + lr;
            int ncol = bn + wn + nt * 8 + 2 * lc;
            #pragma unroll
            for (int half_ = 0; half_ < 2; half_++) {
                int m = mrow + half_ * 8;
                float v0 = acc[mt][nt][half_ * 2 + 0];
                float v1 = acc[mt][nt][half_ * 2 + 1];
                if (bias) { v0 += bias[ncol]; v1 += bias[ncol + 1]; }
                if (ACT == 1) { v0 = fmaxf(v0, 0.f); v1 = fmaxf(v1, 0.f); }
                if (ACT == 2) {
                    float u = v0;
                    v0 = 0.5f * u * (1.f + tanhf(0.7978845608028654f * (u + 0.044715f * u * u * u)));
                    u = v1;
                    v1 = 0.5f * u * (1.f + tanhf(0.7978845608028654f * (u + 0.044715f * u * u * u)));
                }
                long long off = (long long)m * ldc + ncol + co;
                if (ACT == 3) {
                    float s0 = 1.f / (1.f + expf(-v0));
                    float s1 = 1.f / (1.f + expf(-v1));
                    long long o1 = (long long)m * ldr1 + ncol;
                    long long o2 = (long long)m * ldr2 + ncol;
                    float r1x, r1y;
                    if (RH) {
                        __half2 rh = *(const __half2*)(resh + o1);
                        r1x = __half2float(rh.x); r1y = __half2float(rh.y);
                    } else {
                        float2 r1 = *(const float2*)(res + o1);
                        r1x = r1.x; r1y = r1.y;
                    }
                    float2 r2 = *(const float2*)(res2 + o2);
                    v0 = s0 * r1x + (1.f - s0) * r2.x;
                    v1 = s1 * r1y + (1.f - s1) * r2.y;
                } else if (resv) {
                    float2 r1 = *(const float2*)(res + (long long)m * ldr1 + ncol + co);
                    v0 += r1.x; v1 += r1.y;
                }
                if (CH) {
                    __half2 hv = __floats2half2_rn(v0, v1);
                    *(__half2*)((__half*)Cv + off) = hv;
                } else {
                    float2 o2v = {v0, v1};
                    *(float2*)((float*)Cv + off) = o2v;
                }
            }
        }
    }
}

// ============================================================================
// Flash attention fp16 over fused qkv buffer [BSX][2304], ldmatrix loads,
// one block sync per kt stage.
// smem: sP[128][136] | sK[2][128][72] | sV[2][128][72] = 108544 B
// ============================================================================
#define FS_P 0
#define FS_K 17408
#define FS_V 35840
#define FS_TOT_BYTES 108544

__global__ void __launch_bounds__(256) flash_k(
    const __half* __restrict__ qkv, const int* __restrict__ mask,
    __half* __restrict__ outc)
{
    extern __shared__ __half fh[];
    __half* sP = fh + FS_P;
    __half* sK = fh + FS_K;
    __half* sV = fh + FS_V;

    const int t = threadIdx.x, lane = t & 31, w = t >> 5;
    const int lr = lane >> 2, lc = lane & 3;
    const int z = blockIdx.y, b = z / NH, hh = z % NH;
    const int bm = blockIdx.x * 128;
    const long long base = (long long)b * SEQ * QKVW + hh * DHD;
    const __half* qp = qkv + base;
    const __half* kp = qkv + base + EMB;
    const __half* vp = qkv + base + 2 * EMB;
    const int* mrow = mask + b * SEQ;

    const uint32_t fbase = (uint32_t)__cvta_generic_to_shared(fh);
    const uint32_t pbase = fbase;                   // sP
    const uint32_t kbase = fbase + FS_K * 2;        // sK
    // ldmatrix lane offsets: K pitch 72 halves = 144 B; P pitch 136 halves = 272 B
    const uint32_t offK = (uint32_t)((((lane >> 4) & 1) * 8 + (lane & 7)) * 144 + ((lane >> 3) & 1) * 16);
    const uint32_t offP = (uint32_t)((lane & 15) * 272 + (lane >> 4) * 16);

    #pragma unroll
    for (int j = 0; j < 4; j++) {
        int flat = t + j * 256;
        int row = flat >> 3, q8 = (flat & 7) << 3;
        cpa16(&sP[row * 136 + q8], qp + (long long)(bm + row) * QKVW + q8);
    }
    cpa_commit();

    auto issueKV = [&](int kt) {
        int buf = kt & 1;
        #pragma unroll
        for (int j = 0; j < 4; j++) {
            int flat = t + j * 256;
            int row = flat >> 3, q8 = (flat & 7) << 3;
            cpa16(&sK[buf * 9216 + row * 72 + q8],
                  kp + (long long)(kt * 128 + row) * QKVW + q8);
        }
        #pragma unroll
        for (int j = 0; j < 4; j++) {
            int flat = t + j * 256;
            int row = flat >> 3, q8 = (flat & 7) << 3;
            cpa16(&sV[buf * 9216 + row * 72 + q8],
                  vp + (long long)(kt * 128 + row) * QKVW + q8);
        }
        cpa_commit();
    };
    issueKV(0);

    cpa_wait1();    // Q staged
    __syncthreads();

    const int wq = w * 16;
    uint32_t qf[4][4];
    #pragma unroll
    for (int ks = 0; ks < 4; ks++)
        ldsm4(qf[ks], pbase + (uint32_t)wq * 272 + ks * 32 + offP);
    __syncthreads();   // all warps done reading Q from sP

    float ctx[8][4];
    #pragma unroll
    for (int nt = 0; nt < 8; nt++)
        #pragma unroll
        for (int i = 0; i < 4; i++) ctx[nt][i] = 0.f;
    float m0 = -1e30f, m1 = -1e30f, l0 = 0.f, l1 = 0.f;

    for (int kt = 0; kt < 16; kt++) {
        cpa_wait0();        // KV kt complete (only outstanding group)
        __syncthreads();    // all warps done with previous stage buffers
        if (kt + 1 < 16) issueKV(kt + 1);

        const int buf = kt & 1;
        const uint32_t kB = kbase + (uint32_t)buf * (9216 * 2);
        const __half* bV = &sV[buf * 9216];

        // ---- S = Q K^T ----
        float S[16][4];
        #pragma unroll
        for (int nt = 0; nt < 16; nt++)
            #pragma unroll
            for (int i = 0; i < 4; i++) S[nt][i] = 0.f;
        #pragma unroll
        for (int ks = 0; ks < 4; ks++) {
            #pragma unroll
            for (int p = 0; p < 8; p++) {
                uint32_t bb[4];
                ldsm4(bb, kB + (uint32_t)(p * 16) * 144 + ks * 32 + offK);
                mma_f16(S[p * 2],     qf[ks], bb[0], bb[1]);
                mma_f16(S[p * 2 + 1], qf[ks], bb[2], bb[3]);
            }
        }

        // ---- scale + mask + row max ----
        float nm0 = -1e30f, nm1 = -1e30f;
        #pragma unroll
        for (int nt = 0; nt < 16; nt++) {
            int c0 = kt * 128 + nt * 8 + 2 * lc;
            int2 mg = *(const int2*)&mrow[c0];
            float s0 = S[nt][0] * 0.125f, s1 = S[nt][1] * 0.125f;
            float s2 = S[nt][2] * 0.125f, s3 = S[nt][3] * 0.125f;
            if (mg.x == 0) { s0 = -10000.f; s2 = -10000.f; }
            if (mg.y == 0) { s1 = -10000.f; s3 = -10000.f; }
            S[nt][0] = s0; S[nt][1] = s1; S[nt][2] = s2; S[nt][3] = s3;
            nm0 = fmaxf(nm0, fmaxf(s0, s1));
            nm1 = fmaxf(nm1, fmaxf(s2, s3));
        }
        nm0 = fmaxf(nm0, __shfl_xor_sync(0xffffffffu, nm0, 1));
        nm0 = fmaxf(nm0, __shfl_xor_sync(0xffffffffu, nm0, 2));
        nm1 = fmaxf(nm1, __shfl_xor_sync(0xffffffffu, nm1, 1));
        nm1 = fmaxf(nm1, __shfl_xor_sync(0xffffffffu, nm1, 2));
        float M0 = fmaxf(m0, nm0), M1 = fmaxf(m1, nm1);
        float a0 = expf(m0 - M0), a1 = expf(m1 - M1);

        // ---- exp, row sum, store P (fp16, warp-private rows) ----
        float r0 = 0.f, r1 = 0.f;
        #pragma unroll
        for (int nt = 0; nt < 16; nt++) {
            float p0 = expf(S[nt][0] - M0), p1 = expf(S[nt][1] - M0);
            float p2 = expf(S[nt][2] - M1), p3 = expf(S[nt][3] - M1);
            r0 += p0 + p1; r1 += p2 + p3;
            *(__half2*)(sP + (wq + lr) * 136 + nt * 8 + 2 * lc)     = __floats2half2_rn(p0, p1);
            *(__half2*)(sP + (wq + lr + 8) * 136 + nt * 8 + 2 * lc) = __floats2half2_rn(p2, p3);
        }
        r0 += __shfl_xor_sync(0xffffffffu, r0, 1);
        r0 += __shfl_xor_sync(0xffffffffu, r0, 2);
        r1 += __shfl_xor_sync(0xffffffffu, r1, 1);
        r1 += __shfl_xor_sync(0xffffffffu, r1, 2);
        l0 = l0 * a0 + r0;
        l1 = l1 * a1 + r1;
        m0 = M0; m1 = M1;
        #pragma unroll
        for (int nt = 0; nt < 8; nt++) {
            ctx[nt][0] *= a0; ctx[nt][1] *= a0;
            ctx[nt][2] *= a1; ctx[nt][3] *= a1;
        }
        __syncwarp();

        // ---- ctx += P V ----
        #pragma unroll
        for (int ks = 0; ks < 8; ks++) {
            uint32_t af[4];
            ldsm4(af, pbase + (uint32_t)wq * 272 + ks * 32 + offP);
            #pragma unroll
            for (int nt = 0; nt < 8; nt++) {
                uint32_t b0, b1;
                ldsm2t(b0, b1, bV + (ks * 16 + (lane & 15)) * 72 + nt * 8);
                mma_f16(ctx[nt], af, b0, b1);
            }
        }
    }

    float il0 = 1.f / l0, il1 = 1.f / l1;
    #pragma unroll
    for (int nt = 0; nt < 8; nt++) {
        long long row0 = (long long)b * SEQ + bm + wq + lr;
        int col = hh * DHD + nt * 8 + 2 * lc;
        *(__half2*)&outc[row0 * CATW + col] = __floats2half2_rn(ctx[nt][0] * il0, ctx[nt][1] * il0);
        *(__half2*)&outc[(row0 + 8) * CATW + col] = __floats2half2_rn(ctx[nt][2] * il1, ctx[nt][3] * il1);
    }
}

// ---- weight transpose + fp32->fp16: in [K][N] -> out [N][K] ----
__global__ void wt_k(const float* __restrict__ in, __half* __restrict__ out, int K, int N)
{
    __shared__ float tile[32][33];
    int bx = blockIdx.x * 32, by = blockIdx.y * 32;
    int tx = threadIdx.x, ty = threadIdx.y;
    #pragma unroll
    for (int j = ty; j < 32; j += 8)
        tile[j][tx] = in[(long long)(by + j) * N + bx + tx];
    __syncthreads();
    #pragma unroll
    for (int j = ty; j < 32; j += 8)
        out[(long long)(bx + j) * K + by + tx] = __float2half(tile[tx][j]);
}

// ---- fused: hh = fp16(h); hn_h = fp16(h/||h||); x = LN1(h) fp32 + fp16 ----
__global__ void l2ln_k(const float* __restrict__ h,
                       const float* __restrict__ gma, const float* __restrict__ bta)
{
    int row = blockIdx.x, t = threadIdx.x;
    const float* xr = h + (long long)row * EMB;
    __shared__ float sh[EMB];
    __shared__ float r1[256], r2[256];
    float s = 0.f, ss = 0.f;
    for (int i = t; i < EMB; i += 256) { float v = xr[i]; sh[i] = v; s += v; ss += v * v; }
    r1[t] = s; r2[t] = ss; __syncthreads();
    for (int st = 128; st > 0; st >>= 1) {
        if (t < st) { r1[t] += r1[t + st]; r2[t] += r2[t + st]; }
        __syncthreads();
    }
    float mu   = r1[0] / EMB;
    float var  = r2[0] / EMB - mu * mu;
    float ri   = rsqrtf(var + 1e-6f);
    float invn = 1.f / (sqrtf(r2[0]) + 1e-8f);
    for (int i = t; i < EMB; i += 256) {
        float v = sh[i];
        g_hh [(long long)row * EMB + i] = __float2half(v);
        g_hnh[(long long)row * EMB + i] = __float2half(v * invn);
        float xo = (v - mu) * ri * gma[i] + bta[i];
        g_x [(long long)row * EMB + i] = xo;
        g_xh[(long long)row * EMB + i] = __float2half(xo);
    }
}

// ---- layernorm -> fp16 output ----
__global__ void lnh_k(const float* __restrict__ x, __half* __restrict__ oh,
                      const float* __restrict__ gma, const float* __restrict__ bta, int D)
{
    int row = blockIdx.x, t = threadIdx.x;
    const float* xr = x + (long long)row * D;
    __shared__ float red[256];
    __shared__ float s_mu, s_ri;
    float s = 0.f;
    for (int i = t; i < D; i += 256) s += xr[i];
    red[t] = s; __syncthreads();
    for (int st = 128; st > 0; st >>= 1) { if (t < st) red[t] += red[t + st]; __syncthreads(); }
    if (t == 0) s_mu = red[0] / D;
    __syncthreads();
    float mu = s_mu;
    float v = 0.f;
    for (int i = t; i < D; i += 256) { float d = xr[i] - mu; v += d * d; }
    __syncthreads();
    red[t] = v; __syncthreads();
    for (int st = 128; st > 0; st >>= 1) { if (t < st) red[t] += red[t + st]; __syncthreads(); }
    if (t == 0) s_ri = rsqrtf(red[0] / D + 1e-6f);
    __syncthreads();
    float ri = s_ri;
    for (int i = t; i < D; i += 256)
        oh[(long long)row * D + i] = __float2half((xr[i] - mu) * ri * gma[i] + bta[i]);
}

// ---- k-NN (u32 packed keys) + fused combine -> g_combh ----
// key = (dist_bits & ~0x7FF) | j   (dist >= 0 here, 11-bit index, stable ties)
__global__ void knn_k()
{
    int row = blockIdx.x;
    int b = row >> 11, i = row & (SEQ - 1);
    const float* dr = g_dist + (long long)row * SEQ;
    int t = threadIdx.x, lane = t & 31, w = t >> 5;

    __shared__ uint32_t cand[128];
    __shared__ uint32_t fin[KNN];
    __shared__ float    swt[KNN];
    __shared__ int      sidx[KNN];

    uint32_t v[8];
    int base = w * 256;
    #pragma unroll
    for (int r = 0; r < 8; r++) {
        int j = base + r * 32 + lane;
        float d = (j == i) ? 1e9f : (1.f - dr[j]);
        v[r] = (__float_as_uint(d) & 0xFFFFF800u) | (unsigned)j;
    }

    #pragma unroll
    for (int it = 0; it < KNN; it++) {
        uint32_t m = v[0];
        #pragma unroll
        for (int r = 1; r < 8; r++) m = min(m, v[r]);
        #pragma unroll
        for (int s = 16; s > 0; s >>= 1)
            m = min(m, __shfl_xor_sync(0xffffffffu, m, s));
        if (lane == 0) cand[w * KNN + it] = m;
        #pragma unroll
        for (int r = 0; r < 8; r++) if (v[r] == m) v[r] = 0xFFFFFFFFu;
    }
    __syncthreads();

    if (w == 0) {
        uint32_t c[4];
        #pragma unroll
        for (int r = 0; r < 4; r++) c[r] = cand[r * 32 + lane];
        #pragma unroll
        for (int it = 0; it < KNN; it++) {
            uint32_t m01 = min(c[0], c[1]);
            uint32_t m23 = min(c[2], c[3]);
            uint32_t m = min(m01, m23);
            #pragma unroll
            for (int s = 16; s > 0; s >>= 1)
                m = min(m, __shfl_xor_sync(0xffffffffu, m, s));
            if (lane == 0) fin[it] = m;
            #pragma unroll
            for (int r = 0; r < 4; r++) if (c[r] == m) c[r] = 0xFFFFFFFFu;
        }
        __syncwarp();
        if (lane < KNN) {
            float d0 = __uint_as_float(fin[0] & 0xFFFFF800u);
            float dk = __uint_as_float(fin[lane] & 0xFFFFF800u);
            float wk = expf(d0 - dk);
            float sum = wk;
            #pragma unroll
            for (int s = 8; s > 0; s >>= 1)
                sum += __shfl_xor_sync(0x0000ffffu, sum, s);
            swt[lane]  = wk / sum;
            sidx[lane] = b * SEQ + (int)(fin[lane] & 0x7FFu);
        }
    }
    __syncthreads();

    // fused combine: combined = topo + sum_k w_k * topo[nbr_k]  -> fp16
    if (t < TT) {
        float acc = g_topo[(long long)row * TT + t];
        #pragma unroll
        for (int k2 = 0; k2 < KNN; k2++)
            acc += swt[k2] * g_topo[(long long)sidx[k2] * TT + t];
        g_combh[(long long)row * TT + t] = __float2half(acc);
    }
}

// ============================================================================
#define HG_SMEM (3 * 128 * 24 * 2 * 2)   // 36864 B

extern "C" void kernel_launch(void* const* d_in, const int* in_sizes, int n_in,
                              void* d_out, int out_size)
{
    const float* h      = (const float*)d_in[0];
    const int*   mask   = (const int*)  d_in[1];
    const float* W_topo = (const float*)d_in[2];
    const float* b_topo = (const float*)d_in[3];
    const float* W_m1   = (const float*)d_in[4];
    const float* b_m1   = (const float*)d_in[5];
    const float* W_m2   = (const float*)d_in[6];
    const float* b_m2   = (const float*)d_in[7];
    const float* ln_t_s = (const float*)d_in[8];
    const float* ln_t_b = (const float*)d_in[9];
    const float* W_p1   = (const float*)d_in[10];
    const float* b_p1   = (const float*)d_in[11];
    const float* W_p2   = (const float*)d_in[12];
    const float* b_p2   = (const float*)d_in[13];
    const float* ln1_s  = (const float*)d_in[14];
    const float* ln1_b  = (const float*)d_in[15];
    const float* Wq     = (const float*)d_in[16];
    const float* Wk     = (const float*)d_in[17];
    const float* Wv     = (const float*)d_in[18];
    const float* W_gate = (const float*)d_in[19];
    const float* b_gate = (const float*)d_in[20];
    const float* W_o    = (const float*)d_in[21];
    const float* b_o    = (const float*)d_in[22];
    const float* ln2_s  = (const float*)d_in[23];
    const float* ln2_b  = (const float*)d_in[24];
    const float* W_f1   = (const float*)d_in[25];
    const float* b_f1   = (const float*)d_in[26];
    const float* W_f2   = (const float*)d_in[27];
    const float* b_f2   = (const float*)d_in[28];
    float* out = (float*)d_out;

    float *x, *topo, *tt, *h1, *dist;
    __half *xh, *combh, *tmp256h, *tth, *qkvh, *cath, *ctxh, *yh, *ffh, *hh, *hnh;
    __half *wt_topo, *wt_m1, *wt_m2, *wt_p1, *wt_p2, *wt_qkv, *wt_gate, *wt_o, *wt_f1, *wt_f2;
    cudaGetSymbolAddress((void**)&x,       g_x);
    cudaGetSymbolAddress((void**)&topo,    g_topo);
    cudaGetSymbolAddress((void**)&tt,      g_tt);
    cudaGetSymbolAddress((void**)&h1,      g_h1);
    cudaGetSymbolAddress((void**)&dist,    g_dist);
    cudaGetSymbolAddress((void**)&hh,      g_hh);
    cudaGetSymbolAddress((void**)&hnh,     g_hnh);
    cudaGetSymbolAddress((void**)&xh,      g_xh);
    cudaGetSymbolAddress((void**)&combh,   g_combh);
    cudaGetSymbolAddress((void**)&tmp256h, g_tmp256h);
    cudaGetSymbolAddress((void**)&tth,     g_tth);
    cudaGetSymbolAddress((void**)&qkvh,    g_qkvh);
    cudaGetSymbolAddress((void**)&cath,    g_cath);
    cudaGetSymbolAddress((void**)&ctxh,    g_ctxh);
    cudaGetSymbolAddress((void**)&yh,      g_yh);
    cudaGetSymbolAddress((void**)&ffh,     g_ffh);
    cudaGetSymbolAddress((void**)&wt_topo, g_wt_topo);
    cudaGetSymbolAddress((void**)&wt_m1,   g_wt_m1);
    cudaGetSymbolAddress((void**)&wt_m2,   g_wt_m2);
    cudaGetSymbolAddress((void**)&wt_p1,   g_wt_p1);
    cudaGetSymbolAddress((void**)&wt_p2,   g_wt_p2);
    cudaGetSymbolAddress((void**)&wt_qkv,  g_wt_qkv);
    cudaGetSymbolAddress((void**)&wt_gate, g_wt_gate);
    cudaGetSymbolAddress((void**)&wt_o,    g_wt_o);
    cudaGetSymbolAddress((void**)&wt_f1,   g_wt_f1);
    cudaGetSymbolAddress((void**)&wt_f2,   g_wt_f2);

    const long long SE = (long long)SEQ * EMB;
    const long long SS = (long long)SEQ * SEQ;

    cudaFuncSetAttribute((const void*)flash_k, cudaFuncAttributeMaxDynamicSharedMemorySize, FS_TOT_BYTES);

    // ---- streams/events (created once, outside any capture) ----
    static cudaStream_t st1 = nullptr, st2 = nullptr;
    static cudaEvent_t e_fork, e_ln, e_b1, e_w2;
    if (!st1) {
        cudaStreamCreateWithFlags(&st1, cudaStreamNonBlocking);
        cudaStreamCreateWithFlags(&st2, cudaStreamNonBlocking);
        cudaEventCreateWithFlags(&e_fork, cudaEventDisableTiming);
        cudaEventCreateWithFlags(&e_ln,   cudaEventDisableTiming);
        cudaEventCreateWithFlags(&e_b1,   cudaEventDisableTiming);
        cudaEventCreateWithFlags(&e_w2,   cudaEventDisableTiming);
    }

    dim3 tb(32, 8);

    // ---- fork ----
    cudaEventRecord(e_fork, 0);
    cudaStreamWaitEvent(st1, e_fork, 0);
    cudaStreamWaitEvent(st2, e_fork, 0);

    // ---- s0: fused convert + l2norm + LN1 ----
    l2ln_k<<<BSX, 256>>>(h, ln1_s, ln1_b);
    cudaEventRecord(e_ln, 0);

    // ---- s2: tail weight transposes ----
    wt_k<<<dim3(EMB / 32, CATW / 32), tb, 0, st2>>>(W_gate, wt_gate, CATW, EMB);
    wt_k<<<dim3(EMB / 32, EMB / 32),  tb, 0, st2>>>(W_o, wt_o, EMB, EMB);
    wt_k<<<dim3(FF / 32, EMB / 32),   tb, 0, st2>>>(W_f1, wt_f1, EMB, FF);
    wt_k<<<dim3(EMB / 32, FF / 32),   tb, 0, st2>>>(W_f2, wt_f2, FF, EMB);
    cudaEventRecord(e_w2, st2);

    // ---- s1: topo branch ----
    wt_k<<<dim3(TT / 32, EMB / 32), tb, 0, st1>>>(W_topo, wt_topo, EMB, TT);
    wt_k<<<dim3(256 / 32, TT / 32), tb, 0, st1>>>(W_m1, wt_m1, TT, 256);
    wt_k<<<dim3(TT / 32, 256 / 32), tb, 0, st1>>>(W_m2, wt_m2, 256, TT);
    wt_k<<<dim3(TT / 32, TT / 32),  tb, 0, st1>>>(W_p1, wt_p1, TT, TT);
    wt_k<<<dim3(TT / 32, TT / 32),  tb, 0, st1>>>(W_p2, wt_p2, TT, TT);
    cudaStreamWaitEvent(st1, e_ln, 0);
    hgemm<0, 0, 0><<<dim3(1, 32, 1), 256, HG_SMEM, st1>>>(hh, wt_topo, topo, b_topo, nullptr, nullptr,
        EMB, EMB, EMB, TT, 0, 0, 1, 0, 0, 0, 0, 0, 0);
    hgemm<0, 0, 0><<<dim3(16, 16, 2), 256, HG_SMEM, st1>>>(hnh, hnh, dist, nullptr, nullptr, nullptr,
        EMB, EMB, EMB, SEQ, 0, 0, 2, SE, 0, SE, 0, SS, 0);
    knn_k<<<BSX, 256, 0, st1>>>();
    hgemm<1, 1, 0><<<dim3(2, 32, 1), 256, HG_SMEM, st1>>>(combh, wt_m1, tmp256h, b_m1, nullptr, nullptr,
        TT, TT, TT, 256, 0, 0, 1, 0, 0, 0, 0, 0, 0);
    hgemm<0, 0, 0><<<dim3(1, 32, 1), 256, HG_SMEM, st1>>>(tmp256h, wt_m2, tt, b_m2, nullptr, nullptr,
        256, 256, 256, TT, 0, 0, 1, 0, 0, 0, 0, 0, 0);
    lnh_k<<<BSX, 256, 0, st1>>>(tt, tth, ln_t_s, ln_t_b, TT);
    hgemm<1, 1, 0><<<dim3(1, 32, 1), 256, HG_SMEM, st1>>>(tth, wt_p1, tmp256h, b_p1, nullptr, nullptr,
        TT, TT, TT, TT, 0, 0, 1, 0, 0, 0, 0, 0, 0);
    hgemm<0, 1, 0><<<dim3(1, 32, 1), 256, HG_SMEM, st1>>>(tmp256h, wt_p2, cath + EMB, b_p2, nullptr, nullptr,
        TT, TT, TT, CATW, 0, 0, 1, 0, 0, 0, 0, 0, 0);
    cudaEventRecord(e_b1, st1);

    // ---- s0: attention branch (fused QKV) ----
    wt_k<<<dim3(EMB / 32, EMB / 32), tb>>>(Wq, wt_qkv, EMB, EMB);
    wt_k<<<dim3(EMB / 32, EMB / 32), tb>>>(Wk, wt_qkv + (long long)EMB * EMB, EMB, EMB);
    wt_k<<<dim3(EMB / 32, EMB / 32), tb>>>(Wv, wt_qkv + 2LL * EMB * EMB, EMB, EMB);
    hgemm<0, 1, 0><<<dim3(QKVW / 128, 32, 1), 256, HG_SMEM>>>(xh, wt_qkv, qkvh, nullptr, nullptr, nullptr,
        EMB, EMB, EMB, QKVW, 0, 0, 1, 0, 0, 0, 0, 0, 0);
    flash_k<<<dim3(16, BB * NH), 256, FS_TOT_BYTES>>>(qkvh, mask, cath);

    // ---- join ----
    cudaStreamWaitEvent(0, e_b1, 0);
    cudaStreamWaitEvent(0, e_w2, 0);

    // ---- tail ----
    hgemm<3, 1, 1><<<dim3(6, 32, 1), 256, HG_SMEM>>>(cath, wt_gate, ctxh, b_gate, cath, x,
        CATW, CATW, CATW, EMB, CATW, EMB, 1, 0, 0, 0, 0, 0, 0);
    hgemm<0, 0, 0><<<dim3(6, 32, 1), 256, HG_SMEM>>>(ctxh, wt_o, h1, b_o, h, nullptr,
        EMB, EMB, EMB, EMB, EMB, 0, 1, 0, 0, 0, 0, 0, 0);
    lnh_k<<<BSX, 256>>>(h1, yh, ln2_s, ln2_b, EMB);
    hgemm<2, 1, 0><<<dim3(24, 32, 1), 256, HG_SMEM>>>(yh, wt_f1, ffh, b_f1, nullptr, nullptr,
        EMB, EMB, EMB, FF, 0, 0, 1, 0, 0, 0, 0, 0, 0);
    hgemm<0, 0, 0><<<dim3(6, 32, 1), 256, HG_SMEM>>>(ffh, wt_f2, out, b_f2, h1, nullptr,
        FF, FF, FF, EMB, EMB, 0, 1, 0, 0, 0, 0, 0, 0);
}

// round 12
// speedup vs baseline: 2.1680x; 1.0283x over previous
#include <cuda_runtime.h>
#include <cuda_fp16.h>
#include <math.h>
#include <stdint.h>

// ---- problem constants ----
#define BSX 4096   // B*S
#define BB  2
#define SEQ 2048
#define EMB 768
#define TT  128
#define NH  12
#define DHD 64
#define FF  3072
#define KNN 16
#define CATW (EMB + TT)   // 896
#define QKVW (3 * EMB)    // 2304

// ---- fp32 scratch ----
__device__ float g_topo[BSX * TT];
__device__ float g_tt[BSX * TT];
__device__ float g_h1[BSX * EMB];
__device__ float g_dist[(long long)BB * SEQ * SEQ];

// ---- fp16 scratch ----
__device__ __half g_hh[BSX * EMB];
__device__ __half g_hnh[BSX * EMB];
__device__ __half g_xh[BSX * EMB];
__device__ __half g_combh[BSX * TT];
__device__ __half g_tmp256h[BSX * 256];
__device__ __half g_tth[BSX * TT];
__device__ __half g_qkvh[(long long)BSX * QKVW];
__device__ __half g_cath[BSX * CATW];
__device__ __half g_ctxh[BSX * EMB];
__device__ __half g_yh[BSX * EMB];
__device__ __half g_ffh[(long long)BSX * FF];

// ---- transposed fp16 weights [N][K] ----
__device__ __half g_wt_topo[TT * EMB];
__device__ __half g_wt_m1[256 * TT];
__device__ __half g_wt_m2[TT * 256];
__device__ __half g_wt_p1[TT * TT];
__device__ __half g_wt_p2[TT * TT];
__device__ __half g_wt_qkv[QKVW * EMB];
__device__ __half g_wt_gate[EMB * CATW];
__device__ __half g_wt_o[EMB * EMB];
__device__ __half g_wt_f1[FF * EMB];
__device__ __half g_wt_f2[EMB * FF];

__device__ __forceinline__ void mma_f16(float* c, const uint32_t* a, uint32_t b0, uint32_t b1) {
    asm volatile(
        "mma.sync.aligned.m16n8k16.row.col.f32.f16.f16.f32 "
        "{%0,%1,%2,%3},{%4,%5,%6,%7},{%8,%9},{%0,%1,%2,%3};"
        : "+f"(c[0]), "+f"(c[1]), "+f"(c[2]), "+f"(c[3])
        : "r"(a[0]), "r"(a[1]), "r"(a[2]), "r"(a[3]), "r"(b0), "r"(b1));
}

__device__ __forceinline__ void cpa16(void* s, const void* g) {
    unsigned sa = (unsigned)__cvta_generic_to_shared(s);
    asm volatile("cp.async.cg.shared.global [%0], [%1], 16;" :: "r"(sa), "l"(g));
}
__device__ __forceinline__ void cpa_commit() { asm volatile("cp.async.commit_group;"); }
__device__ __forceinline__ void cpa_wait1()  { asm volatile("cp.async.wait_group 1;"); }
__device__ __forceinline__ void cpa_wait0()  { asm volatile("cp.async.wait_group 0;"); }

__device__ __forceinline__ void ldsm4(uint32_t* r, uint32_t addr) {
    asm volatile("ldmatrix.sync.aligned.m8n8.x4.shared.b16 {%0,%1,%2,%3}, [%4];"
                 : "=r"(r[0]), "=r"(r[1]), "=r"(r[2]), "=r"(r[3]) : "r"(addr));
}

__device__ __forceinline__ void ldsm4t(uint32_t* r, uint32_t addr) {
    asm volatile("ldmatrix.sync.aligned.m8n8.x4.trans.shared.b16 {%0,%1,%2,%3}, [%4];"
                 : "=r"(r[0]), "=r"(r[1]), "=r"(r[2]), "=r"(r[3]) : "r"(addr));
}

__device__ __forceinline__ uint32_t h2ex2(uint32_t x) {
    uint32_t y;
    asm("ex2.approx.f16x2 %0, %1;" : "=r"(y) : "r"(x));
    return y;
}

// ============================================================================
// fp16 tensor-core GEMM (m16n8k16), cp.async 3-stage pipeline, ldmatrix
// fragment loads, one __syncthreads per k16 stage.
// A [M,K] fp16 row-major; B [N,K] fp16 row-major (K-major).
// ACT: 0 none, 1 relu, 2 gelu, 3 sigmoid-mix. CH: C half. RH: res half.
// R2H: res2 half (ACT3 only).
// ============================================================================
#define HSTG (128 * 24)

template<int ACT, int CH, int RH, int R2H>
__global__ void __launch_bounds__(256) hgemm(
    const __half* __restrict__ A, const __half* __restrict__ B,
    void* __restrict__ Cv, const float* __restrict__ bias,
    const void* __restrict__ resv, const void* __restrict__ res2v,
    int K, int lda, int ldb, int ldc, int ldr1, int ldr2,
    int zdiv, long long sA1, long long sA2,
    long long sB1, long long sB2, long long sC1, long long sC2)
{
    extern __shared__ __half hs[];
    __half* As = hs;                 // [3][128][24]
    __half* Bs = hs + 3 * HSTG;      // [3][128][24]

    int z = blockIdx.z;
    long long zm = z % zdiv, zd = z / zdiv;
    A += zm * sA1 + zd * sA2;
    B += zm * sB1 + zd * sB2;
    long long co = zm * sC1 + zd * sC2;

    const int t    = threadIdx.x;
    const int lane = t & 31;
    const int wid  = t >> 5;
    const int lr   = lane >> 2;
    const int lc   = lane & 3;
    const int wm   = (wid & 3) * 32;
    const int wn   = (wid >> 2) * 64;
    const int bm   = blockIdx.y * 128;
    const int bn   = blockIdx.x * 128;

    const uint32_t sbase = (uint32_t)__cvta_generic_to_shared(hs);
    const uint32_t offA = (uint32_t)((lane & 15) * 48 + (lane >> 4) * 16);
    const uint32_t offB = (uint32_t)((((lane >> 4) & 1) * 8 + (lane & 7)) * 48 + ((lane >> 3) & 1) * 16);

    float acc[2][8][4];
    #pragma unroll
    for (int mt = 0; mt < 2; mt++)
        #pragma unroll
        for (int nt = 0; nt < 8; nt++)
            #pragma unroll
            for (int i = 0; i < 4; i++) acc[mt][nt][i] = 0.f;

    auto issue = [&](int buf, int k0) {
        int row = t >> 1, kq = (t & 1) * 8;
        cpa16(&As[buf * HSTG + row * 24 + kq],
              A + (long long)(bm + row) * lda + k0 + kq);
        cpa16(&Bs[buf * HSTG + row * 24 + kq],
              B + (long long)(bn + row) * ldb + k0 + kq);
        cpa_commit();
    };

    const int iters = K >> 4;
    issue(0, 0);
    issue(1, 16);

    for (int kb = 0; kb < iters; kb++) {
        cpa_wait1();
        __syncthreads();
        int cur = kb - (kb / 3) * 3;
        uint32_t aB = sbase + (uint32_t)cur * (HSTG * 2);
        uint32_t bB = sbase + (uint32_t)(3 + cur) * (HSTG * 2);

        uint32_t af[2][4];
        #pragma unroll
        for (int mt = 0; mt < 2; mt++)
            ldsm4(af[mt], aB + (wm + mt * 16) * 48 + offA);

        #pragma unroll
        for (int p = 0; p < 4; p++) {
            uint32_t bb[4];
            ldsm4(bb, bB + (wn + p * 16) * 48 + offB);
            #pragma unroll
            for (int sub = 0; sub < 2; sub++)
                #pragma unroll
                for (int mt = 0; mt < 2; mt++)
                    mma_f16(acc[mt][p * 2 + sub], af[mt], bb[sub * 2], bb[sub * 2 + 1]);
        }

        int nst  = kb + 2;
        int nbuf = nst - (nst / 3) * 3;
        int nk0  = (nst < iters ? nst : iters - 1) << 4;
        issue(nbuf, nk0);
    }

    // epilogue
    const float* res = (const float*)resv;
    const __half* resh = (const __half*)resv;
    #pragma unroll
    for (int mt = 0; mt < 2; mt++) {
        #pragma unroll
        for (int nt = 0; nt < 8; nt++) {
            int mrow = bm + wm + mt * 16 + lr;
            int ncol = bn + wn + nt * 8 + 2 * lc;
            #pragma unroll
            for (int half_ = 0; half_ < 2; half_++) {
                int m = mrow + half_ * 8;
                float v0 = acc[mt][nt][half_ * 2 + 0];
                float v1 = acc[mt][nt][half_ * 2 + 1];
                if (bias) { v0 += bias[ncol]; v1 += bias[ncol + 1]; }
                if (ACT == 1) { v0 = fmaxf(v0, 0.f); v1 = fmaxf(v1, 0.f); }
                if (ACT == 2) {
                    float u = v0;
                    v0 = 0.5f * u * (1.f + tanhf(0.7978845608028654f * (u + 0.044715f * u * u * u)));
                    u = v1;
                    v1 = 0.5f * u * (1.f + tanhf(0.7978845608028654f * (u + 0.044715f * u * u * u)));
                }
                long long off = (long long)m * ldc + ncol + co;
                if (ACT == 3) {
                    float s0 = 1.f / (1.f + expf(-v0));
                    float s1 = 1.f / (1.f + expf(-v1));
                    long long o1 = (long long)m * ldr1 + ncol;
                    long long o2 = (long long)m * ldr2 + ncol;
                    float r1x, r1y, r2x, r2y;
                    if (RH) {
                        __half2 rh = *(const __half2*)(resh + o1);
                        r1x = __half2float(rh.x); r1y = __half2float(rh.y);
                    } else {
                        float2 r1 = *(const float2*)(res + o1);
                        r1x = r1.x; r1y = r1.y;
                    }
                    if (R2H) {
                        __half2 rh2 = *(const __half2*)((const __half*)res2v + o2);
                        r2x = __half2float(rh2.x); r2y = __half2float(rh2.y);
                    } else {
                        float2 r2 = *(const float2*)((const float*)res2v + o2);
                        r2x = r2.x; r2y = r2.y;
                    }
                    v0 = s0 * r1x + (1.f - s0) * r2x;
                    v1 = s1 * r1y + (1.f - s1) * r2y;
                } else if (resv) {
                    float2 r1 = *(const float2*)(res + (long long)m * ldr1 + ncol + co);
                    v0 += r1.x; v1 += r1.y;
                }
                if (CH) {
                    __half2 hv = __floats2half2_rn(v0, v1);
                    *(__half2*)((__half*)Cv + off) = hv;
                } else {
                    float2 o2v = {v0, v1};
                    *(float2*)((float*)Cv + off) = o2v;
                }
            }
        }
    }
}

// ============================================================================
// Flash attention fp16 over fused qkv buffer [BSX][2304].
// ex2.approx.f16x2 softmax; V via ldmatrix.x4.trans.
// smem: sP[128][136] | sK[2][128][72] | sV[2][128][72] = 108544 B
// ============================================================================
#define FS_P 0
#define FS_K 17408
#define FS_V 35840
#define FS_TOT_BYTES 108544
#define LOG2E 1.4426950408889634f

__global__ void __launch_bounds__(256) flash_k(
    const __half* __restrict__ qkv, const int* __restrict__ mask,
    __half* __restrict__ outc)
{
    extern __shared__ __half fh[];
    __half* sP = fh + FS_P;
    __half* sK = fh + FS_K;
    __half* sV = fh + FS_V;

    const int t = threadIdx.x, lane = t & 31, w = t >> 5;
    const int lr = lane >> 2, lc = lane & 3;
    const int z = blockIdx.y, b = z / NH, hh = z % NH;
    const int bm = blockIdx.x * 128;
    const long long base = (long long)b * SEQ * QKVW + hh * DHD;
    const __half* qp = qkv + base;
    const __half* kp = qkv + base + EMB;
    const __half* vp = qkv + base + 2 * EMB;
    const int* mrow = mask + b * SEQ;

    const uint32_t fbase = (uint32_t)__cvta_generic_to_shared(fh);
    const uint32_t pbase = fbase;
    const uint32_t kbase = fbase + FS_K * 2;
    const uint32_t vbase = fbase + FS_V * 2;
    const uint32_t offK = (uint32_t)((((lane >> 4) & 1) * 8 + (lane & 7)) * 144 + ((lane >> 3) & 1) * 16);
    const uint32_t offP = (uint32_t)((lane & 15) * 272 + (lane >> 4) * 16);
    const uint32_t offV = (uint32_t)((lane & 15) * 144 + (lane >> 4) * 16);

    #pragma unroll
    for (int j = 0; j < 4; j++) {
        int flat = t + j * 256;
        int row = flat >> 3, q8 = (flat & 7) << 3;
        cpa16(&sP[row * 136 + q8], qp + (long long)(bm + row) * QKVW + q8);
    }
    cpa_commit();

    auto issueKV = [&](int kt) {
        int buf = kt & 1;
        #pragma unroll
        for (int j = 0; j < 4; j++) {
            int flat = t + j * 256;
            int row = flat >> 3, q8 = (flat & 7) << 3;
            cpa16(&sK[buf * 9216 + row * 72 + q8],
                  kp + (long long)(kt * 128 + row) * QKVW + q8);
        }
        #pragma unroll
        for (int j = 0; j < 4; j++) {
            int flat = t + j * 256;
            int row = flat >> 3, q8 = (flat & 7) << 3;
            cpa16(&sV[buf * 9216 + row * 72 + q8],
                  vp + (long long)(kt * 128 + row) * QKVW + q8);
        }
        cpa_commit();
    };
    issueKV(0);

    cpa_wait1();
    __syncthreads();

    const int wq = w * 16;
    uint32_t qf[4][4];
    #pragma unroll
    for (int ks = 0; ks < 4; ks++)
        ldsm4(qf[ks], pbase + (uint32_t)wq * 272 + ks * 32 + offP);
    __syncthreads();

    float ctx[8][4];
    #pragma unroll
    for (int nt = 0; nt < 8; nt++)
        #pragma unroll
        for (int i = 0; i < 4; i++) ctx[nt][i] = 0.f;
    float m0 = -1e30f, m1 = -1e30f, l0 = 0.f, l1 = 0.f;

    for (int kt = 0; kt < 16; kt++) {
        cpa_wait0();
        __syncthreads();
        if (kt + 1 < 16) issueKV(kt + 1);

        const int buf = kt & 1;
        const uint32_t kB = kbase + (uint32_t)buf * (9216 * 2);
        const uint32_t vB = vbase + (uint32_t)buf * (9216 * 2);

        // ---- S = Q K^T ----
        float S[16][4];
        #pragma unroll
        for (int nt = 0; nt < 16; nt++)
            #pragma unroll
            for (int i = 0; i < 4; i++) S[nt][i] = 0.f;
        #pragma unroll
        for (int ks = 0; ks < 4; ks++) {
            #pragma unroll
            for (int p = 0; p < 8; p++) {
                uint32_t bb[4];
                ldsm4(bb, kB + (uint32_t)(p * 16) * 144 + ks * 32 + offK);
                mma_f16(S[p * 2],     qf[ks], bb[0], bb[1]);
                mma_f16(S[p * 2 + 1], qf[ks], bb[2], bb[3]);
            }
        }

        // ---- scale + mask + row max ----
        float nm0 = -1e30f, nm1 = -1e30f;
        #pragma unroll
        for (int nt = 0; nt < 16; nt++) {
            int c0 = kt * 128 + nt * 8 + 2 * lc;
            int2 mg = *(const int2*)&mrow[c0];
            float s0 = S[nt][0] * 0.125f, s1 = S[nt][1] * 0.125f;
            float s2 = S[nt][2] * 0.125f, s3 = S[nt][3] * 0.125f;
            if (mg.x == 0) { s0 = -10000.f; s2 = -10000.f; }
            if (mg.y == 0) { s1 = -10000.f; s3 = -10000.f; }
            S[nt][0] = s0; S[nt][1] = s1; S[nt][2] = s2; S[nt][3] = s3;
            nm0 = fmaxf(nm0, fmaxf(s0, s1));
            nm1 = fmaxf(nm1, fmaxf(s2, s3));
        }
        nm0 = fmaxf(nm0, __shfl_xor_sync(0xffffffffu, nm0, 1));
        nm0 = fmaxf(nm0, __shfl_xor_sync(0xffffffffu, nm0, 2));
        nm1 = fmaxf(nm1, __shfl_xor_sync(0xffffffffu, nm1, 1));
        nm1 = fmaxf(nm1, __shfl_xor_sync(0xffffffffu, nm1, 2));
        float M0 = fmaxf(m0, nm0), M1 = fmaxf(m1, nm1);
        float a0 = expf(m0 - M0), a1 = expf(m1 - M1);

        // ---- P = 2^((s-M)*log2e) via ex2.f16x2; sum; store fp16 P ----
        float r0 = 0.f, r1 = 0.f;
        #pragma unroll
        for (int nt = 0; nt < 16; nt++) {
            __half2 e01 = __floats2half2_rn((S[nt][0] - M0) * LOG2E, (S[nt][1] - M0) * LOG2E);
            __half2 e23 = __floats2half2_rn((S[nt][2] - M1) * LOG2E, (S[nt][3] - M1) * LOG2E);
            uint32_t p01 = h2ex2(*(uint32_t*)&e01);
            uint32_t p23 = h2ex2(*(uint32_t*)&e23);
            float2 f01 = __half22float2(*(__half2*)&p01);
            float2 f23 = __half22float2(*(__half2*)&p23);
            r0 += f01.x + f01.y;
            r1 += f23.x + f23.y;
            *(uint32_t*)(sP + (wq + lr) * 136 + nt * 8 + 2 * lc)     = p01;
            *(uint32_t*)(sP + (wq + lr + 8) * 136 + nt * 8 + 2 * lc) = p23;
        }
        r0 += __shfl_xor_sync(0xffffffffu, r0, 1);
        r0 += __shfl_xor_sync(0xffffffffu, r0, 2);
        r1 += __shfl_xor_sync(0xffffffffu, r1, 1);
        r1 += __shfl_xor_sync(0xffffffffu, r1, 2);
        l0 = l0 * a0 + r0;
        l1 = l1 * a1 + r1;
        m0 = M0; m1 = M1;
        #pragma unroll
        for (int nt = 0; nt < 8; nt++) {
            ctx[nt][0] *= a0; ctx[nt][1] *= a0;
            ctx[nt][2] *= a1; ctx[nt][3] *= a1;
        }
        __syncwarp();

        // ---- ctx += P V (V fragments via ldmatrix.x4.trans, 2 nt per op) ----
        #pragma unroll
        for (int ks = 0; ks < 8; ks++) {
            uint32_t af[4];
            ldsm4(af, pbase + (uint32_t)wq * 272 + ks * 32 + offP);
            #pragma unroll
            for (int nt = 0; nt < 8; nt += 2) {
                uint32_t bb[4];
                ldsm4t(bb, vB + (uint32_t)(ks * 16) * 144 + (uint32_t)(nt * 16) + offV);
                mma_f16(ctx[nt],     af, bb[0], bb[1]);
                mma_f16(ctx[nt + 1], af, bb[2], bb[3]);
            }
        }
    }

    float il0 = 1.f / l0, il1 = 1.f / l1;
    #pragma unroll
    for (int nt = 0; nt < 8; nt++) {
        long long row0 = (long long)b * SEQ + bm + wq + lr;
        int col = hh * DHD + nt * 8 + 2 * lc;
        *(__half2*)&outc[row0 * CATW + col] = __floats2half2_rn(ctx[nt][0] * il0, ctx[nt][1] * il0);
        *(__half2*)&outc[(row0 + 8) * CATW + col] = __floats2half2_rn(ctx[nt][2] * il1, ctx[nt][3] * il1);
    }
}

// ---- weight transpose + fp32->fp16: in [K][N] -> out [N][K] ----
__global__ void wt_k(const float* __restrict__ in, __half* __restrict__ out, int K, int N)
{
    __shared__ float tile[32][33];
    int bx = blockIdx.x * 32, by = blockIdx.y * 32;
    int tx = threadIdx.x, ty = threadIdx.y;
    #pragma unroll
    for (int j = ty; j < 32; j += 8)
        tile[j][tx] = in[(long long)(by + j) * N + bx + tx];
    __syncthreads();
    #pragma unroll
    for (int j = ty; j < 32; j += 8)
        out[(long long)(bx + j) * K + by + tx] = __float2half(tile[tx][j]);
}

// ---- fused: hh = fp16(h); hn_h = fp16(h/||h||); xh = fp16(LN1(h)) ----
__global__ void l2ln_k(const float* __restrict__ h,
                       const float* __restrict__ gma, const float* __restrict__ bta)
{
    int row = blockIdx.x, t = threadIdx.x;
    const float* xr = h + (long long)row * EMB;
    __shared__ float sh[EMB];
    __shared__ float r1[256], r2[256];
    float s = 0.f, ss = 0.f;
    for (int i = t; i < EMB; i += 256) { float v = xr[i]; sh[i] = v; s += v; ss += v * v; }
    r1[t] = s; r2[t] = ss; __syncthreads();
    for (int st = 128; st > 0; st >>= 1) {
        if (t < st) { r1[t] += r1[t + st]; r2[t] += r2[t + st]; }
        __syncthreads();
    }
    float mu   = r1[0] / EMB;
    float var  = r2[0] / EMB - mu * mu;
    float ri   = rsqrtf(var + 1e-6f);
    float invn = 1.f / (sqrtf(r2[0]) + 1e-8f);
    for (int i = t; i < EMB; i += 256) {
        float v = sh[i];
        g_hh [(long long)row * EMB + i] = __float2half(v);
        g_hnh[(long long)row * EMB + i] = __float2half(v * invn);
        g_xh [(long long)row * EMB + i] = __float2half((v - mu) * ri * gma[i] + bta[i]);
    }
}

// ---- layernorm -> fp16 output ----
__global__ void lnh_k(const float* __restrict__ x, __half* __restrict__ oh,
                      const float* __restrict__ gma, const float* __restrict__ bta, int D)
{
    int row = blockIdx.x, t = threadIdx.x;
    const float* xr = x + (long long)row * D;
    __shared__ float red[256];
    __shared__ float s_mu, s_ri;
    float s = 0.f;
    for (int i = t; i < D; i += 256) s += xr[i];
    red[t] = s; __syncthreads();
    for (int st = 128; st > 0; st >>= 1) { if (t < st) red[t] += red[t + st]; __syncthreads(); }
    if (t == 0) s_mu = red[0] / D;
    __syncthreads();
    float mu = s_mu;
    float v = 0.f;
    for (int i = t; i < D; i += 256) { float d = xr[i] - mu; v += d * d; }
    __syncthreads();
    red[t] = v; __syncthreads();
    for (int st = 128; st > 0; st >>= 1) { if (t < st) red[t] += red[t + st]; __syncthreads(); }
    if (t == 0) s_ri = rsqrtf(red[0] / D + 1e-6f);
    __syncthreads();
    float ri = s_ri;
    for (int i = t; i < D; i += 256)
        oh[(long long)row * D + i] = __float2half((xr[i] - mu) * ri * gma[i] + bta[i]);
}

// ---- k-NN (u32 packed keys) + fused combine -> g_combh ----
__global__ void knn_k()
{
    int row = blockIdx.x;
    int b = row >> 11, i = row & (SEQ - 1);
    const float* dr = g_dist + (long long)row * SEQ;
    int t = threadIdx.x, lane = t & 31, w = t >> 5;

    __shared__ uint32_t cand[128];
    __shared__ uint32_t fin[KNN];
    __shared__ float    swt[KNN];
    __shared__ int      sidx[KNN];

    uint32_t v[8];
    int base = w * 256;
    #pragma unroll
    for (int r = 0; r < 8; r++) {
        int j = base + r * 32 + lane;
        float d = (j == i) ? 1e9f : (1.f - dr[j]);
        v[r] = (__float_as_uint(d) & 0xFFFFF800u) | (unsigned)j;
    }

    #pragma unroll
    for (int it = 0; it < KNN; it++) {
        uint32_t m = v[0];
        #pragma unroll
        for (int r = 1; r < 8; r++) m = min(m, v[r]);
        #pragma unroll
        for (int s = 16; s > 0; s >>= 1)
            m = min(m, __shfl_xor_sync(0xffffffffu, m, s));
        if (lane == 0) cand[w * KNN + it] = m;
        #pragma unroll
        for (int r = 0; r < 8; r++) if (v[r] == m) v[r] = 0xFFFFFFFFu;
    }
    __syncthreads();

    if (w == 0) {
        uint32_t c[4];
        #pragma unroll
        for (int r = 0; r < 4; r++) c[r] = cand[r * 32 + lane];
        #pragma unroll
        for (int it = 0; it < KNN; it++) {
            uint32_t m01 = min(c[0], c[1]);
            uint32_t m23 = min(c[2], c[3]);
            uint32_t m = min(m01, m23);
            #pragma unroll
            for (int s = 16; s > 0; s >>= 1)
                m = min(m, __shfl_xor_sync(0xffffffffu, m, s));
            if (lane == 0) fin[it] = m;
            #pragma unroll
            for (int r = 0; r < 4; r++) if (c[r] == m) c[r] = 0xFFFFFFFFu;
        }
        __syncwarp();
        if (lane < KNN) {
            float d0 = __uint_as_float(fin[0] & 0xFFFFF800u);
            float dk = __uint_as_float(fin[lane] & 0xFFFFF800u);
            float wk = expf(d0 - dk);
            float sum = wk;
            #pragma unroll
            for (int s = 8; s > 0; s >>= 1)
                sum += __shfl_xor_sync(0x0000ffffu, sum, s);
            swt[lane]  = wk / sum;
            sidx[lane] = b * SEQ + (int)(fin[lane] & 0x7FFu);
        }
    }
    __syncthreads();

    if (t < TT) {
        float acc = g_topo[(long long)row * TT + t];
        #pragma unroll
        for (int k2 = 0; k2 < KNN; k2++)
            acc += swt[k2] * g_topo[(long long)sidx[k2] * TT + t];
        g_combh[(long long)row * TT + t] = __float2half(acc);
    }
}

// ============================================================================
#define HG_SMEM (3 * 128 * 24 * 2 * 2)   // 36864 B

extern "C" void kernel_launch(void* const* d_in, const int* in_sizes, int n_in,
                              void* d_out, int out_size)
{
    const float* h      = (const float*)d_in[0];
    const int*   mask   = (const int*)  d_in[1];
    const float* W_topo = (const float*)d_in[2];
    const float* b_topo = (const float*)d_in[3];
    const float* W_m1   = (const float*)d_in[4];
    const float* b_m1   = (const float*)d_in[5];
    const float* W_m2   = (const float*)d_in[6];
    const float* b_m2   = (const float*)d_in[7];
    const float* ln_t_s = (const float*)d_in[8];
    const float* ln_t_b = (const float*)d_in[9];
    const float* W_p1   = (const float*)d_in[10];
    const float* b_p1   = (const float*)d_in[11];
    const float* W_p2   = (const float*)d_in[12];
    const float* b_p2   = (const float*)d_in[13];
    const float* ln1_s  = (const float*)d_in[14];
    const float* ln1_b  = (const float*)d_in[15];
    const float* Wq     = (const float*)d_in[16];
    const float* Wk     = (const float*)d_in[17];
    const float* Wv     = (const float*)d_in[18];
    const float* W_gate = (const float*)d_in[19];
    const float* b_gate = (const float*)d_in[20];
    const float* W_o    = (const float*)d_in[21];
    const float* b_o    = (const float*)d_in[22];
    const float* ln2_s  = (const float*)d_in[23];
    const float* ln2_b  = (const float*)d_in[24];
    const float* W_f1   = (const float*)d_in[25];
    const float* b_f1   = (const float*)d_in[26];
    const float* W_f2   = (const float*)d_in[27];
    const float* b_f2   = (const float*)d_in[28];
    float* out = (float*)d_out;

    float *topo, *tt, *h1, *dist;
    __half *xh, *combh, *tmp256h, *tth, *qkvh, *cath, *ctxh, *yh, *ffh, *hh, *hnh;
    __half *wt_topo, *wt_m1, *wt_m2, *wt_p1, *wt_p2, *wt_qkv, *wt_gate, *wt_o, *wt_f1, *wt_f2;
    cudaGetSymbolAddress((void**)&topo,    g_topo);
    cudaGetSymbolAddress((void**)&tt,      g_tt);
    cudaGetSymbolAddress((void**)&h1,      g_h1);
    cudaGetSymbolAddress((void**)&dist,    g_dist);
    cudaGetSymbolAddress((void**)&hh,      g_hh);
    cudaGetSymbolAddress((void**)&hnh,     g_hnh);
    cudaGetSymbolAddress((void**)&xh,      g_xh);
    cudaGetSymbolAddress((void**)&combh,   g_combh);
    cudaGetSymbolAddress((void**)&tmp256h, g_tmp256h);
    cudaGetSymbolAddress((void**)&tth,     g_tth);
    cudaGetSymbolAddress((void**)&qkvh,    g_qkvh);
    cudaGetSymbolAddress((void**)&cath,    g_cath);
    cudaGetSymbolAddress((void**)&ctxh,    g_ctxh);
    cudaGetSymbolAddress((void**)&yh,      g_yh);
    cudaGetSymbolAddress((void**)&ffh,     g_ffh);
    cudaGetSymbolAddress((void**)&wt_topo, g_wt_topo);
    cudaGetSymbolAddress((void**)&wt_m1,   g_wt_m1);
    cudaGetSymbolAddress((void**)&wt_m2,   g_wt_m2);
    cudaGetSymbolAddress((void**)&wt_p1,   g_wt_p1);
    cudaGetSymbolAddress((void**)&wt_p2,   g_wt_p2);
    cudaGetSymbolAddress((void**)&wt_qkv,  g_wt_qkv);
    cudaGetSymbolAddress((void**)&wt_gate, g_wt_gate);
    cudaGetSymbolAddress((void**)&wt_o,    g_wt_o);
    cudaGetSymbolAddress((void**)&wt_f1,   g_wt_f1);
    cudaGetSymbolAddress((void**)&wt_f2,   g_wt_f2);

    const long long SE = (long long)SEQ * EMB;
    const long long SS = (long long)SEQ * SEQ;

    cudaFuncSetAttribute((const void*)flash_k, cudaFuncAttributeMaxDynamicSharedMemorySize, FS_TOT_BYTES);

    // ---- streams/events (created once, outside any capture) ----
    static cudaStream_t st1 = nullptr, st2 = nullptr;
    static cudaEvent_t e_fork, e_ln, e_b1, e_w2, e_qw;
    if (!st1) {
        cudaStreamCreateWithFlags(&st1, cudaStreamNonBlocking);
        cudaStreamCreateWithFlags(&st2, cudaStreamNonBlocking);
        cudaEventCreateWithFlags(&e_fork, cudaEventDisableTiming);
        cudaEventCreateWithFlags(&e_ln,   cudaEventDisableTiming);
        cudaEventCreateWithFlags(&e_b1,   cudaEventDisableTiming);
        cudaEventCreateWithFlags(&e_w2,   cudaEventDisableTiming);
        cudaEventCreateWithFlags(&e_qw,   cudaEventDisableTiming);
    }

    dim3 tb(32, 8);

    // ---- fork ----
    cudaEventRecord(e_fork, 0);
    cudaStreamWaitEvent(st1, e_fork, 0);
    cudaStreamWaitEvent(st2, e_fork, 0);

    // ---- s0: fused convert + l2norm + LN1 (critical path head) ----
    l2ln_k<<<BSX, 256>>>(h, ln1_s, ln1_b);
    cudaEventRecord(e_ln, 0);

    // ---- st2: qkv weight transposes FIRST (unblock critical path), then tail ----
    wt_k<<<dim3(EMB / 32, EMB / 32), tb, 0, st2>>>(Wq, wt_qkv, EMB, EMB);
    wt_k<<<dim3(EMB / 32, EMB / 32), tb, 0, st2>>>(Wk, wt_qkv + (long long)EMB * EMB, EMB, EMB);
    wt_k<<<dim3(EMB / 32, EMB / 32), tb, 0, st2>>>(Wv, wt_qkv + 2LL * EMB * EMB, EMB, EMB);
    cudaEventRecord(e_qw, st2);
    wt_k<<<dim3(EMB / 32, CATW / 32), tb, 0, st2>>>(W_gate, wt_gate, CATW, EMB);
    wt_k<<<dim3(EMB / 32, EMB / 32),  tb, 0, st2>>>(W_o, wt_o, EMB, EMB);
    wt_k<<<dim3(FF / 32, EMB / 32),   tb, 0, st2>>>(W_f1, wt_f1, EMB, FF);
    wt_k<<<dim3(EMB / 32, FF / 32),   tb, 0, st2>>>(W_f2, wt_f2, FF, EMB);
    cudaEventRecord(e_w2, st2);

    // ---- st1: topo branch ----
    wt_k<<<dim3(TT / 32, EMB / 32), tb, 0, st1>>>(W_topo, wt_topo, EMB, TT);
    wt_k<<<dim3(256 / 32, TT / 32), tb, 0, st1>>>(W_m1, wt_m1, TT, 256);
    wt_k<<<dim3(TT / 32, 256 / 32), tb, 0, st1>>>(W_m2, wt_m2, 256, TT);
    wt_k<<<dim3(TT / 32, TT / 32),  tb, 0, st1>>>(W_p1, wt_p1, TT, TT);
    wt_k<<<dim3(TT / 32, TT / 32),  tb, 0, st1>>>(W_p2, wt_p2, TT, TT);
    cudaStreamWaitEvent(st1, e_ln, 0);
    hgemm<0, 0, 0, 0><<<dim3(1, 32, 1), 256, HG_SMEM, st1>>>(hh, wt_topo, topo, b_topo, nullptr, nullptr,
        EMB, EMB, EMB, TT, 0, 0, 1, 0, 0, 0, 0, 0, 0);
    hgemm<0, 0, 0, 0><<<dim3(16, 16, 2), 256, HG_SMEM, st1>>>(hnh, hnh, dist, nullptr, nullptr, nullptr,
        EMB, EMB, EMB, SEQ, 0, 0, 2, SE, 0, SE, 0, SS, 0);
    knn_k<<<BSX, 256, 0, st1>>>();
    hgemm<1, 1, 0, 0><<<dim3(2, 32, 1), 256, HG_SMEM, st1>>>(combh, wt_m1, tmp256h, b_m1, nullptr, nullptr,
        TT, TT, TT, 256, 0, 0, 1, 0, 0, 0, 0, 0, 0);
    hgemm<0, 0, 0, 0><<<dim3(1, 32, 1), 256, HG_SMEM, st1>>>(tmp256h, wt_m2, tt, b_m2, nullptr, nullptr,
        256, 256, 256, TT, 0, 0, 1, 0, 0, 0, 0, 0, 0);
    lnh_k<<<BSX, 256, 0, st1>>>(tt, tth, ln_t_s, ln_t_b, TT);
    hgemm<1, 1, 0, 0><<<dim3(1, 32, 1), 256, HG_SMEM, st1>>>(tth, wt_p1, tmp256h, b_p1, nullptr, nullptr,
        TT, TT, TT, TT, 0, 0, 1, 0, 0, 0, 0, 0, 0);
    hgemm<0, 1, 0, 0><<<dim3(1, 32, 1), 256, HG_SMEM, st1>>>(tmp256h, wt_p2, cath + EMB, b_p2, nullptr, nullptr,
        TT, TT, TT, CATW, 0, 0, 1, 0, 0, 0, 0, 0, 0);
    cudaEventRecord(e_b1, st1);

    // ---- s0: attention branch (fused QKV) ----
    cudaStreamWaitEvent(0, e_qw, 0);
    hgemm<0, 1, 0, 0><<<dim3(QKVW / 128, 32, 1), 256, HG_SMEM>>>(xh, wt_qkv, qkvh, nullptr, nullptr, nullptr,
        EMB, EMB, EMB, QKVW, 0, 0, 1, 0, 0, 0, 0, 0, 0);
    flash_k<<<dim3(16, BB * NH), 256, FS_TOT_BYTES>>>(qkvh, mask, cath);

    // ---- join ----
    cudaStreamWaitEvent(0, e_b1, 0);
    cudaStreamWaitEvent(0, e_w2, 0);

    // ---- tail ----
    hgemm<3, 1, 1, 1><<<dim3(6, 32, 1), 256, HG_SMEM>>>(cath, wt_gate, ctxh, b_gate, cath, xh,
        CATW, CATW, CATW, EMB, CATW, EMB, 1, 0, 0, 0, 0, 0, 0);
    hgemm<0, 0, 0, 0><<<dim3(6, 32, 1), 256, HG_SMEM>>>(ctxh, wt_o, h1, b_o, h, nullptr,
        EMB, EMB, EMB, EMB, EMB, 0, 1, 0, 0, 0, 0, 0, 0);
    lnh_k<<<BSX, 256>>>(h1, yh, ln2_s, ln2_b, EMB);
    hgemm<2, 1, 0, 0><<<dim3(24, 32, 1), 256, HG_SMEM>>>(yh, wt_f1, ffh, b_f1, nullptr, nullptr,
        EMB, EMB, EMB, FF, 0, 0, 1, 0, 0, 0, 0, 0, 0);
    hgemm<0, 0, 0, 0><<<dim3(6, 32, 1), 256, HG_SMEM>>>(ffh, wt_f2, out, b_f2, h1, nullptr,
        FF, FF, FF, EMB, EMB, 0, 1, 0, 0, 0, 0, 0, 0);
}

// round 13
// speedup vs baseline: 2.3973x; 1.1058x over previous
#include <cuda_runtime.h>
#include <cuda_fp16.h>
#include <math.h>
#include <stdint.h>

// ---- problem constants ----
#define BSX 4096   // B*S
#define BB  2
#define SEQ 2048
#define EMB 768
#define TT  128
#define NH  12
#define DHD 64
#define FF  3072
#define KNN 16
#define CATW (EMB + TT)   // 896
#define QKVW (3 * EMB)    // 2304

// ---- fp32 scratch ----
__device__ float g_topo[BSX * TT];
__device__ float g_tt[BSX * TT];
__device__ float g_h1[BSX * EMB];
__device__ float g_dist[(long long)BB * SEQ * SEQ];

// ---- fp16 scratch ----
__device__ __half g_hh[BSX * EMB];
__device__ __half g_hnh[BSX * EMB];
__device__ __half g_xh[BSX * EMB];
__device__ __half g_combh[BSX * TT];
__device__ __half g_tmp256h[BSX * 256];
__device__ __half g_tth[BSX * TT];
__device__ __half g_qkvh[(long long)BSX * QKVW];
__device__ __half g_cath[BSX * CATW];
__device__ __half g_ctxh[BSX * EMB];
__device__ __half g_yh[BSX * EMB];
__device__ __half g_ffh[(long long)BSX * FF];

// ---- transposed fp16 weights [N][K] ----
__device__ __half g_wt_topo[TT * EMB];
__device__ __half g_wt_m1[256 * TT];
__device__ __half g_wt_m2[TT * 256];
__device__ __half g_wt_p1[TT * TT];
__device__ __half g_wt_p2[TT * TT];
__device__ __half g_wt_qkv[QKVW * EMB];
__device__ __half g_wt_gate[EMB * CATW];
__device__ __half g_wt_o[EMB * EMB];
__device__ __half g_wt_f1[FF * EMB];
__device__ __half g_wt_f2[EMB * FF];

__device__ __forceinline__ void mma_f16(float* c, const uint32_t* a, uint32_t b0, uint32_t b1) {
    asm volatile(
        "mma.sync.aligned.m16n8k16.row.col.f32.f16.f16.f32 "
        "{%0,%1,%2,%3},{%4,%5,%6,%7},{%8,%9},{%0,%1,%2,%3};"
        : "+f"(c[0]), "+f"(c[1]), "+f"(c[2]), "+f"(c[3])
        : "r"(a[0]), "r"(a[1]), "r"(a[2]), "r"(a[3]), "r"(b0), "r"(b1));
}

__device__ __forceinline__ void cpa16(void* s, const void* g) {
    unsigned sa = (unsigned)__cvta_generic_to_shared(s);
    asm volatile("cp.async.cg.shared.global [%0], [%1], 16;" :: "r"(sa), "l"(g));
}
__device__ __forceinline__ void cpa_commit() { asm volatile("cp.async.commit_group;"); }
__device__ __forceinline__ void cpa_wait1()  { asm volatile("cp.async.wait_group 1;"); }
__device__ __forceinline__ void cpa_wait0()  { asm volatile("cp.async.wait_group 0;"); }

__device__ __forceinline__ void ldsm4(uint32_t* r, uint32_t addr) {
    asm volatile("ldmatrix.sync.aligned.m8n8.x4.shared.b16 {%0,%1,%2,%3}, [%4];"
                 : "=r"(r[0]), "=r"(r[1]), "=r"(r[2]), "=r"(r[3]) : "r"(addr));
}

__device__ __forceinline__ void ldsm4t(uint32_t* r, uint32_t addr) {
    asm volatile("ldmatrix.sync.aligned.m8n8.x4.trans.shared.b16 {%0,%1,%2,%3}, [%4];"
                 : "=r"(r[0]), "=r"(r[1]), "=r"(r[2]), "=r"(r[3]) : "r"(addr));
}

__device__ __forceinline__ uint32_t h2ex2(uint32_t x) {
    uint32_t y;
    asm("ex2.approx.f16x2 %0, %1;" : "=r"(y) : "r"(x));
    return y;
}

// ============================================================================
// fp16 tensor-core GEMM (m16n8k16), cp.async 3-stage pipeline with k32
// stages (two k16 sub-steps per stage -> half the syncs), ldmatrix loads.
// A [M,K] fp16 row-major; B [N,K] fp16 row-major (K-major).
// ACT: 0 none, 1 relu, 2 gelu, 3 sigmoid-mix. CH: C half. RH/R2H: res half.
// Requirements: M%128==0, N%128==0, K%32==0.
// smem = 3 stages x 128x40 halves x 2 operands = 61440 B.
// ============================================================================
#define HSTG (128 * 40)   // halves per stage per operand
#define HG_SMEM (3 * HSTG * 2 * 2)

template<int ACT, int CH, int RH, int R2H>
__global__ void __launch_bounds__(256) hgemm(
    const __half* __restrict__ A, const __half* __restrict__ B,
    void* __restrict__ Cv, const float* __restrict__ bias,
    const void* __restrict__ resv, const void* __restrict__ res2v,
    int K, int lda, int ldb, int ldc, int ldr1, int ldr2,
    int zdiv, long long sA1, long long sA2,
    long long sB1, long long sB2, long long sC1, long long sC2)
{
    extern __shared__ __half hs[];
    __half* As = hs;                 // [3][128][40]
    __half* Bs = hs + 3 * HSTG;      // [3][128][40]

    int z = blockIdx.z;
    long long zm = z % zdiv, zd = z / zdiv;
    A += zm * sA1 + zd * sA2;
    B += zm * sB1 + zd * sB2;
    long long co = zm * sC1 + zd * sC2;

    const int t    = threadIdx.x;
    const int lane = t & 31;
    const int wid  = t >> 5;
    const int lr   = lane >> 2;
    const int lc   = lane & 3;
    const int wm   = (wid & 3) * 32;
    const int wn   = (wid >> 2) * 64;
    const int bm   = blockIdx.y * 128;
    const int bn   = blockIdx.x * 128;

    const uint32_t sbase = (uint32_t)__cvta_generic_to_shared(hs);
    // ldmatrix lane byte-offsets, row pitch 40 halves = 80 B
    const uint32_t offA = (uint32_t)((lane & 15) * 80 + (lane >> 4) * 16);
    const uint32_t offB = (uint32_t)((((lane >> 4) & 1) * 8 + (lane & 7)) * 80 + ((lane >> 3) & 1) * 16);

    float acc[2][8][4];
    #pragma unroll
    for (int mt = 0; mt < 2; mt++)
        #pragma unroll
        for (int nt = 0; nt < 8; nt++)
            #pragma unroll
            for (int i = 0; i < 4; i++) acc[mt][nt][i] = 0.f;

    auto issue = [&](int buf, int k0) {
        #pragma unroll
        for (int i = 0; i < 2; i++) {
            int c = t + i * 256;
            int row = c >> 2, kq = (c & 3) * 8;
            cpa16(&As[buf * HSTG + row * 40 + kq],
                  A + (long long)(bm + row) * lda + k0 + kq);
        }
        #pragma unroll
        for (int i = 0; i < 2; i++) {
            int c = t + i * 256;
            int row = c >> 2, kq = (c & 3) * 8;
            cpa16(&Bs[buf * HSTG + row * 40 + kq],
                  B + (long long)(bn + row) * ldb + k0 + kq);
        }
        cpa_commit();
    };

    const int iters = K >> 5;
    issue(0, 0);
    issue(1, 32);

    for (int kb = 0; kb < iters; kb++) {
        cpa_wait1();
        __syncthreads();
        int cur = kb - (kb / 3) * 3;
        uint32_t aB = sbase + (uint32_t)cur * (HSTG * 2);
        uint32_t bB = sbase + (uint32_t)(3 + cur) * (HSTG * 2);

        #pragma unroll
        for (int kk = 0; kk < 2; kk++) {
            uint32_t af[2][4];
            #pragma unroll
            for (int mt = 0; mt < 2; mt++)
                ldsm4(af[mt], aB + (wm + mt * 16) * 80 + kk * 32 + offA);

            #pragma unroll
            for (int p = 0; p < 4; p++) {
                uint32_t bb[4];
                ldsm4(bb, bB + (wn + p * 16) * 80 + kk * 32 + offB);
                #pragma unroll
                for (int sub = 0; sub < 2; sub++)
                    #pragma unroll
                    for (int mt = 0; mt < 2; mt++)
                        mma_f16(acc[mt][p * 2 + sub], af[mt], bb[sub * 2], bb[sub * 2 + 1]);
            }
        }

        int nst  = kb + 2;
        int nbuf = nst - (nst / 3) * 3;
        int nk0  = (nst < iters ? nst : iters - 1) << 5;
        issue(nbuf, nk0);
    }

    // epilogue
    const float* res = (const float*)resv;
    const __half* resh = (const __half*)resv;
    #pragma unroll
    for (int mt = 0; mt < 2; mt++) {
        #pragma unroll
        for (int nt = 0; nt < 8; nt++) {
            int mrow = bm + wm + mt * 16 + lr;
            int ncol = bn + wn + nt * 8 + 2 * lc;
            #pragma unroll
            for (int half_ = 0; half_ < 2; half_++) {
                int m = mrow + half_ * 8;
                float v0 = acc[mt][nt][half_ * 2 + 0];
                float v1 = acc[mt][nt][half_ * 2 + 1];
                if (bias) { v0 += bias[ncol]; v1 += bias[ncol + 1]; }
                if (ACT == 1) { v0 = fmaxf(v0, 0.f); v1 = fmaxf(v1, 0.f); }
                if (ACT == 2) {
                    float u = v0;
                    v0 = 0.5f * u * (1.f + tanhf(0.7978845608028654f * (u + 0.044715f * u * u * u)));
                    u = v1;
                    v1 = 0.5f * u * (1.f + tanhf(0.7978845608028654f * (u + 0.044715f * u * u * u)));
                }
                long long off = (long long)m * ldc + ncol + co;
                if (ACT == 3) {
                    float s0 = 1.f / (1.f + expf(-v0));
                    float s1 = 1.f / (1.f + expf(-v1));
                    long long o1 = (long long)m * ldr1 + ncol;
                    long long o2 = (long long)m * ldr2 + ncol;
                    float r1x, r1y, r2x, r2y;
                    if (RH) {
                        __half2 rh = *(const __half2*)(resh + o1);
                        r1x = __half2float(rh.x); r1y = __half2float(rh.y);
                    } else {
                        float2 r1 = *(const float2*)(res + o1);
                        r1x = r1.x; r1y = r1.y;
                    }
                    if (R2H) {
                        __half2 rh2 = *(const __half2*)((const __half*)res2v + o2);
                        r2x = __half2float(rh2.x); r2y = __half2float(rh2.y);
                    } else {
                        float2 r2 = *(const float2*)((const float*)res2v + o2);
                        r2x = r2.x; r2y = r2.y;
                    }
                    v0 = s0 * r1x + (1.f - s0) * r2x;
                    v1 = s1 * r1y + (1.f - s1) * r2y;
                } else if (resv) {
                    float2 r1 = *(const float2*)(res + (long long)m * ldr1 + ncol + co);
                    v0 += r1.x; v1 += r1.y;
                }
                if (CH) {
                    __half2 hv = __floats2half2_rn(v0, v1);
                    *(__half2*)((__half*)Cv + off) = hv;
                } else {
                    float2 o2v = {v0, v1};
                    *(float2*)((float*)Cv + off) = o2v;
                }
            }
        }
    }
}

// ============================================================================
// Flash attention fp16 over fused qkv buffer [BSX][2304].
// ex2.approx.f16x2 softmax; V via ldmatrix.x4.trans.
// smem: sP[128][136] | sK[2][128][72] | sV[2][128][72] = 108544 B
// ============================================================================
#define FS_P 0
#define FS_K 17408
#define FS_V 35840
#define FS_TOT_BYTES 108544
#define LOG2E 1.4426950408889634f

__global__ void __launch_bounds__(256) flash_k(
    const __half* __restrict__ qkv, const int* __restrict__ mask,
    __half* __restrict__ outc)
{
    extern __shared__ __half fh[];
    __half* sP = fh + FS_P;
    __half* sK = fh + FS_K;
    __half* sV = fh + FS_V;

    const int t = threadIdx.x, lane = t & 31, w = t >> 5;
    const int lr = lane >> 2, lc = lane & 3;
    const int z = blockIdx.y, b = z / NH, hh = z % NH;
    const int bm = blockIdx.x * 128;
    const long long base = (long long)b * SEQ * QKVW + hh * DHD;
    const __half* qp = qkv + base;
    const __half* kp = qkv + base + EMB;
    const __half* vp = qkv + base + 2 * EMB;
    const int* mrow = mask + b * SEQ;

    const uint32_t fbase = (uint32_t)__cvta_generic_to_shared(fh);
    const uint32_t pbase = fbase;
    const uint32_t kbase = fbase + FS_K * 2;
    const uint32_t vbase = fbase + FS_V * 2;
    const uint32_t offK = (uint32_t)((((lane >> 4) & 1) * 8 + (lane & 7)) * 144 + ((lane >> 3) & 1) * 16);
    const uint32_t offP = (uint32_t)((lane & 15) * 272 + (lane >> 4) * 16);
    const uint32_t offV = (uint32_t)((lane & 15) * 144 + (lane >> 4) * 16);

    #pragma unroll
    for (int j = 0; j < 4; j++) {
        int flat = t + j * 256;
        int row = flat >> 3, q8 = (flat & 7) << 3;
        cpa16(&sP[row * 136 + q8], qp + (long long)(bm + row) * QKVW + q8);
    }
    cpa_commit();

    auto issueKV = [&](int kt) {
        int buf = kt & 1;
        #pragma unroll
        for (int j = 0; j < 4; j++) {
            int flat = t + j * 256;
            int row = flat >> 3, q8 = (flat & 7) << 3;
            cpa16(&sK[buf * 9216 + row * 72 + q8],
                  kp + (long long)(kt * 128 + row) * QKVW + q8);
        }
        #pragma unroll
        for (int j = 0; j < 4; j++) {
            int flat = t + j * 256;
            int row = flat >> 3, q8 = (flat & 7) << 3;
            cpa16(&sV[buf * 9216 + row * 72 + q8],
                  vp + (long long)(kt * 128 + row) * QKVW + q8);
        }
        cpa_commit();
    };
    issueKV(0);

    cpa_wait1();
    __syncthreads();

    const int wq = w * 16;
    uint32_t qf[4][4];
    #pragma unroll
    for (int ks = 0; ks < 4; ks++)
        ldsm4(qf[ks], pbase + (uint32_t)wq * 272 + ks * 32 + offP);
    __syncthreads();

    float ctx[8][4];
    #pragma unroll
    for (int nt = 0; nt < 8; nt++)
        #pragma unroll
        for (int i = 0; i < 4; i++) ctx[nt][i] = 0.f;
    float m0 = -1e30f, m1 = -1e30f, l0 = 0.f, l1 = 0.f;

    for (int kt = 0; kt < 16; kt++) {
        cpa_wait0();
        __syncthreads();
        if (kt + 1 < 16) issueKV(kt + 1);

        const int buf = kt & 1;
        const uint32_t kB = kbase + (uint32_t)buf * (9216 * 2);
        const uint32_t vB = vbase + (uint32_t)buf * (9216 * 2);

        // ---- S = Q K^T ----
        float S[16][4];
        #pragma unroll
        for (int nt = 0; nt < 16; nt++)
            #pragma unroll
            for (int i = 0; i < 4; i++) S[nt][i] = 0.f;
        #pragma unroll
        for (int ks = 0; ks < 4; ks++) {
            #pragma unroll
            for (int p = 0; p < 8; p++) {
                uint32_t bb[4];
                ldsm4(bb, kB + (uint32_t)(p * 16) * 144 + ks * 32 + offK);
                mma_f16(S[p * 2],     qf[ks], bb[0], bb[1]);
                mma_f16(S[p * 2 + 1], qf[ks], bb[2], bb[3]);
            }
        }

        // ---- scale + mask + row max ----
        float nm0 = -1e30f, nm1 = -1e30f;
        #pragma unroll
        for (int nt = 0; nt < 16; nt++) {
            int c0 = kt * 128 + nt * 8 + 2 * lc;
            int2 mg = *(const int2*)&mrow[c0];
            float s0 = S[nt][0] * 0.125f, s1 = S[nt][1] * 0.125f;
            float s2 = S[nt][2] * 0.125f, s3 = S[nt][3] * 0.125f;
            if (mg.x == 0) { s0 = -10000.f; s2 = -10000.f; }
            if (mg.y == 0) { s1 = -10000.f; s3 = -10000.f; }
            S[nt][0] = s0; S[nt][1] = s1; S[nt][2] = s2; S[nt][3] = s3;
            nm0 = fmaxf(nm0, fmaxf(s0, s1));
            nm1 = fmaxf(nm1, fmaxf(s2, s3));
        }
        nm0 = fmaxf(nm0, __shfl_xor_sync(0xffffffffu, nm0, 1));
        nm0 = fmaxf(nm0, __shfl_xor_sync(0xffffffffu, nm0, 2));
        nm1 = fmaxf(nm1, __shfl_xor_sync(0xffffffffu, nm1, 1));
        nm1 = fmaxf(nm1, __shfl_xor_sync(0xffffffffu, nm1, 2));
        float M0 = fmaxf(m0, nm0), M1 = fmaxf(m1, nm1);
        float a0 = expf(m0 - M0), a1 = expf(m1 - M1);

        // ---- P via ex2.f16x2; sum; store fp16 P ----
        float r0 = 0.f, r1 = 0.f;
        #pragma unroll
        for (int nt = 0; nt < 16; nt++) {
            __half2 e01 = __floats2half2_rn((S[nt][0] - M0) * LOG2E, (S[nt][1] - M0) * LOG2E);
            __half2 e23 = __floats2half2_rn((S[nt][2] - M1) * LOG2E, (S[nt][3] - M1) * LOG2E);
            uint32_t p01 = h2ex2(*(uint32_t*)&e01);
            uint32_t p23 = h2ex2(*(uint32_t*)&e23);
            float2 f01 = __half22float2(*(__half2*)&p01);
            float2 f23 = __half22float2(*(__half2*)&p23);
            r0 += f01.x + f01.y;
            r1 += f23.x + f23.y;
            *(uint32_t*)(sP + (wq + lr) * 136 + nt * 8 + 2 * lc)     = p01;
            *(uint32_t*)(sP + (wq + lr + 8) * 136 + nt * 8 + 2 * lc) = p23;
        }
        r0 += __shfl_xor_sync(0xffffffffu, r0, 1);
        r0 += __shfl_xor_sync(0xffffffffu, r0, 2);
        r1 += __shfl_xor_sync(0xffffffffu, r1, 1);
        r1 += __shfl_xor_sync(0xffffffffu, r1, 2);
        l0 = l0 * a0 + r0;
        l1 = l1 * a1 + r1;
        m0 = M0; m1 = M1;
        #pragma unroll
        for (int nt = 0; nt < 8; nt++) {
            ctx[nt][0] *= a0; ctx[nt][1] *= a0;
            ctx[nt][2] *= a1; ctx[nt][3] *= a1;
        }
        __syncwarp();

        // ---- ctx += P V ----
        #pragma unroll
        for (int ks = 0; ks < 8; ks++) {
            uint32_t af[4];
            ldsm4(af, pbase + (uint32_t)wq * 272 + ks * 32 + offP);
            #pragma unroll
            for (int nt = 0; nt < 8; nt += 2) {
                uint32_t bb[4];
                ldsm4t(bb, vB + (uint32_t)(ks * 16) * 144 + (uint32_t)(nt * 16) + offV);
                mma_f16(ctx[nt],     af, bb[0], bb[1]);
                mma_f16(ctx[nt + 1], af, bb[2], bb[3]);
            }
        }
    }

    float il0 = 1.f / l0, il1 = 1.f / l1;
    #pragma unroll
    for (int nt = 0; nt < 8; nt++) {
        long long row0 = (long long)b * SEQ + bm + wq + lr;
        int col = hh * DHD + nt * 8 + 2 * lc;
        *(__half2*)&outc[row0 * CATW + col] = __floats2half2_rn(ctx[nt][0] * il0, ctx[nt][1] * il0);
        *(__half2*)&outc[(row0 + 8) * CATW + col] = __floats2half2_rn(ctx[nt][2] * il1, ctx[nt][3] * il1);
    }
}

// ---- weight transpose + fp32->fp16: in [K][N] -> out [N][K] ----
__global__ void wt_k(const float* __restrict__ in, __half* __restrict__ out, int K, int N)
{
    __shared__ float tile[32][33];
    int bx = blockIdx.x * 32, by = blockIdx.y * 32;
    int tx = threadIdx.x, ty = threadIdx.y;
    #pragma unroll
    for (int j = ty; j < 32; j += 8)
        tile[j][tx] = in[(long long)(by + j) * N + bx + tx];
    __syncthreads();
    #pragma unroll
    for (int j = ty; j < 32; j += 8)
        out[(long long)(bx + j) * K + by + tx] = __float2half(tile[tx][j]);
}

// ---- fused: hh = fp16(h); hn_h = fp16(h/||h||); xh = fp16(LN1(h)) ----
__global__ void l2ln_k(const float* __restrict__ h,
                       const float* __restrict__ gma, const float* __restrict__ bta)
{
    int row = blockIdx.x, t = threadIdx.x;
    const float* xr = h + (long long)row * EMB;
    __shared__ float sh[EMB];
    __shared__ float r1[256], r2[256];
    float s = 0.f, ss = 0.f;
    for (int i = t; i < EMB; i += 256) { float v = xr[i]; sh[i] = v; s += v; ss += v * v; }
    r1[t] = s; r2[t] = ss; __syncthreads();
    for (int st = 128; st > 0; st >>= 1) {
        if (t < st) { r1[t] += r1[t + st]; r2[t] += r2[t + st]; }
        __syncthreads();
    }
    float mu   = r1[0] / EMB;
    float var  = r2[0] / EMB - mu * mu;
    float ri   = rsqrtf(var + 1e-6f);
    float invn = 1.f / (sqrtf(r2[0]) + 1e-8f);
    for (int i = t; i < EMB; i += 256) {
        float v = sh[i];
        g_hh [(long long)row * EMB + i] = __float2half(v);
        g_hnh[(long long)row * EMB + i] = __float2half(v * invn);
        g_xh [(long long)row * EMB + i] = __float2half((v - mu) * ri * gma[i] + bta[i]);
    }
}

// ---- layernorm -> fp16 output ----
__global__ void lnh_k(const float* __restrict__ x, __half* __restrict__ oh,
                      const float* __restrict__ gma, const float* __restrict__ bta, int D)
{
    int row = blockIdx.x, t = threadIdx.x;
    const float* xr = x + (long long)row * D;
    __shared__ float red[256];
    __shared__ float s_mu, s_ri;
    float s = 0.f;
    for (int i = t; i < D; i += 256) s += xr[i];
    red[t] = s; __syncthreads();
    for (int st = 128; st > 0; st >>= 1) { if (t < st) red[t] += red[t + st]; __syncthreads(); }
    if (t == 0) s_mu = red[0] / D;
    __syncthreads();
    float mu = s_mu;
    float v = 0.f;
    for (int i = t; i < D; i += 256) { float d = xr[i] - mu; v += d * d; }
    __syncthreads();
    red[t] = v; __syncthreads();
    for (int st = 128; st > 0; st >>= 1) { if (t < st) red[t] += red[t + st]; __syncthreads(); }
    if (t == 0) s_ri = rsqrtf(red[0] / D + 1e-6f);
    __syncthreads();
    float ri = s_ri;
    for (int i = t; i < D; i += 256)
        oh[(long long)row * D + i] = __float2half((xr[i] - mu) * ri * gma[i] + bta[i]);
}

// ---- k-NN (u32 packed keys) + fused combine -> g_combh ----
__global__ void knn_k(int row0)
{
    int row = blockIdx.x + row0;
    int b = row >> 11, i = row & (SEQ - 1);
    const float* dr = g_dist + (long long)row * SEQ;
    int t = threadIdx.x, lane = t & 31, w = t >> 5;

    __shared__ uint32_t cand[128];
    __shared__ uint32_t fin[KNN];
    __shared__ float    swt[KNN];
    __shared__ int      sidx[KNN];

    uint32_t v[8];
    int base = w * 256;
    #pragma unroll
    for (int r = 0; r < 8; r++) {
        int j = base + r * 32 + lane;
        float d = (j == i) ? 1e9f : (1.f - dr[j]);
        v[r] = (__float_as_uint(d) & 0xFFFFF800u) | (unsigned)j;
    }

    #pragma unroll
    for (int it = 0; it < KNN; it++) {
        uint32_t m = v[0];
        #pragma unroll
        for (int r = 1; r < 8; r++) m = min(m, v[r]);
        #pragma unroll
        for (int s = 16; s > 0; s >>= 1)
            m = min(m, __shfl_xor_sync(0xffffffffu, m, s));
        if (lane == 0) cand[w * KNN + it] = m;
        #pragma unroll
        for (int r = 0; r < 8; r++) if (v[r] == m) v[r] = 0xFFFFFFFFu;
    }
    __syncthreads();

    if (w == 0) {
        uint32_t c[4];
        #pragma unroll
        for (int r = 0; r < 4; r++) c[r] = cand[r * 32 + lane];
        #pragma unroll
        for (int it = 0; it < KNN; it++) {
            uint32_t m01 = min(c[0], c[1]);
            uint32_t m23 = min(c[2], c[3]);
            uint32_t m = min(m01, m23);
            #pragma unroll
            for (int s = 16; s > 0; s >>= 1)
                m = min(m, __shfl_xor_sync(0xffffffffu, m, s));
            if (lane == 0) fin[it] = m;
            #pragma unroll
            for (int r = 0; r < 4; r++) if (c[r] == m) c[r] = 0xFFFFFFFFu;
        }
        __syncwarp();
        if (lane < KNN) {
            float d0 = __uint_as_float(fin[0] & 0xFFFFF800u);
            float dk = __uint_as_float(fin[lane] & 0xFFFFF800u);
            float wk = expf(d0 - dk);
            float sum = wk;
            #pragma unroll
            for (int s = 8; s > 0; s >>= 1)
                sum += __shfl_xor_sync(0x0000ffffu, sum, s);
            swt[lane]  = wk / sum;
            sidx[lane] = b * SEQ + (int)(fin[lane] & 0x7FFu);
        }
    }
    __syncthreads();

    if (t < TT) {
        float acc = g_topo[(long long)row * TT + t];
        #pragma unroll
        for (int k2 = 0; k2 < KNN; k2++)
            acc += swt[k2] * g_topo[(long long)sidx[k2] * TT + t];
        g_combh[(long long)row * TT + t] = __float2half(acc);
    }
}

// ============================================================================
extern "C" void kernel_launch(void* const* d_in, const int* in_sizes, int n_in,
                              void* d_out, int out_size)
{
    const float* h      = (const float*)d_in[0];
    const int*   mask   = (const int*)  d_in[1];
    const float* W_topo = (const float*)d_in[2];
    const float* b_topo = (const float*)d_in[3];
    const float* W_m1   = (const float*)d_in[4];
    const float* b_m1   = (const float*)d_in[5];
    const float* W_m2   = (const float*)d_in[6];
    const float* b_m2   = (const float*)d_in[7];
    const float* ln_t_s = (const float*)d_in[8];
    const float* ln_t_b = (const float*)d_in[9];
    const float* W_p1   = (const float*)d_in[10];
    const float* b_p1   = (const float*)d_in[11];
    const float* W_p2   = (const float*)d_in[12];
    const float* b_p2   = (const float*)d_in[13];
    const float* ln1_s  = (const float*)d_in[14];
    const float* ln1_b  = (const float*)d_in[15];
    const float* Wq     = (const float*)d_in[16];
    const float* Wk     = (const float*)d_in[17];
    const float* Wv     = (const float*)d_in[18];
    const float* W_gate = (const float*)d_in[19];
    const float* b_gate = (const float*)d_in[20];
    const float* W_o    = (const float*)d_in[21];
    const float* b_o    = (const float*)d_in[22];
    const float* ln2_s  = (const float*)d_in[23];
    const float* ln2_b  = (const float*)d_in[24];
    const float* W_f1   = (const float*)d_in[25];
    const float* b_f1   = (const float*)d_in[26];
    const float* W_f2   = (const float*)d_in[27];
    const float* b_f2   = (const float*)d_in[28];
    float* out = (float*)d_out;

    float *topo, *tt, *h1, *dist;
    __half *xh, *combh, *tmp256h, *tth, *qkvh, *cath, *ctxh, *yh, *ffh, *hh, *hnh;
    __half *wt_topo, *wt_m1, *wt_m2, *wt_p1, *wt_p2, *wt_qkv, *wt_gate, *wt_o, *wt_f1, *wt_f2;
    cudaGetSymbolAddress((void**)&topo,    g_topo);
    cudaGetSymbolAddress((void**)&tt,      g_tt);
    cudaGetSymbolAddress((void**)&h1,      g_h1);
    cudaGetSymbolAddress((void**)&dist,    g_dist);
    cudaGetSymbolAddress((void**)&hh,      g_hh);
    cudaGetSymbolAddress((void**)&hnh,     g_hnh);
    cudaGetSymbolAddress((void**)&xh,      g_xh);
    cudaGetSymbolAddress((void**)&combh,   g_combh);
    cudaGetSymbolAddress((void**)&tmp256h, g_tmp256h);
    cudaGetSymbolAddress((void**)&tth,     g_tth);
    cudaGetSymbolAddress((void**)&qkvh,    g_qkvh);
    cudaGetSymbolAddress((void**)&cath,    g_cath);
    cudaGetSymbolAddress((void**)&ctxh,    g_ctxh);
    cudaGetSymbolAddress((void**)&yh,      g_yh);
    cudaGetSymbolAddress((void**)&ffh,     g_ffh);
    cudaGetSymbolAddress((void**)&wt_topo, g_wt_topo);
    cudaGetSymbolAddress((void**)&wt_m1,   g_wt_m1);
    cudaGetSymbolAddress((void**)&wt_m2,   g_wt_m2);
    cudaGetSymbolAddress((void**)&wt_p1,   g_wt_p1);
    cudaGetSymbolAddress((void**)&wt_p2,   g_wt_p2);
    cudaGetSymbolAddress((void**)&wt_qkv,  g_wt_qkv);
    cudaGetSymbolAddress((void**)&wt_gate, g_wt_gate);
    cudaGetSymbolAddress((void**)&wt_o,    g_wt_o);
    cudaGetSymbolAddress((void**)&wt_f1,   g_wt_f1);
    cudaGetSymbolAddress((void**)&wt_f2,   g_wt_f2);

    const long long SE = (long long)SEQ * EMB;
    const long long SS = (long long)SEQ * SEQ;

    cudaFuncSetAttribute((const void*)flash_k, cudaFuncAttributeMaxDynamicSharedMemorySize, FS_TOT_BYTES);
    cudaFuncSetAttribute((const void*)hgemm<0, 0, 0, 0>, cudaFuncAttributeMaxDynamicSharedMemorySize, HG_SMEM);
    cudaFuncSetAttribute((const void*)hgemm<0, 1, 0, 0>, cudaFuncAttributeMaxDynamicSharedMemorySize, HG_SMEM);
    cudaFuncSetAttribute((const void*)hgemm<1, 1, 0, 0>, cudaFuncAttributeMaxDynamicSharedMemorySize, HG_SMEM);
    cudaFuncSetAttribute((const void*)hgemm<2, 1, 0, 0>, cudaFuncAttributeMaxDynamicSharedMemorySize, HG_SMEM);
    cudaFuncSetAttribute((const void*)hgemm<3, 1, 1, 1>, cudaFuncAttributeMaxDynamicSharedMemorySize, HG_SMEM);

    // ---- streams/events (created once, outside any capture) ----
    static cudaStream_t st1 = nullptr, st2 = nullptr;
    static cudaEvent_t e_fork, e_ln, e_b1, e_w2, e_qw, e_topo, e_d0, e_k0;
    if (!st1) {
        cudaStreamCreateWithFlags(&st1, cudaStreamNonBlocking);
        cudaStreamCreateWithFlags(&st2, cudaStreamNonBlocking);
        cudaEventCreateWithFlags(&e_fork, cudaEventDisableTiming);
        cudaEventCreateWithFlags(&e_ln,   cudaEventDisableTiming);
        cudaEventCreateWithFlags(&e_b1,   cudaEventDisableTiming);
        cudaEventCreateWithFlags(&e_w2,   cudaEventDisableTiming);
        cudaEventCreateWithFlags(&e_qw,   cudaEventDisableTiming);
        cudaEventCreateWithFlags(&e_topo, cudaEventDisableTiming);
        cudaEventCreateWithFlags(&e_d0,   cudaEventDisableTiming);
        cudaEventCreateWithFlags(&e_k0,   cudaEventDisableTiming);
    }

    dim3 tb(32, 8);

    // ---- fork ----
    cudaEventRecord(e_fork, 0);
    cudaStreamWaitEvent(st1, e_fork, 0);
    cudaStreamWaitEvent(st2, e_fork, 0);

    // ---- s0: fused convert + l2norm + LN1 ----
    l2ln_k<<<BSX, 256>>>(h, ln1_s, ln1_b);
    cudaEventRecord(e_ln, 0);

    // ---- st2: qkv transposes first, then tail transposes ----
    wt_k<<<dim3(EMB / 32, EMB / 32), tb, 0, st2>>>(Wq, wt_qkv, EMB, EMB);
    wt_k<<<dim3(EMB / 32, EMB / 32), tb, 0, st2>>>(Wk, wt_qkv + (long long)EMB * EMB, EMB, EMB);
    wt_k<<<dim3(EMB / 32, EMB / 32), tb, 0, st2>>>(Wv, wt_qkv + 2LL * EMB * EMB, EMB, EMB);
    cudaEventRecord(e_qw, st2);
    wt_k<<<dim3(EMB / 32, CATW / 32), tb, 0, st2>>>(W_gate, wt_gate, CATW, EMB);
    wt_k<<<dim3(EMB / 32, EMB / 32),  tb, 0, st2>>>(W_o, wt_o, EMB, EMB);
    wt_k<<<dim3(FF / 32, EMB / 32),   tb, 0, st2>>>(W_f1, wt_f1, EMB, FF);
    wt_k<<<dim3(EMB / 32, FF / 32),   tb, 0, st2>>>(W_f2, wt_f2, FF, EMB);
    cudaEventRecord(e_w2, st2);

    // ---- st1: topo branch ----
    wt_k<<<dim3(TT / 32, EMB / 32), tb, 0, st1>>>(W_topo, wt_topo, EMB, TT);
    wt_k<<<dim3(256 / 32, TT / 32), tb, 0, st1>>>(W_m1, wt_m1, TT, 256);
    wt_k<<<dim3(TT / 32, 256 / 32), tb, 0, st1>>>(W_m2, wt_m2, 256, TT);
    wt_k<<<dim3(TT / 32, TT / 32),  tb, 0, st1>>>(W_p1, wt_p1, TT, TT);
    wt_k<<<dim3(TT / 32, TT / 32),  tb, 0, st1>>>(W_p2, wt_p2, TT, TT);
    cudaStreamWaitEvent(st1, e_ln, 0);
    hgemm<0, 0, 0, 0><<<dim3(1, 32, 1), 256, HG_SMEM, st1>>>(hh, wt_topo, topo, b_topo, nullptr, nullptr,
        EMB, EMB, EMB, TT, 0, 0, 1, 0, 0, 0, 0, 0, 0);
    cudaEventRecord(e_topo, st1);
    // dist batch 0, then batch 1; knn(b=0) overlaps dist(b=1) on st2
    hgemm<0, 0, 0, 0><<<dim3(16, 16, 1), 256, HG_SMEM, st1>>>(hnh, hnh, dist, nullptr, nullptr, nullptr,
        EMB, EMB, EMB, SEQ, 0, 0, 1, 0, 0, 0, 0, 0, 0);
    cudaEventRecord(e_d0, st1);
    hgemm<0, 0, 0, 0><<<dim3(16, 16, 1), 256, HG_SMEM, st1>>>(hnh + SE, hnh + SE, dist + SS, nullptr, nullptr, nullptr,
        EMB, EMB, EMB, SEQ, 0, 0, 1, 0, 0, 0, 0, 0, 0);
    cudaStreamWaitEvent(st2, e_topo, 0);
    cudaStreamWaitEvent(st2, e_d0, 0);
    knn_k<<<SEQ, 256, 0, st2>>>(0);
    cudaEventRecord(e_k0, st2);
    knn_k<<<SEQ, 256, 0, st1>>>(SEQ);
    cudaStreamWaitEvent(st1, e_k0, 0);
    hgemm<1, 1, 0, 0><<<dim3(2, 32, 1), 256, HG_SMEM, st1>>>(combh, wt_m1, tmp256h, b_m1, nullptr, nullptr,
        TT, TT, TT, 256, 0, 0, 1, 0, 0, 0, 0, 0, 0);
    hgemm<0, 0, 0, 0><<<dim3(1, 32, 1), 256, HG_SMEM, st1>>>(tmp256h, wt_m2, tt, b_m2, nullptr, nullptr,
        256, 256, 256, TT, 0, 0, 1, 0, 0, 0, 0, 0, 0);
    lnh_k<<<BSX, 256, 0, st1>>>(tt, tth, ln_t_s, ln_t_b, TT);
    hgemm<1, 1, 0, 0><<<dim3(1, 32, 1), 256, HG_SMEM, st1>>>(tth, wt_p1, tmp256h, b_p1, nullptr, nullptr,
        TT, TT, TT, TT, 0, 0, 1, 0, 0, 0, 0, 0, 0);
    hgemm<0, 1, 0, 0><<<dim3(1, 32, 1), 256, HG_SMEM, st1>>>(tmp256h, wt_p2, cath + EMB, b_p2, nullptr, nullptr,
        TT, TT, TT, CATW, 0, 0, 1, 0, 0, 0, 0, 0, 0);
    cudaEventRecord(e_b1, st1);

    // ---- s0: attention branch (fused QKV) ----
    cudaStreamWaitEvent(0, e_qw, 0);
    hgemm<0, 1, 0, 0><<<dim3(QKVW / 128, 32, 1), 256, HG_SMEM>>>(xh, wt_qkv, qkvh, nullptr, nullptr, nullptr,
        EMB, EMB, EMB, QKVW, 0, 0, 1, 0, 0, 0, 0, 0, 0);
    flash_k<<<dim3(16, BB * NH), 256, FS_TOT_BYTES>>>(qkvh, mask, cath);

    // ---- join ----
    cudaStreamWaitEvent(0, e_b1, 0);
    cudaStreamWaitEvent(0, e_w2, 0);

    // ---- tail ----
    hgemm<3, 1, 1, 1><<<dim3(6, 32, 1), 256, HG_SMEM>>>(cath, wt_gate, ctxh, b_gate, cath, xh,
        CATW, CATW, CATW, EMB, CATW, EMB, 1, 0, 0, 0, 0, 0, 0);
    hgemm<0, 0, 0, 0><<<dim3(6, 32, 1), 256, HG_SMEM>>>(ctxh, wt_o, h1, b_o, h, nullptr,
        EMB, EMB, EMB, EMB, EMB, 0, 1, 0, 0, 0, 0, 0, 0);
    lnh_k<<<BSX, 256>>>(h1, yh, ln2_s, ln2_b, EMB);
    hgemm<2, 1, 0, 0><<<dim3(24, 32, 1), 256, HG_SMEM>>>(yh, wt_f1, ffh, b_f1, nullptr, nullptr,
        EMB, EMB, EMB, FF, 0, 0, 1, 0, 0, 0, 0, 0, 0);
    hgemm<0, 0, 0, 0><<<dim3(6, 32, 1), 256, HG_SMEM>>>(ffh, wt_f2, out, b_f2, h1, nullptr,
        FF, FF, FF, EMB, EMB, 0, 1, 0, 0, 0, 0, 0, 0);
}

// round 14
// speedup vs baseline: 2.4943x; 1.0405x over previous
#include <cuda_runtime.h>
#include <cuda_fp16.h>
#include <math.h>
#include <stdint.h>

// ---- problem constants ----
#define BSX 4096   // B*S
#define BB  2
#define SEQ 2048
#define EMB 768
#define TT  128
#define NH  12
#define DHD 64
#define FF  3072
#define KNN 16
#define CATW (EMB + TT)   // 896
#define QKVW (3 * EMB)    // 2304

// ---- fp32 scratch ----
__device__ float g_topo[BSX * TT];
__device__ float g_tt[BSX * TT];
__device__ float g_h1[BSX * EMB];
__device__ float g_dist[(long long)BB * SEQ * SEQ];

// ---- fp16 scratch ----
__device__ __half g_hh[BSX * EMB];
__device__ __half g_hnh[BSX * EMB];
__device__ __half g_xh[BSX * EMB];
__device__ __half g_combh[BSX * TT];
__device__ __half g_tmp256h[BSX * 256];
__device__ __half g_tth[BSX * TT];
__device__ __half g_qkvh[(long long)BSX * QKVW];
__device__ __half g_cath[BSX * CATW];
__device__ __half g_ctxh[BSX * EMB];
__device__ __half g_yh[BSX * EMB];
__device__ __half g_ffh[(long long)BSX * FF];

// ---- transposed fp16 weights [N][K] ----
__device__ __half g_wt_topo[TT * EMB];
__device__ __half g_wt_m1[256 * TT];
__device__ __half g_wt_m2[TT * 256];
__device__ __half g_wt_p1[TT * TT];
__device__ __half g_wt_p2[TT * TT];
__device__ __half g_wt_qkv[QKVW * EMB];
__device__ __half g_wt_gate[EMB * CATW];
__device__ __half g_wt_o[EMB * EMB];
__device__ __half g_wt_f1[FF * EMB];
__device__ __half g_wt_f2[EMB * FF];

__device__ __forceinline__ void mma_f16(float* c, const uint32_t* a, uint32_t b0, uint32_t b1) {
    asm volatile(
        "mma.sync.aligned.m16n8k16.row.col.f32.f16.f16.f32 "
        "{%0,%1,%2,%3},{%4,%5,%6,%7},{%8,%9},{%0,%1,%2,%3};"
        : "+f"(c[0]), "+f"(c[1]), "+f"(c[2]), "+f"(c[3])
        : "r"(a[0]), "r"(a[1]), "r"(a[2]), "r"(a[3]), "r"(b0), "r"(b1));
}

__device__ __forceinline__ void cpa16(void* s, const void* g) {
    unsigned sa = (unsigned)__cvta_generic_to_shared(s);
    asm volatile("cp.async.cg.shared.global [%0], [%1], 16;" :: "r"(sa), "l"(g));
}
__device__ __forceinline__ void cpa_commit() { asm volatile("cp.async.commit_group;"); }
__device__ __forceinline__ void cpa_wait1()  { asm volatile("cp.async.wait_group 1;"); }
__device__ __forceinline__ void cpa_wait0()  { asm volatile("cp.async.wait_group 0;"); }

__device__ __forceinline__ void ldsm4(uint32_t* r, uint32_t addr) {
    asm volatile("ldmatrix.sync.aligned.m8n8.x4.shared.b16 {%0,%1,%2,%3}, [%4];"
                 : "=r"(r[0]), "=r"(r[1]), "=r"(r[2]), "=r"(r[3]) : "r"(addr));
}

__device__ __forceinline__ void ldsm4t(uint32_t* r, uint32_t addr) {
    asm volatile("ldmatrix.sync.aligned.m8n8.x4.trans.shared.b16 {%0,%1,%2,%3}, [%4];"
                 : "=r"(r[0]), "=r"(r[1]), "=r"(r[2]), "=r"(r[3]) : "r"(addr));
}

__device__ __forceinline__ uint32_t h2ex2(uint32_t x) {
    uint32_t y;
    asm("ex2.approx.f16x2 %0, %1;" : "=r"(y) : "r"(x));
    return y;
}

// ============================================================================
// fp16 tensor-core GEMM (m16n8k16), cp.async 3-stage k32 pipeline, ldmatrix.
// A [M,K] fp16 row-major; B [N,K] fp16 row-major (K-major).
// ACT: 0 none, 1 relu, 2 gelu, 3 sigmoid-mix. CH: C half. RH/R2H: res half.
// smem = 3 x 128x40 x 2 = 61440 B.
// ============================================================================
#define HSTG (128 * 40)
#define HG_SMEM (3 * HSTG * 2 * 2)

template<int ACT, int CH, int RH, int R2H>
__global__ void __launch_bounds__(256) hgemm(
    const __half* __restrict__ A, const __half* __restrict__ B,
    void* __restrict__ Cv, const float* __restrict__ bias,
    const void* __restrict__ resv, const void* __restrict__ res2v,
    int K, int lda, int ldb, int ldc, int ldr1, int ldr2,
    int zdiv, long long sA1, long long sA2,
    long long sB1, long long sB2, long long sC1, long long sC2)
{
    extern __shared__ __half hs[];
    __half* As = hs;
    __half* Bs = hs + 3 * HSTG;

    int z = blockIdx.z;
    long long zm = z % zdiv, zd = z / zdiv;
    A += zm * sA1 + zd * sA2;
    B += zm * sB1 + zd * sB2;
    long long co = zm * sC1 + zd * sC2;

    const int t    = threadIdx.x;
    const int lane = t & 31;
    const int wid  = t >> 5;
    const int lr   = lane >> 2;
    const int lc   = lane & 3;
    const int wm   = (wid & 3) * 32;
    const int wn   = (wid >> 2) * 64;
    const int bm   = blockIdx.y * 128;
    const int bn   = blockIdx.x * 128;

    const uint32_t sbase = (uint32_t)__cvta_generic_to_shared(hs);
    const uint32_t offA = (uint32_t)((lane & 15) * 80 + (lane >> 4) * 16);
    const uint32_t offB = (uint32_t)((((lane >> 4) & 1) * 8 + (lane & 7)) * 80 + ((lane >> 3) & 1) * 16);

    float acc[2][8][4];
    #pragma unroll
    for (int mt = 0; mt < 2; mt++)
        #pragma unroll
        for (int nt = 0; nt < 8; nt++)
            #pragma unroll
            for (int i = 0; i < 4; i++) acc[mt][nt][i] = 0.f;

    auto issue = [&](int buf, int k0) {
        #pragma unroll
        for (int i = 0; i < 2; i++) {
            int c = t + i * 256;
            int row = c >> 2, kq = (c & 3) * 8;
            cpa16(&As[buf * HSTG + row * 40 + kq],
                  A + (long long)(bm + row) * lda + k0 + kq);
        }
        #pragma unroll
        for (int i = 0; i < 2; i++) {
            int c = t + i * 256;
            int row = c >> 2, kq = (c & 3) * 8;
            cpa16(&Bs[buf * HSTG + row * 40 + kq],
                  B + (long long)(bn + row) * ldb + k0 + kq);
        }
        cpa_commit();
    };

    const int iters = K >> 5;
    issue(0, 0);
    issue(1, 32);

    for (int kb = 0; kb < iters; kb++) {
        cpa_wait1();
        __syncthreads();
        int cur = kb - (kb / 3) * 3;
        uint32_t aB = sbase + (uint32_t)cur * (HSTG * 2);
        uint32_t bB = sbase + (uint32_t)(3 + cur) * (HSTG * 2);

        #pragma unroll
        for (int kk = 0; kk < 2; kk++) {
            uint32_t af[2][4];
            #pragma unroll
            for (int mt = 0; mt < 2; mt++)
                ldsm4(af[mt], aB + (wm + mt * 16) * 80 + kk * 32 + offA);

            #pragma unroll
            for (int p = 0; p < 4; p++) {
                uint32_t bb[4];
                ldsm4(bb, bB + (wn + p * 16) * 80 + kk * 32 + offB);
                #pragma unroll
                for (int sub = 0; sub < 2; sub++)
                    #pragma unroll
                    for (int mt = 0; mt < 2; mt++)
                        mma_f16(acc[mt][p * 2 + sub], af[mt], bb[sub * 2], bb[sub * 2 + 1]);
            }
        }

        int nst  = kb + 2;
        int nbuf = nst - (nst / 3) * 3;
        int nk0  = (nst < iters ? nst : iters - 1) << 5;
        issue(nbuf, nk0);
    }

    const float* res = (const float*)resv;
    const __half* resh = (const __half*)resv;
    #pragma unroll
    for (int mt = 0; mt < 2; mt++) {
        #pragma unroll
        for (int nt = 0; nt < 8; nt++) {
            int mrow = bm + wm + mt * 16 + lr;
            int ncol = bn + wn + nt * 8 + 2 * lc;
            #pragma unroll
            for (int half_ = 0; half_ < 2; half_++) {
                int m = mrow + half_ * 8;
                float v0 = acc[mt][nt][half_ * 2 + 0];
                float v1 = acc[mt][nt][half_ * 2 + 1];
                if (bias) { v0 += bias[ncol]; v1 += bias[ncol + 1]; }
                if (ACT == 1) { v0 = fmaxf(v0, 0.f); v1 = fmaxf(v1, 0.f); }
                if (ACT == 2) {
                    float u = v0;
                    v0 = 0.5f * u * (1.f + tanhf(0.7978845608028654f * (u + 0.044715f * u * u * u)));
                    u = v1;
                    v1 = 0.5f * u * (1.f + tanhf(0.7978845608028654f * (u + 0.044715f * u * u * u)));
                }
                long long off = (long long)m * ldc + ncol + co;
                if (ACT == 3) {
                    float s0 = 1.f / (1.f + expf(-v0));
                    float s1 = 1.f / (1.f + expf(-v1));
                    long long o1 = (long long)m * ldr1 + ncol;
                    long long o2 = (long long)m * ldr2 + ncol;
                    float r1x, r1y, r2x, r2y;
                    if (RH) {
                        __half2 rh = *(const __half2*)(resh + o1);
                        r1x = __half2float(rh.x); r1y = __half2float(rh.y);
                    } else {
                        float2 r1 = *(const float2*)(res + o1);
                        r1x = r1.x; r1y = r1.y;
                    }
                    if (R2H) {
                        __half2 rh2 = *(const __half2*)((const __half*)res2v + o2);
                        r2x = __half2float(rh2.x); r2y = __half2float(rh2.y);
                    } else {
                        float2 r2 = *(const float2*)((const float*)res2v + o2);
                        r2x = r2.x; r2y = r2.y;
                    }
                    v0 = s0 * r1x + (1.f - s0) * r2x;
                    v1 = s1 * r1y + (1.f - s1) * r2y;
                } else if (resv) {
                    float2 r1 = *(const float2*)(res + (long long)m * ldr1 + ncol + co);
                    v0 += r1.x; v1 += r1.y;
                }
                if (CH) {
                    __half2 hv = __floats2half2_rn(v0, v1);
                    *(__half2*)((__half*)Cv + off) = hv;
                } else {
                    float2 o2v = {v0, v1};
                    *(float2*)((float*)Cv + off) = o2v;
                }
            }
        }
    }
}

// ============================================================================
// Flash attention fp16 over fused qkv buffer, z0 offset for batch-split launch.
// smem: sP[128][136] | sK[2][128][72] | sV[2][128][72] = 108544 B
// ============================================================================
#define FS_P 0
#define FS_K 17408
#define FS_V 35840
#define FS_TOT_BYTES 108544
#define LOG2E 1.4426950408889634f

__global__ void __launch_bounds__(256) flash_k(
    const __half* __restrict__ qkv, const int* __restrict__ mask,
    __half* __restrict__ outc, int z0)
{
    extern __shared__ __half fh[];
    __half* sP = fh + FS_P;
    __half* sK = fh + FS_K;
    __half* sV = fh + FS_V;

    const int t = threadIdx.x, lane = t & 31, w = t >> 5;
    const int lr = lane >> 2, lc = lane & 3;
    const int z = blockIdx.y + z0, b = z / NH, hh = z % NH;
    const int bm = blockIdx.x * 128;
    const long long base = (long long)b * SEQ * QKVW + hh * DHD;
    const __half* qp = qkv + base;
    const __half* kp = qkv + base + EMB;
    const __half* vp = qkv + base + 2 * EMB;
    const int* mrow = mask + b * SEQ;

    const uint32_t fbase = (uint32_t)__cvta_generic_to_shared(fh);
    const uint32_t pbase = fbase;
    const uint32_t kbase = fbase + FS_K * 2;
    const uint32_t vbase = fbase + FS_V * 2;
    const uint32_t offK = (uint32_t)((((lane >> 4) & 1) * 8 + (lane & 7)) * 144 + ((lane >> 3) & 1) * 16);
    const uint32_t offP = (uint32_t)((lane & 15) * 272 + (lane >> 4) * 16);
    const uint32_t offV = (uint32_t)((lane & 15) * 144 + (lane >> 4) * 16);

    #pragma unroll
    for (int j = 0; j < 4; j++) {
        int flat = t + j * 256;
        int row = flat >> 3, q8 = (flat & 7) << 3;
        cpa16(&sP[row * 136 + q8], qp + (long long)(bm + row) * QKVW + q8);
    }
    cpa_commit();

    auto issueKV = [&](int kt) {
        int buf = kt & 1;
        #pragma unroll
        for (int j = 0; j < 4; j++) {
            int flat = t + j * 256;
            int row = flat >> 3, q8 = (flat & 7) << 3;
            cpa16(&sK[buf * 9216 + row * 72 + q8],
                  kp + (long long)(kt * 128 + row) * QKVW + q8);
        }
        #pragma unroll
        for (int j = 0; j < 4; j++) {
            int flat = t + j * 256;
            int row = flat >> 3, q8 = (flat & 7) << 3;
            cpa16(&sV[buf * 9216 + row * 72 + q8],
                  vp + (long long)(kt * 128 + row) * QKVW + q8);
        }
        cpa_commit();
    };
    issueKV(0);

    cpa_wait1();
    __syncthreads();

    const int wq = w * 16;
    uint32_t qf[4][4];
    #pragma unroll
    for (int ks = 0; ks < 4; ks++)
        ldsm4(qf[ks], pbase + (uint32_t)wq * 272 + ks * 32 + offP);
    __syncthreads();

    float ctx[8][4];
    #pragma unroll
    for (int nt = 0; nt < 8; nt++)
        #pragma unroll
        for (int i = 0; i < 4; i++) ctx[nt][i] = 0.f;
    float m0 = -1e30f, m1 = -1e30f, l0 = 0.f, l1 = 0.f;

    for (int kt = 0; kt < 16; kt++) {
        cpa_wait0();
        __syncthreads();
        if (kt + 1 < 16) issueKV(kt + 1);

        const int buf = kt & 1;
        const uint32_t kB = kbase + (uint32_t)buf * (9216 * 2);
        const uint32_t vB = vbase + (uint32_t)buf * (9216 * 2);

        float S[16][4];
        #pragma unroll
        for (int nt = 0; nt < 16; nt++)
            #pragma unroll
            for (int i = 0; i < 4; i++) S[nt][i] = 0.f;
        #pragma unroll
        for (int ks = 0; ks < 4; ks++) {
            #pragma unroll
            for (int p = 0; p < 8; p++) {
                uint32_t bb[4];
                ldsm4(bb, kB + (uint32_t)(p * 16) * 144 + ks * 32 + offK);
                mma_f16(S[p * 2],     qf[ks], bb[0], bb[1]);
                mma_f16(S[p * 2 + 1], qf[ks], bb[2], bb[3]);
            }
        }

        float nm0 = -1e30f, nm1 = -1e30f;
        #pragma unroll
        for (int nt = 0; nt < 16; nt++) {
            int c0 = kt * 128 + nt * 8 + 2 * lc;
            int2 mg = *(const int2*)&mrow[c0];
            float s0 = S[nt][0] * 0.125f, s1 = S[nt][1] * 0.125f;
            float s2 = S[nt][2] * 0.125f, s3 = S[nt][3] * 0.125f;
            if (mg.x == 0) { s0 = -10000.f; s2 = -10000.f; }
            if (mg.y == 0) { s1 = -10000.f; s3 = -10000.f; }
            S[nt][0] = s0; S[nt][1] = s1; S[nt][2] = s2; S[nt][3] = s3;
            nm0 = fmaxf(nm0, fmaxf(s0, s1));
            nm1 = fmaxf(nm1, fmaxf(s2, s3));
        }
        nm0 = fmaxf(nm0, __shfl_xor_sync(0xffffffffu, nm0, 1));
        nm0 = fmaxf(nm0, __shfl_xor_sync(0xffffffffu, nm0, 2));
        nm1 = fmaxf(nm1, __shfl_xor_sync(0xffffffffu, nm1, 1));
        nm1 = fmaxf(nm1, __shfl_xor_sync(0xffffffffu, nm1, 2));
        float M0 = fmaxf(m0, nm0), M1 = fmaxf(m1, nm1);
        float a0 = expf(m0 - M0), a1 = expf(m1 - M1);

        float r0 = 0.f, r1 = 0.f;
        #pragma unroll
        for (int nt = 0; nt < 16; nt++) {
            __half2 e01 = __floats2half2_rn((S[nt][0] - M0) * LOG2E, (S[nt][1] - M0) * LOG2E);
            __half2 e23 = __floats2half2_rn((S[nt][2] - M1) * LOG2E, (S[nt][3] - M1) * LOG2E);
            uint32_t p01 = h2ex2(*(uint32_t*)&e01);
            uint32_t p23 = h2ex2(*(uint32_t*)&e23);
            float2 f01 = __half22float2(*(__half2*)&p01);
            float2 f23 = __half22float2(*(__half2*)&p23);
            r0 += f01.x + f01.y;
            r1 += f23.x + f23.y;
            *(uint32_t*)(sP + (wq + lr) * 136 + nt * 8 + 2 * lc)     = p01;
            *(uint32_t*)(sP + (wq + lr + 8) * 136 + nt * 8 + 2 * lc) = p23;
        }
        r0 += __shfl_xor_sync(0xffffffffu, r0, 1);
        r0 += __shfl_xor_sync(0xffffffffu, r0, 2);
        r1 += __shfl_xor_sync(0xffffffffu, r1, 1);
        r1 += __shfl_xor_sync(0xffffffffu, r1, 2);
        l0 = l0 * a0 + r0;
        l1 = l1 * a1 + r1;
        m0 = M0; m1 = M1;
        #pragma unroll
        for (int nt = 0; nt < 8; nt++) {
            ctx[nt][0] *= a0; ctx[nt][1] *= a0;
            ctx[nt][2] *= a1; ctx[nt][3] *= a1;
        }
        __syncwarp();

        #pragma unroll
        for (int ks = 0; ks < 8; ks++) {
            uint32_t af[4];
            ldsm4(af, pbase + (uint32_t)wq * 272 + ks * 32 + offP);
            #pragma unroll
            for (int nt = 0; nt < 8; nt += 2) {
                uint32_t bb[4];
                ldsm4t(bb, vB + (uint32_t)(ks * 16) * 144 + (uint32_t)(nt * 16) + offV);
                mma_f16(ctx[nt],     af, bb[0], bb[1]);
                mma_f16(ctx[nt + 1], af, bb[2], bb[3]);
            }
        }
    }

    float il0 = 1.f / l0, il1 = 1.f / l1;
    #pragma unroll
    for (int nt = 0; nt < 8; nt++) {
        long long row0 = (long long)b * SEQ + bm + wq + lr;
        int col = hh * DHD + nt * 8 + 2 * lc;
        *(__half2*)&outc[row0 * CATW + col] = __floats2half2_rn(ctx[nt][0] * il0, ctx[nt][1] * il0);
        *(__half2*)&outc[(row0 + 8) * CATW + col] = __floats2half2_rn(ctx[nt][2] * il1, ctx[nt][3] * il1);
    }
}

// ---- weight transpose + fp32->fp16 ----
__global__ void wt_k(const float* __restrict__ in, __half* __restrict__ out, int K, int N)
{
    __shared__ float tile[32][33];
    int bx = blockIdx.x * 32, by = blockIdx.y * 32;
    int tx = threadIdx.x, ty = threadIdx.y;
    #pragma unroll
    for (int j = ty; j < 32; j += 8)
        tile[j][tx] = in[(long long)(by + j) * N + bx + tx];
    __syncthreads();
    #pragma unroll
    for (int j = ty; j < 32; j += 8)
        out[(long long)(bx + j) * K + by + tx] = __float2half(tile[tx][j]);
}

// ---- fused: hh, hn_h, xh ----
__global__ void l2ln_k(const float* __restrict__ h,
                       const float* __restrict__ gma, const float* __restrict__ bta)
{
    int row = blockIdx.x, t = threadIdx.x;
    const float* xr = h + (long long)row * EMB;
    __shared__ float sh[EMB];
    __shared__ float r1[256], r2[256];
    float s = 0.f, ss = 0.f;
    for (int i = t; i < EMB; i += 256) { float v = xr[i]; sh[i] = v; s += v; ss += v * v; }
    r1[t] = s; r2[t] = ss; __syncthreads();
    for (int st = 128; st > 0; st >>= 1) {
        if (t < st) { r1[t] += r1[t + st]; r2[t] += r2[t + st]; }
        __syncthreads();
    }
    float mu   = r1[0] / EMB;
    float var  = r2[0] / EMB - mu * mu;
    float ri   = rsqrtf(var + 1e-6f);
    float invn = 1.f / (sqrtf(r2[0]) + 1e-8f);
    for (int i = t; i < EMB; i += 256) {
        float v = sh[i];
        g_hh [(long long)row * EMB + i] = __float2half(v);
        g_hnh[(long long)row * EMB + i] = __float2half(v * invn);
        g_xh [(long long)row * EMB + i] = __float2half((v - mu) * ri * gma[i] + bta[i]);
    }
}

// ---- layernorm -> fp16 output ----
__global__ void lnh_k(const float* __restrict__ x, __half* __restrict__ oh,
                      const float* __restrict__ gma, const float* __restrict__ bta, int D)
{
    int row = blockIdx.x, t = threadIdx.x;
    const float* xr = x + (long long)row * D;
    __shared__ float red[256];
    __shared__ float s_mu, s_ri;
    float s = 0.f;
    for (int i = t; i < D; i += 256) s += xr[i];
    red[t] = s; __syncthreads();
    for (int st = 128; st > 0; st >>= 1) { if (t < st) red[t] += red[t + st]; __syncthreads(); }
    if (t == 0) s_mu = red[0] / D;
    __syncthreads();
    float mu = s_mu;
    float v = 0.f;
    for (int i = t; i < D; i += 256) { float d = xr[i] - mu; v += d * d; }
    __syncthreads();
    red[t] = v; __syncthreads();
    for (int st = 128; st > 0; st >>= 1) { if (t < st) red[t] += red[t + st]; __syncthreads(); }
    if (t == 0) s_ri = rsqrtf(red[0] / D + 1e-6f);
    __syncthreads();
    float ri = s_ri;
    for (int i = t; i < D; i += 256)
        oh[(long long)row * D + i] = __float2half((xr[i] - mu) * ri * gma[i] + bta[i]);
}

// ---- k-NN (u32 packed keys) + fused combine -> g_combh ----
__global__ void knn_k(int row0)
{
    int row = blockIdx.x + row0;
    int b = row >> 11, i = row & (SEQ - 1);
    const float* dr = g_dist + (long long)row * SEQ;
    int t = threadIdx.x, lane = t & 31, w = t >> 5;

    __shared__ uint32_t cand[128];
    __shared__ uint32_t fin[KNN];
    __shared__ float    swt[KNN];
    __shared__ int      sidx[KNN];

    uint32_t v[8];
    int base = w * 256;
    #pragma unroll
    for (int r = 0; r < 8; r++) {
        int j = base + r * 32 + lane;
        float d = (j == i) ? 1e9f : (1.f - dr[j]);
        v[r] = (__float_as_uint(d) & 0xFFFFF800u) | (unsigned)j;
    }

    #pragma unroll
    for (int it = 0; it < KNN; it++) {
        uint32_t m = v[0];
        #pragma unroll
        for (int r = 1; r < 8; r++) m = min(m, v[r]);
        #pragma unroll
        for (int s = 16; s > 0; s >>= 1)
            m = min(m, __shfl_xor_sync(0xffffffffu, m, s));
        if (lane == 0) cand[w * KNN + it] = m;
        #pragma unroll
        for (int r = 0; r < 8; r++) if (v[r] == m) v[r] = 0xFFFFFFFFu;
    }
    __syncthreads();

    if (w == 0) {
        uint32_t c[4];
        #pragma unroll
        for (int r = 0; r < 4; r++) c[r] = cand[r * 32 + lane];
        #pragma unroll
        for (int it = 0; it < KNN; it++) {
            uint32_t m01 = min(c[0], c[1]);
            uint32_t m23 = min(c[2], c[3]);
            uint32_t m = min(m01, m23);
            #pragma unroll
            for (int s = 16; s > 0; s >>= 1)
                m = min(m, __shfl_xor_sync(0xffffffffu, m, s));
            if (lane == 0) fin[it] = m;
            #pragma unroll
            for (int r = 0; r < 4; r++) if (c[r] == m) c[r] = 0xFFFFFFFFu;
        }
        __syncwarp();
        if (lane < KNN) {
            float d0 = __uint_as_float(fin[0] & 0xFFFFF800u);
            float dk = __uint_as_float(fin[lane] & 0xFFFFF800u);
            float wk = expf(d0 - dk);
            float sum = wk;
            #pragma unroll
            for (int s = 8; s > 0; s >>= 1)
                sum += __shfl_xor_sync(0x0000ffffu, sum, s);
            swt[lane]  = wk / sum;
            sidx[lane] = b * SEQ + (int)(fin[lane] & 0x7FFu);
        }
    }
    __syncthreads();

    if (t < TT) {
        float acc = g_topo[(long long)row * TT + t];
        #pragma unroll
        for (int k2 = 0; k2 < KNN; k2++)
            acc += swt[k2] * g_topo[(long long)sidx[k2] * TT + t];
        g_combh[(long long)row * TT + t] = __float2half(acc);
    }
}

// ============================================================================
extern "C" void kernel_launch(void* const* d_in, const int* in_sizes, int n_in,
                              void* d_out, int out_size)
{
    const float* h      = (const float*)d_in[0];
    const int*   mask   = (const int*)  d_in[1];
    const float* W_topo = (const float*)d_in[2];
    const float* b_topo = (const float*)d_in[3];
    const float* W_m1   = (const float*)d_in[4];
    const float* b_m1   = (const float*)d_in[5];
    const float* W_m2   = (const float*)d_in[6];
    const float* b_m2   = (const float*)d_in[7];
    const float* ln_t_s = (const float*)d_in[8];
    const float* ln_t_b = (const float*)d_in[9];
    const float* W_p1   = (const float*)d_in[10];
    const float* b_p1   = (const float*)d_in[11];
    const float* W_p2   = (const float*)d_in[12];
    const float* b_p2   = (const float*)d_in[13];
    const float* ln1_s  = (const float*)d_in[14];
    const float* ln1_b  = (const float*)d_in[15];
    const float* Wq     = (const float*)d_in[16];
    const float* Wk     = (const float*)d_in[17];
    const float* Wv     = (const float*)d_in[18];
    const float* W_gate = (const float*)d_in[19];
    const float* b_gate = (const float*)d_in[20];
    const float* W_o    = (const float*)d_in[21];
    const float* b_o    = (const float*)d_in[22];
    const float* ln2_s  = (const float*)d_in[23];
    const float* ln2_b  = (const float*)d_in[24];
    const float* W_f1   = (const float*)d_in[25];
    const float* b_f1   = (const float*)d_in[26];
    const float* W_f2   = (const float*)d_in[27];
    const float* b_f2   = (const float*)d_in[28];
    float* out = (float*)d_out;

    float *topo, *tt, *h1, *dist;
    __half *xh, *combh, *tmp256h, *tth, *qkvh, *cath, *ctxh, *yh, *ffh, *hh, *hnh;
    __half *wt_topo, *wt_m1, *wt_m2, *wt_p1, *wt_p2, *wt_qkv, *wt_gate, *wt_o, *wt_f1, *wt_f2;
    cudaGetSymbolAddress((void**)&topo,    g_topo);
    cudaGetSymbolAddress((void**)&tt,      g_tt);
    cudaGetSymbolAddress((void**)&h1,      g_h1);
    cudaGetSymbolAddress((void**)&dist,    g_dist);
    cudaGetSymbolAddress((void**)&hh,      g_hh);
    cudaGetSymbolAddress((void**)&hnh,     g_hnh);
    cudaGetSymbolAddress((void**)&xh,      g_xh);
    cudaGetSymbolAddress((void**)&combh,   g_combh);
    cudaGetSymbolAddress((void**)&tmp256h, g_tmp256h);
    cudaGetSymbolAddress((void**)&tth,     g_tth);
    cudaGetSymbolAddress((void**)&qkvh,    g_qkvh);
    cudaGetSymbolAddress((void**)&cath,    g_cath);
    cudaGetSymbolAddress((void**)&ctxh,    g_ctxh);
    cudaGetSymbolAddress((void**)&yh,      g_yh);
    cudaGetSymbolAddress((void**)&ffh,     g_ffh);
    cudaGetSymbolAddress((void**)&wt_topo, g_wt_topo);
    cudaGetSymbolAddress((void**)&wt_m1,   g_wt_m1);
    cudaGetSymbolAddress((void**)&wt_m2,   g_wt_m2);
    cudaGetSymbolAddress((void**)&wt_p1,   g_wt_p1);
    cudaGetSymbolAddress((void**)&wt_p2,   g_wt_p2);
    cudaGetSymbolAddress((void**)&wt_qkv,  g_wt_qkv);
    cudaGetSymbolAddress((void**)&wt_gate, g_wt_gate);
    cudaGetSymbolAddress((void**)&wt_o,    g_wt_o);
    cudaGetSymbolAddress((void**)&wt_f1,   g_wt_f1);
    cudaGetSymbolAddress((void**)&wt_f2,   g_wt_f2);

    const long long SE = (long long)SEQ * EMB;
    const long long SS = (long long)SEQ * SEQ;
    const int HM = BSX / 2;   // rows per half (= one batch)

    cudaFuncSetAttribute((const void*)flash_k, cudaFuncAttributeMaxDynamicSharedMemorySize, FS_TOT_BYTES);
    cudaFuncSetAttribute((const void*)hgemm<0, 0, 0, 0>, cudaFuncAttributeMaxDynamicSharedMemorySize, HG_SMEM);
    cudaFuncSetAttribute((const void*)hgemm<0, 1, 0, 0>, cudaFuncAttributeMaxDynamicSharedMemorySize, HG_SMEM);
    cudaFuncSetAttribute((const void*)hgemm<1, 1, 0, 0>, cudaFuncAttributeMaxDynamicSharedMemorySize, HG_SMEM);
    cudaFuncSetAttribute((const void*)hgemm<2, 1, 0, 0>, cudaFuncAttributeMaxDynamicSharedMemorySize, HG_SMEM);
    cudaFuncSetAttribute((const void*)hgemm<3, 1, 1, 1>, cudaFuncAttributeMaxDynamicSharedMemorySize, HG_SMEM);

    // ---- streams/events ----
    static cudaStream_t st1 = nullptr, st2 = nullptr, st3 = nullptr;
    static cudaEvent_t e_fork, e_ln, e_b1, e_w2, e_qw, e_topo, e_d0, e_k0, e_fl1, e_t1;
    if (!st1) {
        cudaStreamCreateWithFlags(&st1, cudaStreamNonBlocking);
        cudaStreamCreateWithFlags(&st2, cudaStreamNonBlocking);
        cudaStreamCreateWithFlags(&st3, cudaStreamNonBlocking);
        cudaEventCreateWithFlags(&e_fork, cudaEventDisableTiming);
        cudaEventCreateWithFlags(&e_ln,   cudaEventDisableTiming);
        cudaEventCreateWithFlags(&e_b1,   cudaEventDisableTiming);
        cudaEventCreateWithFlags(&e_w2,   cudaEventDisableTiming);
        cudaEventCreateWithFlags(&e_qw,   cudaEventDisableTiming);
        cudaEventCreateWithFlags(&e_topo, cudaEventDisableTiming);
        cudaEventCreateWithFlags(&e_d0,   cudaEventDisableTiming);
        cudaEventCreateWithFlags(&e_k0,   cudaEventDisableTiming);
        cudaEventCreateWithFlags(&e_fl1,  cudaEventDisableTiming);
        cudaEventCreateWithFlags(&e_t1,   cudaEventDisableTiming);
    }

    dim3 tb(32, 8);

    // ---- fork ----
    cudaEventRecord(e_fork, 0);
    cudaStreamWaitEvent(st1, e_fork, 0);
    cudaStreamWaitEvent(st2, e_fork, 0);
    cudaStreamWaitEvent(st3, e_fork, 0);

    // ---- s0: fused convert + l2norm + LN1 ----
    l2ln_k<<<BSX, 256>>>(h, ln1_s, ln1_b);
    cudaEventRecord(e_ln, 0);

    // ---- st2: qkv transposes, then batch-1 attention chain ----
    wt_k<<<dim3(EMB / 32, EMB / 32), tb, 0, st2>>>(Wq, wt_qkv, EMB, EMB);
    wt_k<<<dim3(EMB / 32, EMB / 32), tb, 0, st2>>>(Wk, wt_qkv + (long long)EMB * EMB, EMB, EMB);
    wt_k<<<dim3(EMB / 32, EMB / 32), tb, 0, st2>>>(Wv, wt_qkv + 2LL * EMB * EMB, EMB, EMB);
    cudaEventRecord(e_qw, st2);
    cudaStreamWaitEvent(st2, e_ln, 0);
    hgemm<0, 1, 0, 0><<<dim3(QKVW / 128, HM / 128, 1), 256, HG_SMEM, st2>>>(
        xh + (long long)HM * EMB, wt_qkv, qkvh + (long long)HM * QKVW, nullptr, nullptr, nullptr,
        EMB, EMB, EMB, QKVW, 0, 0, 1, 0, 0, 0, 0, 0, 0);
    flash_k<<<dim3(16, NH), 256, FS_TOT_BYTES, st2>>>(qkvh, mask, cath, NH);
    cudaEventRecord(e_fl1, st2);

    // ---- st3: tail weight transposes + knn(b0) overlap ----
    wt_k<<<dim3(EMB / 32, CATW / 32), tb, 0, st3>>>(W_gate, wt_gate, CATW, EMB);
    wt_k<<<dim3(EMB / 32, EMB / 32),  tb, 0, st3>>>(W_o, wt_o, EMB, EMB);
    wt_k<<<dim3(FF / 32, EMB / 32),   tb, 0, st3>>>(W_f1, wt_f1, EMB, FF);
    wt_k<<<dim3(EMB / 32, FF / 32),   tb, 0, st3>>>(W_f2, wt_f2, FF, EMB);
    cudaEventRecord(e_w2, st3);

    // ---- st1: topo branch ----
    wt_k<<<dim3(TT / 32, EMB / 32), tb, 0, st1>>>(W_topo, wt_topo, EMB, TT);
    wt_k<<<dim3(256 / 32, TT / 32), tb, 0, st1>>>(W_m1, wt_m1, TT, 256);
    wt_k<<<dim3(TT / 32, 256 / 32), tb, 0, st1>>>(W_m2, wt_m2, 256, TT);
    wt_k<<<dim3(TT / 32, TT / 32),  tb, 0, st1>>>(W_p1, wt_p1, TT, TT);
    wt_k<<<dim3(TT / 32, TT / 32),  tb, 0, st1>>>(W_p2, wt_p2, TT, TT);
    cudaStreamWaitEvent(st1, e_ln, 0);
    hgemm<0, 0, 0, 0><<<dim3(1, 32, 1), 256, HG_SMEM, st1>>>(hh, wt_topo, topo, b_topo, nullptr, nullptr,
        EMB, EMB, EMB, TT, 0, 0, 1, 0, 0, 0, 0, 0, 0);
    cudaEventRecord(e_topo, st1);
    hgemm<0, 0, 0, 0><<<dim3(16, 16, 1), 256, HG_SMEM, st1>>>(hnh, hnh, dist, nullptr, nullptr, nullptr,
        EMB, EMB, EMB, SEQ, 0, 0, 1, 0, 0, 0, 0, 0, 0);
    cudaEventRecord(e_d0, st1);
    hgemm<0, 0, 0, 0><<<dim3(16, 16, 1), 256, HG_SMEM, st1>>>(hnh + SE, hnh + SE, dist + SS, nullptr, nullptr, nullptr,
        EMB, EMB, EMB, SEQ, 0, 0, 1, 0, 0, 0, 0, 0, 0);
    cudaStreamWaitEvent(st3, e_topo, 0);
    cudaStreamWaitEvent(st3, e_d0, 0);
    knn_k<<<SEQ, 256, 0, st3>>>(0);
    cudaEventRecord(e_k0, st3);
    knn_k<<<SEQ, 256, 0, st1>>>(SEQ);
    cudaStreamWaitEvent(st1, e_k0, 0);
    hgemm<1, 1, 0, 0><<<dim3(2, 32, 1), 256, HG_SMEM, st1>>>(combh, wt_m1, tmp256h, b_m1, nullptr, nullptr,
        TT, TT, TT, 256, 0, 0, 1, 0, 0, 0, 0, 0, 0);
    hgemm<0, 0, 0, 0><<<dim3(1, 32, 1), 256, HG_SMEM, st1>>>(tmp256h, wt_m2, tt, b_m2, nullptr, nullptr,
        256, 256, 256, TT, 0, 0, 1, 0, 0, 0, 0, 0, 0);
    lnh_k<<<BSX, 256, 0, st1>>>(tt, tth, ln_t_s, ln_t_b, TT);
    hgemm<1, 1, 0, 0><<<dim3(1, 32, 1), 256, HG_SMEM, st1>>>(tth, wt_p1, tmp256h, b_p1, nullptr, nullptr,
        TT, TT, TT, TT, 0, 0, 1, 0, 0, 0, 0, 0, 0);
    hgemm<0, 1, 0, 0><<<dim3(1, 32, 1), 256, HG_SMEM, st1>>>(tmp256h, wt_p2, cath + EMB, b_p2, nullptr, nullptr,
        TT, TT, TT, CATW, 0, 0, 1, 0, 0, 0, 0, 0, 0);
    cudaEventRecord(e_b1, st1);

    // ---- s0: batch-0 attention chain ----
    cudaStreamWaitEvent(0, e_qw, 0);
    hgemm<0, 1, 0, 0><<<dim3(QKVW / 128, HM / 128, 1), 256, HG_SMEM>>>(xh, wt_qkv, qkvh, nullptr, nullptr, nullptr,
        EMB, EMB, EMB, QKVW, 0, 0, 1, 0, 0, 0, 0, 0, 0);
    flash_k<<<dim3(16, NH), 256, FS_TOT_BYTES>>>(qkvh, mask, cath, 0);

    // ---- tail half 0 on s0 (rows 0..HM) ----
    cudaStreamWaitEvent(0, e_b1, 0);
    cudaStreamWaitEvent(0, e_w2, 0);
    hgemm<3, 1, 1, 1><<<dim3(6, HM / 128, 1), 256, HG_SMEM>>>(cath, wt_gate, ctxh, b_gate, cath, xh,
        CATW, CATW, CATW, EMB, CATW, EMB, 1, 0, 0, 0, 0, 0, 0);
    hgemm<0, 0, 0, 0><<<dim3(6, HM / 128, 1), 256, HG_SMEM>>>(ctxh, wt_o, h1, b_o, h, nullptr,
        EMB, EMB, EMB, EMB, EMB, 0, 1, 0, 0, 0, 0, 0, 0);
    lnh_k<<<HM, 256>>>(h1, yh, ln2_s, ln2_b, EMB);
    hgemm<2, 1, 0, 0><<<dim3(24, HM / 128, 1), 256, HG_SMEM>>>(yh, wt_f1, ffh, b_f1, nullptr, nullptr,
        EMB, EMB, EMB, FF, 0, 0, 1, 0, 0, 0, 0, 0, 0);
    hgemm<0, 0, 0, 0><<<dim3(6, HM / 128, 1), 256, HG_SMEM>>>(ffh, wt_f2, out, b_f2, h1, nullptr,
        FF, FF, FF, EMB, EMB, 0, 1, 0, 0, 0, 0, 0, 0);

    // ---- tail half 1 on st1 (rows HM..BSX) ----
    cudaStreamWaitEvent(st1, e_fl1, 0);
    cudaStreamWaitEvent(st1, e_w2, 0);
    {
        const long long rO  = (long long)HM;
        hgemm<3, 1, 1, 1><<<dim3(6, HM / 128, 1), 256, HG_SMEM, st1>>>(
            cath + rO * CATW, wt_gate, ctxh + rO * EMB, b_gate,
            cath + rO * CATW, xh + rO * EMB,
            CATW, CATW, CATW, EMB, CATW, EMB, 1, 0, 0, 0, 0, 0, 0);
        hgemm<0, 0, 0, 0><<<dim3(6, HM / 128, 1), 256, HG_SMEM, st1>>>(
            ctxh + rO * EMB, wt_o, h1 + rO * EMB, b_o, h + rO * EMB, nullptr,
            EMB, EMB, EMB, EMB, EMB, 0, 1, 0, 0, 0, 0, 0, 0);
        lnh_k<<<HM, 256, 0, st1>>>(h1 + rO * EMB, yh + rO * EMB, ln2_s, ln2_b, EMB);
        hgemm<2, 1, 0, 0><<<dim3(24, HM / 128, 1), 256, HG_SMEM, st1>>>(
            yh + rO * EMB, wt_f1, ffh + rO * FF, b_f1, nullptr, nullptr,
            EMB, EMB, EMB, FF, 0, 0, 1, 0, 0, 0, 0, 0, 0);
        hgemm<0, 0, 0, 0><<<dim3(6, HM / 128, 1), 256, HG_SMEM, st1>>>(
            ffh + rO * FF, wt_f2, out + rO * EMB, b_f2, h1 + rO * EMB, nullptr,
            FF, FF, FF, EMB, EMB, 0, 1, 0, 0, 0, 0, 0, 0);
        cudaEventRecord(e_t1, st1);
    }
    cudaStreamWaitEvent(0, e_t1, 0);
}

// round 15
// speedup vs baseline: 2.5074x; 1.0052x over previous
#include <cuda_runtime.h>
#include <cuda_fp16.h>
#include <math.h>
#include <stdint.h>

// ---- problem constants ----
#define BSX 4096   // B*S
#define BB  2
#define SEQ 2048
#define EMB 768
#define TT  128
#define NH  12
#define DHD 64
#define FF  3072
#define KNN 16
#define CATW (EMB + TT)   // 896
#define QKVW (3 * EMB)    // 2304

// ---- fp32 scratch ----
__device__ float g_topo[BSX * TT];
__device__ float g_tt[BSX * TT];
__device__ float g_h1[BSX * EMB];
__device__ float g_dist[(long long)BB * SEQ * SEQ];

// ---- fp16 scratch ----
__device__ __half g_hh[BSX * EMB];
__device__ __half g_hnh[BSX * EMB];
__device__ __half g_xh[BSX * EMB];
__device__ __half g_combh[BSX * TT];
__device__ __half g_tmp256h[BSX * 256];
__device__ __half g_tth[BSX * TT];
__device__ __half g_qkvh[(long long)BSX * QKVW];
__device__ __half g_cath[BSX * CATW];
__device__ __half g_ctxh[BSX * EMB];
__device__ __half g_yh[BSX * EMB];
__device__ __half g_ffh[(long long)BSX * FF];

// ---- transposed fp16 weights [N][K] ----
__device__ __half g_wt_topo[TT * EMB];
__device__ __half g_wt_m1[256 * TT];
__device__ __half g_wt_m2[TT * 256];
__device__ __half g_wt_p1[TT * TT];
__device__ __half g_wt_p2[TT * TT];
__device__ __half g_wt_qkv[QKVW * EMB];
__device__ __half g_wt_gate[EMB * CATW];
__device__ __half g_wt_o[EMB * EMB];
__device__ __half g_wt_f1[FF * EMB];
__device__ __half g_wt_f2[EMB * FF];

__device__ __forceinline__ void mma_f16(float* c, const uint32_t* a, uint32_t b0, uint32_t b1) {
    asm volatile(
        "mma.sync.aligned.m16n8k16.row.col.f32.f16.f16.f32 "
        "{%0,%1,%2,%3},{%4,%5,%6,%7},{%8,%9},{%0,%1,%2,%3};"
        : "+f"(c[0]), "+f"(c[1]), "+f"(c[2]), "+f"(c[3])
        : "r"(a[0]), "r"(a[1]), "r"(a[2]), "r"(a[3]), "r"(b0), "r"(b1));
}

__device__ __forceinline__ void cpa16(void* s, const void* g) {
    unsigned sa = (unsigned)__cvta_generic_to_shared(s);
    asm volatile("cp.async.cg.shared.global [%0], [%1], 16;" :: "r"(sa), "l"(g));
}
__device__ __forceinline__ void cpa_commit() { asm volatile("cp.async.commit_group;"); }
__device__ __forceinline__ void cpa_wait1()  { asm volatile("cp.async.wait_group 1;"); }
__device__ __forceinline__ void cpa_wait0()  { asm volatile("cp.async.wait_group 0;"); }

__device__ __forceinline__ void ldsm4(uint32_t* r, uint32_t addr) {
    asm volatile("ldmatrix.sync.aligned.m8n8.x4.shared.b16 {%0,%1,%2,%3}, [%4];"
                 : "=r"(r[0]), "=r"(r[1]), "=r"(r[2]), "=r"(r[3]) : "r"(addr));
}

__device__ __forceinline__ void ldsm4t(uint32_t* r, uint32_t addr) {
    asm volatile("ldmatrix.sync.aligned.m8n8.x4.trans.shared.b16 {%0,%1,%2,%3}, [%4];"
                 : "=r"(r[0]), "=r"(r[1]), "=r"(r[2]), "=r"(r[3]) : "r"(addr));
}

__device__ __forceinline__ uint32_t h2ex2(uint32_t x) {
    uint32_t y;
    asm("ex2.approx.f16x2 %0, %1;" : "=r"(y) : "r"(x));
    return y;
}

// ============================================================================
// fp16 tensor-core GEMM (m16n8k16), cp.async 3-stage k32 pipeline, ldmatrix.
// ============================================================================
#define HSTG (128 * 40)
#define HG_SMEM (3 * HSTG * 2 * 2)

template<int ACT, int CH, int RH, int R2H>
__global__ void __launch_bounds__(256) hgemm(
    const __half* __restrict__ A, const __half* __restrict__ B,
    void* __restrict__ Cv, const float* __restrict__ bias,
    const void* __restrict__ resv, const void* __restrict__ res2v,
    int K, int lda, int ldb, int ldc, int ldr1, int ldr2,
    int zdiv, long long sA1, long long sA2,
    long long sB1, long long sB2, long long sC1, long long sC2)
{
    extern __shared__ __half hs[];
    __half* As = hs;
    __half* Bs = hs + 3 * HSTG;

    int z = blockIdx.z;
    long long zm = z % zdiv, zd = z / zdiv;
    A += zm * sA1 + zd * sA2;
    B += zm * sB1 + zd * sB2;
    long long co = zm * sC1 + zd * sC2;

    const int t    = threadIdx.x;
    const int lane = t & 31;
    const int wid  = t >> 5;
    const int lr   = lane >> 2;
    const int lc   = lane & 3;
    const int wm   = (wid & 3) * 32;
    const int wn   = (wid >> 2) * 64;
    const int bm   = blockIdx.y * 128;
    const int bn   = blockIdx.x * 128;

    const uint32_t sbase = (uint32_t)__cvta_generic_to_shared(hs);
    const uint32_t offA = (uint32_t)((lane & 15) * 80 + (lane >> 4) * 16);
    const uint32_t offB = (uint32_t)((((lane >> 4) & 1) * 8 + (lane & 7)) * 80 + ((lane >> 3) & 1) * 16);

    float acc[2][8][4];
    #pragma unroll
    for (int mt = 0; mt < 2; mt++)
        #pragma unroll
        for (int nt = 0; nt < 8; nt++)
            #pragma unroll
            for (int i = 0; i < 4; i++) acc[mt][nt][i] = 0.f;

    auto issue = [&](int buf, int k0) {
        #pragma unroll
        for (int i = 0; i < 2; i++) {
            int c = t + i * 256;
            int row = c >> 2, kq = (c & 3) * 8;
            cpa16(&As[buf * HSTG + row * 40 + kq],
                  A + (long long)(bm + row) * lda + k0 + kq);
        }
        #pragma unroll
        for (int i = 0; i < 2; i++) {
            int c = t + i * 256;
            int row = c >> 2, kq = (c & 3) * 8;
            cpa16(&Bs[buf * HSTG + row * 40 + kq],
                  B + (long long)(bn + row) * ldb + k0 + kq);
        }
        cpa_commit();
    };

    const int iters = K >> 5;
    issue(0, 0);
    issue(1, 32);

    for (int kb = 0; kb < iters; kb++) {
        cpa_wait1();
        __syncthreads();
        int cur = kb - (kb / 3) * 3;
        uint32_t aB = sbase + (uint32_t)cur * (HSTG * 2);
        uint32_t bB = sbase + (uint32_t)(3 + cur) * (HSTG * 2);

        #pragma unroll
        for (int kk = 0; kk < 2; kk++) {
            uint32_t af[2][4];
            #pragma unroll
            for (int mt = 0; mt < 2; mt++)
                ldsm4(af[mt], aB + (wm + mt * 16) * 80 + kk * 32 + offA);

            #pragma unroll
            for (int p = 0; p < 4; p++) {
                uint32_t bb[4];
                ldsm4(bb, bB + (wn + p * 16) * 80 + kk * 32 + offB);
                #pragma unroll
                for (int sub = 0; sub < 2; sub++)
                    #pragma unroll
                    for (int mt = 0; mt < 2; mt++)
                        mma_f16(acc[mt][p * 2 + sub], af[mt], bb[sub * 2], bb[sub * 2 + 1]);
            }
        }

        int nst  = kb + 2;
        int nbuf = nst - (nst / 3) * 3;
        int nk0  = (nst < iters ? nst : iters - 1) << 5;
        issue(nbuf, nk0);
    }

    const float* res = (const float*)resv;
    const __half* resh = (const __half*)resv;
    #pragma unroll
    for (int mt = 0; mt < 2; mt++) {
        #pragma unroll
        for (int nt = 0; nt < 8; nt++) {
            int mrow = bm + wm + mt * 16 + lr;
            int ncol = bn + wn + nt * 8 + 2 * lc;
            #pragma unroll
            for (int half_ = 0; half_ < 2; half_++) {
                int m = mrow + half_ * 8;
                float v0 = acc[mt][nt][half_ * 2 + 0];
                float v1 = acc[mt][nt][half_ * 2 + 1];
                if (bias) { v0 += bias[ncol]; v1 += bias[ncol + 1]; }
                if (ACT == 1) { v0 = fmaxf(v0, 0.f); v1 = fmaxf(v1, 0.f); }
                if (ACT == 2) {
                    float u = v0;
                    v0 = 0.5f * u * (1.f + tanhf(0.7978845608028654f * (u + 0.044715f * u * u * u)));
                    u = v1;
                    v1 = 0.5f * u * (1.f + tanhf(0.7978845608028654f * (u + 0.044715f * u * u * u)));
                }
                long long off = (long long)m * ldc + ncol + co;
                if (ACT == 3) {
                    float s0 = 1.f / (1.f + expf(-v0));
                    float s1 = 1.f / (1.f + expf(-v1));
                    long long o1 = (long long)m * ldr1 + ncol;
                    long long o2 = (long long)m * ldr2 + ncol;
                    float r1x, r1y, r2x, r2y;
                    if (RH) {
                        __half2 rh = *(const __half2*)(resh + o1);
                        r1x = __half2float(rh.x); r1y = __half2float(rh.y);
                    } else {
                        float2 r1 = *(const float2*)(res + o1);
                        r1x = r1.x; r1y = r1.y;
                    }
                    if (R2H) {
                        __half2 rh2 = *(const __half2*)((const __half*)res2v + o2);
                        r2x = __half2float(rh2.x); r2y = __half2float(rh2.y);
                    } else {
                        float2 r2 = *(const float2*)((const float*)res2v + o2);
                        r2x = r2.x; r2y = r2.y;
                    }
                    v0 = s0 * r1x + (1.f - s0) * r2x;
                    v1 = s1 * r1y + (1.f - s1) * r2y;
                } else if (resv) {
                    float2 r1 = *(const float2*)(res + (long long)m * ldr1 + ncol + co);
                    v0 += r1.x; v1 += r1.y;
                }
                if (CH) {
                    __half2 hv = __floats2half2_rn(v0, v1);
                    *(__half2*)((__half*)Cv + off) = hv;
                } else {
                    float2 o2v = {v0, v1};
                    *(float2*)((float*)Cv + off) = o2v;
                }
            }
        }
    }
}

// ============================================================================
// Flash attention fp16 over fused qkv buffer, z0 offset for batch-split launch.
// ============================================================================
#define FS_P 0
#define FS_K 17408
#define FS_V 35840
#define FS_TOT_BYTES 108544
#define LOG2E 1.4426950408889634f

__global__ void __launch_bounds__(256) flash_k(
    const __half* __restrict__ qkv, const int* __restrict__ mask,
    __half* __restrict__ outc, int z0)
{
    extern __shared__ __half fh[];
    __half* sP = fh + FS_P;
    __half* sK = fh + FS_K;
    __half* sV = fh + FS_V;

    const int t = threadIdx.x, lane = t & 31, w = t >> 5;
    const int lr = lane >> 2, lc = lane & 3;
    const int z = blockIdx.y + z0, b = z / NH, hh = z % NH;
    const int bm = blockIdx.x * 128;
    const long long base = (long long)b * SEQ * QKVW + hh * DHD;
    const __half* qp = qkv + base;
    const __half* kp = qkv + base + EMB;
    const __half* vp = qkv + base + 2 * EMB;
    const int* mrow = mask + b * SEQ;

    const uint32_t fbase = (uint32_t)__cvta_generic_to_shared(fh);
    const uint32_t pbase = fbase;
    const uint32_t kbase = fbase + FS_K * 2;
    const uint32_t vbase = fbase + FS_V * 2;
    const uint32_t offK = (uint32_t)((((lane >> 4) & 1) * 8 + (lane & 7)) * 144 + ((lane >> 3) & 1) * 16);
    const uint32_t offP = (uint32_t)((lane & 15) * 272 + (lane >> 4) * 16);
    const uint32_t offV = (uint32_t)((lane & 15) * 144 + (lane >> 4) * 16);

    #pragma unroll
    for (int j = 0; j < 4; j++) {
        int flat = t + j * 256;
        int row = flat >> 3, q8 = (flat & 7) << 3;
        cpa16(&sP[row * 136 + q8], qp + (long long)(bm + row) * QKVW + q8);
    }
    cpa_commit();

    auto issueKV = [&](int kt) {
        int buf = kt & 1;
        #pragma unroll
        for (int j = 0; j < 4; j++) {
            int flat = t + j * 256;
            int row = flat >> 3, q8 = (flat & 7) << 3;
            cpa16(&sK[buf * 9216 + row * 72 + q8],
                  kp + (long long)(kt * 128 + row) * QKVW + q8);
        }
        #pragma unroll
        for (int j = 0; j < 4; j++) {
            int flat = t + j * 256;
            int row = flat >> 3, q8 = (flat & 7) << 3;
            cpa16(&sV[buf * 9216 + row * 72 + q8],
                  vp + (long long)(kt * 128 + row) * QKVW + q8);
        }
        cpa_commit();
    };
    issueKV(0);

    cpa_wait1();
    __syncthreads();

    const int wq = w * 16;
    uint32_t qf[4][4];
    #pragma unroll
    for (int ks = 0; ks < 4; ks++)
        ldsm4(qf[ks], pbase + (uint32_t)wq * 272 + ks * 32 + offP);
    __syncthreads();

    float ctx[8][4];
    #pragma unroll
    for (int nt = 0; nt < 8; nt++)
        #pragma unroll
        for (int i = 0; i < 4; i++) ctx[nt][i] = 0.f;
    float m0 = -1e30f, m1 = -1e30f, l0 = 0.f, l1 = 0.f;

    for (int kt = 0; kt < 16; kt++) {
        cpa_wait0();
        __syncthreads();
        if (kt + 1 < 16) issueKV(kt + 1);

        const int buf = kt & 1;
        const uint32_t kB = kbase + (uint32_t)buf * (9216 * 2);
        const uint32_t vB = vbase + (uint32_t)buf * (9216 * 2);

        float S[16][4];
        #pragma unroll
        for (int nt = 0; nt < 16; nt++)
            #pragma unroll
            for (int i = 0; i < 4; i++) S[nt][i] = 0.f;
        #pragma unroll
        for (int ks = 0; ks < 4; ks++) {
            #pragma unroll
            for (int p = 0; p < 8; p++) {
                uint32_t bb[4];
                ldsm4(bb, kB + (uint32_t)(p * 16) * 144 + ks * 32 + offK);
                mma_f16(S[p * 2],     qf[ks], bb[0], bb[1]);
                mma_f16(S[p * 2 + 1], qf[ks], bb[2], bb[3]);
            }
        }

        float nm0 = -1e30f, nm1 = -1e30f;
        #pragma unroll
        for (int nt = 0; nt < 16; nt++) {
            int c0 = kt * 128 + nt * 8 + 2 * lc;
            int2 mg = *(const int2*)&mrow[c0];
            float s0 = S[nt][0] * 0.125f, s1 = S[nt][1] * 0.125f;
            float s2 = S[nt][2] * 0.125f, s3 = S[nt][3] * 0.125f;
            if (mg.x == 0) { s0 = -10000.f; s2 = -10000.f; }
            if (mg.y == 0) { s1 = -10000.f; s3 = -10000.f; }
            S[nt][0] = s0; S[nt][1] = s1; S[nt][2] = s2; S[nt][3] = s3;
            nm0 = fmaxf(nm0, fmaxf(s0, s1));
            nm1 = fmaxf(nm1, fmaxf(s2, s3));
        }
        nm0 = fmaxf(nm0, __shfl_xor_sync(0xffffffffu, nm0, 1));
        nm0 = fmaxf(nm0, __shfl_xor_sync(0xffffffffu, nm0, 2));
        nm1 = fmaxf(nm1, __shfl_xor_sync(0xffffffffu, nm1, 1));
        nm1 = fmaxf(nm1, __shfl_xor_sync(0xffffffffu, nm1, 2));
        float M0 = fmaxf(m0, nm0), M1 = fmaxf(m1, nm1);
        float a0 = expf(m0 - M0), a1 = expf(m1 - M1);

        float r0 = 0.f, r1 = 0.f;
        #pragma unroll
        for (int nt = 0; nt < 16; nt++) {
            __half2 e01 = __floats2half2_rn((S[nt][0] - M0) * LOG2E, (S[nt][1] - M0) * LOG2E);
            __half2 e23 = __floats2half2_rn((S[nt][2] - M1) * LOG2E, (S[nt][3] - M1) * LOG2E);
            uint32_t p01 = h2ex2(*(uint32_t*)&e01);
            uint32_t p23 = h2ex2(*(uint32_t*)&e23);
            float2 f01 = __half22float2(*(__half2*)&p01);
            float2 f23 = __half22float2(*(__half2*)&p23);
            r0 += f01.x + f01.y;
            r1 += f23.x + f23.y;
            *(uint32_t*)(sP + (wq + lr) * 136 + nt * 8 + 2 * lc)     = p01;
            *(uint32_t*)(sP + (wq + lr + 8) * 136 + nt * 8 + 2 * lc) = p23;
        }
        r0 += __shfl_xor_sync(0xffffffffu, r0, 1);
        r0 += __shfl_xor_sync(0xffffffffu, r0, 2);
        r1 += __shfl_xor_sync(0xffffffffu, r1, 1);
        r1 += __shfl_xor_sync(0xffffffffu, r1, 2);
        l0 = l0 * a0 + r0;
        l1 = l1 * a1 + r1;
        m0 = M0; m1 = M1;
        #pragma unroll
        for (int nt = 0; nt < 8; nt++) {
            ctx[nt][0] *= a0; ctx[nt][1] *= a0;
            ctx[nt][2] *= a1; ctx[nt][3] *= a1;
        }
        __syncwarp();

        #pragma unroll
        for (int ks = 0; ks < 8; ks++) {
            uint32_t af[4];
            ldsm4(af, pbase + (uint32_t)wq * 272 + ks * 32 + offP);
            #pragma unroll
            for (int nt = 0; nt < 8; nt += 2) {
                uint32_t bb[4];
                ldsm4t(bb, vB + (uint32_t)(ks * 16) * 144 + (uint32_t)(nt * 16) + offV);
                mma_f16(ctx[nt],     af, bb[0], bb[1]);
                mma_f16(ctx[nt + 1], af, bb[2], bb[3]);
            }
        }
    }

    float il0 = 1.f / l0, il1 = 1.f / l1;
    #pragma unroll
    for (int nt = 0; nt < 8; nt++) {
        long long row0 = (long long)b * SEQ + bm + wq + lr;
        int col = hh * DHD + nt * 8 + 2 * lc;
        *(__half2*)&outc[row0 * CATW + col] = __floats2half2_rn(ctx[nt][0] * il0, ctx[nt][1] * il0);
        *(__half2*)&outc[(row0 + 8) * CATW + col] = __floats2half2_rn(ctx[nt][2] * il1, ctx[nt][3] * il1);
    }
}

// ---- weight transpose + fp32->fp16 ----
__global__ void wt_k(const float* __restrict__ in, __half* __restrict__ out, int K, int N)
{
    __shared__ float tile[32][33];
    int bx = blockIdx.x * 32, by = blockIdx.y * 32;
    int tx = threadIdx.x, ty = threadIdx.y;
    #pragma unroll
    for (int j = ty; j < 32; j += 8)
        tile[j][tx] = in[(long long)(by + j) * N + bx + tx];
    __syncthreads();
    #pragma unroll
    for (int j = ty; j < 32; j += 8)
        out[(long long)(bx + j) * K + by + tx] = __float2half(tile[tx][j]);
}

// ---- fused: hh, hn_h, xh ----
__global__ void l2ln_k(const float* __restrict__ h,
                       const float* __restrict__ gma, const float* __restrict__ bta)
{
    int row = blockIdx.x, t = threadIdx.x;
    const float* xr = h + (long long)row * EMB;
    __shared__ float sh[EMB];
    __shared__ float r1[256], r2[256];
    float s = 0.f, ss = 0.f;
    for (int i = t; i < EMB; i += 256) { float v = xr[i]; sh[i] = v; s += v; ss += v * v; }
    r1[t] = s; r2[t] = ss; __syncthreads();
    for (int st = 128; st > 0; st >>= 1) {
        if (t < st) { r1[t] += r1[t + st]; r2[t] += r2[t + st]; }
        __syncthreads();
    }
    float mu   = r1[0] / EMB;
    float var  = r2[0] / EMB - mu * mu;
    float ri   = rsqrtf(var + 1e-6f);
    float invn = 1.f / (sqrtf(r2[0]) + 1e-8f);
    for (int i = t; i < EMB; i += 256) {
        float v = sh[i];
        g_hh [(long long)row * EMB + i] = __float2half(v);
        g_hnh[(long long)row * EMB + i] = __float2half(v * invn);
        g_xh [(long long)row * EMB + i] = __float2half((v - mu) * ri * gma[i] + bta[i]);
    }
}

// ---- layernorm -> fp16 output, templated block size ----
template<int BLK>
__global__ void lnh_k(const float* __restrict__ x, __half* __restrict__ oh,
                      const float* __restrict__ gma, const float* __restrict__ bta, int D)
{
    int row = blockIdx.x, t = threadIdx.x;
    const float* xr = x + (long long)row * D;
    __shared__ float red[BLK];
    __shared__ float s_mu, s_ri;
    float s = 0.f;
    for (int i = t; i < D; i += BLK) s += xr[i];
    red[t] = s; __syncthreads();
    for (int st = BLK / 2; st > 0; st >>= 1) { if (t < st) red[t] += red[t + st]; __syncthreads(); }
    if (t == 0) s_mu = red[0] / D;
    __syncthreads();
    float mu = s_mu;
    float v = 0.f;
    for (int i = t; i < D; i += BLK) { float d = xr[i] - mu; v += d * d; }
    __syncthreads();
    red[t] = v; __syncthreads();
    for (int st = BLK / 2; st > 0; st >>= 1) { if (t < st) red[t] += red[t + st]; __syncthreads(); }
    if (t == 0) s_ri = rsqrtf(red[0] / D + 1e-6f);
    __syncthreads();
    float ri = s_ri;
    for (int i = t; i < D; i += BLK)
        oh[(long long)row * D + i] = __float2half((xr[i] - mu) * ri * gma[i] + bta[i]);
}

// ---- k-NN (u32 packed keys) + fused combine -> g_combh ----
__global__ void knn_k(int row0)
{
    int row = blockIdx.x + row0;
    int b = row >> 11, i = row & (SEQ - 1);
    const float* dr = g_dist + (long long)row * SEQ;
    int t = threadIdx.x, lane = t & 31, w = t >> 5;

    __shared__ uint32_t cand[128];
    __shared__ uint32_t fin[KNN];
    __shared__ float    swt[KNN];
    __shared__ int      sidx[KNN];

    uint32_t v[8];
    int base = w * 256;
    #pragma unroll
    for (int r = 0; r < 8; r++) {
        int j = base + r * 32 + lane;
        float d = (j == i) ? 1e9f : (1.f - dr[j]);
        v[r] = (__float_as_uint(d) & 0xFFFFF800u) | (unsigned)j;
    }

    #pragma unroll
    for (int it = 0; it < KNN; it++) {
        uint32_t m = v[0];
        #pragma unroll
        for (int r = 1; r < 8; r++) m = min(m, v[r]);
        #pragma unroll
        for (int s = 16; s > 0; s >>= 1)
            m = min(m, __shfl_xor_sync(0xffffffffu, m, s));
        if (lane == 0) cand[w * KNN + it] = m;
        #pragma unroll
        for (int r = 0; r < 8; r++) if (v[r] == m) v[r] = 0xFFFFFFFFu;
    }
    __syncthreads();

    if (w == 0) {
        uint32_t c[4];
        #pragma unroll
        for (int r = 0; r < 4; r++) c[r] = cand[r * 32 + lane];
        #pragma unroll
        for (int it = 0; it < KNN; it++) {
            uint32_t m01 = min(c[0], c[1]);
            uint32_t m23 = min(c[2], c[3]);
            uint32_t m = min(m01, m23);
            #pragma unroll
            for (int s = 16; s > 0; s >>= 1)
                m = min(m, __shfl_xor_sync(0xffffffffu, m, s));
            if (lane == 0) fin[it] = m;
            #pragma unroll
            for (int r = 0; r < 4; r++) if (c[r] == m) c[r] = 0xFFFFFFFFu;
        }
        __syncwarp();
        if (lane < KNN) {
            float d0 = __uint_as_float(fin[0] & 0xFFFFF800u);
            float dk = __uint_as_float(fin[lane] & 0xFFFFF800u);
            float wk = expf(d0 - dk);
            float sum = wk;
            #pragma unroll
            for (int s = 8; s > 0; s >>= 1)
                sum += __shfl_xor_sync(0x0000ffffu, sum, s);
            swt[lane]  = wk / sum;
            sidx[lane] = b * SEQ + (int)(fin[lane] & 0x7FFu);
        }
    }
    __syncthreads();

    if (t < TT) {
        float acc = g_topo[(long long)row * TT + t];
        #pragma unroll
        for (int k2 = 0; k2 < KNN; k2++)
            acc += swt[k2] * g_topo[(long long)sidx[k2] * TT + t];
        g_combh[(long long)row * TT + t] = __float2half(acc);
    }
}

// ============================================================================
extern "C" void kernel_launch(void* const* d_in, const int* in_sizes, int n_in,
                              void* d_out, int out_size)
{
    const float* h      = (const float*)d_in[0];
    const int*   mask   = (const int*)  d_in[1];
    const float* W_topo = (const float*)d_in[2];
    const float* b_topo = (const float*)d_in[3];
    const float* W_m1   = (const float*)d_in[4];
    const float* b_m1   = (const float*)d_in[5];
    const float* W_m2   = (const float*)d_in[6];
    const float* b_m2   = (const float*)d_in[7];
    const float* ln_t_s = (const float*)d_in[8];
    const float* ln_t_b = (const float*)d_in[9];
    const float* W_p1   = (const float*)d_in[10];
    const float* b_p1   = (const float*)d_in[11];
    const float* W_p2   = (const float*)d_in[12];
    const float* b_p2   = (const float*)d_in[13];
    const float* ln1_s  = (const float*)d_in[14];
    const float* ln1_b  = (const float*)d_in[15];
    const float* Wq     = (const float*)d_in[16];
    const float* Wk     = (const float*)d_in[17];
    const float* Wv     = (const float*)d_in[18];
    const float* W_gate = (const float*)d_in[19];
    const float* b_gate = (const float*)d_in[20];
    const float* W_o    = (const float*)d_in[21];
    const float* b_o    = (const float*)d_in[22];
    const float* ln2_s  = (const float*)d_in[23];
    const float* ln2_b  = (const float*)d_in[24];
    const float* W_f1   = (const float*)d_in[25];
    const float* b_f1   = (const float*)d_in[26];
    const float* W_f2   = (const float*)d_in[27];
    const float* b_f2   = (const float*)d_in[28];
    float* out = (float*)d_out;

    float *topo, *tt, *h1, *dist;
    __half *xh, *combh, *tmp256h, *tth, *qkvh, *cath, *ctxh, *yh, *ffh, *hh, *hnh;
    __half *wt_topo, *wt_m1, *wt_m2, *wt_p1, *wt_p2, *wt_qkv, *wt_gate, *wt_o, *wt_f1, *wt_f2;
    cudaGetSymbolAddress((void**)&topo,    g_topo);
    cudaGetSymbolAddress((void**)&tt,      g_tt);
    cudaGetSymbolAddress((void**)&h1,      g_h1);
    cudaGetSymbolAddress((void**)&dist,    g_dist);
    cudaGetSymbolAddress((void**)&hh,      g_hh);
    cudaGetSymbolAddress((void**)&hnh,     g_hnh);
    cudaGetSymbolAddress((void**)&xh,      g_xh);
    cudaGetSymbolAddress((void**)&combh,   g_combh);
    cudaGetSymbolAddress((void**)&tmp256h, g_tmp256h);
    cudaGetSymbolAddress((void**)&tth,     g_tth);
    cudaGetSymbolAddress((void**)&qkvh,    g_qkvh);
    cudaGetSymbolAddress((void**)&cath,    g_cath);
    cudaGetSymbolAddress((void**)&ctxh,    g_ctxh);
    cudaGetSymbolAddress((void**)&yh,      g_yh);
    cudaGetSymbolAddress((void**)&ffh,     g_ffh);
    cudaGetSymbolAddress((void**)&wt_topo, g_wt_topo);
    cudaGetSymbolAddress((void**)&wt_m1,   g_wt_m1);
    cudaGetSymbolAddress((void**)&wt_m2,   g_wt_m2);
    cudaGetSymbolAddress((void**)&wt_p1,   g_wt_p1);
    cudaGetSymbolAddress((void**)&wt_p2,   g_wt_p2);
    cudaGetSymbolAddress((void**)&wt_qkv,  g_wt_qkv);
    cudaGetSymbolAddress((void**)&wt_gate, g_wt_gate);
    cudaGetSymbolAddress((void**)&wt_o,    g_wt_o);
    cudaGetSymbolAddress((void**)&wt_f1,   g_wt_f1);
    cudaGetSymbolAddress((void**)&wt_f2,   g_wt_f2);

    const long long SE = (long long)SEQ * EMB;
    const long long SS = (long long)SEQ * SEQ;
    const int HM = BSX / 2;
    const int QC = 1024;   // dist/knn chunk rows

    cudaFuncSetAttribute((const void*)flash_k, cudaFuncAttributeMaxDynamicSharedMemorySize, FS_TOT_BYTES);
    cudaFuncSetAttribute((const void*)hgemm<0, 0, 0, 0>, cudaFuncAttributeMaxDynamicSharedMemorySize, HG_SMEM);
    cudaFuncSetAttribute((const void*)hgemm<0, 1, 0, 0>, cudaFuncAttributeMaxDynamicSharedMemorySize, HG_SMEM);
    cudaFuncSetAttribute((const void*)hgemm<1, 1, 0, 0>, cudaFuncAttributeMaxDynamicSharedMemorySize, HG_SMEM);
    cudaFuncSetAttribute((const void*)hgemm<2, 1, 0, 0>, cudaFuncAttributeMaxDynamicSharedMemorySize, HG_SMEM);
    cudaFuncSetAttribute((const void*)hgemm<3, 1, 1, 1>, cudaFuncAttributeMaxDynamicSharedMemorySize, HG_SMEM);

    // ---- streams/events ----
    static cudaStream_t st1 = nullptr, st2 = nullptr, st3 = nullptr;
    static cudaEvent_t e_fork, e_ln, e_b1, e_w2, e_qw, e_topo, e_fl1, e_t1, e_kA;
    static cudaEvent_t e_d[4];
    if (!st1) {
        cudaStreamCreateWithFlags(&st1, cudaStreamNonBlocking);
        cudaStreamCreateWithFlags(&st2, cudaStreamNonBlocking);
        cudaStreamCreateWithFlags(&st3, cudaStreamNonBlocking);
        cudaEventCreateWithFlags(&e_fork, cudaEventDisableTiming);
        cudaEventCreateWithFlags(&e_ln,   cudaEventDisableTiming);
        cudaEventCreateWithFlags(&e_b1,   cudaEventDisableTiming);
        cudaEventCreateWithFlags(&e_w2,   cudaEventDisableTiming);
        cudaEventCreateWithFlags(&e_qw,   cudaEventDisableTiming);
        cudaEventCreateWithFlags(&e_topo, cudaEventDisableTiming);
        cudaEventCreateWithFlags(&e_fl1,  cudaEventDisableTiming);
        cudaEventCreateWithFlags(&e_t1,   cudaEventDisableTiming);
        cudaEventCreateWithFlags(&e_kA,   cudaEventDisableTiming);
        for (int c = 0; c < 4; c++) cudaEventCreateWithFlags(&e_d[c], cudaEventDisableTiming);
    }

    dim3 tb(32, 8);

    // ---- fork ----
    cudaEventRecord(e_fork, 0);
    cudaStreamWaitEvent(st1, e_fork, 0);
    cudaStreamWaitEvent(st2, e_fork, 0);
    cudaStreamWaitEvent(st3, e_fork, 0);

    // ---- s0: fused convert + l2norm + LN1 ----
    l2ln_k<<<BSX, 256>>>(h, ln1_s, ln1_b);
    cudaEventRecord(e_ln, 0);

    // ---- st2: qkv transposes, then batch-1 attention chain ----
    wt_k<<<dim3(EMB / 32, EMB / 32), tb, 0, st2>>>(Wq, wt_qkv, EMB, EMB);
    wt_k<<<dim3(EMB / 32, EMB / 32), tb, 0, st2>>>(Wk, wt_qkv + (long long)EMB * EMB, EMB, EMB);
    wt_k<<<dim3(EMB / 32, EMB / 32), tb, 0, st2>>>(Wv, wt_qkv + 2LL * EMB * EMB, EMB, EMB);
    cudaEventRecord(e_qw, st2);
    cudaStreamWaitEvent(st2, e_ln, 0);
    hgemm<0, 1, 0, 0><<<dim3(QKVW / 128, HM / 128, 1), 256, HG_SMEM, st2>>>(
        xh + (long long)HM * EMB, wt_qkv, qkvh + (long long)HM * QKVW, nullptr, nullptr, nullptr,
        EMB, EMB, EMB, QKVW, 0, 0, 1, 0, 0, 0, 0, 0, 0);
    flash_k<<<dim3(16, NH), 256, FS_TOT_BYTES, st2>>>(qkvh, mask, cath, NH);
    cudaEventRecord(e_fl1, st2);

    // ---- st3: tail transposes + topo proj + knn chunks 0..2 ----
    wt_k<<<dim3(EMB / 32, CATW / 32), tb, 0, st3>>>(W_gate, wt_gate, CATW, EMB);
    wt_k<<<dim3(EMB / 32, EMB / 32),  tb, 0, st3>>>(W_o, wt_o, EMB, EMB);
    wt_k<<<dim3(FF / 32, EMB / 32),   tb, 0, st3>>>(W_f1, wt_f1, EMB, FF);
    wt_k<<<dim3(EMB / 32, FF / 32),   tb, 0, st3>>>(W_f2, wt_f2, FF, EMB);
    cudaEventRecord(e_w2, st3);
    // topo-proj weight transpose also on st3 (feeds topo proj here)
    wt_k<<<dim3(TT / 32, EMB / 32), tb, 0, st3>>>(W_topo, wt_topo, EMB, TT);
    cudaStreamWaitEvent(st3, e_ln, 0);
    hgemm<0, 0, 0, 0><<<dim3(1, 32, 1), 256, HG_SMEM, st3>>>(hh, wt_topo, topo, b_topo, nullptr, nullptr,
        EMB, EMB, EMB, TT, 0, 0, 1, 0, 0, 0, 0, 0, 0);
    cudaEventRecord(e_topo, st3);

    // ---- st1: topo-MLP weight transposes, then dist chunks ----
    wt_k<<<dim3(256 / 32, TT / 32), tb, 0, st1>>>(W_m1, wt_m1, TT, 256);
    wt_k<<<dim3(TT / 32, 256 / 32), tb, 0, st1>>>(W_m2, wt_m2, 256, TT);
    wt_k<<<dim3(TT / 32, TT / 32),  tb, 0, st1>>>(W_p1, wt_p1, TT, TT);
    wt_k<<<dim3(TT / 32, TT / 32),  tb, 0, st1>>>(W_p2, wt_p2, TT, TT);
    cudaStreamWaitEvent(st1, e_ln, 0);
    for (int c = 0; c < 4; c++) {
        int b = c >> 1, half = c & 1;
        const __half* Ap = hnh + (long long)b * SE + (long long)half * QC * EMB;
        const __half* Bp = hnh + (long long)b * SE;
        float* Cp = dist + (long long)b * SS + (long long)half * QC * SEQ;
        hgemm<0, 0, 0, 0><<<dim3(16, QC / 128, 1), 256, HG_SMEM, st1>>>(
            Ap, Bp, Cp, nullptr, nullptr, nullptr,
            EMB, EMB, EMB, SEQ, 0, 0, 1, 0, 0, 0, 0, 0, 0);
        cudaEventRecord(e_d[c], st1);
        if (c < 3) {
            // knn chunk c on st3 overlaps dist chunk c+1 on st1
            cudaStreamWaitEvent(st3, e_d[c], 0);
            knn_k<<<QC, 256, 0, st3>>>(c * QC);
        }
    }
    cudaEventRecord(e_kA, st3);
    // last knn chunk on st1 (dist c3 just finished there; needs topo)
    cudaStreamWaitEvent(st1, e_topo, 0);
    knn_k<<<QC, 256, 0, st1>>>(3 * QC);
    cudaStreamWaitEvent(st1, e_kA, 0);

    // ---- st1: topo MLP chain ----
    hgemm<1, 1, 0, 0><<<dim3(2, 32, 1), 256, HG_SMEM, st1>>>(combh, wt_m1, tmp256h, b_m1, nullptr, nullptr,
        TT, TT, TT, 256, 0, 0, 1, 0, 0, 0, 0, 0, 0);
    hgemm<0, 0, 0, 0><<<dim3(1, 32, 1), 256, HG_SMEM, st1>>>(tmp256h, wt_m2, tt, b_m2, nullptr, nullptr,
        256, 256, 256, TT, 0, 0, 1, 0, 0, 0, 0, 0, 0);
    lnh_k<128><<<BSX, 128, 0, st1>>>(tt, tth, ln_t_s, ln_t_b, TT);
    hgemm<1, 1, 0, 0><<<dim3(1, 32, 1), 256, HG_SMEM, st1>>>(tth, wt_p1, tmp256h, b_p1, nullptr, nullptr,
        TT, TT, TT, TT, 0, 0, 1, 0, 0, 0, 0, 0, 0);
    hgemm<0, 1, 0, 0><<<dim3(1, 32, 1), 256, HG_SMEM, st1>>>(tmp256h, wt_p2, cath + EMB, b_p2, nullptr, nullptr,
        TT, TT, TT, CATW, 0, 0, 1, 0, 0, 0, 0, 0, 0);
    cudaEventRecord(e_b1, st1);

    // ---- s0: batch-0 attention chain ----
    cudaStreamWaitEvent(0, e_qw, 0);
    hgemm<0, 1, 0, 0><<<dim3(QKVW / 128, HM / 128, 1), 256, HG_SMEM>>>(xh, wt_qkv, qkvh, nullptr, nullptr, nullptr,
        EMB, EMB, EMB, QKVW, 0, 0, 1, 0, 0, 0, 0, 0, 0);
    flash_k<<<dim3(16, NH), 256, FS_TOT_BYTES>>>(qkvh, mask, cath, 0);

    // ---- tail half 0 on s0 ----
    cudaStreamWaitEvent(0, e_b1, 0);
    cudaStreamWaitEvent(0, e_w2, 0);
    hgemm<3, 1, 1, 1><<<dim3(6, HM / 128, 1), 256, HG_SMEM>>>(cath, wt_gate, ctxh, b_gate, cath, xh,
        CATW, CATW, CATW, EMB, CATW, EMB, 1, 0, 0, 0, 0, 0, 0);
    hgemm<0, 0, 0, 0><<<dim3(6, HM / 128, 1), 256, HG_SMEM>>>(ctxh, wt_o, h1, b_o, h, nullptr,
        EMB, EMB, EMB, EMB, EMB, 0, 1, 0, 0, 0, 0, 0, 0);
    lnh_k<256><<<HM, 256>>>(h1, yh, ln2_s, ln2_b, EMB);
    hgemm<2, 1, 0, 0><<<dim3(24, HM / 128, 1), 256, HG_SMEM>>>(yh, wt_f1, ffh, b_f1, nullptr, nullptr,
        EMB, EMB, EMB, FF, 0, 0, 1, 0, 0, 0, 0, 0, 0);
    hgemm<0, 0, 0, 0><<<dim3(6, HM / 128, 1), 256, HG_SMEM>>>(ffh, wt_f2, out, b_f2, h1, nullptr,
        FF, FF, FF, EMB, EMB, 0, 1, 0, 0, 0, 0, 0, 0);

    // ---- tail half 1 on st1 ----
    cudaStreamWaitEvent(st1, e_fl1, 0);
    cudaStreamWaitEvent(st1, e_w2, 0);
    {
        const long long rO = (long long)HM;
        hgemm<3, 1, 1, 1><<<dim3(6, HM / 128, 1), 256, HG_SMEM, st1>>>(
            cath + rO * CATW, wt_gate, ctxh + rO * EMB, b_gate,
            cath + rO * CATW, xh + rO * EMB,
            CATW, CATW, CATW, EMB, CATW, EMB, 1, 0, 0, 0, 0, 0, 0);
        hgemm<0, 0, 0, 0><<<dim3(6, HM / 128, 1), 256, HG_SMEM, st1>>>(
            ctxh + rO * EMB, wt_o, h1 + rO * EMB, b_o, h + rO * EMB, nullptr,
            EMB, EMB, EMB, EMB, EMB, 0, 1, 0, 0, 0, 0, 0, 0);
        lnh_k<256><<<HM, 256, 0, st1>>>(h1 + rO * EMB, yh + rO * EMB, ln2_s, ln2_b, EMB);
        hgemm<2, 1, 0, 0><<<dim3(24, HM / 128, 1), 256, HG_SMEM, st1>>>(
            yh + rO * EMB, wt_f1, ffh + rO * FF, b_f1, nullptr, nullptr,
            EMB, EMB, EMB, FF, 0, 0, 1, 0, 0, 0, 0, 0, 0);
        hgemm<0, 0, 0, 0><<<dim3(6, HM / 128, 1), 256, HG_SMEM, st1>>>(
            ffh + rO * FF, wt_f2, out + rO * EMB, b_f2, h1 + rO * EMB, nullptr,
            FF, FF, FF, EMB, EMB, 0, 1, 0, 0, 0, 0, 0, 0);
        cudaEventRecord(e_t1, st1);
    }
    cudaStreamWaitEvent(0, e_t1, 0);
}

// round 16
// speedup vs baseline: 2.6118x; 1.0417x over previous
#include <cuda_runtime.h>
#include <cuda_fp16.h>
#include <math.h>
#include <stdint.h>

// ---- problem constants ----
#define BSX 4096   // B*S
#define BB  2
#define SEQ 2048
#define EMB 768
#define TT  128
#define NH  12
#define DHD 64
#define FF  3072
#define KNN 16
#define CATW (EMB + TT)   // 896
#define QKVW (3 * EMB)    // 2304

// ---- fp32 scratch ----
__device__ float g_topo[BSX * TT];
__device__ float g_tt[BSX * TT];
__device__ float g_h1[BSX * EMB];
__device__ float g_dist[(long long)BB * SEQ * SEQ];

// ---- fp16 scratch ----
__device__ __half g_hh[BSX * EMB];
__device__ __half g_hnh[BSX * EMB];
__device__ __half g_xh[BSX * EMB];
__device__ __half g_combh[BSX * TT];
__device__ __half g_tmp256h[BSX * 256];
__device__ __half g_tth[BSX * TT];
__device__ __half g_qkvh[(long long)BSX * QKVW];
__device__ __half g_cath[BSX * CATW];
__device__ __half g_ctxh[BSX * EMB];
__device__ __half g_yh[BSX * EMB];
__device__ __half g_ffh[(long long)BSX * FF];

// ---- transposed fp16 weights [N][K] ----
__device__ __half g_wt_topo[TT * EMB];
__device__ __half g_wt_m1[256 * TT];
__device__ __half g_wt_m2[TT * 256];
__device__ __half g_wt_p1[TT * TT];
__device__ __half g_wt_p2[TT * TT];
__device__ __half g_wt_qkv[QKVW * EMB];
__device__ __half g_wt_gate[EMB * CATW];
__device__ __half g_wt_o[EMB * EMB];
__device__ __half g_wt_f1[FF * EMB];
__device__ __half g_wt_f2[EMB * FF];

__device__ __forceinline__ void mma_f16(float* c, const uint32_t* a, uint32_t b0, uint32_t b1) {
    asm volatile(
        "mma.sync.aligned.m16n8k16.row.col.f32.f16.f16.f32 "
        "{%0,%1,%2,%3},{%4,%5,%6,%7},{%8,%9},{%0,%1,%2,%3};"
        : "+f"(c[0]), "+f"(c[1]), "+f"(c[2]), "+f"(c[3])
        : "r"(a[0]), "r"(a[1]), "r"(a[2]), "r"(a[3]), "r"(b0), "r"(b1));
}

__device__ __forceinline__ void cpa16(void* s, const void* g) {
    unsigned sa = (unsigned)__cvta_generic_to_shared(s);
    asm volatile("cp.async.cg.shared.global [%0], [%1], 16;" :: "r"(sa), "l"(g));
}
__device__ __forceinline__ void cpa_commit() { asm volatile("cp.async.commit_group;"); }
__device__ __forceinline__ void cpa_wait1()  { asm volatile("cp.async.wait_group 1;"); }
__device__ __forceinline__ void cpa_wait0()  { asm volatile("cp.async.wait_group 0;"); }

__device__ __forceinline__ void ldsm4(uint32_t* r, uint32_t addr) {
    asm volatile("ldmatrix.sync.aligned.m8n8.x4.shared.b16 {%0,%1,%2,%3}, [%4];"
                 : "=r"(r[0]), "=r"(r[1]), "=r"(r[2]), "=r"(r[3]) : "r"(addr));
}

__device__ __forceinline__ void ldsm4t(uint32_t* r, uint32_t addr) {
    asm volatile("ldmatrix.sync.aligned.m8n8.x4.trans.shared.b16 {%0,%1,%2,%3}, [%4];"
                 : "=r"(r[0]), "=r"(r[1]), "=r"(r[2]), "=r"(r[3]) : "r"(addr));
}

__device__ __forceinline__ uint32_t h2ex2(uint32_t x) {
    uint32_t y;
    asm("ex2.approx.f16x2 %0, %1;" : "=r"(y) : "r"(x));
    return y;
}

// ============================================================================
// fp16 tensor-core GEMM (m16n8k16), cp.async 3-stage k32 pipeline, ldmatrix.
// SYM=1: C symmetric (A==B base, M==N); compute upper-triangle tiles only,
//        mirror-store the transpose. Lower-triangle blocks exit early.
// ============================================================================
#define HSTG (128 * 40)
#define HG_SMEM (3 * HSTG * 2 * 2)

template<int ACT, int CH, int RH, int R2H, int SYM>
__global__ void __launch_bounds__(256) hgemm(
    const __half* __restrict__ A, const __half* __restrict__ B,
    void* __restrict__ Cv, const float* __restrict__ bias,
    const void* __restrict__ resv, const void* __restrict__ res2v,
    int K, int lda, int ldb, int ldc, int ldr1, int ldr2,
    int zdiv, long long sA1, long long sA2,
    long long sB1, long long sB2, long long sC1, long long sC2)
{
    if (SYM && blockIdx.x < blockIdx.y) return;

    extern __shared__ __half hs[];
    __half* As = hs;
    __half* Bs = hs + 3 * HSTG;

    int z = blockIdx.z;
    long long zm = z % zdiv, zd = z / zdiv;
    A += zm * sA1 + zd * sA2;
    B += zm * sB1 + zd * sB2;
    long long co = zm * sC1 + zd * sC2;

    const int t    = threadIdx.x;
    const int lane = t & 31;
    const int wid  = t >> 5;
    const int lr   = lane >> 2;
    const int lc   = lane & 3;
    const int wm   = (wid & 3) * 32;
    const int wn   = (wid >> 2) * 64;
    const int bm   = blockIdx.y * 128;
    const int bn   = blockIdx.x * 128;

    const uint32_t sbase = (uint32_t)__cvta_generic_to_shared(hs);
    const uint32_t offA = (uint32_t)((lane & 15) * 80 + (lane >> 4) * 16);
    const uint32_t offB = (uint32_t)((((lane >> 4) & 1) * 8 + (lane & 7)) * 80 + ((lane >> 3) & 1) * 16);

    float acc[2][8][4];
    #pragma unroll
    for (int mt = 0; mt < 2; mt++)
        #pragma unroll
        for (int nt = 0; nt < 8; nt++)
            #pragma unroll
            for (int i = 0; i < 4; i++) acc[mt][nt][i] = 0.f;

    auto issue = [&](int buf, int k0) {
        #pragma unroll
        for (int i = 0; i < 2; i++) {
            int c = t + i * 256;
            int row = c >> 2, kq = (c & 3) * 8;
            cpa16(&As[buf * HSTG + row * 40 + kq],
                  A + (long long)(bm + row) * lda + k0 + kq);
        }
        #pragma unroll
        for (int i = 0; i < 2; i++) {
            int c = t + i * 256;
            int row = c >> 2, kq = (c & 3) * 8;
            cpa16(&Bs[buf * HSTG + row * 40 + kq],
                  B + (long long)(bn + row) * ldb + k0 + kq);
        }
        cpa_commit();
    };

    const int iters = K >> 5;
    issue(0, 0);
    issue(1, 32);

    for (int kb = 0; kb < iters; kb++) {
        cpa_wait1();
        __syncthreads();
        int cur = kb - (kb / 3) * 3;
        uint32_t aB = sbase + (uint32_t)cur * (HSTG * 2);
        uint32_t bB = sbase + (uint32_t)(3 + cur) * (HSTG * 2);

        #pragma unroll
        for (int kk = 0; kk < 2; kk++) {
            uint32_t af[2][4];
            #pragma unroll
            for (int mt = 0; mt < 2; mt++)
                ldsm4(af[mt], aB + (wm + mt * 16) * 80 + kk * 32 + offA);

            #pragma unroll
            for (int p = 0; p < 4; p++) {
                uint32_t bb[4];
                ldsm4(bb, bB + (wn + p * 16) * 80 + kk * 32 + offB);
                #pragma unroll
                for (int sub = 0; sub < 2; sub++)
                    #pragma unroll
                    for (int mt = 0; mt < 2; mt++)
                        mma_f16(acc[mt][p * 2 + sub], af[mt], bb[sub * 2], bb[sub * 2 + 1]);
            }
        }

        int nst  = kb + 2;
        int nbuf = nst - (nst / 3) * 3;
        int nk0  = (nst < iters ? nst : iters - 1) << 5;
        issue(nbuf, nk0);
    }

    const float* res = (const float*)resv;
    const __half* resh = (const __half*)resv;
    #pragma unroll
    for (int mt = 0; mt < 2; mt++) {
        #pragma unroll
        for (int nt = 0; nt < 8; nt++) {
            int mrow = bm + wm + mt * 16 + lr;
            int ncol = bn + wn + nt * 8 + 2 * lc;
            #pragma unroll
            for (int half_ = 0; half_ < 2; half_++) {
                int m = mrow + half_ * 8;
                float v0 = acc[mt][nt][half_ * 2 + 0];
                float v1 = acc[mt][nt][half_ * 2 + 1];
                if (bias) { v0 += bias[ncol]; v1 += bias[ncol + 1]; }
                if (ACT == 1) { v0 = fmaxf(v0, 0.f); v1 = fmaxf(v1, 0.f); }
                if (ACT == 2) {
                    // gelu(u) = u * sigmoid(2*c*(u + 0.044715 u^3))
                    float u = v0;
                    float tt2 = 1.5957691216057308f * (u + 0.044715f * u * u * u);
                    v0 = u / (1.f + __expf(-tt2));
                    u = v1;
                    tt2 = 1.5957691216057308f * (u + 0.044715f * u * u * u);
                    v1 = u / (1.f + __expf(-tt2));
                }
                long long off = (long long)m * ldc + ncol + co;
                if (ACT == 3) {
                    float s0 = 1.f / (1.f + __expf(-v0));
                    float s1 = 1.f / (1.f + __expf(-v1));
                    long long o1 = (long long)m * ldr1 + ncol;
                    long long o2 = (long long)m * ldr2 + ncol;
                    float r1x, r1y, r2x, r2y;
                    if (RH) {
                        __half2 rh = *(const __half2*)(resh + o1);
                        r1x = __half2float(rh.x); r1y = __half2float(rh.y);
                    } else {
                        float2 r1 = *(const float2*)(res + o1);
                        r1x = r1.x; r1y = r1.y;
                    }
                    if (R2H) {
                        __half2 rh2 = *(const __half2*)((const __half*)res2v + o2);
                        r2x = __half2float(rh2.x); r2y = __half2float(rh2.y);
                    } else {
                        float2 r2 = *(const float2*)((const float*)res2v + o2);
                        r2x = r2.x; r2y = r2.y;
                    }
                    v0 = s0 * r1x + (1.f - s0) * r2x;
                    v1 = s1 * r1y + (1.f - s1) * r2y;
                } else if (resv) {
                    float2 r1 = *(const float2*)(res + (long long)m * ldr1 + ncol + co);
                    v0 += r1.x; v1 += r1.y;
                }
                if (CH) {
                    __half2 hv = __floats2half2_rn(v0, v1);
                    *(__half2*)((__half*)Cv + off) = hv;
                } else {
                    float2 o2v = {v0, v1};
                    *(float2*)((float*)Cv + off) = o2v;
                    if (SYM && blockIdx.x != blockIdx.y) {
                        // mirror: C[n][m] = C[m][n]
                        ((float*)Cv)[(long long)ncol * ldc + m + co]       = v0;
                        ((float*)Cv)[(long long)(ncol + 1) * ldc + m + co] = v1;
                    }
                }
            }
        }
    }
}

// ============================================================================
// Flash attention fp16 over fused qkv buffer, z0 offset for batch-split launch.
// ============================================================================
#define FS_P 0
#define FS_K 17408
#define FS_V 35840
#define FS_TOT_BYTES 108544
#define LOG2E 1.4426950408889634f

__global__ void __launch_bounds__(256) flash_k(
    const __half* __restrict__ qkv, const int* __restrict__ mask,
    __half* __restrict__ outc, int z0)
{
    extern __shared__ __half fh[];
    __half* sP = fh + FS_P;
    __half* sK = fh + FS_K;
    __half* sV = fh + FS_V;

    const int t = threadIdx.x, lane = t & 31, w = t >> 5;
    const int lr = lane >> 2, lc = lane & 3;
    const int z = blockIdx.y + z0, b = z / NH, hh = z % NH;
    const int bm = blockIdx.x * 128;
    const long long base = (long long)b * SEQ * QKVW + hh * DHD;
    const __half* qp = qkv + base;
    const __half* kp = qkv + base + EMB;
    const __half* vp = qkv + base + 2 * EMB;
    const int* mrow = mask + b * SEQ;

    const uint32_t fbase = (uint32_t)__cvta_generic_to_shared(fh);
    const uint32_t pbase = fbase;
    const uint32_t kbase = fbase + FS_K * 2;
    const uint32_t vbase = fbase + FS_V * 2;
    const uint32_t offK = (uint32_t)((((lane >> 4) & 1) * 8 + (lane & 7)) * 144 + ((lane >> 3) & 1) * 16);
    const uint32_t offP = (uint32_t)((lane & 15) * 272 + (lane >> 4) * 16);
    const uint32_t offV = (uint32_t)((lane & 15) * 144 + (lane >> 4) * 16);

    #pragma unroll
    for (int j = 0; j < 4; j++) {
        int flat = t + j * 256;
        int row = flat >> 3, q8 = (flat & 7) << 3;
        cpa16(&sP[row * 136 + q8], qp + (long long)(bm + row) * QKVW + q8);
    }
    cpa_commit();

    auto issueKV = [&](int kt) {
        int buf = kt & 1;
        #pragma unroll
        for (int j = 0; j < 4; j++) {
            int flat = t + j * 256;
            int row = flat >> 3, q8 = (flat & 7) << 3;
            cpa16(&sK[buf * 9216 + row * 72 + q8],
                  kp + (long long)(kt * 128 + row) * QKVW + q8);
        }
        #pragma unroll
        for (int j = 0; j < 4; j++) {
            int flat = t + j * 256;
            int row = flat >> 3, q8 = (flat & 7) << 3;
            cpa16(&sV[buf * 9216 + row * 72 + q8],
                  vp + (long long)(kt * 128 + row) * QKVW + q8);
        }
        cpa_commit();
    };
    issueKV(0);

    cpa_wait1();
    __syncthreads();

    const int wq = w * 16;
    uint32_t qf[4][4];
    #pragma unroll
    for (int ks = 0; ks < 4; ks++)
        ldsm4(qf[ks], pbase + (uint32_t)wq * 272 + ks * 32 + offP);
    __syncthreads();

    float ctx[8][4];
    #pragma unroll
    for (int nt = 0; nt < 8; nt++)
        #pragma unroll
        for (int i = 0; i < 4; i++) ctx[nt][i] = 0.f;
    float m0 = -1e30f, m1 = -1e30f, l0 = 0.f, l1 = 0.f;

    for (int kt = 0; kt < 16; kt++) {
        cpa_wait0();
        __syncthreads();
        if (kt + 1 < 16) issueKV(kt + 1);

        const int buf = kt & 1;
        const uint32_t kB = kbase + (uint32_t)buf * (9216 * 2);
        const uint32_t vB = vbase + (uint32_t)buf * (9216 * 2);

        float S[16][4];
        #pragma unroll
        for (int nt = 0; nt < 16; nt++)
            #pragma unroll
            for (int i = 0; i < 4; i++) S[nt][i] = 0.f;
        #pragma unroll
        for (int ks = 0; ks < 4; ks++) {
            #pragma unroll
            for (int p = 0; p < 8; p++) {
                uint32_t bb[4];
                ldsm4(bb, kB + (uint32_t)(p * 16) * 144 + ks * 32 + offK);
                mma_f16(S[p * 2],     qf[ks], bb[0], bb[1]);
                mma_f16(S[p * 2 + 1], qf[ks], bb[2], bb[3]);
            }
        }

        float nm0 = -1e30f, nm1 = -1e30f;
        #pragma unroll
        for (int nt = 0; nt < 16; nt++) {
            int c0 = kt * 128 + nt * 8 + 2 * lc;
            int2 mg = *(const int2*)&mrow[c0];
            float s0 = S[nt][0] * 0.125f, s1 = S[nt][1] * 0.125f;
            float s2 = S[nt][2] * 0.125f, s3 = S[nt][3] * 0.125f;
            if (mg.x == 0) { s0 = -10000.f; s2 = -10000.f; }
            if (mg.y == 0) { s1 = -10000.f; s3 = -10000.f; }
            S[nt][0] = s0; S[nt][1] = s1; S[nt][2] = s2; S[nt][3] = s3;
            nm0 = fmaxf(nm0, fmaxf(s0, s1));
            nm1 = fmaxf(nm1, fmaxf(s2, s3));
        }
        nm0 = fmaxf(nm0, __shfl_xor_sync(0xffffffffu, nm0, 1));
        nm0 = fmaxf(nm0, __shfl_xor_sync(0xffffffffu, nm0, 2));
        nm1 = fmaxf(nm1, __shfl_xor_sync(0xffffffffu, nm1, 1));
        nm1 = fmaxf(nm1, __shfl_xor_sync(0xffffffffu, nm1, 2));
        float M0 = fmaxf(m0, nm0), M1 = fmaxf(m1, nm1);
        float a0 = expf(m0 - M0), a1 = expf(m1 - M1);

        float r0 = 0.f, r1 = 0.f;
        #pragma unroll
        for (int nt = 0; nt < 16; nt++) {
            __half2 e01 = __floats2half2_rn((S[nt][0] - M0) * LOG2E, (S[nt][1] - M0) * LOG2E);
            __half2 e23 = __floats2half2_rn((S[nt][2] - M1) * LOG2E, (S[nt][3] - M1) * LOG2E);
            uint32_t p01 = h2ex2(*(uint32_t*)&e01);
            uint32_t p23 = h2ex2(*(uint32_t*)&e23);
            float2 f01 = __half22float2(*(__half2*)&p01);
            float2 f23 = __half22float2(*(__half2*)&p23);
            r0 += f01.x + f01.y;
            r1 += f23.x + f23.y;
            *(uint32_t*)(sP + (wq + lr) * 136 + nt * 8 + 2 * lc)     = p01;
            *(uint32_t*)(sP + (wq + lr + 8) * 136 + nt * 8 + 2 * lc) = p23;
        }
        r0 += __shfl_xor_sync(0xffffffffu, r0, 1);
        r0 += __shfl_xor_sync(0xffffffffu, r0, 2);
        r1 += __shfl_xor_sync(0xffffffffu, r1, 1);
        r1 += __shfl_xor_sync(0xffffffffu, r1, 2);
        l0 = l0 * a0 + r0;
        l1 = l1 * a1 + r1;
        m0 = M0; m1 = M1;
        #pragma unroll
        for (int nt = 0; nt < 8; nt++) {
            ctx[nt][0] *= a0; ctx[nt][1] *= a0;
            ctx[nt][2] *= a1; ctx[nt][3] *= a1;
        }
        __syncwarp();

        #pragma unroll
        for (int ks = 0; ks < 8; ks++) {
            uint32_t af[4];
            ldsm4(af, pbase + (uint32_t)wq * 272 + ks * 32 + offP);
            #pragma unroll
            for (int nt = 0; nt < 8; nt += 2) {
                uint32_t bb[4];
                ldsm4t(bb, vB + (uint32_t)(ks * 16) * 144 + (uint32_t)(nt * 16) + offV);
                mma_f16(ctx[nt],     af, bb[0], bb[1]);
                mma_f16(ctx[nt + 1], af, bb[2], bb[3]);
            }
        }
    }

    float il0 = 1.f / l0, il1 = 1.f / l1;
    #pragma unroll
    for (int nt = 0; nt < 8; nt++) {
        long long row0 = (long long)b * SEQ + bm + wq + lr;
        int col = hh * DHD + nt * 8 + 2 * lc;
        *(__half2*)&outc[row0 * CATW + col] = __floats2half2_rn(ctx[nt][0] * il0, ctx[nt][1] * il0);
        *(__half2*)&outc[(row0 + 8) * CATW + col] = __floats2half2_rn(ctx[nt][2] * il1, ctx[nt][3] * il1);
    }
}

// ---- weight transpose + fp32->fp16 ----
__global__ void wt_k(const float* __restrict__ in, __half* __restrict__ out, int K, int N)
{
    __shared__ float tile[32][33];
    int bx = blockIdx.x * 32, by = blockIdx.y * 32;
    int tx = threadIdx.x, ty = threadIdx.y;
    #pragma unroll
    for (int j = ty; j < 32; j += 8)
        tile[j][tx] = in[(long long)(by + j) * N + bx + tx];
    __syncthreads();
    #pragma unroll
    for (int j = ty; j < 32; j += 8)
        out[(long long)(bx + j) * K + by + tx] = __float2half(tile[tx][j]);
}

// ---- fused: hh, hn_h, xh ----
__global__ void l2ln_k(const float* __restrict__ h,
                       const float* __restrict__ gma, const float* __restrict__ bta)
{
    int row = blockIdx.x, t = threadIdx.x;
    const float* xr = h + (long long)row * EMB;
    __shared__ float sh[EMB];
    __shared__ float r1[256], r2[256];
    float s = 0.f, ss = 0.f;
    for (int i = t; i < EMB; i += 256) { float v = xr[i]; sh[i] = v; s += v; ss += v * v; }
    r1[t] = s; r2[t] = ss; __syncthreads();
    for (int st = 128; st > 0; st >>= 1) {
        if (t < st) { r1[t] += r1[t + st]; r2[t] += r2[t + st]; }
        __syncthreads();
    }
    float mu   = r1[0] / EMB;
    float var  = r2[0] / EMB - mu * mu;
    float ri   = rsqrtf(var + 1e-6f);
    float invn = 1.f / (sqrtf(r2[0]) + 1e-8f);
    for (int i = t; i < EMB; i += 256) {
        float v = sh[i];
        g_hh [(long long)row * EMB + i] = __float2half(v);
        g_hnh[(long long)row * EMB + i] = __float2half(v * invn);
        g_xh [(long long)row * EMB + i] = __float2half((v - mu) * ri * gma[i] + bta[i]);
    }
}

// ---- single-pass layernorm -> fp16 (values held in registers) ----
template<int BLK, int NIT>
__global__ void lnh_k(const float* __restrict__ x, __half* __restrict__ oh,
                      const float* __restrict__ gma, const float* __restrict__ bta, int D)
{
    int row = blockIdx.x, t = threadIdx.x;
    const float* xr = x + (long long)row * D;
    __shared__ float r1[BLK], r2[BLK];
    float xv[NIT];
    float s = 0.f, ss = 0.f;
    #pragma unroll
    for (int i = 0; i < NIT; i++) {
        float v = xr[t + i * BLK];
        xv[i] = v; s += v; ss += v * v;
    }
    r1[t] = s; r2[t] = ss; __syncthreads();
    for (int st = BLK / 2; st > 0; st >>= 1) {
        if (t < st) { r1[t] += r1[t + st]; r2[t] += r2[t + st]; }
        __syncthreads();
    }
    float mu  = r1[0] / D;
    float var = r2[0] / D - mu * mu;
    float ri  = rsqrtf(var + 1e-6f);
    #pragma unroll
    for (int i = 0; i < NIT; i++) {
        int c = t + i * BLK;
        oh[(long long)row * D + c] = __float2half((xv[i] - mu) * ri * gma[c] + bta[c]);
    }
}

// ---- k-NN (u32 packed keys) + fused combine -> g_combh ----
__global__ void knn_k(int row0)
{
    int row = blockIdx.x + row0;
    int b = row >> 11, i = row & (SEQ - 1);
    const float* dr = g_dist + (long long)row * SEQ;
    int t = threadIdx.x, lane = t & 31, w = t >> 5;

    __shared__ uint32_t cand[128];
    __shared__ uint32_t fin[KNN];
    __shared__ float    swt[KNN];
    __shared__ int      sidx[KNN];

    uint32_t v[8];
    int base = w * 256;
    #pragma unroll
    for (int r = 0; r < 8; r++) {
        int j = base + r * 32 + lane;
        float d = (j == i) ? 1e9f : (1.f - dr[j]);
        v[r] = (__float_as_uint(d) & 0xFFFFF800u) | (unsigned)j;
    }

    #pragma unroll
    for (int it = 0; it < KNN; it++) {
        uint32_t m = v[0];
        #pragma unroll
        for (int r = 1; r < 8; r++) m = min(m, v[r]);
        #pragma unroll
        for (int s = 16; s > 0; s >>= 1)
            m = min(m, __shfl_xor_sync(0xffffffffu, m, s));
        if (lane == 0) cand[w * KNN + it] = m;
        #pragma unroll
        for (int r = 0; r < 8; r++) if (v[r] == m) v[r] = 0xFFFFFFFFu;
    }
    __syncthreads();

    if (w == 0) {
        uint32_t c[4];
        #pragma unroll
        for (int r = 0; r < 4; r++) c[r] = cand[r * 32 + lane];
        #pragma unroll
        for (int it = 0; it < KNN; it++) {
            uint32_t m01 = min(c[0], c[1]);
            uint32_t m23 = min(c[2], c[3]);
            uint32_t m = min(m01, m23);
            #pragma unroll
            for (int s = 16; s > 0; s >>= 1)
                m = min(m, __shfl_xor_sync(0xffffffffu, m, s));
            if (lane == 0) fin[it] = m;
            #pragma unroll
            for (int r = 0; r < 4; r++) if (c[r] == m) c[r] = 0xFFFFFFFFu;
        }
        __syncwarp();
        if (lane < KNN) {
            float d0 = __uint_as_float(fin[0] & 0xFFFFF800u);
            float dk = __uint_as_float(fin[lane] & 0xFFFFF800u);
            float wk = expf(d0 - dk);
            float sum = wk;
            #pragma unroll
            for (int s = 8; s > 0; s >>= 1)
                sum += __shfl_xor_sync(0x0000ffffu, sum, s);
            swt[lane]  = wk / sum;
            sidx[lane] = b * SEQ + (int)(fin[lane] & 0x7FFu);
        }
    }
    __syncthreads();

    if (t < TT) {
        float acc = g_topo[(long long)row * TT + t];
        #pragma unroll
        for (int k2 = 0; k2 < KNN; k2++)
            acc += swt[k2] * g_topo[(long long)sidx[k2] * TT + t];
        g_combh[(long long)row * TT + t] = __float2half(acc);
    }
}

// ============================================================================
extern "C" void kernel_launch(void* const* d_in, const int* in_sizes, int n_in,
                              void* d_out, int out_size)
{
    const float* h      = (const float*)d_in[0];
    const int*   mask   = (const int*)  d_in[1];
    const float* W_topo = (const float*)d_in[2];
    const float* b_topo = (const float*)d_in[3];
    const float* W_m1   = (const float*)d_in[4];
    const float* b_m1   = (const float*)d_in[5];
    const float* W_m2   = (const float*)d_in[6];
    const float* b_m2   = (const float*)d_in[7];
    const float* ln_t_s = (const float*)d_in[8];
    const float* ln_t_b = (const float*)d_in[9];
    const float* W_p1   = (const float*)d_in[10];
    const float* b_p1   = (const float*)d_in[11];
    const float* W_p2   = (const float*)d_in[12];
    const float* b_p2   = (const float*)d_in[13];
    const float* ln1_s  = (const float*)d_in[14];
    const float* ln1_b  = (const float*)d_in[15];
    const float* Wq     = (const float*)d_in[16];
    const float* Wk     = (const float*)d_in[17];
    const float* Wv     = (const float*)d_in[18];
    const float* W_gate = (const float*)d_in[19];
    const float* b_gate = (const float*)d_in[20];
    const float* W_o    = (const float*)d_in[21];
    const float* b_o    = (const float*)d_in[22];
    const float* ln2_s  = (const float*)d_in[23];
    const float* ln2_b  = (const float*)d_in[24];
    const float* W_f1   = (const float*)d_in[25];
    const float* b_f1   = (const float*)d_in[26];
    const float* W_f2   = (const float*)d_in[27];
    const float* b_f2   = (const float*)d_in[28];
    float* out = (float*)d_out;

    float *topo, *tt, *h1, *dist;
    __half *xh, *combh, *tmp256h, *tth, *qkvh, *cath, *ctxh, *yh, *ffh, *hh, *hnh;
    __half *wt_topo, *wt_m1, *wt_m2, *wt_p1, *wt_p2, *wt_qkv, *wt_gate, *wt_o, *wt_f1, *wt_f2;
    cudaGetSymbolAddress((void**)&topo,    g_topo);
    cudaGetSymbolAddress((void**)&tt,      g_tt);
    cudaGetSymbolAddress((void**)&h1,      g_h1);
    cudaGetSymbolAddress((void**)&dist,    g_dist);
    cudaGetSymbolAddress((void**)&hh,      g_hh);
    cudaGetSymbolAddress((void**)&hnh,     g_hnh);
    cudaGetSymbolAddress((void**)&xh,      g_xh);
    cudaGetSymbolAddress((void**)&combh,   g_combh);
    cudaGetSymbolAddress((void**)&tmp256h, g_tmp256h);
    cudaGetSymbolAddress((void**)&tth,     g_tth);
    cudaGetSymbolAddress((void**)&qkvh,    g_qkvh);
    cudaGetSymbolAddress((void**)&cath,    g_cath);
    cudaGetSymbolAddress((void**)&ctxh,    g_ctxh);
    cudaGetSymbolAddress((void**)&yh,      g_yh);
    cudaGetSymbolAddress((void**)&ffh,     g_ffh);
    cudaGetSymbolAddress((void**)&wt_topo, g_wt_topo);
    cudaGetSymbolAddress((void**)&wt_m1,   g_wt_m1);
    cudaGetSymbolAddress((void**)&wt_m2,   g_wt_m2);
    cudaGetSymbolAddress((void**)&wt_p1,   g_wt_p1);
    cudaGetSymbolAddress((void**)&wt_p2,   g_wt_p2);
    cudaGetSymbolAddress((void**)&wt_qkv,  g_wt_qkv);
    cudaGetSymbolAddress((void**)&wt_gate, g_wt_gate);
    cudaGetSymbolAddress((void**)&wt_o,    g_wt_o);
    cudaGetSymbolAddress((void**)&wt_f1,   g_wt_f1);
    cudaGetSymbolAddress((void**)&wt_f2,   g_wt_f2);

    const long long SE = (long long)SEQ * EMB;
    const long long SS = (long long)SEQ * SEQ;
    const int HM = BSX / 2;

    cudaFuncSetAttribute((const void*)flash_k, cudaFuncAttributeMaxDynamicSharedMemorySize, FS_TOT_BYTES);
    cudaFuncSetAttribute((const void*)hgemm<0, 0, 0, 0, 0>, cudaFuncAttributeMaxDynamicSharedMemorySize, HG_SMEM);
    cudaFuncSetAttribute((const void*)hgemm<0, 0, 0, 0, 1>, cudaFuncAttributeMaxDynamicSharedMemorySize, HG_SMEM);
    cudaFuncSetAttribute((const void*)hgemm<0, 1, 0, 0, 0>, cudaFuncAttributeMaxDynamicSharedMemorySize, HG_SMEM);
    cudaFuncSetAttribute((const void*)hgemm<1, 1, 0, 0, 0>, cudaFuncAttributeMaxDynamicSharedMemorySize, HG_SMEM);
    cudaFuncSetAttribute((const void*)hgemm<2, 1, 0, 0, 0>, cudaFuncAttributeMaxDynamicSharedMemorySize, HG_SMEM);
    cudaFuncSetAttribute((const void*)hgemm<3, 1, 1, 1, 0>, cudaFuncAttributeMaxDynamicSharedMemorySize, HG_SMEM);

    // ---- streams/events ----
    static cudaStream_t st1 = nullptr, st2 = nullptr, st3 = nullptr;
    static cudaEvent_t e_fork, e_ln, e_b1, e_w2, e_qw, e_topo, e_fl1, e_t1, e_kA, e_d0;
    if (!st1) {
        cudaStreamCreateWithFlags(&st1, cudaStreamNonBlocking);
        cudaStreamCreateWithFlags(&st2, cudaStreamNonBlocking);
        cudaStreamCreateWithFlags(&st3, cudaStreamNonBlocking);
        cudaEventCreateWithFlags(&e_fork, cudaEventDisableTiming);
        cudaEventCreateWithFlags(&e_ln,   cudaEventDisableTiming);
        cudaEventCreateWithFlags(&e_b1,   cudaEventDisableTiming);
        cudaEventCreateWithFlags(&e_w2,   cudaEventDisableTiming);
        cudaEventCreateWithFlags(&e_qw,   cudaEventDisableTiming);
        cudaEventCreateWithFlags(&e_topo, cudaEventDisableTiming);
        cudaEventCreateWithFlags(&e_fl1,  cudaEventDisableTiming);
        cudaEventCreateWithFlags(&e_t1,   cudaEventDisableTiming);
        cudaEventCreateWithFlags(&e_kA,   cudaEventDisableTiming);
        cudaEventCreateWithFlags(&e_d0,   cudaEventDisableTiming);
    }

    dim3 tb(32, 8);

    // ---- fork ----
    cudaEventRecord(e_fork, 0);
    cudaStreamWaitEvent(st1, e_fork, 0);
    cudaStreamWaitEvent(st2, e_fork, 0);
    cudaStreamWaitEvent(st3, e_fork, 0);

    // ---- s0: fused convert + l2norm + LN1 ----
    l2ln_k<<<BSX, 256>>>(h, ln1_s, ln1_b);
    cudaEventRecord(e_ln, 0);

    // ---- st2: qkv transposes, then batch-1 attention chain ----
    wt_k<<<dim3(EMB / 32, EMB / 32), tb, 0, st2>>>(Wq, wt_qkv, EMB, EMB);
    wt_k<<<dim3(EMB / 32, EMB / 32), tb, 0, st2>>>(Wk, wt_qkv + (long long)EMB * EMB, EMB, EMB);
    wt_k<<<dim3(EMB / 32, EMB / 32), tb, 0, st2>>>(Wv, wt_qkv + 2LL * EMB * EMB, EMB, EMB);
    cudaEventRecord(e_qw, st2);
    cudaStreamWaitEvent(st2, e_ln, 0);
    hgemm<0, 1, 0, 0, 0><<<dim3(QKVW / 128, HM / 128, 1), 256, HG_SMEM, st2>>>(
        xh + (long long)HM * EMB, wt_qkv, qkvh + (long long)HM * QKVW, nullptr, nullptr, nullptr,
        EMB, EMB, EMB, QKVW, 0, 0, 1, 0, 0, 0, 0, 0, 0);
    flash_k<<<dim3(16, NH), 256, FS_TOT_BYTES, st2>>>(qkvh, mask, cath, NH);
    cudaEventRecord(e_fl1, st2);

    // ---- st3: tail transposes + topo proj + knn(b0) ----
    wt_k<<<dim3(EMB / 32, CATW / 32), tb, 0, st3>>>(W_gate, wt_gate, CATW, EMB);
    wt_k<<<dim3(EMB / 32, EMB / 32),  tb, 0, st3>>>(W_o, wt_o, EMB, EMB);
    wt_k<<<dim3(FF / 32, EMB / 32),   tb, 0, st3>>>(W_f1, wt_f1, EMB, FF);
    wt_k<<<dim3(EMB / 32, FF / 32),   tb, 0, st3>>>(W_f2, wt_f2, FF, EMB);
    cudaEventRecord(e_w2, st3);
    wt_k<<<dim3(TT / 32, EMB / 32), tb, 0, st3>>>(W_topo, wt_topo, EMB, TT);
    cudaStreamWaitEvent(st3, e_ln, 0);
    hgemm<0, 0, 0, 0, 0><<<dim3(1, 32, 1), 256, HG_SMEM, st3>>>(hh, wt_topo, topo, b_topo, nullptr, nullptr,
        EMB, EMB, EMB, TT, 0, 0, 1, 0, 0, 0, 0, 0, 0);
    cudaEventRecord(e_topo, st3);

    // ---- st1: topo-MLP transposes, then symmetric dist per batch ----
    wt_k<<<dim3(256 / 32, TT / 32), tb, 0, st1>>>(W_m1, wt_m1, TT, 256);
    wt_k<<<dim3(TT / 32, 256 / 32), tb, 0, st1>>>(W_m2, wt_m2, 256, TT);
    wt_k<<<dim3(TT / 32, TT / 32),  tb, 0, st1>>>(W_p1, wt_p1, TT, TT);
    wt_k<<<dim3(TT / 32, TT / 32),  tb, 0, st1>>>(W_p2, wt_p2, TT, TT);
    cudaStreamWaitEvent(st1, e_ln, 0);
    // dist b0 (symmetric): upper-triangle tiles + mirror store
    hgemm<0, 0, 0, 0, 1><<<dim3(16, 16, 1), 256, HG_SMEM, st1>>>(
        hnh, hnh, dist, nullptr, nullptr, nullptr,
        EMB, EMB, EMB, SEQ, 0, 0, 1, 0, 0, 0, 0, 0, 0);
    cudaEventRecord(e_d0, st1);
    // dist b1 (symmetric)
    hgemm<0, 0, 0, 0, 1><<<dim3(16, 16, 1), 256, HG_SMEM, st1>>>(
        hnh + SE, hnh + SE, dist + SS, nullptr, nullptr, nullptr,
        EMB, EMB, EMB, SEQ, 0, 0, 1, 0, 0, 0, 0, 0, 0);
    // knn(b0) on st3 overlaps dist(b1) on st1
    cudaStreamWaitEvent(st3, e_topo, 0);
    cudaStreamWaitEvent(st3, e_d0, 0);
    knn_k<<<SEQ, 256, 0, st3>>>(0);
    cudaEventRecord(e_kA, st3);
    // knn(b1) on st1 (after dist b1; needs topo)
    cudaStreamWaitEvent(st1, e_topo, 0);
    knn_k<<<SEQ, 256, 0, st1>>>(SEQ);
    cudaStreamWaitEvent(st1, e_kA, 0);

    // ---- st1: topo MLP chain ----
    hgemm<1, 1, 0, 0, 0><<<dim3(2, 32, 1), 256, HG_SMEM, st1>>>(combh, wt_m1, tmp256h, b_m1, nullptr, nullptr,
        TT, TT, TT, 256, 0, 0, 1, 0, 0, 0, 0, 0, 0);
    hgemm<0, 0, 0, 0, 0><<<dim3(1, 32, 1), 256, HG_SMEM, st1>>>(tmp256h, wt_m2, tt, b_m2, nullptr, nullptr,
        256, 256, 256, TT, 0, 0, 1, 0, 0, 0, 0, 0, 0);
    lnh_k<128, 1><<<BSX, 128, 0, st1>>>(tt, tth, ln_t_s, ln_t_b, TT);
    hgemm<1, 1, 0, 0, 0><<<dim3(1, 32, 1), 256, HG_SMEM, st1>>>(tth, wt_p1, tmp256h, b_p1, nullptr, nullptr,
        TT, TT, TT, TT, 0, 0, 1, 0, 0, 0, 0, 0, 0);
    hgemm<0, 1, 0, 0, 0><<<dim3(1, 32, 1), 256, HG_SMEM, st1>>>(tmp256h, wt_p2, cath + EMB, b_p2, nullptr, nullptr,
        TT, TT, TT, CATW, 0, 0, 1, 0, 0, 0, 0, 0, 0);
    cudaEventRecord(e_b1, st1);

    // ---- s0: batch-0 attention chain ----
    cudaStreamWaitEvent(0, e_qw, 0);
    hgemm<0, 1, 0, 0, 0><<<dim3(QKVW / 128, HM / 128, 1), 256, HG_SMEM>>>(xh, wt_qkv, qkvh, nullptr, nullptr, nullptr,
        EMB, EMB, EMB, QKVW, 0, 0, 1, 0, 0, 0, 0, 0, 0);
    flash_k<<<dim3(16, NH), 256, FS_TOT_BYTES>>>(qkvh, mask, cath, 0);

    // ---- tail half 0 on s0 ----
    cudaStreamWaitEvent(0, e_b1, 0);
    cudaStreamWaitEvent(0, e_w2, 0);
    hgemm<3, 1, 1, 1, 0><<<dim3(6, HM / 128, 1), 256, HG_SMEM>>>(cath, wt_gate, ctxh, b_gate, cath, xh,
        CATW, CATW, CATW, EMB, CATW, EMB, 1, 0, 0, 0, 0, 0, 0);
    hgemm<0, 0, 0, 0, 0><<<dim3(6, HM / 128, 1), 256, HG_SMEM>>>(ctxh, wt_o, h1, b_o, h, nullptr,
        EMB, EMB, EMB, EMB, EMB, 0, 1, 0, 0, 0, 0, 0, 0);
    lnh_k<256, 3><<<HM, 256>>>(h1, yh, ln2_s, ln2_b, EMB);
    hgemm<2, 1, 0, 0, 0><<<dim3(24, HM / 128, 1), 256, HG_SMEM>>>(yh, wt_f1, ffh, b_f1, nullptr, nullptr,
        EMB, EMB, EMB, FF, 0, 0, 1, 0, 0, 0, 0, 0, 0);
    hgemm<0, 0, 0, 0, 0><<<dim3(6, HM / 128, 1), 256, HG_SMEM>>>(ffh, wt_f2, out, b_f2, h1, nullptr,
        FF, FF, FF, EMB, EMB, 0, 1, 0, 0, 0, 0, 0, 0);

    // ---- tail half 1 on st1 ----
    cudaStreamWaitEvent(st1, e_fl1, 0);
    cudaStreamWaitEvent(st1, e_w2, 0);
    {
        const long long rO = (long long)HM;
        hgemm<3, 1, 1, 1, 0><<<dim3(6, HM / 128, 1), 256, HG_SMEM, st1>>>(
            cath + rO * CATW, wt_gate, ctxh + rO * EMB, b_gate,
            cath + rO * CATW, xh + rO * EMB,
            CATW, CATW, CATW, EMB, CATW, EMB, 1, 0, 0, 0, 0, 0, 0);
        hgemm<0, 0, 0, 0, 0><<<dim3(6, HM / 128, 1), 256, HG_SMEM, st1>>>(
            ctxh + rO * EMB, wt_o, h1 + rO * EMB, b_o, h + rO * EMB, nullptr,
            EMB, EMB, EMB, EMB, EMB, 0, 1, 0, 0, 0, 0, 0, 0);
        lnh_k<256, 3><<<HM, 256, 0, st1>>>(h1 + rO * EMB, yh + rO * EMB, ln2_s, ln2_b, EMB);
        hgemm<2, 1, 0, 0, 0><<<dim3(24, HM / 128, 1), 256, HG_SMEM, st1>>>(
            yh + rO * EMB, wt_f1, ffh + rO * FF, b_f1, nullptr, nullptr,
            EMB, EMB, EMB, FF, 0, 0, 1, 0, 0, 0, 0, 0, 0);
        hgemm<0, 0, 0, 0, 0><<<dim3(6, HM / 128, 1), 256, HG_SMEM, st1>>>(
            ffh + rO * FF, wt_f2, out + rO * EMB, b_f2, h1 + rO * EMB, nullptr,
            FF, FF, FF, EMB, EMB, 0, 1, 0, 0, 0, 0, 0, 0);
        cudaEventRecord(e_t1, st1);
    }
    cudaStreamWaitEvent(0, e_t1, 0);
}